// round 6
// baseline (speedup 1.0000x reference)
#include <cuda_runtime.h>
#include <math.h>
#include <stdint.h>

// ---------------- problem constants ----------------
#define NN   50000
#define PP   3
#define EE   800000
#define FEATD 1000
#define HH   256
#define PHH  512
#define BN_EPS 1e-5f

// ---------------- device scratch (no allocations allowed) ----------------
__device__ uint32_t g_fe_hi[(size_t)NN * (FEATD / 2)];
__device__ uint32_t g_fe_lo[(size_t)NN * (FEATD / 2)];
__device__ uint32_t g_h_hi [(size_t)NN * (HH / 2)];
__device__ uint32_t g_h_lo [(size_t)NN * (HH / 2)];
__device__ float    g_ft[(size_t)NN * (3 * HH)];
__device__ float    g_z0[(size_t)NN * HH];
__device__ float    g_z1[(size_t)NN * HH];
__device__ float    g_z2[(size_t)NN * HH];
__device__ uint32_t g_z0_hi[(size_t)NN * (HH / 2)];
__device__ uint32_t g_z0_lo[(size_t)NN * (HH / 2)];
__device__ uint32_t g_z1_hi[(size_t)NN * (HH / 2)];
__device__ uint32_t g_z1_lo[(size_t)NN * (HH / 2)];
__device__ uint32_t g_z2_hi[(size_t)NN * (HH / 2)];
__device__ uint32_t g_z2_lo[(size_t)NN * (HH / 2)];
__device__ float    g_x [(size_t)NN * PHH];
__device__ uint32_t g_x_hi[(size_t)NN * (PHH / 2)];
__device__ uint32_t g_x_lo[(size_t)NN * (PHH / 2)];
__device__ float    g_vp[(size_t)NN * HH];
// split weights
__device__ uint32_t g_wt_hi[HH * (FEATD / 2)];
__device__ uint32_t g_wt_lo[HH * (FEATD / 2)];
__device__ uint32_t g_wg_hi[3 * HH * (HH / 2)];
__device__ uint32_t g_wg_lo[3 * HH * (HH / 2)];
__device__ uint32_t g_w1_hi[PHH * (HH / 2)];
__device__ uint32_t g_w1_lo[PHH * (HH / 2)];
__device__ uint32_t g_w2_hi[HH * (PHH / 2)];
__device__ uint32_t g_w2_lo[HH * (PHH / 2)];
__device__ uint32_t g_wa_hi[HH * (HH / 2)];
__device__ uint32_t g_wa_lo[HH * (HH / 2)];
__device__ float g_stats[2 * PHH];
__device__ float g_beta_raw[3];
__device__ float g_beta[3];
__device__ float g_loss_acc;

// ---------------- bf16 split helpers --------------------------------------------
__device__ __forceinline__ uint32_t pack_hi(float x0, float x1)
{
    uint32_t r;
    asm("prmt.b32 %0, %1, %2, 0x7632;"
        : "=r"(r) : "r"(__float_as_uint(x0)), "r"(__float_as_uint(x1)));
    return r;
}

__device__ __forceinline__ uint32_t pack_lo(float x0, float x1)
{
    float h0 = __uint_as_float(__float_as_uint(x0) & 0xFFFF0000u);
    float h1 = __uint_as_float(__float_as_uint(x1) & 0xFFFF0000u);
    uint32_t r;
    asm("cvt.rn.bf16x2.f32 %0, %1, %2;" : "=r"(r) : "f"(x1 - h1), "f"(x0 - h0));
    return r;
}

__device__ __forceinline__ void mma_bf16(float* c, const uint32_t* a, const uint32_t* b)
{
    asm volatile(
        "mma.sync.aligned.m16n8k16.row.col.f32.bf16.bf16.f32 "
        "{%0,%1,%2,%3}, {%4,%5,%6,%7}, {%8,%9}, {%0,%1,%2,%3};\n"
        : "+f"(c[0]), "+f"(c[1]), "+f"(c[2]), "+f"(c[3])
        : "r"(a[0]), "r"(a[1]), "r"(a[2]), "r"(a[3]), "r"(b[0]), "r"(b[1]));
}

__device__ __forceinline__ void cp16(uint32_t saddr, const void* gmem, bool pred)
{
    int sz = pred ? 16 : 0;
    asm volatile("cp.async.cg.shared.global [%0], [%1], 16, %2;\n"
                 :: "r"(saddr), "l"(gmem), "r"(sz));
}

// ---------------- generic f32 -> split-bf16 pass --------------------------------
__global__ __launch_bounds__(256)
void split_kernel(const float2* __restrict__ in, uint32_t* __restrict__ hi,
                  uint32_t* __restrict__ lo, size_t npairs)
{
    size_t i = (size_t)blockIdx.x * blockDim.x + threadIdx.x;
    if (i >= npairs) return;
    float2 v = in[i];
    hi[i] = pack_hi(v.x, v.y);
    lo[i] = pack_lo(v.x, v.y);
}

// ---------------- split-bf16 GEMM ------------------------------------------------
// Block tile 128x64, BK=16 (8 bf16x2 pairs), 4 warps (2m x 2n), warp tile 64x32.
// 3 MMAs per atom: lo*hi + hi*lo + hi*hi (lo*lo dropped, ~2^-17 rel).
#define TBM 128
#define TBN 64
#define TPAD 12

#define GS_DECL()                                                                   \
    __shared__ uint32_t AsH[2][TBM][TPAD];                                          \
    __shared__ uint32_t AsL[2][TBM][TPAD];                                          \
    __shared__ uint32_t WsH[2][TBN][TPAD];                                          \
    __shared__ uint32_t WsL[2][TBN][TPAD];                                          \
    const int tid  = threadIdx.x;                                                   \
    const int wid  = tid >> 5;                                                      \
    const int lane = tid & 31;                                                      \
    const int g    = lane >> 2;                                                     \
    const int t    = lane & 3;                                                      \
    const int wm   = (wid & 1) << 6;                                                \
    const int wn   = (wid >> 1) << 5;                                               \
    const int bm   = blockIdx.y * TBM;                                              \
    const int bn   = blockIdx.x * TBN;                                              \
    float acc[4][4][4] = {};

#define GS_LOAD(S, KP0)                                                             \
    {                                                                               \
        _Pragma("unroll")                                                           \
        for (int q = 0; q < 2; ++q) {                                               \
            int idx = tid + (q << 7);                                               \
            int r = idx >> 1, ch = (idx & 1) << 2;                                  \
            int gp = (KP0) + ch;                                                    \
            bool pa = (gp < Kp) && (bm + r < M);                                    \
            size_t off = (size_t)(bm + r) * Kp + gp;                                \
            cp16((uint32_t)__cvta_generic_to_shared(&AsH[S][r][ch]), Ahi + off, pa);\
            cp16((uint32_t)__cvta_generic_to_shared(&AsL[S][r][ch]), Alo + off, pa);\
        }                                                                           \
        {                                                                           \
            int r = tid >> 1, ch = (tid & 1) << 2;                                  \
            int gp = (KP0) + ch;                                                    \
            bool pb = (gp < Kp);                                                    \
            size_t off = (size_t)(bn + r) * Kp + gp;                                \
            cp16((uint32_t)__cvta_generic_to_shared(&WsH[S][r][ch]), Whi + off, pb);\
            cp16((uint32_t)__cvta_generic_to_shared(&WsL[S][r][ch]), Wlo + off, pb);\
        }                                                                           \
    }

#define GS_MAINLOOP()                                                               \
    GS_DECL();                                                                      \
    GS_LOAD(0, 0);                                                                  \
    asm volatile("cp.async.commit_group;\n" ::: "memory");                          \
    int buf = 0;                                                                    \
    for (int kp0 = 0; kp0 < Kp; kp0 += 8) {                                         \
        if (kp0 + 8 < Kp) GS_LOAD(buf ^ 1, kp0 + 8);                                \
        asm volatile("cp.async.commit_group;\n" ::: "memory");                      \
        asm volatile("cp.async.wait_group 1;\n" ::: "memory");                      \
        __syncthreads();                                                            \
        uint32_t aH[4][4], aL[4][4], bH[4][2], bL[4][2];                            \
        _Pragma("unroll")                                                           \
        for (int i = 0; i < 4; ++i) {                                               \
            int rb = wm + (i << 4);                                                 \
            aH[i][0] = AsH[buf][rb + g    ][t    ];                                 \
            aH[i][1] = AsH[buf][rb + g + 8][t    ];                                 \
            aH[i][2] = AsH[buf][rb + g    ][t + 4];                                 \
            aH[i][3] = AsH[buf][rb + g + 8][t + 4];                                 \
            aL[i][0] = AsL[buf][rb + g    ][t    ];                                 \
            aL[i][1] = AsL[buf][rb + g + 8][t    ];                                 \
            aL[i][2] = AsL[buf][rb + g    ][t + 4];                                 \
            aL[i][3] = AsL[buf][rb + g + 8][t + 4];                                 \
        }                                                                           \
        _Pragma("unroll")                                                           \
        for (int j = 0; j < 4; ++j) {                                               \
            int nb = wn + (j << 3);                                                 \
            bH[j][0] = WsH[buf][nb + g][t    ];                                     \
            bH[j][1] = WsH[buf][nb + g][t + 4];                                     \
            bL[j][0] = WsL[buf][nb + g][t    ];                                     \
            bL[j][1] = WsL[buf][nb + g][t + 4];                                     \
        }                                                                           \
        _Pragma("unroll")                                                           \
        for (int i = 0; i < 4; ++i)                                                 \
            _Pragma("unroll")                                                       \
            for (int j = 0; j < 4; ++j) {                                           \
                mma_bf16(acc[i][j], aL[i], bH[j]);                                  \
                mma_bf16(acc[i][j], aH[i], bL[j]);                                  \
                mma_bf16(acc[i][j], aH[i], bH[j]);                                  \
            }                                                                       \
        __syncthreads();                                                            \
        buf ^= 1;                                                                   \
    }

// EPI: 0 = raw f32, 1 = bias+ELU -> split bf16 output (Chi/Clo), 2 = bias f32
template<int EPI>
__global__ __launch_bounds__(128, 3)
void gemm_bf16s_kernel(const uint32_t* __restrict__ Ahi, const uint32_t* __restrict__ Alo,
                       const uint32_t* __restrict__ Whi, const uint32_t* __restrict__ Wlo,
                       const float* __restrict__ bias, float* __restrict__ C,
                       uint32_t* __restrict__ Chi, uint32_t* __restrict__ Clo,
                       int M, int Nc, int Kp)
{
    GS_MAINLOOP();

#pragma unroll
    for (int i = 0; i < 4; ++i) {
#pragma unroll
        for (int j = 0; j < 4; ++j) {
            int r0 = bm + wm + (i << 4) + g;
            int r1 = r0 + 8;
            int c0 = bn + wn + (j << 3) + (t << 1);
            float bx = 0.f, by = 0.f;
            if (EPI >= 1) { bx = bias[c0]; by = bias[c0 + 1]; }
            float v0 = acc[i][j][0], v1 = acc[i][j][1];
            float v2 = acc[i][j][2], v3 = acc[i][j][3];
            if (EPI >= 1) { v0 += bx; v1 += by; v2 += bx; v3 += by; }
            if (EPI == 1) {
                v0 = v0 > 0.f ? v0 : expm1f(v0);
                v1 = v1 > 0.f ? v1 : expm1f(v1);
                v2 = v2 > 0.f ? v2 : expm1f(v2);
                v3 = v3 > 0.f ? v3 : expm1f(v3);
                int pc = c0 >> 1;
                if (r0 < M) {
                    Chi[(size_t)r0 * (Nc / 2) + pc] = pack_hi(v0, v1);
                    Clo[(size_t)r0 * (Nc / 2) + pc] = pack_lo(v0, v1);
                }
                if (r1 < M) {
                    Chi[(size_t)r1 * (Nc / 2) + pc] = pack_hi(v2, v3);
                    Clo[(size_t)r1 * (Nc / 2) + pc] = pack_lo(v2, v3);
                }
            } else {
                if (r0 < M) *(float2*)(C + (size_t)r0 * Nc + c0) = make_float2(v0, v1);
                if (r1 < M) *(float2*)(C + (size_t)r1 * Nc + c0) = make_float2(v2, v3);
            }
        }
    }
}

// fused attention GEMM: beta += sum over tile of tanh(z@W^T + b) * att
__global__ __launch_bounds__(128, 3)
void gemm_att_bf16s_kernel(const uint32_t* __restrict__ Ahi, const uint32_t* __restrict__ Alo,
                           const uint32_t* __restrict__ Whi, const uint32_t* __restrict__ Wlo,
                           const float* __restrict__ bias, const float* __restrict__ att,
                           float* __restrict__ beta_out, int M, int Kp)
{
    GS_MAINLOOP();

    float s = 0.f;
#pragma unroll
    for (int i = 0; i < 4; ++i) {
#pragma unroll
        for (int j = 0; j < 4; ++j) {
            int r0 = bm + wm + (i << 4) + g;
            int r1 = r0 + 8;
            int c0 = bn + wn + (j << 3) + (t << 1);
            float bx = bias[c0], by = bias[c0 + 1];
            float ax = att[c0],  ay = att[c0 + 1];
            if (r0 < M) s += tanhf(acc[i][j][0] + bx) * ax + tanhf(acc[i][j][1] + by) * ay;
            if (r1 < M) s += tanhf(acc[i][j][2] + bx) * ax + tanhf(acc[i][j][3] + by) * ay;
        }
    }
    __shared__ float red[128];
    red[tid] = s;
    __syncthreads();
    for (int o = 64; o > 0; o >>= 1) {
        if (tid < o) red[tid] += red[tid + o];
        __syncthreads();
    }
    if (tid == 0) atomicAdd(beta_out, red[0]);
}

// ---------------- SpMM scatter: z[dst] += val * ft[src]  (vector RED) ----------
__global__ __launch_bounds__(256)
void spmm_kernel(const float4* __restrict__ ft, int stride4,
                 const int* __restrict__ src, const int* __restrict__ dst,
                 const float* __restrict__ vals, float4* __restrict__ z)
{
    int gid = blockIdx.x * blockDim.x + threadIdx.x;
    if (gid >= EE * 64) return;
    int e = gid >> 6;
    int c = gid & 63;
    int s = src[e];
    int d = dst[e];
    float v = vals[e];
    float4 f = ft[(size_t)s * stride4 + c];
    float4* p = &z[(size_t)d * 64 + c];
    asm volatile("red.global.add.v4.f32 [%0], {%1,%2,%3,%4};"
                 :: "l"(p), "f"(v * f.x), "f"(v * f.y), "f"(v * f.z), "f"(v * f.w)
                 : "memory");
}

// ---------------- z = prelu(z + b, a); also emit split-bf16 ---------------------
__global__ __launch_bounds__(256)
void bias_prelu_kernel(float4* __restrict__ z, uint32_t* __restrict__ zhi,
                       uint32_t* __restrict__ zlo, const float* __restrict__ b,
                       const float* __restrict__ a_ptr)
{
    int i = blockIdx.x * blockDim.x + threadIdx.x;
    if (i >= NN * 64) return;
    float a = *a_ptr;
    float4 bv = *(const float4*)(b + ((i & 63) << 2));
    float4 x = z[i];
    x.x += bv.x; x.y += bv.y; x.z += bv.z; x.w += bv.w;
    x.x = x.x >= 0.f ? x.x : a * x.x;
    x.y = x.y >= 0.f ? x.y : a * x.y;
    x.z = x.z >= 0.f ? x.z : a * x.z;
    x.w = x.w >= 0.f ? x.w : a * x.w;
    z[i] = x;
    size_t p = (size_t)i << 1;
    zhi[p]     = pack_hi(x.x, x.y);
    zhi[p + 1] = pack_hi(x.z, x.w);
    zlo[p]     = pack_lo(x.x, x.y);
    zlo[p + 1] = pack_lo(x.z, x.w);
}

// ---------------- BN column stats -----------------------------------------------
__global__ __launch_bounds__(256)
void colstats_kernel(const float* __restrict__ x, float* __restrict__ stats)
{
    int c = blockIdx.x * 256 + threadIdx.x;
    float s = 0.f, sq = 0.f;
    for (int r = blockIdx.y; r < NN; r += gridDim.y) {
        float v = x[(size_t)r * PHH + c];
        s += v;
        sq += v * v;
    }
    atomicAdd(&stats[c], s);
    atomicAdd(&stats[PHH + c], sq);
}

// ---------------- BN + PReLU -> split-bf16 output -------------------------------
__global__ __launch_bounds__(256)
void bn_prelu_kernel(const float4* __restrict__ x, uint32_t* __restrict__ xhi,
                     uint32_t* __restrict__ xlo, const float* __restrict__ stats,
                     const float* __restrict__ g, const float* __restrict__ b,
                     const float* __restrict__ a_ptr)
{
    int i = blockIdx.x * blockDim.x + threadIdx.x;
    if (i >= NN * (PHH / 4)) return;
    int c = (i & (PHH / 4 - 1)) << 2;
    float a = *a_ptr;
    float4 sm = *(const float4*)(stats + c);
    float4 sq = *(const float4*)(stats + PHH + c);
    float4 gv = *(const float4*)(g + c);
    float4 bv = *(const float4*)(b + c);
    float4 v = x[i];
    float invN = 1.f / (float)NN;

    float mu, var, sc, sh, y;
    mu = sm.x * invN; var = sq.x * invN - mu * mu; sc = gv.x * rsqrtf(var + BN_EPS);
    sh = bv.x - mu * sc; y = v.x * sc + sh; v.x = y >= 0.f ? y : a * y;
    mu = sm.y * invN; var = sq.y * invN - mu * mu; sc = gv.y * rsqrtf(var + BN_EPS);
    sh = bv.y - mu * sc; y = v.y * sc + sh; v.y = y >= 0.f ? y : a * y;
    mu = sm.z * invN; var = sq.z * invN - mu * mu; sc = gv.z * rsqrtf(var + BN_EPS);
    sh = bv.z - mu * sc; y = v.z * sc + sh; v.z = y >= 0.f ? y : a * y;
    mu = sm.w * invN; var = sq.w * invN - mu * mu; sc = gv.w * rsqrtf(var + BN_EPS);
    sh = bv.w - mu * sc; y = v.w * sc + sh; v.w = y >= 0.f ? y : a * y;

    size_t p = (size_t)i << 1;
    xhi[p]     = pack_hi(v.x, v.y);
    xhi[p + 1] = pack_hi(v.z, v.w);
    xlo[p]     = pack_lo(v.x, v.y);
    xlo[p + 1] = pack_lo(v.z, v.w);
}

// ---------------- cosine loss accumulation (one warp per node) ------------------
__global__ __launch_bounds__(256)
void loss_kernel(const float4* __restrict__ p, const float4* __restrict__ t1,
                 const float4* __restrict__ t2, float* __restrict__ acc)
{
    int gid  = blockIdx.x * blockDim.x + threadIdx.x;
    int node = gid >> 5;
    int lane = gid & 31;
    float pp = 0.f, n1 = 0.f, n2 = 0.f, d1 = 0.f, d2 = 0.f;
    if (node < NN) {
        size_t base = (size_t)node * 64;
#pragma unroll
        for (int r = 0; r < 2; ++r) {
            float4 a  = p [base + lane + 32 * r];
            float4 b  = t1[base + lane + 32 * r];
            float4 cc = t2[base + lane + 32 * r];
            pp += a.x * a.x + a.y * a.y + a.z * a.z + a.w * a.w;
            n1 += b.x * b.x + b.y * b.y + b.z * b.z + b.w * b.w;
            n2 += cc.x * cc.x + cc.y * cc.y + cc.z * cc.z + cc.w * cc.w;
            d1 += a.x * b.x + a.y * b.y + a.z * b.z + a.w * b.w;
            d2 += a.x * cc.x + a.y * cc.y + a.z * cc.z + a.w * cc.w;
        }
    }
#pragma unroll
    for (int o = 16; o > 0; o >>= 1) {
        pp += __shfl_down_sync(0xffffffffu, pp, o);
        n1 += __shfl_down_sync(0xffffffffu, n1, o);
        n2 += __shfl_down_sync(0xffffffffu, n2, o);
        d1 += __shfl_down_sync(0xffffffffu, d1, o);
        d2 += __shfl_down_sync(0xffffffffu, d2, o);
    }
    __shared__ float sacc[8];
    float contrib = 0.f;
    if (lane == 0 && node < NN) {
        float np  = fmaxf(sqrtf(pp), 1e-12f);
        float nn1 = fmaxf(sqrtf(n1), 1e-12f);
        float nn2 = fmaxf(sqrtf(n2), 1e-12f);
        contrib = d1 / (np * nn1) + d2 / (np * nn2);
    }
    int wid = threadIdx.x >> 5;
    if (lane == 0) sacc[wid] = contrib;
    __syncthreads();
    if (threadIdx.x == 0) {
        float s = 0.f;
#pragma unroll
        for (int i = 0; i < 8; ++i) s += sacc[i];
        atomicAdd(acc, s);
    }
}

// ---------------- finalize: softmax(beta), loss --------------------------------
__global__ void finalize_kernel(float* __restrict__ out_loss, int write_loss)
{
    float invN = 1.f / (float)NN;
    float b0 = g_beta_raw[0] * invN;
    float b1 = g_beta_raw[1] * invN;
    float b2 = g_beta_raw[2] * invN;
    float m = fmaxf(b0, fmaxf(b1, b2));
    float e0 = expf(b0 - m), e1 = expf(b1 - m), e2 = expf(b2 - m);
    float s = e0 + e1 + e2;
    g_beta[0] = e0 / s;
    g_beta[1] = e1 / s;
    g_beta[2] = e2 / s;
    if (write_loss) *out_loss = 2.0f - g_loss_acc * invN;
}

// ---------------- z_out = b0*z1 + b1*z2 + b2*z0 ---------------------------------
__global__ __launch_bounds__(256)
void zout_kernel(float4* __restrict__ out, const float4* __restrict__ z1,
                 const float4* __restrict__ z2, const float4* __restrict__ z0)
{
    int i = blockIdx.x * blockDim.x + threadIdx.x;
    if (i >= NN * 64) return;
    float b0 = g_beta[0], b1 = g_beta[1], b2 = g_beta[2];
    float4 a = z1[i], b = z2[i], c = z0[i];
    float4 r;
    r.x = b0 * a.x + b1 * b.x + b2 * c.x;
    r.y = b0 * a.y + b1 * b.y + b2 * c.y;
    r.z = b0 * a.z + b1 * b.z + b2 * c.z;
    r.w = b0 * a.w + b1 * b.w + b2 * c.w;
    out[i] = r;
}

// ---------------- host ----------------------------------------------------------
#define GETSYM(var, sym) cudaGetSymbolAddress((void**)&var, sym)

extern "C" void kernel_launch(void* const* d_in, const int* in_sizes, int n_in,
                              void* d_out, int out_size)
{
    const float* feats   = (const float*)d_in[0];
    const int*   src     = (const int*)  d_in[1];
    const int*   dst     = (const int*)  d_in[2];
    const float* vals    = (const float*)d_in[3];
    const float* W_trans = (const float*)d_in[4];
    const float* b_trans = (const float*)d_in[5];
    const float* W_gcn   = (const float*)d_in[6];
    const float* b_gcn   = (const float*)d_in[7];
    const float* a_gcn   = (const float*)d_in[8];
    const float* W1      = (const float*)d_in[9];
    const float* b1      = (const float*)d_in[10];
    const float* bn_g    = (const float*)d_in[11];
    const float* bn_b    = (const float*)d_in[12];
    const float* a_pred  = (const float*)d_in[13];
    const float* W2      = (const float*)d_in[14];
    const float* b2      = (const float*)d_in[15];
    const float* W_att   = (const float*)d_in[16];
    const float* b_att   = (const float*)d_in[17];
    const float* att     = (const float*)d_in[18];

    uint32_t *fe_hi, *fe_lo, *h_hi, *h_lo, *z0h, *z0l, *z1h, *z1l, *z2h, *z2l;
    uint32_t *x_hi, *x_lo, *wt_hi, *wt_lo, *wg_hi, *wg_lo, *w1_hi, *w1_lo;
    uint32_t *w2_hi, *w2_lo, *wa_hi, *wa_lo;
    float *ft, *z0, *z1, *z2, *x, *vp, *stats, *beta_raw, *loss_acc;
    GETSYM(fe_hi, g_fe_hi); GETSYM(fe_lo, g_fe_lo);
    GETSYM(h_hi, g_h_hi);   GETSYM(h_lo, g_h_lo);
    GETSYM(z0h, g_z0_hi); GETSYM(z0l, g_z0_lo);
    GETSYM(z1h, g_z1_hi); GETSYM(z1l, g_z1_lo);
    GETSYM(z2h, g_z2_hi); GETSYM(z2l, g_z2_lo);
    GETSYM(x_hi, g_x_hi); GETSYM(x_lo, g_x_lo);
    GETSYM(wt_hi, g_wt_hi); GETSYM(wt_lo, g_wt_lo);
    GETSYM(wg_hi, g_wg_hi); GETSYM(wg_lo, g_wg_lo);
    GETSYM(w1_hi, g_w1_hi); GETSYM(w1_lo, g_w1_lo);
    GETSYM(w2_hi, g_w2_hi); GETSYM(w2_lo, g_w2_lo);
    GETSYM(wa_hi, g_wa_hi); GETSYM(wa_lo, g_wa_lo);
    GETSYM(ft, g_ft);
    GETSYM(z0, g_z0); GETSYM(z1, g_z1); GETSYM(z2, g_z2);
    GETSYM(x, g_x);   GETSYM(vp, g_vp);
    GETSYM(stats, g_stats); GETSYM(beta_raw, g_beta_raw); GETSYM(loss_acc, g_loss_acc);

    const size_t zbytes = (size_t)NN * HH * sizeof(float);
    cudaMemsetAsync(z0, 0, zbytes);
    cudaMemsetAsync(z1, 0, zbytes);
    cudaMemsetAsync(z2, 0, zbytes);
    cudaMemsetAsync(stats, 0, 2 * PHH * sizeof(float));
    cudaMemsetAsync(beta_raw, 0, 3 * sizeof(float));
    cudaMemsetAsync(loss_acc, 0, sizeof(float));

    // split inputs -> bf16 hi/lo
    {
        size_t np = (size_t)NN * (FEATD / 2);
        split_kernel<<<(int)((np + 255) / 256), 256>>>((const float2*)feats, fe_hi, fe_lo, np);
        np = (size_t)HH * (FEATD / 2);
        split_kernel<<<(int)((np + 255) / 256), 256>>>((const float2*)W_trans, wt_hi, wt_lo, np);
        np = (size_t)3 * HH * (HH / 2);
        split_kernel<<<(int)((np + 255) / 256), 256>>>((const float2*)W_gcn, wg_hi, wg_lo, np);
        np = (size_t)PHH * (HH / 2);
        split_kernel<<<(int)((np + 255) / 256), 256>>>((const float2*)W1, w1_hi, w1_lo, np);
        np = (size_t)HH * (PHH / 2);
        split_kernel<<<(int)((np + 255) / 256), 256>>>((const float2*)W2, w2_hi, w2_lo, np);
        np = (size_t)HH * (HH / 2);
        split_kernel<<<(int)((np + 255) / 256), 256>>>((const float2*)W_att, wa_hi, wa_lo, np);
    }

    const int mb = (NN + TBM - 1) / TBM;   // 391

    // h = elu(feats @ W_trans^T + b_trans) -> split-bf16 h
    gemm_bf16s_kernel<1><<<dim3(HH / TBN, mb), 128>>>(
        fe_hi, fe_lo, wt_hi, wt_lo, b_trans, nullptr, h_hi, h_lo, NN, HH, FEATD / 2);

    // fused GCN GEMM: ft[N, 768] = h @ [W_gcn0;W_gcn1;W_gcn2]^T
    gemm_bf16s_kernel<0><<<dim3(3 * HH / TBN, mb), 128>>>(
        h_hi, h_lo, wg_hi, wg_lo, nullptr, ft, nullptr, nullptr, NN, 3 * HH, HH / 2);

    // three SpMM + bias/prelu passes (bias_prelu also emits split z)
    float* zs[3] = {z0, z1, z2};
    uint32_t* zsh[3] = {z0h, z1h, z2h};
    uint32_t* zsl[3] = {z0l, z1l, z2l};
    for (int v = 0; v < PP; ++v) {
        spmm_kernel<<<(EE * 64) / 256, 256>>>((const float4*)ft + v * (HH / 4), 3 * HH / 4,
                                              src + (size_t)v * EE, dst + (size_t)v * EE,
                                              vals + (size_t)v * EE, (float4*)zs[v]);
        bias_prelu_kernel<<<(NN * 64) / 256, 256>>>((float4*)zs[v], zsh[v], zsl[v],
                                                    b_gcn + (size_t)v * HH, a_gcn + v);
    }

    // student predictor
    gemm_bf16s_kernel<2><<<dim3(PHH / TBN, mb), 128>>>(
        z0h, z0l, w1_hi, w1_lo, b1, x, nullptr, nullptr, NN, PHH, HH / 2);
    colstats_kernel<<<dim3(2, 512), 256>>>(x, stats);
    bn_prelu_kernel<<<(NN * PHH / 4) / 256, 256>>>((const float4*)x, x_hi, x_lo,
                                                   stats, bn_g, bn_b, a_pred);
    gemm_bf16s_kernel<2><<<dim3(HH / TBN, mb), 128>>>(
        x_hi, x_lo, w2_hi, w2_lo, b2, vp, nullptr, nullptr, NN, HH, PHH / 2);

    // cosine losses vs teachers (views 1 and 2)
    loss_kernel<<<(NN * 32) / 256, 256>>>((const float4*)vp, (const float4*)z1,
                                          (const float4*)z2, loss_acc);

    // type-level attention: z_sum order = [teacher1, teacher2, student]
    gemm_att_bf16s_kernel<<<dim3(HH / TBN, mb), 128>>>(z1h, z1l, wa_hi, wa_lo,
                                                       b_att, att, beta_raw + 0, NN, HH / 2);
    gemm_att_bf16s_kernel<<<dim3(HH / TBN, mb), 128>>>(z2h, z2l, wa_hi, wa_lo,
                                                       b_att, att, beta_raw + 1, NN, HH / 2);
    gemm_att_bf16s_kernel<<<dim3(HH / TBN, mb), 128>>>(z0h, z0l, wa_hi, wa_lo,
                                                       b_att, att, beta_raw + 2, NN, HH / 2);

    float* outf = (float*)d_out;
    int write_loss = (out_size > NN * HH) ? 1 : 0;
    finalize_kernel<<<1, 1>>>(outf + (size_t)NN * HH, write_loss);
    zout_kernel<<<(NN * 64) / 256, 256>>>((float4*)outf, (const float4*)z1,
                                          (const float4*)z2, (const float4*)z0);
}

// round 8
// speedup vs baseline: 1.0401x; 1.0401x over previous
#include <cuda_runtime.h>
#include <math.h>
#include <stdint.h>

// ---------------- problem constants ----------------
#define NN   50000
#define PP   3
#define EE   800000
#define FEATD 1000
#define HH   256
#define PHH  512
#define BN_EPS 1e-5f

// ---------------- device scratch (no allocations allowed) ----------------
__device__ uint32_t g_fe_hi[(size_t)NN * (FEATD / 2)];
__device__ uint32_t g_fe_lo[(size_t)NN * (FEATD / 2)];
__device__ uint32_t g_h_hi [(size_t)NN * (HH / 2)];
__device__ uint32_t g_h_lo [(size_t)NN * (HH / 2)];
__device__ float    g_ft[(size_t)NN * (3 * HH)];
__device__ float    g_z   [(size_t)3 * NN * HH];       // z0|z1|z2 contiguous
__device__ uint32_t g_z_hi[(size_t)3 * NN * (HH / 2)];
__device__ uint32_t g_z_lo[(size_t)3 * NN * (HH / 2)];
__device__ float    g_x [(size_t)NN * PHH];
__device__ uint32_t g_x_hi[(size_t)NN * (PHH / 2)];
__device__ uint32_t g_x_lo[(size_t)NN * (PHH / 2)];
__device__ float    g_vp[(size_t)NN * HH];
// split weights
__device__ uint32_t g_wt_hi[HH * (FEATD / 2)];
__device__ uint32_t g_wt_lo[HH * (FEATD / 2)];
__device__ uint32_t g_wg_hi[3 * HH * (HH / 2)];
__device__ uint32_t g_wg_lo[3 * HH * (HH / 2)];
__device__ uint32_t g_w1_hi[PHH * (HH / 2)];
__device__ uint32_t g_w1_lo[PHH * (HH / 2)];
__device__ uint32_t g_w2_hi[HH * (PHH / 2)];
__device__ uint32_t g_w2_lo[HH * (PHH / 2)];
__device__ uint32_t g_wa_hi[HH * (HH / 2)];
__device__ uint32_t g_wa_lo[HH * (HH / 2)];
__device__ float g_stats[2 * PHH];
__device__ float g_beta_raw[3];
__device__ float g_beta[3];
__device__ float g_loss_acc;

// ---------------- bf16 split helpers --------------------------------------------
__device__ __forceinline__ uint32_t pack_hi(float x0, float x1)
{
    uint32_t r;
    asm("prmt.b32 %0, %1, %2, 0x7632;"
        : "=r"(r) : "r"(__float_as_uint(x0)), "r"(__float_as_uint(x1)));
    return r;
}

__device__ __forceinline__ uint32_t pack_lo(float x0, float x1)
{
    float h0 = __uint_as_float(__float_as_uint(x0) & 0xFFFF0000u);
    float h1 = __uint_as_float(__float_as_uint(x1) & 0xFFFF0000u);
    uint32_t r;
    asm("cvt.rn.bf16x2.f32 %0, %1, %2;" : "=r"(r) : "f"(x1 - h1), "f"(x0 - h0));
    return r;
}

__device__ __forceinline__ void mma_bf16(float* c, const uint32_t* a, const uint32_t* b)
{
    asm volatile(
        "mma.sync.aligned.m16n8k16.row.col.f32.bf16.bf16.f32 "
        "{%0,%1,%2,%3}, {%4,%5,%6,%7}, {%8,%9}, {%0,%1,%2,%3};\n"
        : "+f"(c[0]), "+f"(c[1]), "+f"(c[2]), "+f"(c[3])
        : "r"(a[0]), "r"(a[1]), "r"(a[2]), "r"(a[3]), "r"(b[0]), "r"(b[1]));
}

__device__ __forceinline__ void cp16(uint32_t saddr, const void* gmem, bool pred)
{
    int sz = pred ? 16 : 0;
    asm volatile("cp.async.cg.shared.global [%0], [%1], 16, %2;\n"
                 :: "r"(saddr), "l"(gmem), "r"(sz));
}

// ---------------- generic f32 -> split-bf16 pass --------------------------------
__global__ __launch_bounds__(256)
void split_kernel(const float2* __restrict__ in, uint32_t* __restrict__ hi,
                  uint32_t* __restrict__ lo, size_t npairs)
{
    size_t i = (size_t)blockIdx.x * blockDim.x + threadIdx.x;
    if (i >= npairs) return;
    float2 v = in[i];
    hi[i] = pack_hi(v.x, v.y);
    lo[i] = pack_lo(v.x, v.y);
}

// ---------------- split-bf16 GEMM ------------------------------------------------
// Block tile 128x128, BK=16 (8 bf16x2 pairs), 8 warps (2m x 4n), warp tile 64x32.
// 3 MMAs per atom: lo*hi + hi*lo + hi*hi (lo*lo dropped, ~2^-17 rel).
// Total static smem = 48 KB exactly; attention kernel reuses AsH for reduction.
#define TBM 128
#define TBN 128
#define TPAD 12

#define GS_DECL()                                                                   \
    __shared__ uint32_t AsH[2][TBM][TPAD];                                          \
    __shared__ uint32_t AsL[2][TBM][TPAD];                                          \
    __shared__ uint32_t WsH[2][TBN][TPAD];                                          \
    __shared__ uint32_t WsL[2][TBN][TPAD];                                          \
    const int tid  = threadIdx.x;                                                   \
    const int wid  = tid >> 5;                                                      \
    const int lane = tid & 31;                                                      \
    const int g    = lane >> 2;                                                     \
    const int t    = lane & 3;                                                      \
    const int wm   = (wid & 1) << 6;                                                \
    const int wn   = (wid >> 1) << 5;                                               \
    const int bm   = blockIdx.y * TBM;                                              \
    const int bn   = blockIdx.x * TBN;                                              \
    float acc[4][4][4] = {};

#define GS_LOAD(S, KP0)                                                             \
    {                                                                               \
        int r  = tid >> 1, ch = (tid & 1) << 2;                                     \
        int gp = (KP0) + ch;                                                        \
        bool pa = (gp < Kp) && (bm + r < M);                                        \
        size_t offa = (size_t)(bm + r) * Kp + gp;                                   \
        cp16((uint32_t)__cvta_generic_to_shared(&AsH[S][r][ch]), Ahi + offa, pa);   \
        cp16((uint32_t)__cvta_generic_to_shared(&AsL[S][r][ch]), Alo + offa, pa);   \
        bool pb = (gp < Kp);                                                        \
        size_t offb = (size_t)(bn + r) * Kp + gp;                                   \
        cp16((uint32_t)__cvta_generic_to_shared(&WsH[S][r][ch]), Whi + offb, pb);   \
        cp16((uint32_t)__cvta_generic_to_shared(&WsL[S][r][ch]), Wlo + offb, pb);   \
    }

#define GS_MAINLOOP()                                                               \
    GS_DECL();                                                                      \
    GS_LOAD(0, 0);                                                                  \
    asm volatile("cp.async.commit_group;\n" ::: "memory");                          \
    int buf = 0;                                                                    \
    for (int kp0 = 0; kp0 < Kp; kp0 += 8) {                                         \
        if (kp0 + 8 < Kp) GS_LOAD(buf ^ 1, kp0 + 8);                                \
        asm volatile("cp.async.commit_group;\n" ::: "memory");                      \
        asm volatile("cp.async.wait_group 1;\n" ::: "memory");                      \
        __syncthreads();                                                            \
        uint32_t aH[4][4], aL[4][4], bH[4][2], bL[4][2];                            \
        _Pragma("unroll")                                                           \
        for (int i = 0; i < 4; ++i) {                                               \
            int rb = wm + (i << 4);                                                 \
            aH[i][0] = AsH[buf][rb + g    ][t    ];                                 \
            aH[i][1] = AsH[buf][rb + g + 8][t    ];                                 \
            aH[i][2] = AsH[buf][rb + g    ][t + 4];                                 \
            aH[i][3] = AsH[buf][rb + g + 8][t + 4];                                 \
            aL[i][0] = AsL[buf][rb + g    ][t    ];                                 \
            aL[i][1] = AsL[buf][rb + g + 8][t    ];                                 \
            aL[i][2] = AsL[buf][rb + g    ][t + 4];                                 \
            aL[i][3] = AsL[buf][rb + g + 8][t + 4];                                 \
        }                                                                           \
        _Pragma("unroll")                                                           \
        for (int j = 0; j < 4; ++j) {                                               \
            int nb = wn + (j << 3);                                                 \
            bH[j][0] = WsH[buf][nb + g][t    ];                                     \
            bH[j][1] = WsH[buf][nb + g][t + 4];                                     \
            bL[j][0] = WsL[buf][nb + g][t    ];                                     \
            bL[j][1] = WsL[buf][nb + g][t + 4];                                     \
        }                                                                           \
        _Pragma("unroll")                                                           \
        for (int i = 0; i < 4; ++i)                                                 \
            _Pragma("unroll")                                                       \
            for (int j = 0; j < 4; ++j) {                                           \
                mma_bf16(acc[i][j], aL[i], bH[j]);                                  \
                mma_bf16(acc[i][j], aH[i], bL[j]);                                  \
                mma_bf16(acc[i][j], aH[i], bH[j]);                                  \
            }                                                                       \
        __syncthreads();                                                            \
        buf ^= 1;                                                                   \
    }

// EPI: 0 = raw f32, 1 = bias+ELU -> split bf16 output (Chi/Clo), 2 = bias f32
template<int EPI>
__global__ __launch_bounds__(256, 2)
void gemm_bf16s_kernel(const uint32_t* __restrict__ Ahi, const uint32_t* __restrict__ Alo,
                       const uint32_t* __restrict__ Whi, const uint32_t* __restrict__ Wlo,
                       const float* __restrict__ bias, float* __restrict__ C,
                       uint32_t* __restrict__ Chi, uint32_t* __restrict__ Clo,
                       int M, int Nc, int Kp)
{
    GS_MAINLOOP();

#pragma unroll
    for (int i = 0; i < 4; ++i) {
#pragma unroll
        for (int j = 0; j < 4; ++j) {
            int r0 = bm + wm + (i << 4) + g;
            int r1 = r0 + 8;
            int c0 = bn + wn + (j << 3) + (t << 1);
            float bx = 0.f, by = 0.f;
            if (EPI >= 1) { bx = bias[c0]; by = bias[c0 + 1]; }
            float v0 = acc[i][j][0], v1 = acc[i][j][1];
            float v2 = acc[i][j][2], v3 = acc[i][j][3];
            if (EPI >= 1) { v0 += bx; v1 += by; v2 += bx; v3 += by; }
            if (EPI == 1) {
                v0 = v0 > 0.f ? v0 : expm1f(v0);
                v1 = v1 > 0.f ? v1 : expm1f(v1);
                v2 = v2 > 0.f ? v2 : expm1f(v2);
                v3 = v3 > 0.f ? v3 : expm1f(v3);
                int pc = c0 >> 1;
                if (r0 < M) {
                    Chi[(size_t)r0 * (Nc / 2) + pc] = pack_hi(v0, v1);
                    Clo[(size_t)r0 * (Nc / 2) + pc] = pack_lo(v0, v1);
                }
                if (r1 < M) {
                    Chi[(size_t)r1 * (Nc / 2) + pc] = pack_hi(v2, v3);
                    Clo[(size_t)r1 * (Nc / 2) + pc] = pack_lo(v2, v3);
                }
            } else {
                if (r0 < M) *(float2*)(C + (size_t)r0 * Nc + c0) = make_float2(v0, v1);
                if (r1 < M) *(float2*)(C + (size_t)r1 * Nc + c0) = make_float2(v2, v3);
            }
        }
    }
}

// fused attention GEMM over all 3 views: blockIdx.z = storage view (z0,z1,z2)
// beta index: view0(student)->2, view1->0, view2->1
// Reduction scratch aliases AsH (dead after mainloop) to stay within 48 KB smem.
__global__ __launch_bounds__(256, 2)
void gemm_att_bf16s_kernel(const uint32_t* __restrict__ Zhi, const uint32_t* __restrict__ Zlo,
                           const uint32_t* __restrict__ Whi, const uint32_t* __restrict__ Wlo,
                           const float* __restrict__ bias, const float* __restrict__ att,
                           float* __restrict__ beta_raw, int M, int Kp)
{
    const int view = blockIdx.z;
    const uint32_t* Ahi = Zhi + (size_t)view * NN * (HH / 2);
    const uint32_t* Alo = Zlo + (size_t)view * NN * (HH / 2);

    GS_MAINLOOP();

    float s = 0.f;
#pragma unroll
    for (int i = 0; i < 4; ++i) {
#pragma unroll
        for (int j = 0; j < 4; ++j) {
            int r0 = bm + wm + (i << 4) + g;
            int r1 = r0 + 8;
            int c0 = bn + wn + (j << 3) + (t << 1);
            float bx = bias[c0], by = bias[c0 + 1];
            float ax = att[c0],  ay = att[c0 + 1];
            if (r0 < M) s += tanhf(acc[i][j][0] + bx) * ax + tanhf(acc[i][j][1] + by) * ay;
            if (r1 < M) s += tanhf(acc[i][j][2] + bx) * ax + tanhf(acc[i][j][3] + by) * ay;
        }
    }
    float* red = (float*)&AsH[0][0][0];   // reuse pipeline smem (dead now)
    __syncthreads();
    red[tid] = s;
    __syncthreads();
    for (int o = 128; o > 0; o >>= 1) {
        if (tid < o) red[tid] += red[tid + o];
        __syncthreads();
    }
    if (tid == 0) {
        int bidx = (view + 2) % 3;
        atomicAdd(&beta_raw[bidx], red[0]);
    }
}

// ---------------- SpMM scatter, all 3 views: blockIdx.y = view ------------------
__global__ __launch_bounds__(256)
void spmm_kernel(const float4* __restrict__ ft,
                 const int* __restrict__ src, const int* __restrict__ dst,
                 const float* __restrict__ vals, float4* __restrict__ z)
{
    int gid = blockIdx.x * blockDim.x + threadIdx.x;
    if (gid >= EE * 64) return;
    int v4 = blockIdx.y;
    int e = gid >> 6;
    int c = gid & 63;
    size_t eoff = (size_t)v4 * EE + e;
    int s = src[eoff];
    int d = dst[eoff];
    float vv = vals[eoff];
    float4 f = ft[(size_t)s * (3 * HH / 4) + v4 * (HH / 4) + c];
    float4* p = &z[(size_t)v4 * NN * (HH / 4) + (size_t)d * 64 + c];
    asm volatile("red.global.add.v4.f32 [%0], {%1,%2,%3,%4};"
                 :: "l"(p), "f"(vv * f.x), "f"(vv * f.y), "f"(vv * f.z), "f"(vv * f.w)
                 : "memory");
}

// ---------------- z = prelu(z + b, a), all 3 views; also emit split-bf16 --------
__global__ __launch_bounds__(256)
void bias_prelu_kernel(float4* __restrict__ z, uint32_t* __restrict__ zhi,
                       uint32_t* __restrict__ zlo, const float* __restrict__ b_all,
                       const float* __restrict__ a_all)
{
    int i = blockIdx.x * blockDim.x + threadIdx.x;
    if (i >= NN * 64) return;
    int v = blockIdx.y;
    size_t idx = (size_t)v * NN * 64 + i;
    float a = a_all[v];
    float4 bv = *(const float4*)(b_all + v * HH + ((i & 63) << 2));
    float4 x = z[idx];
    x.x += bv.x; x.y += bv.y; x.z += bv.z; x.w += bv.w;
    x.x = x.x >= 0.f ? x.x : a * x.x;
    x.y = x.y >= 0.f ? x.y : a * x.y;
    x.z = x.z >= 0.f ? x.z : a * x.z;
    x.w = x.w >= 0.f ? x.w : a * x.w;
    z[idx] = x;
    size_t p = idx << 1;
    zhi[p]     = pack_hi(x.x, x.y);
    zhi[p + 1] = pack_hi(x.z, x.w);
    zlo[p]     = pack_lo(x.x, x.y);
    zlo[p + 1] = pack_lo(x.z, x.w);
}

// ---------------- BN column stats -----------------------------------------------
__global__ __launch_bounds__(256)
void colstats_kernel(const float* __restrict__ x, float* __restrict__ stats)
{
    int c = blockIdx.x * 256 + threadIdx.x;
    float s = 0.f, sq = 0.f;
    for (int r = blockIdx.y; r < NN; r += gridDim.y) {
        float v = x[(size_t)r * PHH + c];
        s += v;
        sq += v * v;
    }
    atomicAdd(&stats[c], s);
    atomicAdd(&stats[PHH + c], sq);
}

// ---------------- BN + PReLU -> split-bf16 output -------------------------------
__global__ __launch_bounds__(256)
void bn_prelu_kernel(const float4* __restrict__ x, uint32_t* __restrict__ xhi,
                     uint32_t* __restrict__ xlo, const float* __restrict__ stats,
                     const float* __restrict__ g, const float* __restrict__ b,
                     const float* __restrict__ a_ptr)
{
    int i = blockIdx.x * blockDim.x + threadIdx.x;
    if (i >= NN * (PHH / 4)) return;
    int c = (i & (PHH / 4 - 1)) << 2;
    float a = *a_ptr;
    float4 sm = *(const float4*)(stats + c);
    float4 sq = *(const float4*)(stats + PHH + c);
    float4 gv = *(const float4*)(g + c);
    float4 bv = *(const float4*)(b + c);
    float4 v = x[i];
    float invN = 1.f / (float)NN;

    float mu, var, sc, sh, y;
    mu = sm.x * invN; var = sq.x * invN - mu * mu; sc = gv.x * rsqrtf(var + BN_EPS);
    sh = bv.x - mu * sc; y = v.x * sc + sh; v.x = y >= 0.f ? y : a * y;
    mu = sm.y * invN; var = sq.y * invN - mu * mu; sc = gv.y * rsqrtf(var + BN_EPS);
    sh = bv.y - mu * sc; y = v.y * sc + sh; v.y = y >= 0.f ? y : a * y;
    mu = sm.z * invN; var = sq.z * invN - mu * mu; sc = gv.z * rsqrtf(var + BN_EPS);
    sh = bv.z - mu * sc; y = v.z * sc + sh; v.z = y >= 0.f ? y : a * y;
    mu = sm.w * invN; var = sq.w * invN - mu * mu; sc = gv.w * rsqrtf(var + BN_EPS);
    sh = bv.w - mu * sc; y = v.w * sc + sh; v.w = y >= 0.f ? y : a * y;

    size_t p = (size_t)i << 1;
    xhi[p]     = pack_hi(v.x, v.y);
    xhi[p + 1] = pack_hi(v.z, v.w);
    xlo[p]     = pack_lo(v.x, v.y);
    xlo[p + 1] = pack_lo(v.z, v.w);
}

// ---------------- cosine loss accumulation (one warp per node) ------------------
__global__ __launch_bounds__(256)
void loss_kernel(const float4* __restrict__ p, const float4* __restrict__ t1,
                 const float4* __restrict__ t2, float* __restrict__ acc)
{
    int gid  = blockIdx.x * blockDim.x + threadIdx.x;
    int node = gid >> 5;
    int lane = gid & 31;
    float pp = 0.f, n1 = 0.f, n2 = 0.f, d1 = 0.f, d2 = 0.f;
    if (node < NN) {
        size_t base = (size_t)node * 64;
#pragma unroll
        for (int r = 0; r < 2; ++r) {
            float4 a  = p [base + lane + 32 * r];
            float4 b  = t1[base + lane + 32 * r];
            float4 cc = t2[base + lane + 32 * r];
            pp += a.x * a.x + a.y * a.y + a.z * a.z + a.w * a.w;
            n1 += b.x * b.x + b.y * b.y + b.z * b.z + b.w * b.w;
            n2 += cc.x * cc.x + cc.y * cc.y + cc.z * cc.z + cc.w * cc.w;
            d1 += a.x * b.x + a.y * b.y + a.z * b.z + a.w * b.w;
            d2 += a.x * cc.x + a.y * cc.y + a.z * cc.z + a.w * cc.w;
        }
    }
#pragma unroll
    for (int o = 16; o > 0; o >>= 1) {
        pp += __shfl_down_sync(0xffffffffu, pp, o);
        n1 += __shfl_down_sync(0xffffffffu, n1, o);
        n2 += __shfl_down_sync(0xffffffffu, n2, o);
        d1 += __shfl_down_sync(0xffffffffu, d1, o);
        d2 += __shfl_down_sync(0xffffffffu, d2, o);
    }
    __shared__ float sacc[8];
    float contrib = 0.f;
    if (lane == 0 && node < NN) {
        float np  = fmaxf(sqrtf(pp), 1e-12f);
        float nn1 = fmaxf(sqrtf(n1), 1e-12f);
        float nn2 = fmaxf(sqrtf(n2), 1e-12f);
        contrib = d1 / (np * nn1) + d2 / (np * nn2);
    }
    int wid = threadIdx.x >> 5;
    if (lane == 0) sacc[wid] = contrib;
    __syncthreads();
    if (threadIdx.x == 0) {
        float s = 0.f;
#pragma unroll
        for (int i = 0; i < 8; ++i) s += sacc[i];
        atomicAdd(acc, s);
    }
}

// ---------------- finalize: softmax(beta), loss --------------------------------
__global__ void finalize_kernel(float* __restrict__ out_loss, int write_loss)
{
    float invN = 1.f / (float)NN;
    float b0 = g_beta_raw[0] * invN;
    float b1 = g_beta_raw[1] * invN;
    float b2 = g_beta_raw[2] * invN;
    float m = fmaxf(b0, fmaxf(b1, b2));
    float e0 = expf(b0 - m), e1 = expf(b1 - m), e2 = expf(b2 - m);
    float s = e0 + e1 + e2;
    g_beta[0] = e0 / s;
    g_beta[1] = e1 / s;
    g_beta[2] = e2 / s;
    if (write_loss) *out_loss = 2.0f - g_loss_acc * invN;
}

// ---------------- z_out = b0*z1 + b1*z2 + b2*z0 ---------------------------------
__global__ __launch_bounds__(256)
void zout_kernel(float4* __restrict__ out, const float4* __restrict__ z1,
                 const float4* __restrict__ z2, const float4* __restrict__ z0)
{
    int i = blockIdx.x * blockDim.x + threadIdx.x;
    if (i >= NN * 64) return;
    float b0 = g_beta[0], b1 = g_beta[1], b2 = g_beta[2];
    float4 a = z1[i], b = z2[i], c = z0[i];
    float4 r;
    r.x = b0 * a.x + b1 * b.x + b2 * c.x;
    r.y = b0 * a.y + b1 * b.y + b2 * c.y;
    r.z = b0 * a.z + b1 * b.z + b2 * c.z;
    r.w = b0 * a.w + b1 * b.w + b2 * c.w;
    out[i] = r;
}

// ---------------- host ----------------------------------------------------------
#define GETSYM(var, sym) cudaGetSymbolAddress((void**)&var, sym)

extern "C" void kernel_launch(void* const* d_in, const int* in_sizes, int n_in,
                              void* d_out, int out_size)
{
    const float* feats   = (const float*)d_in[0];
    const int*   src     = (const int*)  d_in[1];
    const int*   dst     = (const int*)  d_in[2];
    const float* vals    = (const float*)d_in[3];
    const float* W_trans = (const float*)d_in[4];
    const float* b_trans = (const float*)d_in[5];
    const float* W_gcn   = (const float*)d_in[6];
    const float* b_gcn   = (const float*)d_in[7];
    const float* a_gcn   = (const float*)d_in[8];
    const float* W1      = (const float*)d_in[9];
    const float* b1      = (const float*)d_in[10];
    const float* bn_g    = (const float*)d_in[11];
    const float* bn_b    = (const float*)d_in[12];
    const float* a_pred  = (const float*)d_in[13];
    const float* W2      = (const float*)d_in[14];
    const float* b2      = (const float*)d_in[15];
    const float* W_att   = (const float*)d_in[16];
    const float* b_att   = (const float*)d_in[17];
    const float* att     = (const float*)d_in[18];

    uint32_t *fe_hi, *fe_lo, *h_hi, *h_lo, *zh, *zl;
    uint32_t *x_hi, *x_lo, *wt_hi, *wt_lo, *wg_hi, *wg_lo, *w1_hi, *w1_lo;
    uint32_t *w2_hi, *w2_lo, *wa_hi, *wa_lo;
    float *ft, *z, *x, *vp, *stats, *beta_raw, *loss_acc;
    GETSYM(fe_hi, g_fe_hi); GETSYM(fe_lo, g_fe_lo);
    GETSYM(h_hi, g_h_hi);   GETSYM(h_lo, g_h_lo);
    GETSYM(zh, g_z_hi); GETSYM(zl, g_z_lo);
    GETSYM(x_hi, g_x_hi); GETSYM(x_lo, g_x_lo);
    GETSYM(wt_hi, g_wt_hi); GETSYM(wt_lo, g_wt_lo);
    GETSYM(wg_hi, g_wg_hi); GETSYM(wg_lo, g_wg_lo);
    GETSYM(w1_hi, g_w1_hi); GETSYM(w1_lo, g_w1_lo);
    GETSYM(w2_hi, g_w2_hi); GETSYM(w2_lo, g_w2_lo);
    GETSYM(wa_hi, g_wa_hi); GETSYM(wa_lo, g_wa_lo);
    GETSYM(ft, g_ft); GETSYM(z, g_z);
    GETSYM(x, g_x);   GETSYM(vp, g_vp);
    GETSYM(stats, g_stats); GETSYM(beta_raw, g_beta_raw); GETSYM(loss_acc, g_loss_acc);

    float* z0 = z;                           // view0 = student
    float* z1 = z + (size_t)NN * HH;         // view1 = teacher1
    float* z2 = z + (size_t)2 * NN * HH;     // view2 = teacher2
    uint32_t* z0h = zh;
    uint32_t* z0l = zl;

    cudaMemsetAsync(z, 0, (size_t)3 * NN * HH * sizeof(float));
    cudaMemsetAsync(stats, 0, 2 * PHH * sizeof(float));
    cudaMemsetAsync(beta_raw, 0, 3 * sizeof(float));
    cudaMemsetAsync(loss_acc, 0, sizeof(float));

    // split inputs -> bf16 hi/lo
    {
        size_t np = (size_t)NN * (FEATD / 2);
        split_kernel<<<(int)((np + 255) / 256), 256>>>((const float2*)feats, fe_hi, fe_lo, np);
        np = (size_t)HH * (FEATD / 2);
        split_kernel<<<(int)((np + 255) / 256), 256>>>((const float2*)W_trans, wt_hi, wt_lo, np);
        np = (size_t)3 * HH * (HH / 2);
        split_kernel<<<(int)((np + 255) / 256), 256>>>((const float2*)W_gcn, wg_hi, wg_lo, np);
        np = (size_t)PHH * (HH / 2);
        split_kernel<<<(int)((np + 255) / 256), 256>>>((const float2*)W1, w1_hi, w1_lo, np);
        np = (size_t)HH * (PHH / 2);
        split_kernel<<<(int)((np + 255) / 256), 256>>>((const float2*)W2, w2_hi, w2_lo, np);
        np = (size_t)HH * (HH / 2);
        split_kernel<<<(int)((np + 255) / 256), 256>>>((const float2*)W_att, wa_hi, wa_lo, np);
    }

    const int mb = (NN + TBM - 1) / TBM;   // 391

    // h = elu(feats @ W_trans^T + b_trans) -> split-bf16 h
    gemm_bf16s_kernel<1><<<dim3(HH / TBN, mb), 256>>>(
        fe_hi, fe_lo, wt_hi, wt_lo, b_trans, nullptr, h_hi, h_lo, NN, HH, FEATD / 2);

    // fused GCN GEMM: ft[N, 768] = h @ [W_gcn0;W_gcn1;W_gcn2]^T
    gemm_bf16s_kernel<0><<<dim3(3 * HH / TBN, mb), 256>>>(
        h_hi, h_lo, wg_hi, wg_lo, nullptr, ft, nullptr, nullptr, NN, 3 * HH, HH / 2);

    // all 3 SpMMs in one launch, then all 3 bias/prelu in one launch
    spmm_kernel<<<dim3((EE * 64) / 256, 3), 256>>>((const float4*)ft, src, dst, vals,
                                                   (float4*)z);
    bias_prelu_kernel<<<dim3((NN * 64) / 256, 3), 256>>>((float4*)z, zh, zl, b_gcn, a_gcn);

    // student predictor
    gemm_bf16s_kernel<2><<<dim3(PHH / TBN, mb), 256>>>(
        z0h, z0l, w1_hi, w1_lo, b1, x, nullptr, nullptr, NN, PHH, HH / 2);
    colstats_kernel<<<dim3(2, 512), 256>>>(x, stats);
    bn_prelu_kernel<<<(NN * PHH / 4) / 256, 256>>>((const float4*)x, x_hi, x_lo,
                                                   stats, bn_g, bn_b, a_pred);
    gemm_bf16s_kernel<2><<<dim3(HH / TBN, mb), 256>>>(
        x_hi, x_lo, w2_hi, w2_lo, b2, vp, nullptr, nullptr, NN, HH, PHH / 2);

    // cosine losses vs teachers (views 1 and 2)
    loss_kernel<<<(NN * 32) / 256, 256>>>((const float4*)vp, (const float4*)z1,
                                          (const float4*)z2, loss_acc);

    // type-level attention, all 3 views in one launch
    gemm_att_bf16s_kernel<<<dim3(HH / TBN, mb, 3), 256>>>(zh, zl, wa_hi, wa_lo,
                                                          b_att, att, beta_raw, NN, HH / 2);

    float* outf = (float*)d_out;
    int write_loss = (out_size > NN * HH) ? 1 : 0;
    finalize_kernel<<<1, 1>>>(outf + (size_t)NN * HH, write_loss);
    zout_kernel<<<(NN * 64) / 256, 256>>>((float4*)outf, (const float4*)z1,
                                          (const float4*)z2, (const float4*)z0);
}

// round 9
// speedup vs baseline: 1.3308x; 1.2795x over previous
#include <cuda_runtime.h>
#include <math.h>
#include <stdint.h>

// ---------------- problem constants ----------------
#define NN   50000
#define PP   3
#define EE   800000
#define FEATD 1000
#define HH   256
#define PHH  512
#define BN_EPS 1e-5f

// ---------------- device scratch (no allocations allowed) ----------------
__device__ uint32_t g_h_hi [(size_t)NN * (HH / 2)];
__device__ uint32_t g_h_lo [(size_t)NN * (HH / 2)];
__device__ float    g_ft[(size_t)NN * (3 * HH)];
__device__ float    g_z   [(size_t)3 * NN * HH];       // z0|z1|z2 contiguous
__device__ uint32_t g_z_hi[(size_t)3 * NN * (HH / 2)];
__device__ uint32_t g_z_lo[(size_t)3 * NN * (HH / 2)];
__device__ float    g_x [(size_t)NN * PHH];
__device__ uint32_t g_x_hi[(size_t)NN * (PHH / 2)];
__device__ uint32_t g_x_lo[(size_t)NN * (PHH / 2)];
__device__ float    g_vp[(size_t)NN * HH];
// CSR scratch
__device__ int   g_deg[3 * NN];
__device__ int   g_rowptr[3 * (NN + 1)];
__device__ int   g_cursor[3 * NN];
__device__ int   g_esrc[(size_t)3 * EE];
__device__ float g_eval[(size_t)3 * EE];
// split weights
__device__ uint32_t g_wt_hi[HH * (FEATD / 2)];
__device__ uint32_t g_wt_lo[HH * (FEATD / 2)];
__device__ uint32_t g_wg_hi[3 * HH * (HH / 2)];
__device__ uint32_t g_wg_lo[3 * HH * (HH / 2)];
__device__ uint32_t g_w1_hi[PHH * (HH / 2)];
__device__ uint32_t g_w1_lo[PHH * (HH / 2)];
__device__ uint32_t g_w2_hi[HH * (PHH / 2)];
__device__ uint32_t g_w2_lo[HH * (PHH / 2)];
__device__ uint32_t g_wa_hi[HH * (HH / 2)];
__device__ uint32_t g_wa_lo[HH * (HH / 2)];
__device__ float g_stats[2 * PHH];
__device__ float g_beta_raw[3];
__device__ float g_beta[3];
__device__ float g_loss_acc;

// ---------------- bf16 split helpers --------------------------------------------
__device__ __forceinline__ uint32_t pack_hi(float x0, float x1)
{
    uint32_t r;
    asm("prmt.b32 %0, %1, %2, 0x7632;"
        : "=r"(r) : "r"(__float_as_uint(x0)), "r"(__float_as_uint(x1)));
    return r;
}

__device__ __forceinline__ uint32_t pack_lo(float x0, float x1)
{
    float h0 = __uint_as_float(__float_as_uint(x0) & 0xFFFF0000u);
    float h1 = __uint_as_float(__float_as_uint(x1) & 0xFFFF0000u);
    uint32_t r;
    asm("cvt.rn.bf16x2.f32 %0, %1, %2;" : "=r"(r) : "f"(x1 - h1), "f"(x0 - h0));
    return r;
}

__device__ __forceinline__ void mma_bf16(float* c, const uint32_t* a, const uint32_t* b)
{
    asm volatile(
        "mma.sync.aligned.m16n8k16.row.col.f32.bf16.bf16.f32 "
        "{%0,%1,%2,%3}, {%4,%5,%6,%7}, {%8,%9}, {%0,%1,%2,%3};\n"
        : "+f"(c[0]), "+f"(c[1]), "+f"(c[2]), "+f"(c[3])
        : "r"(a[0]), "r"(a[1]), "r"(a[2]), "r"(a[3]), "r"(b[0]), "r"(b[1]));
}

__device__ __forceinline__ void cp16(uint32_t saddr, const void* gmem, bool pred)
{
    int sz = pred ? 16 : 0;
    asm volatile("cp.async.cg.shared.global [%0], [%1], 16, %2;\n"
                 :: "r"(saddr), "l"(gmem), "r"(sz));
}

// ---------------- generic f32 -> split-bf16 pass (weights only) -----------------
__global__ __launch_bounds__(256)
void split_kernel(const float2* __restrict__ in, uint32_t* __restrict__ hi,
                  uint32_t* __restrict__ lo, size_t npairs)
{
    size_t i = (size_t)blockIdx.x * blockDim.x + threadIdx.x;
    if (i >= npairs) return;
    float2 v = in[i];
    hi[i] = pack_hi(v.x, v.y);
    lo[i] = pack_lo(v.x, v.y);
}

// ---------------- CSR build ------------------------------------------------------
__global__ __launch_bounds__(256)
void hist_kernel(const int* __restrict__ dst, int* __restrict__ deg)
{
    int i = blockIdx.x * 256 + threadIdx.x;
    if (i >= 3 * EE) return;
    int v = i / EE;
    atomicAdd(&deg[v * NN + dst[i]], 1);
}

// one block per view, 1024 threads; exclusive scan of deg -> rowptr + cursor
__global__ __launch_bounds__(1024)
void scan_kernel(const int* __restrict__ deg, int* __restrict__ rowptr,
                 int* __restrict__ cursor)
{
    const int CH = (NN + 1023) / 1024;   // 49
    int v = blockIdx.x;
    const int* d = deg + v * NN;
    int* rp = rowptr + v * (NN + 1);
    int* cur = cursor + v * NN;
    int t = threadIdx.x;
    int lane = t & 31, w = t >> 5;
    __shared__ int warpsums[32];

    int base = t * CH;
    int local[CH];
    int sum = 0;
#pragma unroll
    for (int k = 0; k < CH; ++k) {
        int idx = base + k;
        int val = (idx < NN) ? d[idx] : 0;
        local[k] = sum;
        sum += val;
    }
    int s = sum;
#pragma unroll
    for (int o = 1; o < 32; o <<= 1) {
        int y = __shfl_up_sync(0xffffffffu, s, o);
        if (lane >= o) s += y;
    }
    if (lane == 31) warpsums[w] = s;
    __syncthreads();
    if (w == 0) {
        int ws = warpsums[lane];
#pragma unroll
        for (int o = 1; o < 32; o <<= 1) {
            int y = __shfl_up_sync(0xffffffffu, ws, o);
            if (lane >= o) ws += y;
        }
        warpsums[lane] = ws;
    }
    __syncthreads();
    int offset = (w > 0 ? warpsums[w - 1] : 0) + (s - sum);
#pragma unroll
    for (int k = 0; k < CH; ++k) {
        int idx = base + k;
        if (idx < NN) {
            int val = offset + local[k];
            rp[idx] = val;
            cur[idx] = val;
        }
    }
    if (t == 1023) rp[NN] = EE;
}

__global__ __launch_bounds__(256)
void scatter_kernel(const int* __restrict__ src, const int* __restrict__ dst,
                    const float* __restrict__ vals, int* __restrict__ cursor,
                    int* __restrict__ esrc, float* __restrict__ eval_)
{
    int i = blockIdx.x * 256 + threadIdx.x;
    if (i >= 3 * EE) return;
    int v = i / EE;
    int d = dst[i];
    int pos = atomicAdd(&cursor[v * NN + d], 1);
    esrc[(size_t)v * EE + pos] = src[i];
    eval_[(size_t)v * EE + pos] = vals[i];
}

// ---------------- CSR SpMM + bias + PReLU + split-bf16 emit ---------------------
// grid: (NN*64/256, 3). thread -> (node, float4-chunk); accumulate in regs, write once.
__global__ __launch_bounds__(256)
void spmm_csr_kernel(const float4* __restrict__ ft, const int* __restrict__ rowptr,
                     const int* __restrict__ esrc, const float* __restrict__ eval_,
                     float4* __restrict__ z, uint32_t* __restrict__ zhi,
                     uint32_t* __restrict__ zlo, const float* __restrict__ b_all,
                     const float* __restrict__ a_all)
{
    int gid = blockIdx.x * 256 + threadIdx.x;
    if (gid >= NN * 64) return;
    int v = blockIdx.y;
    int n = gid >> 6;
    int c = gid & 63;
    const int* rp = rowptr + v * (NN + 1);
    int i  = rp[n];
    int s1 = rp[n + 1];
    const int*   es = esrc  + (size_t)v * EE;
    const float* ev = eval_ + (size_t)v * EE;
    const size_t cbase = (size_t)v * 64 + c;

    float4 acc = make_float4(0.f, 0.f, 0.f, 0.f);
    for (; i + 2 <= s1; i += 2) {
        int sa = es[i];     float va = ev[i];
        int sb = es[i + 1]; float vb = ev[i + 1];
        float4 fa = ft[(size_t)sa * (3 * HH / 4) + cbase];
        float4 fb = ft[(size_t)sb * (3 * HH / 4) + cbase];
        acc.x += va * fa.x; acc.y += va * fa.y; acc.z += va * fa.z; acc.w += va * fa.w;
        acc.x += vb * fb.x; acc.y += vb * fb.y; acc.z += vb * fb.z; acc.w += vb * fb.w;
    }
    if (i < s1) {
        int sa = es[i]; float va = ev[i];
        float4 fa = ft[(size_t)sa * (3 * HH / 4) + cbase];
        acc.x += va * fa.x; acc.y += va * fa.y; acc.z += va * fa.z; acc.w += va * fa.w;
    }

    float a = a_all[v];
    float4 bv = *(const float4*)(b_all + v * HH + (c << 2));
    acc.x += bv.x; acc.y += bv.y; acc.z += bv.z; acc.w += bv.w;
    acc.x = acc.x >= 0.f ? acc.x : a * acc.x;
    acc.y = acc.y >= 0.f ? acc.y : a * acc.y;
    acc.z = acc.z >= 0.f ? acc.z : a * acc.z;
    acc.w = acc.w >= 0.f ? acc.w : a * acc.w;

    size_t idx = (size_t)v * NN * 64 + (size_t)n * 64 + c;
    z[idx] = acc;
    size_t p = idx << 1;
    zhi[p]     = pack_hi(acc.x, acc.y);
    zhi[p + 1] = pack_hi(acc.z, acc.w);
    zlo[p]     = pack_lo(acc.x, acc.y);
    zlo[p + 1] = pack_lo(acc.z, acc.w);
}

// ---------------- split-bf16 GEMM ------------------------------------------------
// Block tile 128x128, BK=16 (8 bf16x2 pairs), 8 warps (2m x 4n), warp tile 64x32.
// 3 MMAs per atom: lo*hi + hi*lo + hi*hi (lo*lo dropped, ~2^-17 rel).
#define TBM 128
#define TBN 128
#define TPAD 12

#define GS_DECL()                                                                   \
    __shared__ uint32_t AsH[2][TBM][TPAD];                                          \
    __shared__ uint32_t AsL[2][TBM][TPAD];                                          \
    __shared__ uint32_t WsH[2][TBN][TPAD];                                          \
    __shared__ uint32_t WsL[2][TBN][TPAD];                                          \
    const int tid  = threadIdx.x;                                                   \
    const int wid  = tid >> 5;                                                      \
    const int lane = tid & 31;                                                      \
    const int g    = lane >> 2;                                                     \
    const int t    = lane & 3;                                                      \
    const int wm   = (wid & 1) << 6;                                                \
    const int wn   = (wid >> 1) << 5;                                               \
    const int bm   = blockIdx.y * TBM;                                              \
    const int bn   = blockIdx.x * TBN;                                              \
    float acc[4][4][4] = {};

#define GS_LOAD(S, KP0)                                                             \
    {                                                                               \
        int r  = tid >> 1, ch = (tid & 1) << 2;                                     \
        int gp = (KP0) + ch;                                                        \
        bool pa = (gp < Kp) && (bm + r < M);                                        \
        size_t offa = (size_t)(bm + r) * Kp + gp;                                   \
        cp16((uint32_t)__cvta_generic_to_shared(&AsH[S][r][ch]), Ahi + offa, pa);   \
        cp16((uint32_t)__cvta_generic_to_shared(&AsL[S][r][ch]), Alo + offa, pa);   \
        bool pb = (gp < Kp);                                                        \
        size_t offb = (size_t)(bn + r) * Kp + gp;                                   \
        cp16((uint32_t)__cvta_generic_to_shared(&WsH[S][r][ch]), Whi + offb, pb);   \
        cp16((uint32_t)__cvta_generic_to_shared(&WsL[S][r][ch]), Wlo + offb, pb);   \
    }

// A loaded as raw f32 and split in registers (for feats GEMM; kills split pass)
#define GS_LOAD_AF32(S, KP0)                                                        \
    {                                                                               \
        int r  = tid >> 1, ch = (tid & 1) << 2;                                     \
        int gp = (KP0) + ch;                                                        \
        float4 f0 = make_float4(0.f, 0.f, 0.f, 0.f), f1 = f0;                       \
        if (gp < Kp && bm + r < M) {                                                \
            const float* ap = Af32 + (size_t)(bm + r) * (Kp * 2) + gp * 2;          \
            f0 = *(const float4*)ap;                                                \
            f1 = *(const float4*)(ap + 4);                                          \
        }                                                                           \
        AsH[S][r][ch + 0] = pack_hi(f0.x, f0.y); AsL[S][r][ch + 0] = pack_lo(f0.x, f0.y); \
        AsH[S][r][ch + 1] = pack_hi(f0.z, f0.w); AsL[S][r][ch + 1] = pack_lo(f0.z, f0.w); \
        AsH[S][r][ch + 2] = pack_hi(f1.x, f1.y); AsL[S][r][ch + 2] = pack_lo(f1.x, f1.y); \
        AsH[S][r][ch + 3] = pack_hi(f1.z, f1.w); AsL[S][r][ch + 3] = pack_lo(f1.z, f1.w); \
        bool pb = (gp < Kp);                                                        \
        size_t offb = (size_t)(bn + r) * Kp + gp;                                   \
        cp16((uint32_t)__cvta_generic_to_shared(&WsH[S][r][ch]), Whi + offb, pb);   \
        cp16((uint32_t)__cvta_generic_to_shared(&WsL[S][r][ch]), Wlo + offb, pb);   \
    }

#define GS_COMPUTE()                                                                \
    {                                                                               \
        uint32_t aH[4][4], aL[4][4], bH[4][2], bL[4][2];                            \
        _Pragma("unroll")                                                           \
        for (int i = 0; i < 4; ++i) {                                               \
            int rb = wm + (i << 4);                                                 \
            aH[i][0] = AsH[buf][rb + g    ][t    ];                                 \
            aH[i][1] = AsH[buf][rb + g + 8][t    ];                                 \
            aH[i][2] = AsH[buf][rb + g    ][t + 4];                                 \
            aH[i][3] = AsH[buf][rb + g + 8][t + 4];                                 \
            aL[i][0] = AsL[buf][rb + g    ][t    ];                                 \
            aL[i][1] = AsL[buf][rb + g + 8][t    ];                                 \
            aL[i][2] = AsL[buf][rb + g    ][t + 4];                                 \
            aL[i][3] = AsL[buf][rb + g + 8][t + 4];                                 \
        }                                                                           \
        _Pragma("unroll")                                                           \
        for (int j = 0; j < 4; ++j) {                                               \
            int nb = wn + (j << 3);                                                 \
            bH[j][0] = WsH[buf][nb + g][t    ];                                     \
            bH[j][1] = WsH[buf][nb + g][t + 4];                                     \
            bL[j][0] = WsL[buf][nb + g][t    ];                                     \
            bL[j][1] = WsL[buf][nb + g][t + 4];                                     \
        }                                                                           \
        _Pragma("unroll")                                                           \
        for (int i = 0; i < 4; ++i)                                                 \
            _Pragma("unroll")                                                       \
            for (int j = 0; j < 4; ++j) {                                           \
                mma_bf16(acc[i][j], aL[i], bH[j]);                                  \
                mma_bf16(acc[i][j], aH[i], bL[j]);                                  \
                mma_bf16(acc[i][j], aH[i], bH[j]);                                  \
            }                                                                       \
    }

#define GS_MAINLOOP(LOADM)                                                          \
    LOADM(0, 0);                                                                    \
    asm volatile("cp.async.commit_group;\n" ::: "memory");                          \
    int buf = 0;                                                                    \
    for (int kp0 = 0; kp0 < Kp; kp0 += 8) {                                         \
        if (kp0 + 8 < Kp) LOADM(buf ^ 1, kp0 + 8);                                  \
        asm volatile("cp.async.commit_group;\n" ::: "memory");                      \
        asm volatile("cp.async.wait_group 1;\n" ::: "memory");                      \
        __syncthreads();                                                            \
        GS_COMPUTE();                                                               \
        __syncthreads();                                                            \
        buf ^= 1;                                                                   \
    }

// EPI: 0 = raw f32, 2 = bias f32
template<int EPI>
__global__ __launch_bounds__(256, 2)
void gemm_bf16s_kernel(const uint32_t* __restrict__ Ahi, const uint32_t* __restrict__ Alo,
                       const uint32_t* __restrict__ Whi, const uint32_t* __restrict__ Wlo,
                       const float* __restrict__ bias, float* __restrict__ C,
                       int M, int Nc, int Kp)
{
    GS_DECL();
    GS_MAINLOOP(GS_LOAD);

#pragma unroll
    for (int i = 0; i < 4; ++i) {
#pragma unroll
        for (int j = 0; j < 4; ++j) {
            int r0 = bm + wm + (i << 4) + g;
            int r1 = r0 + 8;
            int c0 = bn + wn + (j << 3) + (t << 1);
            float bx = 0.f, by = 0.f;
            if (EPI == 2) { bx = bias[c0]; by = bias[c0 + 1]; }
            float v0 = acc[i][j][0] + bx, v1 = acc[i][j][1] + by;
            float v2 = acc[i][j][2] + bx, v3 = acc[i][j][3] + by;
            if (r0 < M) *(float2*)(C + (size_t)r0 * Nc + c0) = make_float2(v0, v1);
            if (r1 < M) *(float2*)(C + (size_t)r1 * Nc + c0) = make_float2(v2, v3);
        }
    }
}

// feats GEMM: A = raw f32, epilogue bias+ELU -> split bf16 h
__global__ __launch_bounds__(256, 2)
void gemm_bf16s_af32_kernel(const float* __restrict__ Af32,
                            const uint32_t* __restrict__ Whi, const uint32_t* __restrict__ Wlo,
                            const float* __restrict__ bias,
                            uint32_t* __restrict__ Chi, uint32_t* __restrict__ Clo,
                            int M, int Nc, int Kp)
{
    GS_DECL();
    GS_MAINLOOP(GS_LOAD_AF32);

#pragma unroll
    for (int i = 0; i < 4; ++i) {
#pragma unroll
        for (int j = 0; j < 4; ++j) {
            int r0 = bm + wm + (i << 4) + g;
            int r1 = r0 + 8;
            int c0 = bn + wn + (j << 3) + (t << 1);
            float bx = bias[c0], by = bias[c0 + 1];
            float v0 = acc[i][j][0] + bx, v1 = acc[i][j][1] + by;
            float v2 = acc[i][j][2] + bx, v3 = acc[i][j][3] + by;
            v0 = v0 > 0.f ? v0 : expm1f(v0);
            v1 = v1 > 0.f ? v1 : expm1f(v1);
            v2 = v2 > 0.f ? v2 : expm1f(v2);
            v3 = v3 > 0.f ? v3 : expm1f(v3);
            int pc = c0 >> 1;
            if (r0 < M) {
                Chi[(size_t)r0 * (Nc / 2) + pc] = pack_hi(v0, v1);
                Clo[(size_t)r0 * (Nc / 2) + pc] = pack_lo(v0, v1);
            }
            if (r1 < M) {
                Chi[(size_t)r1 * (Nc / 2) + pc] = pack_hi(v2, v3);
                Clo[(size_t)r1 * (Nc / 2) + pc] = pack_lo(v2, v3);
            }
        }
    }
}

// fused attention GEMM over all 3 views: blockIdx.z = storage view (z0,z1,z2)
// beta index: view0(student)->2, view1->0, view2->1
// Reduction scratch aliases AsH (dead after mainloop) to stay within 48 KB smem.
__global__ __launch_bounds__(256, 2)
void gemm_att_bf16s_kernel(const uint32_t* __restrict__ Zhi, const uint32_t* __restrict__ Zlo,
                           const uint32_t* __restrict__ Whi, const uint32_t* __restrict__ Wlo,
                           const float* __restrict__ bias, const float* __restrict__ att,
                           float* __restrict__ beta_raw, int M, int Kp)
{
    const int view = blockIdx.z;
    const uint32_t* Ahi = Zhi + (size_t)view * NN * (HH / 2);
    const uint32_t* Alo = Zlo + (size_t)view * NN * (HH / 2);

    GS_DECL();
    GS_MAINLOOP(GS_LOAD);

    float s = 0.f;
#pragma unroll
    for (int i = 0; i < 4; ++i) {
#pragma unroll
        for (int j = 0; j < 4; ++j) {
            int r0 = bm + wm + (i << 4) + g;
            int r1 = r0 + 8;
            int c0 = bn + wn + (j << 3) + (t << 1);
            float bx = bias[c0], by = bias[c0 + 1];
            float ax = att[c0],  ay = att[c0 + 1];
            if (r0 < M) s += tanhf(acc[i][j][0] + bx) * ax + tanhf(acc[i][j][1] + by) * ay;
            if (r1 < M) s += tanhf(acc[i][j][2] + bx) * ax + tanhf(acc[i][j][3] + by) * ay;
        }
    }
    float* red = (float*)&AsH[0][0][0];   // reuse pipeline smem (dead now)
    __syncthreads();
    red[tid] = s;
    __syncthreads();
    for (int o = 128; o > 0; o >>= 1) {
        if (tid < o) red[tid] += red[tid + o];
        __syncthreads();
    }
    if (tid == 0) {
        int bidx = (view + 2) % 3;
        atomicAdd(&beta_raw[bidx], red[0]);
    }
}

// ---------------- BN column stats -----------------------------------------------
__global__ __launch_bounds__(256)
void colstats_kernel(const float* __restrict__ x, float* __restrict__ stats)
{
    int c = blockIdx.x * 256 + threadIdx.x;
    float s = 0.f, sq = 0.f;
    for (int r = blockIdx.y; r < NN; r += gridDim.y) {
        float v = x[(size_t)r * PHH + c];
        s += v;
        sq += v * v;
    }
    atomicAdd(&stats[c], s);
    atomicAdd(&stats[PHH + c], sq);
}

// ---------------- BN + PReLU -> split-bf16 output -------------------------------
__global__ __launch_bounds__(256)
void bn_prelu_kernel(const float4* __restrict__ x, uint32_t* __restrict__ xhi,
                     uint32_t* __restrict__ xlo, const float* __restrict__ stats,
                     const float* __restrict__ g, const float* __restrict__ b,
                     const float* __restrict__ a_ptr)
{
    int i = blockIdx.x * blockDim.x + threadIdx.x;
    if (i >= NN * (PHH / 4)) return;
    int c = (i & (PHH / 4 - 1)) << 2;
    float a = *a_ptr;
    float4 sm = *(const float4*)(stats + c);
    float4 sq = *(const float4*)(stats + PHH + c);
    float4 gv = *(const float4*)(g + c);
    float4 bv = *(const float4*)(b + c);
    float4 v = x[i];
    float invN = 1.f / (float)NN;

    float mu, var, sc, sh, y;
    mu = sm.x * invN; var = sq.x * invN - mu * mu; sc = gv.x * rsqrtf(var + BN_EPS);
    sh = bv.x - mu * sc; y = v.x * sc + sh; v.x = y >= 0.f ? y : a * y;
    mu = sm.y * invN; var = sq.y * invN - mu * mu; sc = gv.y * rsqrtf(var + BN_EPS);
    sh = bv.y - mu * sc; y = v.y * sc + sh; v.y = y >= 0.f ? y : a * y;
    mu = sm.z * invN; var = sq.z * invN - mu * mu; sc = gv.z * rsqrtf(var + BN_EPS);
    sh = bv.z - mu * sc; y = v.z * sc + sh; v.z = y >= 0.f ? y : a * y;
    mu = sm.w * invN; var = sq.w * invN - mu * mu; sc = gv.w * rsqrtf(var + BN_EPS);
    sh = bv.w - mu * sc; y = v.w * sc + sh; v.w = y >= 0.f ? y : a * y;

    size_t p = (size_t)i << 1;
    xhi[p]     = pack_hi(v.x, v.y);
    xhi[p + 1] = pack_hi(v.z, v.w);
    xlo[p]     = pack_lo(v.x, v.y);
    xlo[p + 1] = pack_lo(v.z, v.w);
}

// ---------------- cosine loss accumulation (one warp per node) ------------------
__global__ __launch_bounds__(256)
void loss_kernel(const float4* __restrict__ p, const float4* __restrict__ t1,
                 const float4* __restrict__ t2, float* __restrict__ acc)
{
    int gid  = blockIdx.x * blockDim.x + threadIdx.x;
    int node = gid >> 5;
    int lane = gid & 31;
    float pp = 0.f, n1 = 0.f, n2 = 0.f, d1 = 0.f, d2 = 0.f;
    if (node < NN) {
        size_t base = (size_t)node * 64;
#pragma unroll
        for (int r = 0; r < 2; ++r) {
            float4 a  = p [base + lane + 32 * r];
            float4 b  = t1[base + lane + 32 * r];
            float4 cc = t2[base + lane + 32 * r];
            pp += a.x * a.x + a.y * a.y + a.z * a.z + a.w * a.w;
            n1 += b.x * b.x + b.y * b.y + b.z * b.z + b.w * b.w;
            n2 += cc.x * cc.x + cc.y * cc.y + cc.z * cc.z + cc.w * cc.w;
            d1 += a.x * b.x + a.y * b.y + a.z * b.z + a.w * b.w;
            d2 += a.x * cc.x + a.y * cc.y + a.z * cc.z + a.w * cc.w;
        }
    }
#pragma unroll
    for (int o = 16; o > 0; o >>= 1) {
        pp += __shfl_down_sync(0xffffffffu, pp, o);
        n1 += __shfl_down_sync(0xffffffffu, n1, o);
        n2 += __shfl_down_sync(0xffffffffu, n2, o);
        d1 += __shfl_down_sync(0xffffffffu, d1, o);
        d2 += __shfl_down_sync(0xffffffffu, d2, o);
    }
    __shared__ float sacc[8];
    float contrib = 0.f;
    if (lane == 0 && node < NN) {
        float np  = fmaxf(sqrtf(pp), 1e-12f);
        float nn1 = fmaxf(sqrtf(n1), 1e-12f);
        float nn2 = fmaxf(sqrtf(n2), 1e-12f);
        contrib = d1 / (np * nn1) + d2 / (np * nn2);
    }
    int wid = threadIdx.x >> 5;
    if (lane == 0) sacc[wid] = contrib;
    __syncthreads();
    if (threadIdx.x == 0) {
        float s = 0.f;
#pragma unroll
        for (int i = 0; i < 8; ++i) s += sacc[i];
        atomicAdd(acc, s);
    }
}

// ---------------- finalize: softmax(beta), loss --------------------------------
__global__ void finalize_kernel(float* __restrict__ out_loss, int write_loss)
{
    float invN = 1.f / (float)NN;
    float b0 = g_beta_raw[0] * invN;
    float b1 = g_beta_raw[1] * invN;
    float b2 = g_beta_raw[2] * invN;
    float m = fmaxf(b0, fmaxf(b1, b2));
    float e0 = expf(b0 - m), e1 = expf(b1 - m), e2 = expf(b2 - m);
    float s = e0 + e1 + e2;
    g_beta[0] = e0 / s;
    g_beta[1] = e1 / s;
    g_beta[2] = e2 / s;
    if (write_loss) *out_loss = 2.0f - g_loss_acc * invN;
}

// ---------------- z_out = b0*z1 + b1*z2 + b2*z0 ---------------------------------
__global__ __launch_bounds__(256)
void zout_kernel(float4* __restrict__ out, const float4* __restrict__ z1,
                 const float4* __restrict__ z2, const float4* __restrict__ z0)
{
    int i = blockIdx.x * blockDim.x + threadIdx.x;
    if (i >= NN * 64) return;
    float b0 = g_beta[0], b1 = g_beta[1], b2 = g_beta[2];
    float4 a = z1[i], b = z2[i], c = z0[i];
    float4 r;
    r.x = b0 * a.x + b1 * b.x + b2 * c.x;
    r.y = b0 * a.y + b1 * b.y + b2 * c.y;
    r.z = b0 * a.z + b1 * b.z + b2 * c.z;
    r.w = b0 * a.w + b1 * b.w + b2 * c.w;
    out[i] = r;
}

// ---------------- host ----------------------------------------------------------
#define GETSYM(var, sym) cudaGetSymbolAddress((void**)&var, sym)

extern "C" void kernel_launch(void* const* d_in, const int* in_sizes, int n_in,
                              void* d_out, int out_size)
{
    const float* feats   = (const float*)d_in[0];
    const int*   src     = (const int*)  d_in[1];
    const int*   dst     = (const int*)  d_in[2];
    const float* vals    = (const float*)d_in[3];
    const float* W_trans = (const float*)d_in[4];
    const float* b_trans = (const float*)d_in[5];
    const float* W_gcn   = (const float*)d_in[6];
    const float* b_gcn   = (const float*)d_in[7];
    const float* a_gcn   = (const float*)d_in[8];
    const float* W1      = (const float*)d_in[9];
    const float* b1      = (const float*)d_in[10];
    const float* bn_g    = (const float*)d_in[11];
    const float* bn_b    = (const float*)d_in[12];
    const float* a_pred  = (const float*)d_in[13];
    const float* W2      = (const float*)d_in[14];
    const float* b2      = (const float*)d_in[15];
    const float* W_att   = (const float*)d_in[16];
    const float* b_att   = (const float*)d_in[17];
    const float* att     = (const float*)d_in[18];

    uint32_t *h_hi, *h_lo, *zh, *zl;
    uint32_t *x_hi, *x_lo, *wt_hi, *wt_lo, *wg_hi, *wg_lo, *w1_hi, *w1_lo;
    uint32_t *w2_hi, *w2_lo, *wa_hi, *wa_lo;
    float *ft, *z, *x, *vp, *stats, *beta_raw, *loss_acc;
    int *deg, *rowptr, *cursor, *esrc;
    float *eval_;
    GETSYM(h_hi, g_h_hi);   GETSYM(h_lo, g_h_lo);
    GETSYM(zh, g_z_hi); GETSYM(zl, g_z_lo);
    GETSYM(x_hi, g_x_hi); GETSYM(x_lo, g_x_lo);
    GETSYM(wt_hi, g_wt_hi); GETSYM(wt_lo, g_wt_lo);
    GETSYM(wg_hi, g_wg_hi); GETSYM(wg_lo, g_wg_lo);
    GETSYM(w1_hi, g_w1_hi); GETSYM(w1_lo, g_w1_lo);
    GETSYM(w2_hi, g_w2_hi); GETSYM(w2_lo, g_w2_lo);
    GETSYM(wa_hi, g_wa_hi); GETSYM(wa_lo, g_wa_lo);
    GETSYM(ft, g_ft); GETSYM(z, g_z);
    GETSYM(x, g_x);   GETSYM(vp, g_vp);
    GETSYM(stats, g_stats); GETSYM(beta_raw, g_beta_raw); GETSYM(loss_acc, g_loss_acc);
    GETSYM(deg, g_deg); GETSYM(rowptr, g_rowptr); GETSYM(cursor, g_cursor);
    GETSYM(esrc, g_esrc); GETSYM(eval_, g_eval);

    float* z0 = z;                           // view0 = student
    float* z1 = z + (size_t)NN * HH;         // view1 = teacher1
    float* z2 = z + (size_t)2 * NN * HH;     // view2 = teacher2
    uint32_t* z0h = zh;
    uint32_t* z0l = zl;

    cudaMemsetAsync(deg, 0, 3 * NN * sizeof(int));
    cudaMemsetAsync(stats, 0, 2 * PHH * sizeof(float));
    cudaMemsetAsync(beta_raw, 0, 3 * sizeof(float));
    cudaMemsetAsync(loss_acc, 0, sizeof(float));

    // CSR build (all 3 views)
    hist_kernel<<<(3 * EE + 255) / 256, 256>>>(dst, deg);
    scan_kernel<<<3, 1024>>>(deg, rowptr, cursor);
    scatter_kernel<<<(3 * EE + 255) / 256, 256>>>(src, dst, vals, cursor, esrc, eval_);

    // split weights -> bf16 hi/lo (small, L2-resident)
    {
        size_t np = (size_t)HH * (FEATD / 2);
        split_kernel<<<(int)((np + 255) / 256), 256>>>((const float2*)W_trans, wt_hi, wt_lo, np);
        np = (size_t)3 * HH * (HH / 2);
        split_kernel<<<(int)((np + 255) / 256), 256>>>((const float2*)W_gcn, wg_hi, wg_lo, np);
        np = (size_t)PHH * (HH / 2);
        split_kernel<<<(int)((np + 255) / 256), 256>>>((const float2*)W1, w1_hi, w1_lo, np);
        np = (size_t)HH * (PHH / 2);
        split_kernel<<<(int)((np + 255) / 256), 256>>>((const float2*)W2, w2_hi, w2_lo, np);
        np = (size_t)HH * (HH / 2);
        split_kernel<<<(int)((np + 255) / 256), 256>>>((const float2*)W_att, wa_hi, wa_lo, np);
    }

    const int mb = (NN + TBM - 1) / TBM;   // 391

    // h = elu(feats @ W_trans^T + b_trans): A read as f32, split in-kernel
    gemm_bf16s_af32_kernel<<<dim3(HH / TBN, mb), 256>>>(
        feats, wt_hi, wt_lo, b_trans, h_hi, h_lo, NN, HH, FEATD / 2);

    // fused GCN GEMM: ft[N, 768] = h @ [W_gcn0;W_gcn1;W_gcn2]^T
    gemm_bf16s_kernel<0><<<dim3(3 * HH / TBN, mb), 256>>>(
        h_hi, h_lo, wg_hi, wg_lo, nullptr, ft, NN, 3 * HH, HH / 2);

    // CSR SpMM + bias + prelu + split emission, all 3 views
    spmm_csr_kernel<<<dim3((NN * 64 + 255) / 256, 3), 256>>>(
        (const float4*)ft, rowptr, esrc, eval_, (float4*)z, zh, zl, b_gcn, a_gcn);

    // student predictor
    gemm_bf16s_kernel<2><<<dim3(PHH / TBN, mb), 256>>>(
        z0h, z0l, w1_hi, w1_lo, b1, x, NN, PHH, HH / 2);
    colstats_kernel<<<dim3(2, 512), 256>>>(x, stats);
    bn_prelu_kernel<<<(NN * PHH / 4) / 256, 256>>>((const float4*)x, x_hi, x_lo,
                                                   stats, bn_g, bn_b, a_pred);
    gemm_bf16s_kernel<2><<<dim3(HH / TBN, mb), 256>>>(
        x_hi, x_lo, w2_hi, w2_lo, b2, vp, NN, HH, PHH / 2);

    // cosine losses vs teachers (views 1 and 2)
    loss_kernel<<<(NN * 32) / 256, 256>>>((const float4*)vp, (const float4*)z1,
                                          (const float4*)z2, loss_acc);

    // type-level attention, all 3 views in one launch
    gemm_att_bf16s_kernel<<<dim3(HH / TBN, mb, 3), 256>>>(zh, zl, wa_hi, wa_lo,
                                                          b_att, att, beta_raw, NN, HH / 2);

    float* outf = (float*)d_out;
    int write_loss = (out_size > NN * HH) ? 1 : 0;
    finalize_kernel<<<1, 1>>>(outf + (size_t)NN * HH, write_loss);
    zout_kernel<<<(NN * 64) / 256, 256>>>((float4*)outf, (const float4*)z1,
                                          (const float4*)z2, (const float4*)z0);
}

// round 10
// speedup vs baseline: 1.3331x; 1.0018x over previous
#include <cuda_runtime.h>
#include <math.h>
#include <stdint.h>

// ---------------- problem constants ----------------
#define NN   50000
#define PP   3
#define EE   800000
#define FEATD 1000
#define HH   256
#define PHH  512
#define BN_EPS 1e-5f

// ---------------- device scratch (no allocations allowed) ----------------
__device__ uint32_t g_h_hi [(size_t)NN * (HH / 2)];
__device__ uint32_t g_h_lo [(size_t)NN * (HH / 2)];
__device__ float    g_ft[(size_t)3 * NN * HH];         // view-major [3][N][256]
__device__ float    g_z   [(size_t)3 * NN * HH];       // z0|z1|z2 contiguous
__device__ uint32_t g_z_hi[(size_t)3 * NN * (HH / 2)];
__device__ uint32_t g_z_lo[(size_t)3 * NN * (HH / 2)];
__device__ float    g_x [(size_t)NN * PHH];
__device__ uint32_t g_x_hi[(size_t)NN * (PHH / 2)];
__device__ uint32_t g_x_lo[(size_t)NN * (PHH / 2)];
__device__ float    g_vp[(size_t)NN * HH];
// CSR scratch
__device__ int   g_deg[3 * NN];
__device__ int   g_rowptr[3 * (NN + 1)];
__device__ int   g_cursor[3 * NN];
__device__ int   g_esrc[(size_t)3 * EE];
__device__ float g_eval[(size_t)3 * EE];
// split weights
__device__ uint32_t g_wt_hi[HH * (FEATD / 2)];
__device__ uint32_t g_wt_lo[HH * (FEATD / 2)];
__device__ uint32_t g_wg_hi[3 * HH * (HH / 2)];
__device__ uint32_t g_wg_lo[3 * HH * (HH / 2)];
__device__ uint32_t g_w1_hi[PHH * (HH / 2)];
__device__ uint32_t g_w1_lo[PHH * (HH / 2)];
__device__ uint32_t g_w2_hi[HH * (PHH / 2)];
__device__ uint32_t g_w2_lo[HH * (PHH / 2)];
__device__ uint32_t g_wa_hi[HH * (HH / 2)];
__device__ uint32_t g_wa_lo[HH * (HH / 2)];
__device__ float g_stats[2 * PHH];
__device__ float g_beta_raw[3];
__device__ float g_beta[3];
__device__ float g_loss_acc;

// ---------------- bf16 split helpers --------------------------------------------
__device__ __forceinline__ uint32_t pack_hi(float x0, float x1)
{
    uint32_t r;
    asm("prmt.b32 %0, %1, %2, 0x7632;"
        : "=r"(r) : "r"(__float_as_uint(x0)), "r"(__float_as_uint(x1)));
    return r;
}

__device__ __forceinline__ uint32_t pack_lo(float x0, float x1)
{
    float h0 = __uint_as_float(__float_as_uint(x0) & 0xFFFF0000u);
    float h1 = __uint_as_float(__float_as_uint(x1) & 0xFFFF0000u);
    uint32_t r;
    asm("cvt.rn.bf16x2.f32 %0, %1, %2;" : "=r"(r) : "f"(x1 - h1), "f"(x0 - h0));
    return r;
}

__device__ __forceinline__ void mma_bf16(float* c, const uint32_t* a, const uint32_t* b)
{
    asm volatile(
        "mma.sync.aligned.m16n8k16.row.col.f32.bf16.bf16.f32 "
        "{%0,%1,%2,%3}, {%4,%5,%6,%7}, {%8,%9}, {%0,%1,%2,%3};\n"
        : "+f"(c[0]), "+f"(c[1]), "+f"(c[2]), "+f"(c[3])
        : "r"(a[0]), "r"(a[1]), "r"(a[2]), "r"(a[3]), "r"(b[0]), "r"(b[1]));
}

__device__ __forceinline__ void cp16(uint32_t saddr, const void* gmem, bool pred)
{
    int sz = pred ? 16 : 0;
    asm volatile("cp.async.cg.shared.global [%0], [%1], 16, %2;\n"
                 :: "r"(saddr), "l"(gmem), "r"(sz));
}

// ---------------- generic f32 -> split-bf16 pass (weights only) -----------------
__global__ __launch_bounds__(256)
void split_kernel(const float2* __restrict__ in, uint32_t* __restrict__ hi,
                  uint32_t* __restrict__ lo, size_t npairs)
{
    size_t i = (size_t)blockIdx.x * blockDim.x + threadIdx.x;
    if (i >= npairs) return;
    float2 v = in[i];
    hi[i] = pack_hi(v.x, v.y);
    lo[i] = pack_lo(v.x, v.y);
}

// ---------------- CSR build ------------------------------------------------------
__global__ __launch_bounds__(256)
void hist_kernel(const int* __restrict__ dst, int* __restrict__ deg)
{
    int i = blockIdx.x * 256 + threadIdx.x;
    if (i >= 3 * EE) return;
    int v = i / EE;
    atomicAdd(&deg[v * NN + dst[i]], 1);
}

// one block per view, 1024 threads; exclusive scan of deg -> rowptr + cursor
__global__ __launch_bounds__(1024)
void scan_kernel(const int* __restrict__ deg, int* __restrict__ rowptr,
                 int* __restrict__ cursor)
{
    const int CH = (NN + 1023) / 1024;   // 49
    int v = blockIdx.x;
    const int* d = deg + v * NN;
    int* rp = rowptr + v * (NN + 1);
    int* cur = cursor + v * NN;
    int t = threadIdx.x;
    int lane = t & 31, w = t >> 5;
    __shared__ int warpsums[32];

    int base = t * CH;
    int local[CH];
    int sum = 0;
#pragma unroll
    for (int k = 0; k < CH; ++k) {
        int idx = base + k;
        int val = (idx < NN) ? d[idx] : 0;
        local[k] = sum;
        sum += val;
    }
    int s = sum;
#pragma unroll
    for (int o = 1; o < 32; o <<= 1) {
        int y = __shfl_up_sync(0xffffffffu, s, o);
        if (lane >= o) s += y;
    }
    if (lane == 31) warpsums[w] = s;
    __syncthreads();
    if (w == 0) {
        int ws = warpsums[lane];
#pragma unroll
        for (int o = 1; o < 32; o <<= 1) {
            int y = __shfl_up_sync(0xffffffffu, ws, o);
            if (lane >= o) ws += y;
        }
        warpsums[lane] = ws;
    }
    __syncthreads();
    int offset = (w > 0 ? warpsums[w - 1] : 0) + (s - sum);
#pragma unroll
    for (int k = 0; k < CH; ++k) {
        int idx = base + k;
        if (idx < NN) {
            int val = offset + local[k];
            rp[idx] = val;
            cur[idx] = val;
        }
    }
    if (t == 1023) rp[NN] = EE;
}

__global__ __launch_bounds__(256)
void scatter_kernel(const int* __restrict__ src, const int* __restrict__ dst,
                    const float* __restrict__ vals, int* __restrict__ cursor,
                    int* __restrict__ esrc, float* __restrict__ eval_)
{
    int i = blockIdx.x * 256 + threadIdx.x;
    if (i >= 3 * EE) return;
    int v = i / EE;
    int d = dst[i];
    int pos = atomicAdd(&cursor[v * NN + d], 1);
    esrc[(size_t)v * EE + pos] = src[i];
    eval_[(size_t)v * EE + pos] = vals[i];
}

// ---------------- CSR SpMM + bias + PReLU + split-bf16 emit (one view) ----------
// ftv is the view's contiguous [N][64] float4 slice (51 MB, L2-resident).
__global__ __launch_bounds__(256)
void spmm_csr_kernel(const float4* __restrict__ ftv, const int* __restrict__ rp,
                     const int* __restrict__ es, const float* __restrict__ ev,
                     float4* __restrict__ zv, uint32_t* __restrict__ zhiv,
                     uint32_t* __restrict__ zlov, const float* __restrict__ bvp,
                     const float* __restrict__ avp)
{
    int gid = blockIdx.x * 256 + threadIdx.x;
    if (gid >= NN * 64) return;
    int n = gid >> 6;
    int c = gid & 63;
    int i  = rp[n];
    int s1 = rp[n + 1];

    float4 acc = make_float4(0.f, 0.f, 0.f, 0.f);
    for (; i + 2 <= s1; i += 2) {
        int sa = es[i];     float va = ev[i];
        int sb = es[i + 1]; float vb = ev[i + 1];
        float4 fa = ftv[(size_t)sa * 64 + c];
        float4 fb = ftv[(size_t)sb * 64 + c];
        acc.x += va * fa.x; acc.y += va * fa.y; acc.z += va * fa.z; acc.w += va * fa.w;
        acc.x += vb * fb.x; acc.y += vb * fb.y; acc.z += vb * fb.z; acc.w += vb * fb.w;
    }
    if (i < s1) {
        int sa = es[i]; float va = ev[i];
        float4 fa = ftv[(size_t)sa * 64 + c];
        acc.x += va * fa.x; acc.y += va * fa.y; acc.z += va * fa.z; acc.w += va * fa.w;
    }

    float a = *avp;
    float4 bv = *(const float4*)(bvp + (c << 2));
    acc.x += bv.x; acc.y += bv.y; acc.z += bv.z; acc.w += bv.w;
    acc.x = acc.x >= 0.f ? acc.x : a * acc.x;
    acc.y = acc.y >= 0.f ? acc.y : a * acc.y;
    acc.z = acc.z >= 0.f ? acc.z : a * acc.z;
    acc.w = acc.w >= 0.f ? acc.w : a * acc.w;

    size_t idx = (size_t)n * 64 + c;
    zv[idx] = acc;
    size_t p = idx << 1;
    zhiv[p]     = pack_hi(acc.x, acc.y);
    zhiv[p + 1] = pack_hi(acc.z, acc.w);
    zlov[p]     = pack_lo(acc.x, acc.y);
    zlov[p + 1] = pack_lo(acc.z, acc.w);
}

// ---------------- split-bf16 GEMM ------------------------------------------------
// Block tile 128x128, BK=16 (8 bf16x2 pairs), 8 warps (2m x 4n), warp tile 64x32.
// 3 MMAs per atom: lo*hi + hi*lo + hi*hi (lo*lo dropped, ~2^-17 rel).
#define TBM 128
#define TBN 128
#define TPAD 12

#define GS_DECL()                                                                   \
    __shared__ uint32_t AsH[2][TBM][TPAD];                                          \
    __shared__ uint32_t AsL[2][TBM][TPAD];                                          \
    __shared__ uint32_t WsH[2][TBN][TPAD];                                          \
    __shared__ uint32_t WsL[2][TBN][TPAD];                                          \
    const int tid  = threadIdx.x;                                                   \
    const int wid  = tid >> 5;                                                      \
    const int lane = tid & 31;                                                      \
    const int g    = lane >> 2;                                                     \
    const int t    = lane & 3;                                                      \
    const int wm   = (wid & 1) << 6;                                                \
    const int wn   = (wid >> 1) << 5;                                               \
    const int bm   = blockIdx.y * TBM;                                              \
    const int bn   = blockIdx.x * TBN;                                              \
    float acc[4][4][4] = {};

#define GS_LOAD(S, KP0)                                                             \
    {                                                                               \
        int r  = tid >> 1, ch = (tid & 1) << 2;                                     \
        int gp = (KP0) + ch;                                                        \
        bool pa = (gp < Kp) && (bm + r < M);                                        \
        size_t offa = (size_t)(bm + r) * Kp + gp;                                   \
        cp16((uint32_t)__cvta_generic_to_shared(&AsH[S][r][ch]), Ahi + offa, pa);   \
        cp16((uint32_t)__cvta_generic_to_shared(&AsL[S][r][ch]), Alo + offa, pa);   \
        bool pb = (gp < Kp);                                                        \
        size_t offb = (size_t)(bn + r) * Kp + gp;                                   \
        cp16((uint32_t)__cvta_generic_to_shared(&WsH[S][r][ch]), Whi + offb, pb);   \
        cp16((uint32_t)__cvta_generic_to_shared(&WsL[S][r][ch]), Wlo + offb, pb);   \
    }

// A loaded as raw f32 and split in registers (for feats GEMM; kills split pass)
#define GS_LOAD_AF32(S, KP0)                                                        \
    {                                                                               \
        int r  = tid >> 1, ch = (tid & 1) << 2;                                     \
        int gp = (KP0) + ch;                                                        \
        float4 f0 = make_float4(0.f, 0.f, 0.f, 0.f), f1 = f0;                       \
        if (gp < Kp && bm + r < M) {                                                \
            const float* ap = Af32 + (size_t)(bm + r) * (Kp * 2) + gp * 2;          \
            f0 = *(const float4*)ap;                                                \
            f1 = *(const float4*)(ap + 4);                                          \
        }                                                                           \
        AsH[S][r][ch + 0] = pack_hi(f0.x, f0.y); AsL[S][r][ch + 0] = pack_lo(f0.x, f0.y); \
        AsH[S][r][ch + 1] = pack_hi(f0.z, f0.w); AsL[S][r][ch + 1] = pack_lo(f0.z, f0.w); \
        AsH[S][r][ch + 2] = pack_hi(f1.x, f1.y); AsL[S][r][ch + 2] = pack_lo(f1.x, f1.y); \
        AsH[S][r][ch + 3] = pack_hi(f1.z, f1.w); AsL[S][r][ch + 3] = pack_lo(f1.z, f1.w); \
        bool pb = (gp < Kp);                                                        \
        size_t offb = (size_t)(bn + r) * Kp + gp;                                   \
        cp16((uint32_t)__cvta_generic_to_shared(&WsH[S][r][ch]), Whi + offb, pb);   \
        cp16((uint32_t)__cvta_generic_to_shared(&WsL[S][r][ch]), Wlo + offb, pb);   \
    }

#define GS_COMPUTE()                                                                \
    {                                                                               \
        uint32_t aH[4][4], aL[4][4], bH[4][2], bL[4][2];                            \
        _Pragma("unroll")                                                           \
        for (int i = 0; i < 4; ++i) {                                               \
            int rb = wm + (i << 4);                                                 \
            aH[i][0] = AsH[buf][rb + g    ][t    ];                                 \
            aH[i][1] = AsH[buf][rb + g + 8][t    ];                                 \
            aH[i][2] = AsH[buf][rb + g    ][t + 4];                                 \
            aH[i][3] = AsH[buf][rb + g + 8][t + 4];                                 \
            aL[i][0] = AsL[buf][rb + g    ][t    ];                                 \
            aL[i][1] = AsL[buf][rb + g + 8][t    ];                                 \
            aL[i][2] = AsL[buf][rb + g    ][t + 4];                                 \
            aL[i][3] = AsL[buf][rb + g + 8][t + 4];                                 \
        }                                                                           \
        _Pragma("unroll")                                                           \
        for (int j = 0; j < 4; ++j) {                                               \
            int nb = wn + (j << 3);                                                 \
            bH[j][0] = WsH[buf][nb + g][t    ];                                     \
            bH[j][1] = WsH[buf][nb + g][t + 4];                                     \
            bL[j][0] = WsL[buf][nb + g][t    ];                                     \
            bL[j][1] = WsL[buf][nb + g][t + 4];                                     \
        }                                                                           \
        _Pragma("unroll")                                                           \
        for (int i = 0; i < 4; ++i)                                                 \
            _Pragma("unroll")                                                       \
            for (int j = 0; j < 4; ++j) {                                           \
                mma_bf16(acc[i][j], aL[i], bH[j]);                                  \
                mma_bf16(acc[i][j], aH[i], bL[j]);                                  \
                mma_bf16(acc[i][j], aH[i], bH[j]);                                  \
            }                                                                       \
    }

#define GS_MAINLOOP(LOADM)                                                          \
    LOADM(0, 0);                                                                    \
    asm volatile("cp.async.commit_group;\n" ::: "memory");                          \
    int buf = 0;                                                                    \
    for (int kp0 = 0; kp0 < Kp; kp0 += 8) {                                         \
        if (kp0 + 8 < Kp) LOADM(buf ^ 1, kp0 + 8);                                  \
        asm volatile("cp.async.commit_group;\n" ::: "memory");                      \
        asm volatile("cp.async.wait_group 1;\n" ::: "memory");                      \
        __syncthreads();                                                            \
        GS_COMPUTE();                                                               \
        __syncthreads();                                                            \
        buf ^= 1;                                                                   \
    }

// EPI: 0 = raw f32 (VIEWMAJ: out[v][r][c] with views 256 wide), 2 = bias f32
template<int EPI, int VIEWMAJ>
__global__ __launch_bounds__(256, 2)
void gemm_bf16s_kernel(const uint32_t* __restrict__ Ahi, const uint32_t* __restrict__ Alo,
                       const uint32_t* __restrict__ Whi, const uint32_t* __restrict__ Wlo,
                       const float* __restrict__ bias, float* __restrict__ C,
                       int M, int Nc, int Kp)
{
    GS_DECL();
    GS_MAINLOOP(GS_LOAD);

#pragma unroll
    for (int i = 0; i < 4; ++i) {
#pragma unroll
        for (int j = 0; j < 4; ++j) {
            int r0 = bm + wm + (i << 4) + g;
            int r1 = r0 + 8;
            int c0 = bn + wn + (j << 3) + (t << 1);
            float bx = 0.f, by = 0.f;
            if (EPI == 2) { bx = bias[c0]; by = bias[c0 + 1]; }
            float v0 = acc[i][j][0] + bx, v1 = acc[i][j][1] + by;
            float v2 = acc[i][j][2] + bx, v3 = acc[i][j][3] + by;
            if (VIEWMAJ) {
                int vv = c0 >> 8;
                int cc = c0 & 255;
                float* base = C + (size_t)vv * NN * HH + cc;
                if (r0 < M) *(float2*)(base + (size_t)r0 * HH) = make_float2(v0, v1);
                if (r1 < M) *(float2*)(base + (size_t)r1 * HH) = make_float2(v2, v3);
            } else {
                if (r0 < M) *(float2*)(C + (size_t)r0 * Nc + c0) = make_float2(v0, v1);
                if (r1 < M) *(float2*)(C + (size_t)r1 * Nc + c0) = make_float2(v2, v3);
            }
        }
    }
}

// feats GEMM: A = raw f32, epilogue bias+ELU -> split bf16 h
__global__ __launch_bounds__(256, 2)
void gemm_bf16s_af32_kernel(const float* __restrict__ Af32,
                            const uint32_t* __restrict__ Whi, const uint32_t* __restrict__ Wlo,
                            const float* __restrict__ bias,
                            uint32_t* __restrict__ Chi, uint32_t* __restrict__ Clo,
                            int M, int Nc, int Kp)
{
    GS_DECL();
    GS_MAINLOOP(GS_LOAD_AF32);

#pragma unroll
    for (int i = 0; i < 4; ++i) {
#pragma unroll
        for (int j = 0; j < 4; ++j) {
            int r0 = bm + wm + (i << 4) + g;
            int r1 = r0 + 8;
            int c0 = bn + wn + (j << 3) + (t << 1);
            float bx = bias[c0], by = bias[c0 + 1];
            float v0 = acc[i][j][0] + bx, v1 = acc[i][j][1] + by;
            float v2 = acc[i][j][2] + bx, v3 = acc[i][j][3] + by;
            v0 = v0 > 0.f ? v0 : expm1f(v0);
            v1 = v1 > 0.f ? v1 : expm1f(v1);
            v2 = v2 > 0.f ? v2 : expm1f(v2);
            v3 = v3 > 0.f ? v3 : expm1f(v3);
            int pc = c0 >> 1;
            if (r0 < M) {
                Chi[(size_t)r0 * (Nc / 2) + pc] = pack_hi(v0, v1);
                Clo[(size_t)r0 * (Nc / 2) + pc] = pack_lo(v0, v1);
            }
            if (r1 < M) {
                Chi[(size_t)r1 * (Nc / 2) + pc] = pack_hi(v2, v3);
                Clo[(size_t)r1 * (Nc / 2) + pc] = pack_lo(v2, v3);
            }
        }
    }
}

// fused attention GEMM over all 3 views: blockIdx.z = storage view (z0,z1,z2)
// beta index: view0(student)->2, view1->0, view2->1
// Reduction scratch aliases AsH (dead after mainloop) to stay within 48 KB smem.
__global__ __launch_bounds__(256, 2)
void gemm_att_bf16s_kernel(const uint32_t* __restrict__ Zhi, const uint32_t* __restrict__ Zlo,
                           const uint32_t* __restrict__ Whi, const uint32_t* __restrict__ Wlo,
                           const float* __restrict__ bias, const float* __restrict__ att,
                           float* __restrict__ beta_raw, int M, int Kp)
{
    const int view = blockIdx.z;
    const uint32_t* Ahi = Zhi + (size_t)view * NN * (HH / 2);
    const uint32_t* Alo = Zlo + (size_t)view * NN * (HH / 2);

    GS_DECL();
    GS_MAINLOOP(GS_LOAD);

    float s = 0.f;
#pragma unroll
    for (int i = 0; i < 4; ++i) {
#pragma unroll
        for (int j = 0; j < 4; ++j) {
            int r0 = bm + wm + (i << 4) + g;
            int r1 = r0 + 8;
            int c0 = bn + wn + (j << 3) + (t << 1);
            float bx = bias[c0], by = bias[c0 + 1];
            float ax = att[c0],  ay = att[c0 + 1];
            if (r0 < M) s += tanhf(acc[i][j][0] + bx) * ax + tanhf(acc[i][j][1] + by) * ay;
            if (r1 < M) s += tanhf(acc[i][j][2] + bx) * ax + tanhf(acc[i][j][3] + by) * ay;
        }
    }
    float* red = (float*)&AsH[0][0][0];   // reuse pipeline smem (dead now)
    __syncthreads();
    red[tid] = s;
    __syncthreads();
    for (int o = 128; o > 0; o >>= 1) {
        if (tid < o) red[tid] += red[tid + o];
        __syncthreads();
    }
    if (tid == 0) {
        int bidx = (view + 2) % 3;
        atomicAdd(&beta_raw[bidx], red[0]);
    }
}

// ---------------- BN column stats -----------------------------------------------
__global__ __launch_bounds__(256)
void colstats_kernel(const float* __restrict__ x, float* __restrict__ stats)
{
    int c = blockIdx.x * 256 + threadIdx.x;
    float s = 0.f, sq = 0.f;
    for (int r = blockIdx.y; r < NN; r += gridDim.y) {
        float v = x[(size_t)r * PHH + c];
        s += v;
        sq += v * v;
    }
    atomicAdd(&stats[c], s);
    atomicAdd(&stats[PHH + c], sq);
}

// ---------------- BN + PReLU -> split-bf16 output -------------------------------
__global__ __launch_bounds__(256)
void bn_prelu_kernel(const float4* __restrict__ x, uint32_t* __restrict__ xhi,
                     uint32_t* __restrict__ xlo, const float* __restrict__ stats,
                     const float* __restrict__ g, const float* __restrict__ b,
                     const float* __restrict__ a_ptr)
{
    int i = blockIdx.x * blockDim.x + threadIdx.x;
    if (i >= NN * (PHH / 4)) return;
    int c = (i & (PHH / 4 - 1)) << 2;
    float a = *a_ptr;
    float4 sm = *(const float4*)(stats + c);
    float4 sq = *(const float4*)(stats + PHH + c);
    float4 gv = *(const float4*)(g + c);
    float4 bv = *(const float4*)(b + c);
    float4 v = x[i];
    float invN = 1.f / (float)NN;

    float mu, var, sc, sh, y;
    mu = sm.x * invN; var = sq.x * invN - mu * mu; sc = gv.x * rsqrtf(var + BN_EPS);
    sh = bv.x - mu * sc; y = v.x * sc + sh; v.x = y >= 0.f ? y : a * y;
    mu = sm.y * invN; var = sq.y * invN - mu * mu; sc = gv.y * rsqrtf(var + BN_EPS);
    sh = bv.y - mu * sc; y = v.y * sc + sh; v.y = y >= 0.f ? y : a * y;
    mu = sm.z * invN; var = sq.z * invN - mu * mu; sc = gv.z * rsqrtf(var + BN_EPS);
    sh = bv.z - mu * sc; y = v.z * sc + sh; v.z = y >= 0.f ? y : a * y;
    mu = sm.w * invN; var = sq.w * invN - mu * mu; sc = gv.w * rsqrtf(var + BN_EPS);
    sh = bv.w - mu * sc; y = v.w * sc + sh; v.w = y >= 0.f ? y : a * y;

    size_t p = (size_t)i << 1;
    xhi[p]     = pack_hi(v.x, v.y);
    xhi[p + 1] = pack_hi(v.z, v.w);
    xlo[p]     = pack_lo(v.x, v.y);
    xlo[p + 1] = pack_lo(v.z, v.w);
}

// ---------------- cosine loss accumulation (one warp per node) ------------------
__global__ __launch_bounds__(256)
void loss_kernel(const float4* __restrict__ p, const float4* __restrict__ t1,
                 const float4* __restrict__ t2, float* __restrict__ acc)
{
    int gid  = blockIdx.x * blockDim.x + threadIdx.x;
    int node = gid >> 5;
    int lane = gid & 31;
    float pp = 0.f, n1 = 0.f, n2 = 0.f, d1 = 0.f, d2 = 0.f;
    if (node < NN) {
        size_t base = (size_t)node * 64;
#pragma unroll
        for (int r = 0; r < 2; ++r) {
            float4 a  = p [base + lane + 32 * r];
            float4 b  = t1[base + lane + 32 * r];
            float4 cc = t2[base + lane + 32 * r];
            pp += a.x * a.x + a.y * a.y + a.z * a.z + a.w * a.w;
            n1 += b.x * b.x + b.y * b.y + b.z * b.z + b.w * b.w;
            n2 += cc.x * cc.x + cc.y * cc.y + cc.z * cc.z + cc.w * cc.w;
            d1 += a.x * b.x + a.y * b.y + a.z * b.z + a.w * b.w;
            d2 += a.x * cc.x + a.y * cc.y + a.z * cc.z + a.w * cc.w;
        }
    }
#pragma unroll
    for (int o = 16; o > 0; o >>= 1) {
        pp += __shfl_down_sync(0xffffffffu, pp, o);
        n1 += __shfl_down_sync(0xffffffffu, n1, o);
        n2 += __shfl_down_sync(0xffffffffu, n2, o);
        d1 += __shfl_down_sync(0xffffffffu, d1, o);
        d2 += __shfl_down_sync(0xffffffffu, d2, o);
    }
    __shared__ float sacc[8];
    float contrib = 0.f;
    if (lane == 0 && node < NN) {
        float np  = fmaxf(sqrtf(pp), 1e-12f);
        float nn1 = fmaxf(sqrtf(n1), 1e-12f);
        float nn2 = fmaxf(sqrtf(n2), 1e-12f);
        contrib = d1 / (np * nn1) + d2 / (np * nn2);
    }
    int wid = threadIdx.x >> 5;
    if (lane == 0) sacc[wid] = contrib;
    __syncthreads();
    if (threadIdx.x == 0) {
        float s = 0.f;
#pragma unroll
        for (int i = 0; i < 8; ++i) s += sacc[i];
        atomicAdd(acc, s);
    }
}

// ---------------- finalize: softmax(beta), loss --------------------------------
__global__ void finalize_kernel(float* __restrict__ out_loss, int write_loss)
{
    float invN = 1.f / (float)NN;
    float b0 = g_beta_raw[0] * invN;
    float b1 = g_beta_raw[1] * invN;
    float b2 = g_beta_raw[2] * invN;
    float m = fmaxf(b0, fmaxf(b1, b2));
    float e0 = expf(b0 - m), e1 = expf(b1 - m), e2 = expf(b2 - m);
    float s = e0 + e1 + e2;
    g_beta[0] = e0 / s;
    g_beta[1] = e1 / s;
    g_beta[2] = e2 / s;
    if (write_loss) *out_loss = 2.0f - g_loss_acc * invN;
}

// ---------------- z_out = b0*z1 + b1*z2 + b2*z0 ---------------------------------
__global__ __launch_bounds__(256)
void zout_kernel(float4* __restrict__ out, const float4* __restrict__ z1,
                 const float4* __restrict__ z2, const float4* __restrict__ z0)
{
    int i = blockIdx.x * blockDim.x + threadIdx.x;
    if (i >= NN * 64) return;
    float b0 = g_beta[0], b1 = g_beta[1], b2 = g_beta[2];
    float4 a = z1[i], b = z2[i], c = z0[i];
    float4 r;
    r.x = b0 * a.x + b1 * b.x + b2 * c.x;
    r.y = b0 * a.y + b1 * b.y + b2 * c.y;
    r.z = b0 * a.z + b1 * b.z + b2 * c.z;
    r.w = b0 * a.w + b1 * b.w + b2 * c.w;
    out[i] = r;
}

// ---------------- host ----------------------------------------------------------
#define GETSYM(var, sym) cudaGetSymbolAddress((void**)&var, sym)

extern "C" void kernel_launch(void* const* d_in, const int* in_sizes, int n_in,
                              void* d_out, int out_size)
{
    const float* feats   = (const float*)d_in[0];
    const int*   src     = (const int*)  d_in[1];
    const int*   dst     = (const int*)  d_in[2];
    const float* vals    = (const float*)d_in[3];
    const float* W_trans = (const float*)d_in[4];
    const float* b_trans = (const float*)d_in[5];
    const float* W_gcn   = (const float*)d_in[6];
    const float* b_gcn   = (const float*)d_in[7];
    const float* a_gcn   = (const float*)d_in[8];
    const float* W1      = (const float*)d_in[9];
    const float* b1      = (const float*)d_in[10];
    const float* bn_g    = (const float*)d_in[11];
    const float* bn_b    = (const float*)d_in[12];
    const float* a_pred  = (const float*)d_in[13];
    const float* W2      = (const float*)d_in[14];
    const float* b2      = (const float*)d_in[15];
    const float* W_att   = (const float*)d_in[16];
    const float* b_att   = (const float*)d_in[17];
    const float* att     = (const float*)d_in[18];

    uint32_t *h_hi, *h_lo, *zh, *zl;
    uint32_t *x_hi, *x_lo, *wt_hi, *wt_lo, *wg_hi, *wg_lo, *w1_hi, *w1_lo;
    uint32_t *w2_hi, *w2_lo, *wa_hi, *wa_lo;
    float *ft, *z, *x, *vp, *stats, *beta_raw, *loss_acc;
    int *deg, *rowptr, *cursor, *esrc;
    float *eval_;
    GETSYM(h_hi, g_h_hi);   GETSYM(h_lo, g_h_lo);
    GETSYM(zh, g_z_hi); GETSYM(zl, g_z_lo);
    GETSYM(x_hi, g_x_hi); GETSYM(x_lo, g_x_lo);
    GETSYM(wt_hi, g_wt_hi); GETSYM(wt_lo, g_wt_lo);
    GETSYM(wg_hi, g_wg_hi); GETSYM(wg_lo, g_wg_lo);
    GETSYM(w1_hi, g_w1_hi); GETSYM(w1_lo, g_w1_lo);
    GETSYM(w2_hi, g_w2_hi); GETSYM(w2_lo, g_w2_lo);
    GETSYM(wa_hi, g_wa_hi); GETSYM(wa_lo, g_wa_lo);
    GETSYM(ft, g_ft); GETSYM(z, g_z);
    GETSYM(x, g_x);   GETSYM(vp, g_vp);
    GETSYM(stats, g_stats); GETSYM(beta_raw, g_beta_raw); GETSYM(loss_acc, g_loss_acc);
    GETSYM(deg, g_deg); GETSYM(rowptr, g_rowptr); GETSYM(cursor, g_cursor);
    GETSYM(esrc, g_esrc); GETSYM(eval_, g_eval);

    float* z0 = z;                           // view0 = student
    float* z1 = z + (size_t)NN * HH;         // view1 = teacher1
    float* z2 = z + (size_t)2 * NN * HH;     // view2 = teacher2
    uint32_t* z0h = zh;
    uint32_t* z0l = zl;

    cudaMemsetAsync(deg, 0, 3 * NN * sizeof(int));
    cudaMemsetAsync(stats, 0, 2 * PHH * sizeof(float));
    cudaMemsetAsync(beta_raw, 0, 3 * sizeof(float));
    cudaMemsetAsync(loss_acc, 0, sizeof(float));

    // CSR build (all 3 views)
    hist_kernel<<<(3 * EE + 255) / 256, 256>>>(dst, deg);
    scan_kernel<<<3, 1024>>>(deg, rowptr, cursor);
    scatter_kernel<<<(3 * EE + 255) / 256, 256>>>(src, dst, vals, cursor, esrc, eval_);

    // split weights -> bf16 hi/lo (small, L2-resident)
    {
        size_t np = (size_t)HH * (FEATD / 2);
        split_kernel<<<(int)((np + 255) / 256), 256>>>((const float2*)W_trans, wt_hi, wt_lo, np);
        np = (size_t)3 * HH * (HH / 2);
        split_kernel<<<(int)((np + 255) / 256), 256>>>((const float2*)W_gcn, wg_hi, wg_lo, np);
        np = (size_t)PHH * (HH / 2);
        split_kernel<<<(int)((np + 255) / 256), 256>>>((const float2*)W1, w1_hi, w1_lo, np);
        np = (size_t)HH * (PHH / 2);
        split_kernel<<<(int)((np + 255) / 256), 256>>>((const float2*)W2, w2_hi, w2_lo, np);
        np = (size_t)HH * (HH / 2);
        split_kernel<<<(int)((np + 255) / 256), 256>>>((const float2*)W_att, wa_hi, wa_lo, np);
    }

    const int mb = (NN + TBM - 1) / TBM;   // 391

    // h = elu(feats @ W_trans^T + b_trans): A read as f32, split in-kernel
    gemm_bf16s_af32_kernel<<<dim3(HH / TBN, mb), 256>>>(
        feats, wt_hi, wt_lo, b_trans, h_hi, h_lo, NN, HH, FEATD / 2);

    // fused GCN GEMM -> view-major ft [3][N][256]
    gemm_bf16s_kernel<0, 1><<<dim3(3 * HH / TBN, mb), 256>>>(
        h_hi, h_lo, wg_hi, wg_lo, nullptr, ft, NN, 3 * HH, HH / 2);

    // CSR SpMM per view, sequential (keeps each 51 MB ft slice L2-resident)
    for (int v = 0; v < PP; ++v) {
        spmm_csr_kernel<<<(NN * 64 + 255) / 256, 256>>>(
            (const float4*)(ft + (size_t)v * NN * HH),
            rowptr + v * (NN + 1),
            esrc + (size_t)v * EE, eval_ + (size_t)v * EE,
            (float4*)(z + (size_t)v * NN * HH),
            zh + (size_t)v * NN * (HH / 2), zl + (size_t)v * NN * (HH / 2),
            b_gcn + (size_t)v * HH, a_gcn + v);
    }

    // student predictor
    gemm_bf16s_kernel<2, 0><<<dim3(PHH / TBN, mb), 256>>>(
        z0h, z0l, w1_hi, w1_lo, b1, x, NN, PHH, HH / 2);
    colstats_kernel<<<dim3(2, 512), 256>>>(x, stats);
    bn_prelu_kernel<<<(NN * PHH / 4) / 256, 256>>>((const float4*)x, x_hi, x_lo,
                                                   stats, bn_g, bn_b, a_pred);
    gemm_bf16s_kernel<2, 0><<<dim3(HH / TBN, mb), 256>>>(
        x_hi, x_lo, w2_hi, w2_lo, b2, vp, NN, HH, PHH / 2);

    // cosine losses vs teachers (views 1 and 2)
    loss_kernel<<<(NN * 32) / 256, 256>>>((const float4*)vp, (const float4*)z1,
                                          (const float4*)z2, loss_acc);

    // type-level attention, all 3 views in one launch
    gemm_att_bf16s_kernel<<<dim3(HH / TBN, mb, 3), 256>>>(zh, zl, wa_hi, wa_lo,
                                                          b_att, att, beta_raw, NN, HH / 2);

    float* outf = (float*)d_out;
    int write_loss = (out_size > NN * HH) ? 1 : 0;
    finalize_kernel<<<1, 1>>>(outf + (size_t)NN * HH, write_loss);
    zout_kernel<<<(NN * 64) / 256, 256>>>((float4*)outf, (const float4*)z1,
                                          (const float4*)z2, (const float4*)z0);
}

// round 11
// speedup vs baseline: 1.4352x; 1.0766x over previous
#include <cuda_runtime.h>
#include <math.h>
#include <stdint.h>

// ---------------- problem constants ----------------
#define NN   50000
#define PP   3
#define EE   800000
#define FEATD 1000
#define HH   256
#define PHH  512
#define BN_EPS 1e-5f

// ---------------- device scratch (no allocations allowed) ----------------
__device__ uint32_t g_h_hi [(size_t)NN * (HH / 2)];
__device__ uint32_t g_h_lo [(size_t)NN * (HH / 2)];
__device__ float    g_ft[(size_t)3 * NN * HH];         // view-major [3][N][256]
__device__ uint32_t g_z_hi[(size_t)3 * NN * (HH / 2)];
__device__ uint32_t g_z_lo[(size_t)3 * NN * (HH / 2)];
__device__ uint32_t g_x_hi[(size_t)NN * (PHH / 2)];
__device__ uint32_t g_x_lo[(size_t)NN * (PHH / 2)];
__device__ float    g_vp[(size_t)NN * HH];
// CSR scratch
__device__ int   g_deg[3 * NN];
__device__ int   g_rowptr[3 * (NN + 1)];
__device__ int   g_cursor[3 * NN];
__device__ int   g_esrc[(size_t)3 * EE];
__device__ float g_eval[(size_t)3 * EE];
// split weights
__device__ uint32_t g_wt_hi[HH * (FEATD / 2)];
__device__ uint32_t g_wt_lo[HH * (FEATD / 2)];
__device__ uint32_t g_wg_hi[3 * HH * (HH / 2)];
__device__ uint32_t g_wg_lo[3 * HH * (HH / 2)];
__device__ uint32_t g_w1_hi[PHH * (HH / 2)];
__device__ uint32_t g_w1_lo[PHH * (HH / 2)];
__device__ uint32_t g_w2_hi[HH * (PHH / 2)];
__device__ uint32_t g_w2_lo[HH * (PHH / 2)];
__device__ uint32_t g_wa_hi[HH * (HH / 2)];
__device__ float g_stats[2 * PHH];
__device__ float g_beta_raw[3];
__device__ float g_beta[3];
__device__ float g_loss_acc;

// ---------------- bf16 split helpers --------------------------------------------
__device__ __forceinline__ uint32_t pack_hi(float x0, float x1)
{
    uint32_t r;
    asm("prmt.b32 %0, %1, %2, 0x7632;"
        : "=r"(r) : "r"(__float_as_uint(x0)), "r"(__float_as_uint(x1)));
    return r;
}

__device__ __forceinline__ uint32_t pack_lo(float x0, float x1)
{
    float h0 = __uint_as_float(__float_as_uint(x0) & 0xFFFF0000u);
    float h1 = __uint_as_float(__float_as_uint(x1) & 0xFFFF0000u);
    uint32_t r;
    asm("cvt.rn.bf16x2.f32 %0, %1, %2;" : "=r"(r) : "f"(x1 - h1), "f"(x0 - h0));
    return r;
}

// reconstruct two f32 from packed hi/lo bf16 pairs (element0 in low half)
__device__ __forceinline__ void unpack2(uint32_t hi, uint32_t lo, float& f0, float& f1)
{
    f0 = __uint_as_float(hi << 16)          + __uint_as_float(lo << 16);
    f1 = __uint_as_float(hi & 0xFFFF0000u)  + __uint_as_float(lo & 0xFFFF0000u);
}

__device__ __forceinline__ void mma_bf16(float* c, const uint32_t* a, const uint32_t* b)
{
    asm volatile(
        "mma.sync.aligned.m16n8k16.row.col.f32.bf16.bf16.f32 "
        "{%0,%1,%2,%3}, {%4,%5,%6,%7}, {%8,%9}, {%0,%1,%2,%3};\n"
        : "+f"(c[0]), "+f"(c[1]), "+f"(c[2]), "+f"(c[3])
        : "r"(a[0]), "r"(a[1]), "r"(a[2]), "r"(a[3]), "r"(b[0]), "r"(b[1]));
}

__device__ __forceinline__ void cp16(uint32_t saddr, const void* gmem, bool pred)
{
    int sz = pred ? 16 : 0;
    asm volatile("cp.async.cg.shared.global [%0], [%1], 16, %2;\n"
                 :: "r"(saddr), "l"(gmem), "r"(sz));
}

// ---------------- generic f32 -> split-bf16 pass (weights only) -----------------
__global__ __launch_bounds__(256)
void split_kernel(const float2* __restrict__ in, uint32_t* __restrict__ hi,
                  uint32_t* __restrict__ lo, size_t npairs)
{
    size_t i = (size_t)blockIdx.x * blockDim.x + threadIdx.x;
    if (i >= npairs) return;
    float2 v = in[i];
    hi[i] = pack_hi(v.x, v.y);
    if (lo) lo[i] = pack_lo(v.x, v.y);
}

// ---------------- CSR build ------------------------------------------------------
__global__ __launch_bounds__(256)
void hist_kernel(const int* __restrict__ dst, int* __restrict__ deg)
{
    int i = blockIdx.x * 256 + threadIdx.x;
    if (i >= 3 * EE) return;
    int v = i / EE;
    atomicAdd(&deg[v * NN + dst[i]], 1);
}

__global__ __launch_bounds__(1024)
void scan_kernel(const int* __restrict__ deg, int* __restrict__ rowptr,
                 int* __restrict__ cursor)
{
    const int CH = (NN + 1023) / 1024;   // 49
    int v = blockIdx.x;
    const int* d = deg + v * NN;
    int* rp = rowptr + v * (NN + 1);
    int* cur = cursor + v * NN;
    int t = threadIdx.x;
    int lane = t & 31, w = t >> 5;
    __shared__ int warpsums[32];

    int base = t * CH;
    int local[CH];
    int sum = 0;
#pragma unroll
    for (int k = 0; k < CH; ++k) {
        int idx = base + k;
        int val = (idx < NN) ? d[idx] : 0;
        local[k] = sum;
        sum += val;
    }
    int s = sum;
#pragma unroll
    for (int o = 1; o < 32; o <<= 1) {
        int y = __shfl_up_sync(0xffffffffu, s, o);
        if (lane >= o) s += y;
    }
    if (lane == 31) warpsums[w] = s;
    __syncthreads();
    if (w == 0) {
        int ws = warpsums[lane];
#pragma unroll
        for (int o = 1; o < 32; o <<= 1) {
            int y = __shfl_up_sync(0xffffffffu, ws, o);
            if (lane >= o) ws += y;
        }
        warpsums[lane] = ws;
    }
    __syncthreads();
    int offset = (w > 0 ? warpsums[w - 1] : 0) + (s - sum);
#pragma unroll
    for (int k = 0; k < CH; ++k) {
        int idx = base + k;
        if (idx < NN) {
            int val = offset + local[k];
            rp[idx] = val;
            cur[idx] = val;
        }
    }
    if (t == 1023) rp[NN] = EE;
}

__global__ __launch_bounds__(256)
void scatter_kernel(const int* __restrict__ src, const int* __restrict__ dst,
                    const float* __restrict__ vals, int* __restrict__ cursor,
                    int* __restrict__ esrc, float* __restrict__ eval_)
{
    int i = blockIdx.x * 256 + threadIdx.x;
    if (i >= 3 * EE) return;
    int v = i / EE;
    int d = dst[i];
    int pos = atomicAdd(&cursor[v * NN + d], 1);
    esrc[(size_t)v * EE + pos] = src[i];
    eval_[(size_t)v * EE + pos] = vals[i];
}

// ---------------- CSR SpMM + bias + PReLU -> split-bf16 only (one view) ---------
__global__ __launch_bounds__(256)
void spmm_csr_kernel(const float4* __restrict__ ftv, const int* __restrict__ rp,
                     const int* __restrict__ es, const float* __restrict__ ev,
                     uint32_t* __restrict__ zhiv, uint32_t* __restrict__ zlov,
                     const float* __restrict__ bvp, const float* __restrict__ avp)
{
    int gid = blockIdx.x * 256 + threadIdx.x;
    if (gid >= NN * 64) return;
    int n = gid >> 6;
    int c = gid & 63;
    int i  = rp[n];
    int s1 = rp[n + 1];

    float4 acc = make_float4(0.f, 0.f, 0.f, 0.f);
    for (; i + 2 <= s1; i += 2) {
        int sa = es[i];     float va = ev[i];
        int sb = es[i + 1]; float vb = ev[i + 1];
        float4 fa = ftv[(size_t)sa * 64 + c];
        float4 fb = ftv[(size_t)sb * 64 + c];
        acc.x += va * fa.x; acc.y += va * fa.y; acc.z += va * fa.z; acc.w += va * fa.w;
        acc.x += vb * fb.x; acc.y += vb * fb.y; acc.z += vb * fb.z; acc.w += vb * fb.w;
    }
    if (i < s1) {
        int sa = es[i]; float va = ev[i];
        float4 fa = ftv[(size_t)sa * 64 + c];
        acc.x += va * fa.x; acc.y += va * fa.y; acc.z += va * fa.z; acc.w += va * fa.w;
    }

    float a = *avp;
    float4 bv = *(const float4*)(bvp + (c << 2));
    acc.x += bv.x; acc.y += bv.y; acc.z += bv.z; acc.w += bv.w;
    acc.x = acc.x >= 0.f ? acc.x : a * acc.x;
    acc.y = acc.y >= 0.f ? acc.y : a * acc.y;
    acc.z = acc.z >= 0.f ? acc.z : a * acc.z;
    acc.w = acc.w >= 0.f ? acc.w : a * acc.w;

    size_t p = ((size_t)n * 64 + c) << 1;
    zhiv[p]     = pack_hi(acc.x, acc.y);
    zhiv[p + 1] = pack_hi(acc.z, acc.w);
    zlov[p]     = pack_lo(acc.x, acc.y);
    zlov[p + 1] = pack_lo(acc.z, acc.w);
}

// ---------------- split-bf16 GEMM ------------------------------------------------
#define TBM 128
#define TBN 128
#define TPAD 12

#define GS_DECL()                                                                   \
    __shared__ uint32_t AsH[2][TBM][TPAD];                                          \
    __shared__ uint32_t AsL[2][TBM][TPAD];                                          \
    __shared__ uint32_t WsH[2][TBN][TPAD];                                          \
    __shared__ uint32_t WsL[2][TBN][TPAD];                                          \
    const int tid  = threadIdx.x;                                                   \
    const int wid  = tid >> 5;                                                      \
    const int lane = tid & 31;                                                      \
    const int g    = lane >> 2;                                                     \
    const int t    = lane & 3;                                                      \
    const int wm   = (wid & 1) << 6;                                                \
    const int wn   = (wid >> 1) << 5;                                               \
    const int bm   = blockIdx.y * TBM;                                              \
    const int bn   = blockIdx.x * TBN;                                              \
    float acc[4][4][4] = {};

#define GS_LOAD(S, KP0)                                                             \
    {                                                                               \
        int r  = tid >> 1, ch = (tid & 1) << 2;                                     \
        int gp = (KP0) + ch;                                                        \
        bool pa = (gp < Kp) && (bm + r < M);                                        \
        size_t offa = (size_t)(bm + r) * Kp + gp;                                   \
        cp16((uint32_t)__cvta_generic_to_shared(&AsH[S][r][ch]), Ahi + offa, pa);   \
        cp16((uint32_t)__cvta_generic_to_shared(&AsL[S][r][ch]), Alo + offa, pa);   \
        bool pb = (gp < Kp);                                                        \
        size_t offb = (size_t)(bn + r) * Kp + gp;                                   \
        cp16((uint32_t)__cvta_generic_to_shared(&WsH[S][r][ch]), Whi + offb, pb);   \
        cp16((uint32_t)__cvta_generic_to_shared(&WsL[S][r][ch]), Wlo + offb, pb);   \
    }

#define GS_LOAD_AF32(S, KP0)                                                        \
    {                                                                               \
        int r  = tid >> 1, ch = (tid & 1) << 2;                                     \
        int gp = (KP0) + ch;                                                        \
        float4 f0 = make_float4(0.f, 0.f, 0.f, 0.f), f1 = f0;                       \
        if (gp < Kp && bm + r < M) {                                                \
            const float* ap = Af32 + (size_t)(bm + r) * (Kp * 2) + gp * 2;          \
            f0 = *(const float4*)ap;                                                \
            f1 = *(const float4*)(ap + 4);                                          \
        }                                                                           \
        AsH[S][r][ch + 0] = pack_hi(f0.x, f0.y); AsL[S][r][ch + 0] = pack_lo(f0.x, f0.y); \
        AsH[S][r][ch + 1] = pack_hi(f0.z, f0.w); AsL[S][r][ch + 1] = pack_lo(f0.z, f0.w); \
        AsH[S][r][ch + 2] = pack_hi(f1.x, f1.y); AsL[S][r][ch + 2] = pack_lo(f1.x, f1.y); \
        AsH[S][r][ch + 3] = pack_hi(f1.z, f1.w); AsL[S][r][ch + 3] = pack_lo(f1.z, f1.w); \
        bool pb = (gp < Kp);                                                        \
        size_t offb = (size_t)(bn + r) * Kp + gp;                                   \
        cp16((uint32_t)__cvta_generic_to_shared(&WsH[S][r][ch]), Whi + offb, pb);   \
        cp16((uint32_t)__cvta_generic_to_shared(&WsL[S][r][ch]), Wlo + offb, pb);   \
    }

#define GS_COMPUTE()                                                                \
    {                                                                               \
        uint32_t aH[4][4], aL[4][4], bH[4][2], bL[4][2];                            \
        _Pragma("unroll")                                                           \
        for (int i = 0; i < 4; ++i) {                                               \
            int rb = wm + (i << 4);                                                 \
            aH[i][0] = AsH[buf][rb + g    ][t    ];                                 \
            aH[i][1] = AsH[buf][rb + g + 8][t    ];                                 \
            aH[i][2] = AsH[buf][rb + g    ][t + 4];                                 \
            aH[i][3] = AsH[buf][rb + g + 8][t + 4];                                 \
            aL[i][0] = AsL[buf][rb + g    ][t    ];                                 \
            aL[i][1] = AsL[buf][rb + g + 8][t    ];                                 \
            aL[i][2] = AsL[buf][rb + g    ][t + 4];                                 \
            aL[i][3] = AsL[buf][rb + g + 8][t + 4];                                 \
        }                                                                           \
        _Pragma("unroll")                                                           \
        for (int j = 0; j < 4; ++j) {                                               \
            int nb = wn + (j << 3);                                                 \
            bH[j][0] = WsH[buf][nb + g][t    ];                                     \
            bH[j][1] = WsH[buf][nb + g][t + 4];                                     \
            bL[j][0] = WsL[buf][nb + g][t    ];                                     \
            bL[j][1] = WsL[buf][nb + g][t + 4];                                     \
        }                                                                           \
        _Pragma("unroll")                                                           \
        for (int i = 0; i < 4; ++i)                                                 \
            _Pragma("unroll")                                                       \
            for (int j = 0; j < 4; ++j) {                                           \
                mma_bf16(acc[i][j], aL[i], bH[j]);                                  \
                mma_bf16(acc[i][j], aH[i], bL[j]);                                  \
                mma_bf16(acc[i][j], aH[i], bH[j]);                                  \
            }                                                                       \
    }

#define GS_MAINLOOP(LOADM)                                                          \
    LOADM(0, 0);                                                                    \
    asm volatile("cp.async.commit_group;\n" ::: "memory");                          \
    int buf = 0;                                                                    \
    for (int kp0 = 0; kp0 < Kp; kp0 += 8) {                                         \
        if (kp0 + 8 < Kp) LOADM(buf ^ 1, kp0 + 8);                                  \
        asm volatile("cp.async.commit_group;\n" ::: "memory");                      \
        asm volatile("cp.async.wait_group 1;\n" ::: "memory");                      \
        __syncthreads();                                                            \
        GS_COMPUTE();                                                               \
        __syncthreads();                                                            \
        buf ^= 1;                                                                   \
    }

// EPI: 0 = raw f32 view-major, 2 = bias f32, 3 = bias -> split bf16 + BN stats
template<int EPI>
__global__ __launch_bounds__(256, 2)
void gemm_bf16s_kernel(const uint32_t* __restrict__ Ahi, const uint32_t* __restrict__ Alo,
                       const uint32_t* __restrict__ Whi, const uint32_t* __restrict__ Wlo,
                       const float* __restrict__ bias, float* __restrict__ C,
                       uint32_t* __restrict__ Chi, uint32_t* __restrict__ Clo,
                       float* __restrict__ stats, int M, int Nc, int Kp)
{
    GS_DECL();
    GS_MAINLOOP(GS_LOAD);

    float* sSum = (float*)&AsH[0][0][0];      // 128 floats
    float* sSq  = sSum + 128;                 // 128 floats
    if (EPI == 3) {
        __syncthreads();
        if (tid < 128) { sSum[tid] = 0.f; sSq[tid] = 0.f; }
        __syncthreads();
    }

#pragma unroll
    for (int j = 0; j < 4; ++j) {
        float cs0 = 0.f, cq0 = 0.f, cs1 = 0.f, cq1 = 0.f;
#pragma unroll
        for (int i = 0; i < 4; ++i) {
            int r0 = bm + wm + (i << 4) + g;
            int r1 = r0 + 8;
            int c0 = bn + wn + (j << 3) + (t << 1);
            float bx = 0.f, by = 0.f;
            if (EPI >= 2) { bx = bias[c0]; by = bias[c0 + 1]; }
            float v0 = acc[i][j][0] + bx, v1 = acc[i][j][1] + by;
            float v2 = acc[i][j][2] + bx, v3 = acc[i][j][3] + by;
            if (EPI == 0) {
                int vv = c0 >> 8;
                int cc = c0 & 255;
                float* base = C + (size_t)vv * NN * HH + cc;
                if (r0 < M) *(float2*)(base + (size_t)r0 * HH) = make_float2(v0, v1);
                if (r1 < M) *(float2*)(base + (size_t)r1 * HH) = make_float2(v2, v3);
            } else if (EPI == 2) {
                if (r0 < M) *(float2*)(C + (size_t)r0 * Nc + c0) = make_float2(v0, v1);
                if (r1 < M) *(float2*)(C + (size_t)r1 * Nc + c0) = make_float2(v2, v3);
            } else {
                int pc = c0 >> 1;
                if (r0 < M) {
                    Chi[(size_t)r0 * (Nc / 2) + pc] = pack_hi(v0, v1);
                    Clo[(size_t)r0 * (Nc / 2) + pc] = pack_lo(v0, v1);
                    cs0 += v0; cq0 += v0 * v0; cs1 += v1; cq1 += v1 * v1;
                }
                if (r1 < M) {
                    Chi[(size_t)r1 * (Nc / 2) + pc] = pack_hi(v2, v3);
                    Clo[(size_t)r1 * (Nc / 2) + pc] = pack_lo(v2, v3);
                    cs0 += v2; cq0 += v2 * v2; cs1 += v3; cq1 += v3 * v3;
                }
            }
        }
        if (EPI == 3) {
            int lc = wn + (j << 3) + (t << 1);
            atomicAdd(&sSum[lc], cs0);     atomicAdd(&sSq[lc], cq0);
            atomicAdd(&sSum[lc + 1], cs1); atomicAdd(&sSq[lc + 1], cq1);
        }
    }
    if (EPI == 3) {
        __syncthreads();
        if (tid < 128) {
            atomicAdd(&stats[bn + tid], sSum[tid]);
            atomicAdd(&stats[PHH + bn + tid], sSq[tid]);
        }
    }
}

// feats GEMM: A = raw f32, epilogue bias+ELU -> split bf16 h
__global__ __launch_bounds__(256, 2)
void gemm_bf16s_af32_kernel(const float* __restrict__ Af32,
                            const uint32_t* __restrict__ Whi, const uint32_t* __restrict__ Wlo,
                            const float* __restrict__ bias,
                            uint32_t* __restrict__ Chi, uint32_t* __restrict__ Clo,
                            int M, int Nc, int Kp)
{
    GS_DECL();
    GS_MAINLOOP(GS_LOAD_AF32);

#pragma unroll
    for (int i = 0; i < 4; ++i) {
#pragma unroll
        for (int j = 0; j < 4; ++j) {
            int r0 = bm + wm + (i << 4) + g;
            int r1 = r0 + 8;
            int c0 = bn + wn + (j << 3) + (t << 1);
            float bx = bias[c0], by = bias[c0 + 1];
            float v0 = acc[i][j][0] + bx, v1 = acc[i][j][1] + by;
            float v2 = acc[i][j][2] + bx, v3 = acc[i][j][3] + by;
            v0 = v0 > 0.f ? v0 : expm1f(v0);
            v1 = v1 > 0.f ? v1 : expm1f(v1);
            v2 = v2 > 0.f ? v2 : expm1f(v2);
            v3 = v3 > 0.f ? v3 : expm1f(v3);
            int pc = c0 >> 1;
            if (r0 < M) {
                Chi[(size_t)r0 * (Nc / 2) + pc] = pack_hi(v0, v1);
                Clo[(size_t)r0 * (Nc / 2) + pc] = pack_lo(v0, v1);
            }
            if (r1 < M) {
                Chi[(size_t)r1 * (Nc / 2) + pc] = pack_hi(v2, v3);
                Clo[(size_t)r1 * (Nc / 2) + pc] = pack_lo(v2, v3);
            }
        }
    }
}

// attention GEMM: single-pass bf16, hi operands only; feeds beta via mean-reduce.
// blockIdx.z = view; beta index = (view+2)%3.
__global__ __launch_bounds__(256, 2)
void gemm_att_bf16_kernel(const uint32_t* __restrict__ Zhi,
                          const uint32_t* __restrict__ Whi,
                          const float* __restrict__ bias, const float* __restrict__ att,
                          float* __restrict__ beta_raw, int M, int Kp)
{
    __shared__ uint32_t AsH[2][TBM][TPAD];
    __shared__ uint32_t WsH[2][TBN][TPAD];
    const int tid  = threadIdx.x;
    const int wid  = tid >> 5;
    const int lane = tid & 31;
    const int g    = lane >> 2;
    const int t    = lane & 3;
    const int wm   = (wid & 1) << 6;
    const int wn   = (wid >> 1) << 5;
    const int bm   = blockIdx.y * TBM;
    const int bn   = blockIdx.x * TBN;
    const int view = blockIdx.z;
    const uint32_t* Ahi = Zhi + (size_t)view * NN * (HH / 2);
    float acc[4][4][4] = {};

#define GA_LOAD(S, KP0)                                                             \
    {                                                                               \
        int r  = tid >> 1, ch = (tid & 1) << 2;                                     \
        int gp = (KP0) + ch;                                                        \
        bool pa = (gp < Kp) && (bm + r < M);                                        \
        cp16((uint32_t)__cvta_generic_to_shared(&AsH[S][r][ch]),                    \
             Ahi + (size_t)(bm + r) * Kp + gp, pa);                                 \
        cp16((uint32_t)__cvta_generic_to_shared(&WsH[S][r][ch]),                    \
             Whi + (size_t)(bn + r) * Kp + gp, (gp < Kp));                          \
    }

    GA_LOAD(0, 0);
    asm volatile("cp.async.commit_group;\n" ::: "memory");
    int buf = 0;
    for (int kp0 = 0; kp0 < Kp; kp0 += 8) {
        if (kp0 + 8 < Kp) GA_LOAD(buf ^ 1, kp0 + 8);
        asm volatile("cp.async.commit_group;\n" ::: "memory");
        asm volatile("cp.async.wait_group 1;\n" ::: "memory");
        __syncthreads();
        uint32_t aH[4][4], bH[4][2];
#pragma unroll
        for (int i = 0; i < 4; ++i) {
            int rb = wm + (i << 4);
            aH[i][0] = AsH[buf][rb + g    ][t    ];
            aH[i][1] = AsH[buf][rb + g + 8][t    ];
            aH[i][2] = AsH[buf][rb + g    ][t + 4];
            aH[i][3] = AsH[buf][rb + g + 8][t + 4];
        }
#pragma unroll
        for (int j = 0; j < 4; ++j) {
            int nb = wn + (j << 3);
            bH[j][0] = WsH[buf][nb + g][t    ];
            bH[j][1] = WsH[buf][nb + g][t + 4];
        }
#pragma unroll
        for (int i = 0; i < 4; ++i)
#pragma unroll
            for (int j = 0; j < 4; ++j)
                mma_bf16(acc[i][j], aH[i], bH[j]);
        __syncthreads();
        buf ^= 1;
    }
#undef GA_LOAD

    float s = 0.f;
#pragma unroll
    for (int i = 0; i < 4; ++i) {
#pragma unroll
        for (int j = 0; j < 4; ++j) {
            int r0 = bm + wm + (i << 4) + g;
            int r1 = r0 + 8;
            int c0 = bn + wn + (j << 3) + (t << 1);
            float bx = bias[c0], by = bias[c0 + 1];
            float ax = att[c0],  ay = att[c0 + 1];
            if (r0 < M) s += tanhf(acc[i][j][0] + bx) * ax + tanhf(acc[i][j][1] + by) * ay;
            if (r1 < M) s += tanhf(acc[i][j][2] + bx) * ax + tanhf(acc[i][j][3] + by) * ay;
        }
    }
    float* red = (float*)&AsH[0][0][0];
    __syncthreads();
    red[tid] = s;
    __syncthreads();
    for (int o = 128; o > 0; o >>= 1) {
        if (tid < o) red[tid] += red[tid + o];
        __syncthreads();
    }
    if (tid == 0) {
        int bidx = (view + 2) % 3;
        atomicAdd(&beta_raw[bidx], red[0]);
    }
}

// ---------------- BN + PReLU on split-bf16 x (in place) -------------------------
__global__ __launch_bounds__(256)
void bn_prelu_kernel(uint32_t* __restrict__ xhi, uint32_t* __restrict__ xlo,
                     const float* __restrict__ stats,
                     const float* __restrict__ g, const float* __restrict__ b,
                     const float* __restrict__ a_ptr)
{
    int i = blockIdx.x * blockDim.x + threadIdx.x;
    if (i >= NN * (PHH / 4)) return;
    int c = (i & (PHH / 4 - 1)) << 2;
    float a = *a_ptr;
    float4 sm = *(const float4*)(stats + c);
    float4 sq = *(const float4*)(stats + PHH + c);
    float4 gv = *(const float4*)(g + c);
    float4 bv = *(const float4*)(b + c);
    uint2 h = ((const uint2*)xhi)[i];
    uint2 l = ((const uint2*)xlo)[i];
    float4 v;
    unpack2(h.x, l.x, v.x, v.y);
    unpack2(h.y, l.y, v.z, v.w);
    float invN = 1.f / (float)NN;

    float mu, var, sc, sh, y;
    mu = sm.x * invN; var = sq.x * invN - mu * mu; sc = gv.x * rsqrtf(var + BN_EPS);
    sh = bv.x - mu * sc; y = v.x * sc + sh; v.x = y >= 0.f ? y : a * y;
    mu = sm.y * invN; var = sq.y * invN - mu * mu; sc = gv.y * rsqrtf(var + BN_EPS);
    sh = bv.y - mu * sc; y = v.y * sc + sh; v.y = y >= 0.f ? y : a * y;
    mu = sm.z * invN; var = sq.z * invN - mu * mu; sc = gv.z * rsqrtf(var + BN_EPS);
    sh = bv.z - mu * sc; y = v.z * sc + sh; v.z = y >= 0.f ? y : a * y;
    mu = sm.w * invN; var = sq.w * invN - mu * mu; sc = gv.w * rsqrtf(var + BN_EPS);
    sh = bv.w - mu * sc; y = v.w * sc + sh; v.w = y >= 0.f ? y : a * y;

    uint2 nh, nl;
    nh.x = pack_hi(v.x, v.y); nl.x = pack_lo(v.x, v.y);
    nh.y = pack_hi(v.z, v.w); nl.y = pack_lo(v.z, v.w);
    ((uint2*)xhi)[i] = nh;
    ((uint2*)xlo)[i] = nl;
}

// ---------------- cosine loss (one warp per node; teachers from split-bf16) -----
__global__ __launch_bounds__(256)
void loss_kernel(const float4* __restrict__ p,
                 const uint32_t* __restrict__ zh, const uint32_t* __restrict__ zl,
                 float* __restrict__ acc)
{
    const uint32_t* t1h = zh + (size_t)NN * (HH / 2);
    const uint32_t* t1l = zl + (size_t)NN * (HH / 2);
    const uint32_t* t2h = zh + (size_t)2 * NN * (HH / 2);
    const uint32_t* t2l = zl + (size_t)2 * NN * (HH / 2);
    int gid  = blockIdx.x * blockDim.x + threadIdx.x;
    int node = gid >> 5;
    int lane = gid & 31;
    float pp = 0.f, n1 = 0.f, n2 = 0.f, d1 = 0.f, d2 = 0.f;
    if (node < NN) {
        size_t base4 = (size_t)node * 64;
        size_t baseu = (size_t)node * 128;
#pragma unroll
        for (int r = 0; r < 2; ++r) {
            int q = lane + 32 * r;
            float4 a = p[base4 + q];
            uint2 h1 = *(const uint2*)&t1h[baseu + 2 * q];
            uint2 l1 = *(const uint2*)&t1l[baseu + 2 * q];
            uint2 h2 = *(const uint2*)&t2h[baseu + 2 * q];
            uint2 l2 = *(const uint2*)&t2l[baseu + 2 * q];
            float4 b, cc;
            unpack2(h1.x, l1.x, b.x, b.y);  unpack2(h1.y, l1.y, b.z, b.w);
            unpack2(h2.x, l2.x, cc.x, cc.y); unpack2(h2.y, l2.y, cc.z, cc.w);
            pp += a.x * a.x + a.y * a.y + a.z * a.z + a.w * a.w;
            n1 += b.x * b.x + b.y * b.y + b.z * b.z + b.w * b.w;
            n2 += cc.x * cc.x + cc.y * cc.y + cc.z * cc.z + cc.w * cc.w;
            d1 += a.x * b.x + a.y * b.y + a.z * b.z + a.w * b.w;
            d2 += a.x * cc.x + a.y * cc.y + a.z * cc.z + a.w * cc.w;
        }
    }
#pragma unroll
    for (int o = 16; o > 0; o >>= 1) {
        pp += __shfl_down_sync(0xffffffffu, pp, o);
        n1 += __shfl_down_sync(0xffffffffu, n1, o);
        n2 += __shfl_down_sync(0xffffffffu, n2, o);
        d1 += __shfl_down_sync(0xffffffffu, d1, o);
        d2 += __shfl_down_sync(0xffffffffu, d2, o);
    }
    __shared__ float sacc[8];
    float contrib = 0.f;
    if (lane == 0 && node < NN) {
        float np  = fmaxf(sqrtf(pp), 1e-12f);
        float nn1 = fmaxf(sqrtf(n1), 1e-12f);
        float nn2 = fmaxf(sqrtf(n2), 1e-12f);
        contrib = d1 / (np * nn1) + d2 / (np * nn2);
    }
    int wid = threadIdx.x >> 5;
    if (lane == 0) sacc[wid] = contrib;
    __syncthreads();
    if (threadIdx.x == 0) {
        float s = 0.f;
#pragma unroll
        for (int i = 0; i < 8; ++i) s += sacc[i];
        atomicAdd(acc, s);
    }
}

// ---------------- finalize: softmax(beta), loss --------------------------------
__global__ void finalize_kernel(float* __restrict__ out_loss, int write_loss)
{
    float invN = 1.f / (float)NN;
    float b0 = g_beta_raw[0] * invN;
    float b1 = g_beta_raw[1] * invN;
    float b2 = g_beta_raw[2] * invN;
    float m = fmaxf(b0, fmaxf(b1, b2));
    float e0 = expf(b0 - m), e1 = expf(b1 - m), e2 = expf(b2 - m);
    float s = e0 + e1 + e2;
    g_beta[0] = e0 / s;
    g_beta[1] = e1 / s;
    g_beta[2] = e2 / s;
    if (write_loss) *out_loss = 2.0f - g_loss_acc * invN;
}

// ---------------- z_out = b0*z1 + b1*z2 + b2*z0 (from split-bf16) ----------------
__global__ __launch_bounds__(256)
void zout_kernel(float4* __restrict__ out, const uint32_t* __restrict__ zh,
                 const uint32_t* __restrict__ zl)
{
    int i = blockIdx.x * blockDim.x + threadIdx.x;
    if (i >= NN * 64) return;
    float b2 = g_beta[2], b0 = g_beta[0], b1 = g_beta[1];   // student, t1, t2
    const size_t vstride = (size_t)NN * (HH / 2);
    size_t u = (size_t)i * 2;
    uint2 h0 = *(const uint2*)&zh[u];
    uint2 l0 = *(const uint2*)&zl[u];
    uint2 h1 = *(const uint2*)&zh[vstride + u];
    uint2 l1 = *(const uint2*)&zl[vstride + u];
    uint2 h2 = *(const uint2*)&zh[2 * vstride + u];
    uint2 l2 = *(const uint2*)&zl[2 * vstride + u];
    float4 a, b, c;
    unpack2(h0.x, l0.x, c.x, c.y); unpack2(h0.y, l0.y, c.z, c.w);   // student
    unpack2(h1.x, l1.x, a.x, a.y); unpack2(h1.y, l1.y, a.z, a.w);   // teacher1
    unpack2(h2.x, l2.x, b.x, b.y); unpack2(h2.y, l2.y, b.z, b.w);   // teacher2
    float4 r;
    r.x = b0 * a.x + b1 * b.x + b2 * c.x;
    r.y = b0 * a.y + b1 * b.y + b2 * c.y;
    r.z = b0 * a.z + b1 * b.z + b2 * c.z;
    r.w = b0 * a.w + b1 * b.w + b2 * c.w;
    out[i] = r;
}

// ---------------- host ----------------------------------------------------------
#define GETSYM(var, sym) cudaGetSymbolAddress((void**)&var, sym)

extern "C" void kernel_launch(void* const* d_in, const int* in_sizes, int n_in,
                              void* d_out, int out_size)
{
    const float* feats   = (const float*)d_in[0];
    const int*   src     = (const int*)  d_in[1];
    const int*   dst     = (const int*)  d_in[2];
    const float* vals    = (const float*)d_in[3];
    const float* W_trans = (const float*)d_in[4];
    const float* b_trans = (const float*)d_in[5];
    const float* W_gcn   = (const float*)d_in[6];
    const float* b_gcn   = (const float*)d_in[7];
    const float* a_gcn   = (const float*)d_in[8];
    const float* W1      = (const float*)d_in[9];
    const float* b1      = (const float*)d_in[10];
    const float* bn_g    = (const float*)d_in[11];
    const float* bn_b    = (const float*)d_in[12];
    const float* a_pred  = (const float*)d_in[13];
    const float* W2      = (const float*)d_in[14];
    const float* b2      = (const float*)d_in[15];
    const float* W_att   = (const float*)d_in[16];
    const float* b_att   = (const float*)d_in[17];
    const float* att     = (const float*)d_in[18];

    uint32_t *h_hi, *h_lo, *zh, *zl;
    uint32_t *x_hi, *x_lo, *wt_hi, *wt_lo, *wg_hi, *wg_lo, *w1_hi, *w1_lo;
    uint32_t *w2_hi, *w2_lo, *wa_hi;
    float *ft, *vp, *stats, *beta_raw, *loss_acc;
    int *deg, *rowptr, *cursor, *esrc;
    float *eval_;
    GETSYM(h_hi, g_h_hi);   GETSYM(h_lo, g_h_lo);
    GETSYM(zh, g_z_hi); GETSYM(zl, g_z_lo);
    GETSYM(x_hi, g_x_hi); GETSYM(x_lo, g_x_lo);
    GETSYM(wt_hi, g_wt_hi); GETSYM(wt_lo, g_wt_lo);
    GETSYM(wg_hi, g_wg_hi); GETSYM(wg_lo, g_wg_lo);
    GETSYM(w1_hi, g_w1_hi); GETSYM(w1_lo, g_w1_lo);
    GETSYM(w2_hi, g_w2_hi); GETSYM(w2_lo, g_w2_lo);
    GETSYM(wa_hi, g_wa_hi);
    GETSYM(ft, g_ft);
    GETSYM(vp, g_vp);
    GETSYM(stats, g_stats); GETSYM(beta_raw, g_beta_raw); GETSYM(loss_acc, g_loss_acc);
    GETSYM(deg, g_deg); GETSYM(rowptr, g_rowptr); GETSYM(cursor, g_cursor);
    GETSYM(esrc, g_esrc); GETSYM(eval_, g_eval);

    cudaMemsetAsync(deg, 0, 3 * NN * sizeof(int));
    cudaMemsetAsync(stats, 0, 2 * PHH * sizeof(float));
    cudaMemsetAsync(beta_raw, 0, 3 * sizeof(float));
    cudaMemsetAsync(loss_acc, 0, sizeof(float));

    // CSR build (all 3 views)
    hist_kernel<<<(3 * EE + 255) / 256, 256>>>(dst, deg);
    scan_kernel<<<3, 1024>>>(deg, rowptr, cursor);
    scatter_kernel<<<(3 * EE + 255) / 256, 256>>>(src, dst, vals, cursor, esrc, eval_);

    // split weights -> bf16 hi/lo (small, L2-resident)
    {
        size_t np = (size_t)HH * (FEATD / 2);
        split_kernel<<<(int)((np + 255) / 256), 256>>>((const float2*)W_trans, wt_hi, wt_lo, np);
        np = (size_t)3 * HH * (HH / 2);
        split_kernel<<<(int)((np + 255) / 256), 256>>>((const float2*)W_gcn, wg_hi, wg_lo, np);
        np = (size_t)PHH * (HH / 2);
        split_kernel<<<(int)((np + 255) / 256), 256>>>((const float2*)W1, w1_hi, w1_lo, np);
        np = (size_t)HH * (PHH / 2);
        split_kernel<<<(int)((np + 255) / 256), 256>>>((const float2*)W2, w2_hi, w2_lo, np);
        np = (size_t)HH * (HH / 2);
        split_kernel<<<(int)((np + 255) / 256), 256>>>((const float2*)W_att, wa_hi, nullptr, np);
    }

    const int mb = (NN + TBM - 1) / TBM;   // 391

    // h = elu(feats @ W_trans^T + b_trans): A read as f32, split in-kernel
    gemm_bf16s_af32_kernel<<<dim3(HH / TBN, mb), 256>>>(
        feats, wt_hi, wt_lo, b_trans, h_hi, h_lo, NN, HH, FEATD / 2);

    // fused GCN GEMM -> view-major ft [3][N][256]
    gemm_bf16s_kernel<0><<<dim3(3 * HH / TBN, mb), 256>>>(
        h_hi, h_lo, wg_hi, wg_lo, nullptr, ft, nullptr, nullptr, nullptr,
        NN, 3 * HH, HH / 2);

    // CSR SpMM per view -> split-bf16 z only
    for (int v = 0; v < PP; ++v) {
        spmm_csr_kernel<<<(NN * 64 + 255) / 256, 256>>>(
            (const float4*)(ft + (size_t)v * NN * HH),
            rowptr + v * (NN + 1),
            esrc + (size_t)v * EE, eval_ + (size_t)v * EE,
            zh + (size_t)v * NN * (HH / 2), zl + (size_t)v * NN * (HH / 2),
            b_gcn + (size_t)v * HH, a_gcn + v);
    }

    // student predictor: GEMM1 emits split x + fused BN stats
    gemm_bf16s_kernel<3><<<dim3(PHH / TBN, mb), 256>>>(
        zh, zl, w1_hi, w1_lo, b1, nullptr, x_hi, x_lo, stats, NN, PHH, HH / 2);
    bn_prelu_kernel<<<(NN * PHH / 4) / 256, 256>>>(x_hi, x_lo, stats, bn_g, bn_b, a_pred);
    gemm_bf16s_kernel<2><<<dim3(HH / TBN, mb), 256>>>(
        x_hi, x_lo, w2_hi, w2_lo, b2, vp, nullptr, nullptr, nullptr, NN, HH, PHH / 2);

    // cosine losses vs teachers (views 1 and 2, reconstructed from splits)
    loss_kernel<<<(NN * 32) / 256, 256>>>((const float4*)vp, zh, zl, loss_acc);

    // type-level attention, all 3 views, single-pass bf16 (hi only)
    gemm_att_bf16_kernel<<<dim3(HH / TBN, mb, 3), 256>>>(zh, wa_hi, b_att, att,
                                                         beta_raw, NN, HH / 2);

    float* outf = (float*)d_out;
    int write_loss = (out_size > NN * HH) ? 1 : 0;
    finalize_kernel<<<1, 1>>>(outf + (size_t)NN * HH, write_loss);
    zout_kernel<<<(NN * 64) / 256, 256>>>((float4*)outf, zh, zl);
}

// round 12
// speedup vs baseline: 1.4866x; 1.0358x over previous
#include <cuda_runtime.h>
#include <math.h>
#include <stdint.h>

// ---------------- problem constants ----------------
#define NN   50000
#define PP   3
#define EE   800000
#define FEATD 1000
#define HH   256
#define PHH  512
#define BN_EPS 1e-5f

// ---------------- device scratch (no allocations allowed) ----------------
__device__ uint32_t g_h_hi [(size_t)NN * (HH / 2)];
__device__ uint32_t g_h_lo [(size_t)NN * (HH / 2)];
__device__ float    g_ft[(size_t)3 * NN * HH];         // view-major [3][N][256]
__device__ uint32_t g_z_hi[(size_t)3 * NN * (HH / 2)];
__device__ uint32_t g_z_lo[(size_t)3 * NN * (HH / 2)];
__device__ uint32_t g_x_hi[(size_t)NN * (PHH / 2)];
__device__ uint32_t g_x_lo[(size_t)NN * (PHH / 2)];
__device__ float    g_vp[(size_t)NN * HH];
// CSR scratch
__device__ int   g_deg[3 * NN];
__device__ int   g_rowptr[3 * (NN + 1)];
__device__ int   g_cursor[3 * NN];
__device__ int   g_esrc[(size_t)3 * EE];
__device__ float g_eval[(size_t)3 * EE];
// split weights
__device__ uint32_t g_wt_hi[HH * (FEATD / 2)];
__device__ uint32_t g_wt_lo[HH * (FEATD / 2)];
__device__ uint32_t g_wg_hi[3 * HH * (HH / 2)];
__device__ uint32_t g_wg_lo[3 * HH * (HH / 2)];
__device__ uint32_t g_w1_hi[PHH * (HH / 2)];
__device__ uint32_t g_w1_lo[PHH * (HH / 2)];
__device__ uint32_t g_w2_hi[HH * (PHH / 2)];
__device__ uint32_t g_w2_lo[HH * (PHH / 2)];
__device__ uint32_t g_wa_hi[HH * (HH / 2)];
__device__ uint32_t g_wa_lo[HH * (HH / 2)];
__device__ float g_stats[2 * PHH];
__device__ float g_beta_raw[3];
__device__ float g_beta[3];
__device__ float g_loss_acc;

// ---------------- bf16 split helpers --------------------------------------------
__device__ __forceinline__ uint32_t pack_hi(float x0, float x1)
{
    uint32_t r;
    asm("prmt.b32 %0, %1, %2, 0x7632;"
        : "=r"(r) : "r"(__float_as_uint(x0)), "r"(__float_as_uint(x1)));
    return r;
}

__device__ __forceinline__ uint32_t pack_lo(float x0, float x1)
{
    float h0 = __uint_as_float(__float_as_uint(x0) & 0xFFFF0000u);
    float h1 = __uint_as_float(__float_as_uint(x1) & 0xFFFF0000u);
    uint32_t r;
    asm("cvt.rn.bf16x2.f32 %0, %1, %2;" : "=r"(r) : "f"(x1 - h1), "f"(x0 - h0));
    return r;
}

__device__ __forceinline__ void unpack2(uint32_t hi, uint32_t lo, float& f0, float& f1)
{
    f0 = __uint_as_float(hi << 16)          + __uint_as_float(lo << 16);
    f1 = __uint_as_float(hi & 0xFFFF0000u)  + __uint_as_float(lo & 0xFFFF0000u);
}

__device__ __forceinline__ void mma_bf16(float* c, const uint32_t* a, const uint32_t* b)
{
    asm volatile(
        "mma.sync.aligned.m16n8k16.row.col.f32.bf16.bf16.f32 "
        "{%0,%1,%2,%3}, {%4,%5,%6,%7}, {%8,%9}, {%0,%1,%2,%3};\n"
        : "+f"(c[0]), "+f"(c[1]), "+f"(c[2]), "+f"(c[3])
        : "r"(a[0]), "r"(a[1]), "r"(a[2]), "r"(a[3]), "r"(b[0]), "r"(b[1]));
}

__device__ __forceinline__ void ldsm_x4(uint32_t* r, uint32_t saddr)
{
    asm volatile("ldmatrix.sync.aligned.m8n8.x4.shared.b16 {%0,%1,%2,%3}, [%4];"
                 : "=r"(r[0]), "=r"(r[1]), "=r"(r[2]), "=r"(r[3]) : "r"(saddr));
}

__device__ __forceinline__ void cp16(uint32_t saddr, const void* gmem, bool pred)
{
    int sz = pred ? 16 : 0;
    asm volatile("cp.async.cg.shared.global [%0], [%1], 16, %2;\n"
                 :: "r"(saddr), "l"(gmem), "r"(sz));
}

// ---------------- generic f32 -> split-bf16 pass (weights only) -----------------
__global__ __launch_bounds__(256)
void split_kernel(const float2* __restrict__ in, uint32_t* __restrict__ hi,
                  uint32_t* __restrict__ lo, size_t npairs)
{
    size_t i = (size_t)blockIdx.x * blockDim.x + threadIdx.x;
    if (i >= npairs) return;
    float2 v = in[i];
    hi[i] = pack_hi(v.x, v.y);
    if (lo) lo[i] = pack_lo(v.x, v.y);
}

// ---------------- CSR build ------------------------------------------------------
__global__ __launch_bounds__(256)
void hist_kernel(const int* __restrict__ dst, int* __restrict__ deg)
{
    int i = blockIdx.x * 256 + threadIdx.x;
    if (i >= 3 * EE) return;
    int v = i / EE;
    atomicAdd(&deg[v * NN + dst[i]], 1);
}

__global__ __launch_bounds__(1024)
void scan_kernel(const int* __restrict__ deg, int* __restrict__ rowptr,
                 int* __restrict__ cursor)
{
    const int CH = (NN + 1023) / 1024;   // 49
    int v = blockIdx.x;
    const int* d = deg + v * NN;
    int* rp = rowptr + v * (NN + 1);
    int* cur = cursor + v * NN;
    int t = threadIdx.x;
    int lane = t & 31, w = t >> 5;
    __shared__ int warpsums[32];

    int base = t * CH;
    int local[CH];
    int sum = 0;
#pragma unroll
    for (int k = 0; k < CH; ++k) {
        int idx = base + k;
        int val = (idx < NN) ? d[idx] : 0;
        local[k] = sum;
        sum += val;
    }
    int s = sum;
#pragma unroll
    for (int o = 1; o < 32; o <<= 1) {
        int y = __shfl_up_sync(0xffffffffu, s, o);
        if (lane >= o) s += y;
    }
    if (lane == 31) warpsums[w] = s;
    __syncthreads();
    if (w == 0) {
        int ws = warpsums[lane];
#pragma unroll
        for (int o = 1; o < 32; o <<= 1) {
            int y = __shfl_up_sync(0xffffffffu, ws, o);
            if (lane >= o) ws += y;
        }
        warpsums[lane] = ws;
    }
    __syncthreads();
    int offset = (w > 0 ? warpsums[w - 1] : 0) + (s - sum);
#pragma unroll
    for (int k = 0; k < CH; ++k) {
        int idx = base + k;
        if (idx < NN) {
            int val = offset + local[k];
            rp[idx] = val;
            cur[idx] = val;
        }
    }
    if (t == 1023) rp[NN] = EE;
}

__global__ __launch_bounds__(256)
void scatter_kernel(const int* __restrict__ src, const int* __restrict__ dst,
                    const float* __restrict__ vals, int* __restrict__ cursor,
                    int* __restrict__ esrc, float* __restrict__ eval_)
{
    int i = blockIdx.x * 256 + threadIdx.x;
    if (i >= 3 * EE) return;
    int v = i / EE;
    int d = dst[i];
    int pos = atomicAdd(&cursor[v * NN + d], 1);
    esrc[(size_t)v * EE + pos] = src[i];
    eval_[(size_t)v * EE + pos] = vals[i];
}

// ---------------- CSR SpMM + bias + PReLU -> split-bf16 only (one view) ---------
__global__ __launch_bounds__(256)
void spmm_csr_kernel(const float4* __restrict__ ftv, const int* __restrict__ rp,
                     const int* __restrict__ es, const float* __restrict__ ev,
                     uint32_t* __restrict__ zhiv, uint32_t* __restrict__ zlov,
                     const float* __restrict__ bvp, const float* __restrict__ avp)
{
    int gid = blockIdx.x * 256 + threadIdx.x;
    if (gid >= NN * 64) return;
    int n = gid >> 6;
    int c = gid & 63;
    int i  = rp[n];
    int s1 = rp[n + 1];

    float4 acc = make_float4(0.f, 0.f, 0.f, 0.f);
    for (; i + 2 <= s1; i += 2) {
        int sa = es[i];     float va = ev[i];
        int sb = es[i + 1]; float vb = ev[i + 1];
        float4 fa = ftv[(size_t)sa * 64 + c];
        float4 fb = ftv[(size_t)sb * 64 + c];
        acc.x += va * fa.x; acc.y += va * fa.y; acc.z += va * fa.z; acc.w += va * fa.w;
        acc.x += vb * fb.x; acc.y += vb * fb.y; acc.z += vb * fb.z; acc.w += vb * fb.w;
    }
    if (i < s1) {
        int sa = es[i]; float va = ev[i];
        float4 fa = ftv[(size_t)sa * 64 + c];
        acc.x += va * fa.x; acc.y += va * fa.y; acc.z += va * fa.z; acc.w += va * fa.w;
    }

    float a = *avp;
    float4 bv = *(const float4*)(bvp + (c << 2));
    acc.x += bv.x; acc.y += bv.y; acc.z += bv.z; acc.w += bv.w;
    acc.x = acc.x >= 0.f ? acc.x : a * acc.x;
    acc.y = acc.y >= 0.f ? acc.y : a * acc.y;
    acc.z = acc.z >= 0.f ? acc.z : a * acc.z;
    acc.w = acc.w >= 0.f ? acc.w : a * acc.w;

    size_t p = ((size_t)n * 64 + c) << 1;
    zhiv[p]     = pack_hi(acc.x, acc.y);
    zhiv[p + 1] = pack_hi(acc.z, acc.w);
    zlov[p]     = pack_lo(acc.x, acc.y);
    zlov[p + 1] = pack_lo(acc.z, acc.w);
}

// ---------------- split-bf16 GEMM ------------------------------------------------
// Block tile 128x128, BK=16 elems (8 u32), 8 warps (2m x 4n), warp tile 64x32.
// 3 MMAs per atom. Fragment loads via ldmatrix.x4 (conflict-free at TPAD=12).
#define TBM 128
#define TBN 128
#define TPAD 12
#define STG_BYTES (TBM * TPAD * 4)   // per-stage stride (A and W identical)

#define GS_DECL()                                                                   \
    __shared__ __align__(16) uint32_t AsH[2][TBM][TPAD];                            \
    __shared__ __align__(16) uint32_t AsL[2][TBM][TPAD];                            \
    __shared__ __align__(16) uint32_t WsH[2][TBN][TPAD];                            \
    __shared__ __align__(16) uint32_t WsL[2][TBN][TPAD];                            \
    const int tid  = threadIdx.x;                                                   \
    const int wid  = tid >> 5;                                                      \
    const int lane = tid & 31;                                                      \
    const int g    = lane >> 2;                                                     \
    const int t    = lane & 3;                                                      \
    const int wm   = (wid & 1) << 6;                                                \
    const int wn   = (wid >> 1) << 5;                                               \
    const int bm   = blockIdx.y * TBM;                                              \
    const int bn   = blockIdx.x * TBN;                                              \
    const uint32_t sAsH = (uint32_t)__cvta_generic_to_shared(&AsH[0][0][0]);        \
    const uint32_t sAsL = (uint32_t)__cvta_generic_to_shared(&AsL[0][0][0]);        \
    const uint32_t sWsH = (uint32_t)__cvta_generic_to_shared(&WsH[0][0][0]);        \
    const uint32_t sWsL = (uint32_t)__cvta_generic_to_shared(&WsL[0][0][0]);        \
    const uint32_t offA = (uint32_t)(((wm + (lane & 7) + ((lane >> 3) & 1) * 8)     \
                                      * TPAD + ((lane >> 4) << 2)) * 4);            \
    const uint32_t offB = (uint32_t)(((wn + ((lane >> 4) & 1) * 8 + (lane & 7))     \
                                      * TPAD + (((lane >> 3) & 1) << 2)) * 4);      \
    float acc[4][4][4] = {};

#define GS_LOAD(S, KP0)                                                             \
    {                                                                               \
        int r  = tid >> 1, ch = (tid & 1) << 2;                                     \
        int gp = (KP0) + ch;                                                        \
        bool pa = (gp < Kp) && (bm + r < M);                                        \
        size_t offa = (size_t)(bm + r) * Kp + gp;                                   \
        cp16((uint32_t)__cvta_generic_to_shared(&AsH[S][r][ch]), Ahi + offa, pa);   \
        cp16((uint32_t)__cvta_generic_to_shared(&AsL[S][r][ch]), Alo + offa, pa);   \
        bool pb = (gp < Kp);                                                        \
        size_t offb = (size_t)(bn + r) * Kp + gp;                                   \
        cp16((uint32_t)__cvta_generic_to_shared(&WsH[S][r][ch]), Whi + offb, pb);   \
        cp16((uint32_t)__cvta_generic_to_shared(&WsL[S][r][ch]), Wlo + offb, pb);   \
    }

#define GS_LOAD_AF32(S, KP0)                                                        \
    {                                                                               \
        int r  = tid >> 1, ch = (tid & 1) << 2;                                     \
        int gp = (KP0) + ch;                                                        \
        float4 f0 = make_float4(0.f, 0.f, 0.f, 0.f), f1 = f0;                       \
        if (gp < Kp && bm + r < M) {                                                \
            const float* ap = Af32 + (size_t)(bm + r) * (Kp * 2) + gp * 2;          \
            f0 = *(const float4*)ap;                                                \
            f1 = *(const float4*)(ap + 4);                                          \
        }                                                                           \
        AsH[S][r][ch + 0] = pack_hi(f0.x, f0.y); AsL[S][r][ch + 0] = pack_lo(f0.x, f0.y); \
        AsH[S][r][ch + 1] = pack_hi(f0.z, f0.w); AsL[S][r][ch + 1] = pack_lo(f0.z, f0.w); \
        AsH[S][r][ch + 2] = pack_hi(f1.x, f1.y); AsL[S][r][ch + 2] = pack_lo(f1.x, f1.y); \
        AsH[S][r][ch + 3] = pack_hi(f1.z, f1.w); AsL[S][r][ch + 3] = pack_lo(f1.z, f1.w); \
        bool pb = (gp < Kp);                                                        \
        size_t offb = (size_t)(bn + r) * Kp + gp;                                   \
        cp16((uint32_t)__cvta_generic_to_shared(&WsH[S][r][ch]), Whi + offb, pb);   \
        cp16((uint32_t)__cvta_generic_to_shared(&WsL[S][r][ch]), Wlo + offb, pb);   \
    }

#define GS_COMPUTE()                                                                \
    {                                                                               \
        uint32_t aH[4][4], aL[4][4], bH[4][2], bL[4][2];                            \
        uint32_t bs = (uint32_t)buf * STG_BYTES;                                    \
        _Pragma("unroll")                                                           \
        for (int i = 0; i < 4; ++i) {                                               \
            uint32_t ao = bs + offA + (uint32_t)(i * 16 * TPAD * 4);                \
            ldsm_x4(aH[i], sAsH + ao);                                              \
            ldsm_x4(aL[i], sAsL + ao);                                              \
        }                                                                           \
        _Pragma("unroll")                                                           \
        for (int jj = 0; jj < 2; ++jj) {                                            \
            uint32_t bo = bs + offB + (uint32_t)(jj * 16 * TPAD * 4);               \
            uint32_t tH[4], tL[4];                                                  \
            ldsm_x4(tH, sWsH + bo);                                                 \
            ldsm_x4(tL, sWsL + bo);                                                 \
            bH[2 * jj][0] = tH[0]; bH[2 * jj][1] = tH[1];                           \
            bH[2 * jj + 1][0] = tH[2]; bH[2 * jj + 1][1] = tH[3];                   \
            bL[2 * jj][0] = tL[0]; bL[2 * jj][1] = tL[1];                           \
            bL[2 * jj + 1][0] = tL[2]; bL[2 * jj + 1][1] = tL[3];                   \
        }                                                                           \
        _Pragma("unroll")                                                           \
        for (int i = 0; i < 4; ++i)                                                 \
            _Pragma("unroll")                                                       \
            for (int j = 0; j < 4; ++j) {                                           \
                mma_bf16(acc[i][j], aL[i], bH[j]);                                  \
                mma_bf16(acc[i][j], aH[i], bL[j]);                                  \
                mma_bf16(acc[i][j], aH[i], bH[j]);                                  \
            }                                                                       \
    }

#define GS_MAINLOOP(LOADM)                                                          \
    LOADM(0, 0);                                                                    \
    asm volatile("cp.async.commit_group;\n" ::: "memory");                          \
    int buf = 0;                                                                    \
    for (int kp0 = 0; kp0 < Kp; kp0 += 8) {                                         \
        if (kp0 + 8 < Kp) LOADM(buf ^ 1, kp0 + 8);                                  \
        asm volatile("cp.async.commit_group;\n" ::: "memory");                      \
        asm volatile("cp.async.wait_group 1;\n" ::: "memory");                      \
        __syncthreads();                                                            \
        GS_COMPUTE();                                                               \
        __syncthreads();                                                            \
        buf ^= 1;                                                                   \
    }

// EPI: 0 = raw f32 view-major, 2 = bias f32, 3 = bias -> split bf16 + BN stats
template<int EPI>
__global__ __launch_bounds__(256, 2)
void gemm_bf16s_kernel(const uint32_t* __restrict__ Ahi, const uint32_t* __restrict__ Alo,
                       const uint32_t* __restrict__ Whi, const uint32_t* __restrict__ Wlo,
                       const float* __restrict__ bias, float* __restrict__ C,
                       uint32_t* __restrict__ Chi, uint32_t* __restrict__ Clo,
                       float* __restrict__ stats, int M, int Nc, int Kp)
{
    GS_DECL();
    GS_MAINLOOP(GS_LOAD);

    float* sSum = (float*)&AsH[0][0][0];      // 128 floats (dead pipeline smem)
    float* sSq  = sSum + 128;
    if (EPI == 3) {
        __syncthreads();
        if (tid < 128) { sSum[tid] = 0.f; sSq[tid] = 0.f; }
        __syncthreads();
    }

#pragma unroll
    for (int j = 0; j < 4; ++j) {
        float cs0 = 0.f, cq0 = 0.f, cs1 = 0.f, cq1 = 0.f;
#pragma unroll
        for (int i = 0; i < 4; ++i) {
            int r0 = bm + wm + (i << 4) + g;
            int r1 = r0 + 8;
            int c0 = bn + wn + (j << 3) + (t << 1);
            float bx = 0.f, by = 0.f;
            if (EPI >= 2) { bx = bias[c0]; by = bias[c0 + 1]; }
            float v0 = acc[i][j][0] + bx, v1 = acc[i][j][1] + by;
            float v2 = acc[i][j][2] + bx, v3 = acc[i][j][3] + by;
            if (EPI == 0) {
                int vv = c0 >> 8;
                int cc = c0 & 255;
                float* base = C + (size_t)vv * NN * HH + cc;
                if (r0 < M) *(float2*)(base + (size_t)r0 * HH) = make_float2(v0, v1);
                if (r1 < M) *(float2*)(base + (size_t)r1 * HH) = make_float2(v2, v3);
            } else if (EPI == 2) {
                if (r0 < M) *(float2*)(C + (size_t)r0 * Nc + c0) = make_float2(v0, v1);
                if (r1 < M) *(float2*)(C + (size_t)r1 * Nc + c0) = make_float2(v2, v3);
            } else {
                int pc = c0 >> 1;
                if (r0 < M) {
                    Chi[(size_t)r0 * (Nc / 2) + pc] = pack_hi(v0, v1);
                    Clo[(size_t)r0 * (Nc / 2) + pc] = pack_lo(v0, v1);
                    cs0 += v0; cq0 += v0 * v0; cs1 += v1; cq1 += v1 * v1;
                }
                if (r1 < M) {
                    Chi[(size_t)r1 * (Nc / 2) + pc] = pack_hi(v2, v3);
                    Clo[(size_t)r1 * (Nc / 2) + pc] = pack_lo(v2, v3);
                    cs0 += v2; cq0 += v2 * v2; cs1 += v3; cq1 += v3 * v3;
                }
            }
        }
        if (EPI == 3) {
            int lc = wn + (j << 3) + (t << 1);
            atomicAdd(&sSum[lc], cs0);     atomicAdd(&sSq[lc], cq0);
            atomicAdd(&sSum[lc + 1], cs1); atomicAdd(&sSq[lc + 1], cq1);
        }
    }
    if (EPI == 3) {
        __syncthreads();
        if (tid < 128) {
            atomicAdd(&stats[bn + tid], sSum[tid]);
            atomicAdd(&stats[PHH + bn + tid], sSq[tid]);
        }
    }
}

// feats GEMM: A = raw f32, epilogue bias+ELU -> split bf16 h
__global__ __launch_bounds__(256, 2)
void gemm_bf16s_af32_kernel(const float* __restrict__ Af32,
                            const uint32_t* __restrict__ Whi, const uint32_t* __restrict__ Wlo,
                            const float* __restrict__ bias,
                            uint32_t* __restrict__ Chi, uint32_t* __restrict__ Clo,
                            int M, int Nc, int Kp)
{
    GS_DECL();
    GS_MAINLOOP(GS_LOAD_AF32);

#pragma unroll
    for (int i = 0; i < 4; ++i) {
#pragma unroll
        for (int j = 0; j < 4; ++j) {
            int r0 = bm + wm + (i << 4) + g;
            int r1 = r0 + 8;
            int c0 = bn + wn + (j << 3) + (t << 1);
            float bx = bias[c0], by = bias[c0 + 1];
            float v0 = acc[i][j][0] + bx, v1 = acc[i][j][1] + by;
            float v2 = acc[i][j][2] + bx, v3 = acc[i][j][3] + by;
            v0 = v0 > 0.f ? v0 : expm1f(v0);
            v1 = v1 > 0.f ? v1 : expm1f(v1);
            v2 = v2 > 0.f ? v2 : expm1f(v2);
            v3 = v3 > 0.f ? v3 : expm1f(v3);
            int pc = c0 >> 1;
            if (r0 < M) {
                Chi[(size_t)r0 * (Nc / 2) + pc] = pack_hi(v0, v1);
                Clo[(size_t)r0 * (Nc / 2) + pc] = pack_lo(v0, v1);
            }
            if (r1 < M) {
                Chi[(size_t)r1 * (Nc / 2) + pc] = pack_hi(v2, v3);
                Clo[(size_t)r1 * (Nc / 2) + pc] = pack_lo(v2, v3);
            }
        }
    }
}

// attention GEMM: z hi-only x split W (zH*WH + zH*WL) — kills systematic W error.
// blockIdx.z = view; beta index = (view+2)%3.
__global__ __launch_bounds__(256, 2)
void gemm_att_bf16_kernel(const uint32_t* __restrict__ Zhi,
                          const uint32_t* __restrict__ Whi, const uint32_t* __restrict__ Wlo,
                          const float* __restrict__ bias, const float* __restrict__ att,
                          float* __restrict__ beta_raw, int M, int Kp)
{
    __shared__ __align__(16) uint32_t AsH[2][TBM][TPAD];
    __shared__ __align__(16) uint32_t WsH[2][TBN][TPAD];
    __shared__ __align__(16) uint32_t WsL[2][TBN][TPAD];
    const int tid  = threadIdx.x;
    const int wid  = tid >> 5;
    const int lane = tid & 31;
    const int g    = lane >> 2;
    const int t    = lane & 3;
    const int wm   = (wid & 1) << 6;
    const int wn   = (wid >> 1) << 5;
    const int bm   = blockIdx.y * TBM;
    const int bn   = blockIdx.x * TBN;
    const int view = blockIdx.z;
    const uint32_t* Ahi = Zhi + (size_t)view * NN * (HH / 2);
    const uint32_t sAsH = (uint32_t)__cvta_generic_to_shared(&AsH[0][0][0]);
    const uint32_t sWsH = (uint32_t)__cvta_generic_to_shared(&WsH[0][0][0]);
    const uint32_t sWsL = (uint32_t)__cvta_generic_to_shared(&WsL[0][0][0]);
    const uint32_t offA = (uint32_t)(((wm + (lane & 7) + ((lane >> 3) & 1) * 8)
                                      * TPAD + ((lane >> 4) << 2)) * 4);
    const uint32_t offB = (uint32_t)(((wn + ((lane >> 4) & 1) * 8 + (lane & 7))
                                      * TPAD + (((lane >> 3) & 1) << 2)) * 4);
    float acc[4][4][4] = {};

#define GA_LOAD(S, KP0)                                                             \
    {                                                                               \
        int r  = tid >> 1, ch = (tid & 1) << 2;                                     \
        int gp = (KP0) + ch;                                                        \
        bool pa = (gp < Kp) && (bm + r < M);                                        \
        cp16((uint32_t)__cvta_generic_to_shared(&AsH[S][r][ch]),                    \
             Ahi + (size_t)(bm + r) * Kp + gp, pa);                                 \
        bool pb = (gp < Kp);                                                        \
        cp16((uint32_t)__cvta_generic_to_shared(&WsH[S][r][ch]),                    \
             Whi + (size_t)(bn + r) * Kp + gp, pb);                                 \
        cp16((uint32_t)__cvta_generic_to_shared(&WsL[S][r][ch]),                    \
             Wlo + (size_t)(bn + r) * Kp + gp, pb);                                 \
    }

    GA_LOAD(0, 0);
    asm volatile("cp.async.commit_group;\n" ::: "memory");
    int buf = 0;
    for (int kp0 = 0; kp0 < Kp; kp0 += 8) {
        if (kp0 + 8 < Kp) GA_LOAD(buf ^ 1, kp0 + 8);
        asm volatile("cp.async.commit_group;\n" ::: "memory");
        asm volatile("cp.async.wait_group 1;\n" ::: "memory");
        __syncthreads();
        uint32_t aH[4][4], bH[4][2], bL[4][2];
        uint32_t bs = (uint32_t)buf * STG_BYTES;
#pragma unroll
        for (int i = 0; i < 4; ++i)
            ldsm_x4(aH[i], sAsH + bs + offA + (uint32_t)(i * 16 * TPAD * 4));
#pragma unroll
        for (int jj = 0; jj < 2; ++jj) {
            uint32_t bo = bs + offB + (uint32_t)(jj * 16 * TPAD * 4);
            uint32_t tH[4], tL[4];
            ldsm_x4(tH, sWsH + bo);
            ldsm_x4(tL, sWsL + bo);
            bH[2 * jj][0] = tH[0]; bH[2 * jj][1] = tH[1];
            bH[2 * jj + 1][0] = tH[2]; bH[2 * jj + 1][1] = tH[3];
            bL[2 * jj][0] = tL[0]; bL[2 * jj][1] = tL[1];
            bL[2 * jj + 1][0] = tL[2]; bL[2 * jj + 1][1] = tL[3];
        }
#pragma unroll
        for (int i = 0; i < 4; ++i)
#pragma unroll
            for (int j = 0; j < 4; ++j) {
                mma_bf16(acc[i][j], aH[i], bL[j]);
                mma_bf16(acc[i][j], aH[i], bH[j]);
            }
        __syncthreads();
        buf ^= 1;
    }
#undef GA_LOAD

    float s = 0.f;
#pragma unroll
    for (int i = 0; i < 4; ++i) {
#pragma unroll
        for (int j = 0; j < 4; ++j) {
            int r0 = bm + wm + (i << 4) + g;
            int r1 = r0 + 8;
            int c0 = bn + wn + (j << 3) + (t << 1);
            float bx = bias[c0], by = bias[c0 + 1];
            float ax = att[c0],  ay = att[c0 + 1];
            if (r0 < M) s += tanhf(acc[i][j][0] + bx) * ax + tanhf(acc[i][j][1] + by) * ay;
            if (r1 < M) s += tanhf(acc[i][j][2] + bx) * ax + tanhf(acc[i][j][3] + by) * ay;
        }
    }
    float* red = (float*)&AsH[0][0][0];
    __syncthreads();
    red[tid] = s;
    __syncthreads();
    for (int o = 128; o > 0; o >>= 1) {
        if (tid < o) red[tid] += red[tid + o];
        __syncthreads();
    }
    if (tid == 0) {
        int bidx = (view + 2) % 3;
        atomicAdd(&beta_raw[bidx], red[0]);
    }
}

// ---------------- BN + PReLU on split-bf16 x (in place) -------------------------
__global__ __launch_bounds__(256)
void bn_prelu_kernel(uint32_t* __restrict__ xhi, uint32_t* __restrict__ xlo,
                     const float* __restrict__ stats,
                     const float* __restrict__ g, const float* __restrict__ b,
                     const float* __restrict__ a_ptr)
{
    int i = blockIdx.x * blockDim.x + threadIdx.x;
    if (i >= NN * (PHH / 4)) return;
    int c = (i & (PHH / 4 - 1)) << 2;
    float a = *a_ptr;
    float4 sm = *(const float4*)(stats + c);
    float4 sq = *(const float4*)(stats + PHH + c);
    float4 gv = *(const float4*)(g + c);
    float4 bv = *(const float4*)(b + c);
    uint2 h = ((const uint2*)xhi)[i];
    uint2 l = ((const uint2*)xlo)[i];
    float4 v;
    unpack2(h.x, l.x, v.x, v.y);
    unpack2(h.y, l.y, v.z, v.w);
    float invN = 1.f / (float)NN;

    float mu, var, sc, sh, y;
    mu = sm.x * invN; var = sq.x * invN - mu * mu; sc = gv.x * rsqrtf(var + BN_EPS);
    sh = bv.x - mu * sc; y = v.x * sc + sh; v.x = y >= 0.f ? y : a * y;
    mu = sm.y * invN; var = sq.y * invN - mu * mu; sc = gv.y * rsqrtf(var + BN_EPS);
    sh = bv.y - mu * sc; y = v.y * sc + sh; v.y = y >= 0.f ? y : a * y;
    mu = sm.z * invN; var = sq.z * invN - mu * mu; sc = gv.z * rsqrtf(var + BN_EPS);
    sh = bv.z - mu * sc; y = v.z * sc + sh; v.z = y >= 0.f ? y : a * y;
    mu = sm.w * invN; var = sq.w * invN - mu * mu; sc = gv.w * rsqrtf(var + BN_EPS);
    sh = bv.w - mu * sc; y = v.w * sc + sh; v.w = y >= 0.f ? y : a * y;

    uint2 nh, nl;
    nh.x = pack_hi(v.x, v.y); nl.x = pack_lo(v.x, v.y);
    nh.y = pack_hi(v.z, v.w); nl.y = pack_lo(v.z, v.w);
    ((uint2*)xhi)[i] = nh;
    ((uint2*)xlo)[i] = nl;
}

// ---------------- cosine loss (one warp per node; teachers from split-bf16) -----
__global__ __launch_bounds__(256)
void loss_kernel(const float4* __restrict__ p,
                 const uint32_t* __restrict__ zh, const uint32_t* __restrict__ zl,
                 float* __restrict__ acc)
{
    const uint32_t* t1h = zh + (size_t)NN * (HH / 2);
    const uint32_t* t1l = zl + (size_t)NN * (HH / 2);
    const uint32_t* t2h = zh + (size_t)2 * NN * (HH / 2);
    const uint32_t* t2l = zl + (size_t)2 * NN * (HH / 2);
    int gid  = blockIdx.x * blockDim.x + threadIdx.x;
    int node = gid >> 5;
    int lane = gid & 31;
    float pp = 0.f, n1 = 0.f, n2 = 0.f, d1 = 0.f, d2 = 0.f;
    if (node < NN) {
        size_t base4 = (size_t)node * 64;
        size_t baseu = (size_t)node * 128;
#pragma unroll
        for (int r = 0; r < 2; ++r) {
            int q = lane + 32 * r;
            float4 a = p[base4 + q];
            uint2 h1 = *(const uint2*)&t1h[baseu + 2 * q];
            uint2 l1 = *(const uint2*)&t1l[baseu + 2 * q];
            uint2 h2 = *(const uint2*)&t2h[baseu + 2 * q];
            uint2 l2 = *(const uint2*)&t2l[baseu + 2 * q];
            float4 b, cc;
            unpack2(h1.x, l1.x, b.x, b.y);  unpack2(h1.y, l1.y, b.z, b.w);
            unpack2(h2.x, l2.x, cc.x, cc.y); unpack2(h2.y, l2.y, cc.z, cc.w);
            pp += a.x * a.x + a.y * a.y + a.z * a.z + a.w * a.w;
            n1 += b.x * b.x + b.y * b.y + b.z * b.z + b.w * b.w;
            n2 += cc.x * cc.x + cc.y * cc.y + cc.z * cc.z + cc.w * cc.w;
            d1 += a.x * b.x + a.y * b.y + a.z * b.z + a.w * b.w;
            d2 += a.x * cc.x + a.y * cc.y + a.z * cc.z + a.w * cc.w;
        }
    }
#pragma unroll
    for (int o = 16; o > 0; o >>= 1) {
        pp += __shfl_down_sync(0xffffffffu, pp, o);
        n1 += __shfl_down_sync(0xffffffffu, n1, o);
        n2 += __shfl_down_sync(0xffffffffu, n2, o);
        d1 += __shfl_down_sync(0xffffffffu, d1, o);
        d2 += __shfl_down_sync(0xffffffffu, d2, o);
    }
    __shared__ float sacc[8];
    float contrib = 0.f;
    if (lane == 0 && node < NN) {
        float np  = fmaxf(sqrtf(pp), 1e-12f);
        float nn1 = fmaxf(sqrtf(n1), 1e-12f);
        float nn2 = fmaxf(sqrtf(n2), 1e-12f);
        contrib = d1 / (np * nn1) + d2 / (np * nn2);
    }
    int wid = threadIdx.x >> 5;
    if (lane == 0) sacc[wid] = contrib;
    __syncthreads();
    if (threadIdx.x == 0) {
        float s = 0.f;
#pragma unroll
        for (int i = 0; i < 8; ++i) s += sacc[i];
        atomicAdd(acc, s);
    }
}

// ---------------- finalize: softmax(beta), loss --------------------------------
__global__ void finalize_kernel(float* __restrict__ out_loss, int write_loss)
{
    float invN = 1.f / (float)NN;
    float b0 = g_beta_raw[0] * invN;
    float b1 = g_beta_raw[1] * invN;
    float b2 = g_beta_raw[2] * invN;
    float m = fmaxf(b0, fmaxf(b1, b2));
    float e0 = expf(b0 - m), e1 = expf(b1 - m), e2 = expf(b2 - m);
    float s = e0 + e1 + e2;
    g_beta[0] = e0 / s;
    g_beta[1] = e1 / s;
    g_beta[2] = e2 / s;
    if (write_loss) *out_loss = 2.0f - g_loss_acc * invN;
}

// ---------------- z_out = b0*z1 + b1*z2 + b2*z0 (from split-bf16) ----------------
__global__ __launch_bounds__(256)
void zout_kernel(float4* __restrict__ out, const uint32_t* __restrict__ zh,
                 const uint32_t* __restrict__ zl)
{
    int i = blockIdx.x * blockDim.x + threadIdx.x;
    if (i >= NN * 64) return;
    float b2 = g_beta[2], b0 = g_beta[0], b1 = g_beta[1];   // student, t1, t2
    const size_t vstride = (size_t)NN * (HH / 2);
    size_t u = (size_t)i * 2;
    uint2 h0 = *(const uint2*)&zh[u];
    uint2 l0 = *(const uint2*)&zl[u];
    uint2 h1 = *(const uint2*)&zh[vstride + u];
    uint2 l1 = *(const uint2*)&zl[vstride + u];
    uint2 h2 = *(const uint2*)&zh[2 * vstride + u];
    uint2 l2 = *(const uint2*)&zl[2 * vstride + u];
    float4 a, b, c;
    unpack2(h0.x, l0.x, c.x, c.y); unpack2(h0.y, l0.y, c.z, c.w);   // student
    unpack2(h1.x, l1.x, a.x, a.y); unpack2(h1.y, l1.y, a.z, a.w);   // teacher1
    unpack2(h2.x, l2.x, b.x, b.y); unpack2(h2.y, l2.y, b.z, b.w);   // teacher2
    float4 r;
    r.x = b0 * a.x + b1 * b.x + b2 * c.x;
    r.y = b0 * a.y + b1 * b.y + b2 * c.y;
    r.z = b0 * a.z + b1 * b.z + b2 * c.z;
    r.w = b0 * a.w + b1 * b.w + b2 * c.w;
    out[i] = r;
}

// ---------------- host ----------------------------------------------------------
#define GETSYM(var, sym) cudaGetSymbolAddress((void**)&var, sym)

extern "C" void kernel_launch(void* const* d_in, const int* in_sizes, int n_in,
                              void* d_out, int out_size)
{
    const float* feats   = (const float*)d_in[0];
    const int*   src     = (const int*)  d_in[1];
    const int*   dst     = (const int*)  d_in[2];
    const float* vals    = (const float*)d_in[3];
    const float* W_trans = (const float*)d_in[4];
    const float* b_trans = (const float*)d_in[5];
    const float* W_gcn   = (const float*)d_in[6];
    const float* b_gcn   = (const float*)d_in[7];
    const float* a_gcn   = (const float*)d_in[8];
    const float* W1      = (const float*)d_in[9];
    const float* b1      = (const float*)d_in[10];
    const float* bn_g    = (const float*)d_in[11];
    const float* bn_b    = (const float*)d_in[12];
    const float* a_pred  = (const float*)d_in[13];
    const float* W2      = (const float*)d_in[14];
    const float* b2      = (const float*)d_in[15];
    const float* W_att   = (const float*)d_in[16];
    const float* b_att   = (const float*)d_in[17];
    const float* att     = (const float*)d_in[18];

    uint32_t *h_hi, *h_lo, *zh, *zl;
    uint32_t *x_hi, *x_lo, *wt_hi, *wt_lo, *wg_hi, *wg_lo, *w1_hi, *w1_lo;
    uint32_t *w2_hi, *w2_lo, *wa_hi, *wa_lo;
    float *ft, *vp, *stats, *beta_raw, *loss_acc;
    int *deg, *rowptr, *cursor, *esrc;
    float *eval_;
    GETSYM(h_hi, g_h_hi);   GETSYM(h_lo, g_h_lo);
    GETSYM(zh, g_z_hi); GETSYM(zl, g_z_lo);
    GETSYM(x_hi, g_x_hi); GETSYM(x_lo, g_x_lo);
    GETSYM(wt_hi, g_wt_hi); GETSYM(wt_lo, g_wt_lo);
    GETSYM(wg_hi, g_wg_hi); GETSYM(wg_lo, g_wg_lo);
    GETSYM(w1_hi, g_w1_hi); GETSYM(w1_lo, g_w1_lo);
    GETSYM(w2_hi, g_w2_hi); GETSYM(w2_lo, g_w2_lo);
    GETSYM(wa_hi, g_wa_hi); GETSYM(wa_lo, g_wa_lo);
    GETSYM(ft, g_ft);
    GETSYM(vp, g_vp);
    GETSYM(stats, g_stats); GETSYM(beta_raw, g_beta_raw); GETSYM(loss_acc, g_loss_acc);
    GETSYM(deg, g_deg); GETSYM(rowptr, g_rowptr); GETSYM(cursor, g_cursor);
    GETSYM(esrc, g_esrc); GETSYM(eval_, g_eval);

    cudaMemsetAsync(deg, 0, 3 * NN * sizeof(int));
    cudaMemsetAsync(stats, 0, 2 * PHH * sizeof(float));
    cudaMemsetAsync(beta_raw, 0, 3 * sizeof(float));
    cudaMemsetAsync(loss_acc, 0, sizeof(float));

    // CSR build (all 3 views)
    hist_kernel<<<(3 * EE + 255) / 256, 256>>>(dst, deg);
    scan_kernel<<<3, 1024>>>(deg, rowptr, cursor);
    scatter_kernel<<<(3 * EE + 255) / 256, 256>>>(src, dst, vals, cursor, esrc, eval_);

    // split weights -> bf16 hi/lo (small, L2-resident)
    {
        size_t np = (size_t)HH * (FEATD / 2);
        split_kernel<<<(int)((np + 255) / 256), 256>>>((const float2*)W_trans, wt_hi, wt_lo, np);
        np = (size_t)3 * HH * (HH / 2);
        split_kernel<<<(int)((np + 255) / 256), 256>>>((const float2*)W_gcn, wg_hi, wg_lo, np);
        np = (size_t)PHH * (HH / 2);
        split_kernel<<<(int)((np + 255) / 256), 256>>>((const float2*)W1, w1_hi, w1_lo, np);
        np = (size_t)HH * (PHH / 2);
        split_kernel<<<(int)((np + 255) / 256), 256>>>((const float2*)W2, w2_hi, w2_lo, np);
        np = (size_t)HH * (HH / 2);
        split_kernel<<<(int)((np + 255) / 256), 256>>>((const float2*)W_att, wa_hi, wa_lo, np);
    }

    const int mb = (NN + TBM - 1) / TBM;   // 391

    // h = elu(feats @ W_trans^T + b_trans): A read as f32, split in-kernel
    gemm_bf16s_af32_kernel<<<dim3(HH / TBN, mb), 256>>>(
        feats, wt_hi, wt_lo, b_trans, h_hi, h_lo, NN, HH, FEATD / 2);

    // fused GCN GEMM -> view-major ft [3][N][256]
    gemm_bf16s_kernel<0><<<dim3(3 * HH / TBN, mb), 256>>>(
        h_hi, h_lo, wg_hi, wg_lo, nullptr, ft, nullptr, nullptr, nullptr,
        NN, 3 * HH, HH / 2);

    // CSR SpMM per view -> split-bf16 z only
    for (int v = 0; v < PP; ++v) {
        spmm_csr_kernel<<<(NN * 64 + 255) / 256, 256>>>(
            (const float4*)(ft + (size_t)v * NN * HH),
            rowptr + v * (NN + 1),
            esrc + (size_t)v * EE, eval_ + (size_t)v * EE,
            zh + (size_t)v * NN * (HH / 2), zl + (size_t)v * NN * (HH / 2),
            b_gcn + (size_t)v * HH, a_gcn + v);
    }

    // student predictor: GEMM1 emits split x + fused BN stats
    gemm_bf16s_kernel<3><<<dim3(PHH / TBN, mb), 256>>>(
        zh, zl, w1_hi, w1_lo, b1, nullptr, x_hi, x_lo, stats, NN, PHH, HH / 2);
    bn_prelu_kernel<<<(NN * PHH / 4) / 256, 256>>>(x_hi, x_lo, stats, bn_g, bn_b, a_pred);
    gemm_bf16s_kernel<2><<<dim3(HH / TBN, mb), 256>>>(
        x_hi, x_lo, w2_hi, w2_lo, b2, vp, nullptr, nullptr, nullptr, NN, HH, PHH / 2);

    // cosine losses vs teachers (views 1 and 2, reconstructed from splits)
    loss_kernel<<<(NN * 32) / 256, 256>>>((const float4*)vp, zh, zl, loss_acc);

    // type-level attention, all 3 views, zH x (WH + WL)
    gemm_att_bf16_kernel<<<dim3(HH / TBN, mb, 3), 256>>>(zh, wa_hi, wa_lo, b_att, att,
                                                         beta_raw, NN, HH / 2);

    float* outf = (float*)d_out;
    int write_loss = (out_size > NN * HH) ? 1 : 0;
    finalize_kernel<<<1, 1>>>(outf + (size_t)NN * HH, write_loss);
    zout_kernel<<<(NN * 64) / 256, 256>>>((float4*)outf, zh, zl);
}

// round 13
// speedup vs baseline: 1.5946x; 1.0727x over previous
#include <cuda_runtime.h>
#include <math.h>
#include <stdint.h>

// ---------------- problem constants ----------------
#define NN   50000
#define PP   3
#define EE   800000
#define FEATD 1000
#define HH   256
#define PHH  512
#define BN_EPS 1e-5f

// ---------------- device scratch (no allocations allowed) ----------------
__device__ uint32_t g_h_hi [(size_t)NN * (HH / 2)];
__device__ uint32_t g_h_lo [(size_t)NN * (HH / 2)];
__device__ float    g_ft[(size_t)3 * NN * HH];         // view-major [3][N][256]
__device__ uint32_t g_z_hi[(size_t)3 * NN * (HH / 2)];
__device__ uint32_t g_z_lo[(size_t)3 * NN * (HH / 2)];
__device__ uint32_t g_x_hi[(size_t)NN * (PHH / 2)];
__device__ uint32_t g_x_lo[(size_t)NN * (PHH / 2)];
__device__ float    g_vp[(size_t)NN * HH];
// CSR scratch
__device__ int   g_deg[3 * NN];
__device__ int   g_rowptr[3 * (NN + 1)];
__device__ int   g_cursor[3 * NN];
__device__ int   g_esrc[(size_t)3 * EE];
__device__ float g_eval[(size_t)3 * EE];
// split weights
__device__ uint32_t g_wt_hi[HH * (FEATD / 2)];
__device__ uint32_t g_wt_lo[HH * (FEATD / 2)];
__device__ uint32_t g_wg_hi[3 * HH * (HH / 2)];
__device__ uint32_t g_wg_lo[3 * HH * (HH / 2)];
__device__ uint32_t g_w1_hi[PHH * (HH / 2)];
__device__ uint32_t g_w1_lo[PHH * (HH / 2)];
__device__ uint32_t g_w2_hi[HH * (PHH / 2)];
__device__ uint32_t g_w2_lo[HH * (PHH / 2)];
__device__ uint32_t g_wa_hi[HH * (HH / 2)];
__device__ uint32_t g_wa_lo[HH * (HH / 2)];
__device__ float g_stats[2 * PHH];
__device__ float g_beta_raw[3];
__device__ float g_beta[3];
__device__ float g_loss_acc;

// ---------------- bf16 split helpers --------------------------------------------
__device__ __forceinline__ uint32_t pack_hi(float x0, float x1)
{
    uint32_t r;
    asm("prmt.b32 %0, %1, %2, 0x7632;"
        : "=r"(r) : "r"(__float_as_uint(x0)), "r"(__float_as_uint(x1)));
    return r;
}

__device__ __forceinline__ uint32_t pack_lo(float x0, float x1)
{
    float h0 = __uint_as_float(__float_as_uint(x0) & 0xFFFF0000u);
    float h1 = __uint_as_float(__float_as_uint(x1) & 0xFFFF0000u);
    uint32_t r;
    asm("cvt.rn.bf16x2.f32 %0, %1, %2;" : "=r"(r) : "f"(x1 - h1), "f"(x0 - h0));
    return r;
}

__device__ __forceinline__ void unpack2(uint32_t hi, uint32_t lo, float& f0, float& f1)
{
    f0 = __uint_as_float(hi << 16)          + __uint_as_float(lo << 16);
    f1 = __uint_as_float(hi & 0xFFFF0000u)  + __uint_as_float(lo & 0xFFFF0000u);
}

__device__ __forceinline__ void mma_bf16(float* c, const uint32_t* a, const uint32_t* b)
{
    asm volatile(
        "mma.sync.aligned.m16n8k16.row.col.f32.bf16.bf16.f32 "
        "{%0,%1,%2,%3}, {%4,%5,%6,%7}, {%8,%9}, {%0,%1,%2,%3};\n"
        : "+f"(c[0]), "+f"(c[1]), "+f"(c[2]), "+f"(c[3])
        : "r"(a[0]), "r"(a[1]), "r"(a[2]), "r"(a[3]), "r"(b[0]), "r"(b[1]));
}

__device__ __forceinline__ void ldsm_x4(uint32_t* r, uint32_t saddr)
{
    asm volatile("ldmatrix.sync.aligned.m8n8.x4.shared.b16 {%0,%1,%2,%3}, [%4];"
                 : "=r"(r[0]), "=r"(r[1]), "=r"(r[2]), "=r"(r[3]) : "r"(saddr));
}

__device__ __forceinline__ void cp16(uint32_t saddr, const void* gmem, bool pred)
{
    int sz = pred ? 16 : 0;
    asm volatile("cp.async.cg.shared.global [%0], [%1], 16, %2;\n"
                 :: "r"(saddr), "l"(gmem), "r"(sz));
}

// ---------------- generic f32 -> split-bf16 pass (weights only) -----------------
__global__ __launch_bounds__(256)
void split_kernel(const float2* __restrict__ in, uint32_t* __restrict__ hi,
                  uint32_t* __restrict__ lo, size_t npairs)
{
    size_t i = (size_t)blockIdx.x * blockDim.x + threadIdx.x;
    if (i >= npairs) return;
    float2 v = in[i];
    hi[i] = pack_hi(v.x, v.y);
    if (lo) lo[i] = pack_lo(v.x, v.y);
}

// ---------------- CSR build ------------------------------------------------------
__global__ __launch_bounds__(256)
void hist_kernel(const int* __restrict__ dst, int* __restrict__ deg)
{
    int i = blockIdx.x * 256 + threadIdx.x;
    if (i >= 3 * EE) return;
    int v = i / EE;
    atomicAdd(&deg[v * NN + dst[i]], 1);
}

__global__ __launch_bounds__(1024)
void scan_kernel(const int* __restrict__ deg, int* __restrict__ rowptr,
                 int* __restrict__ cursor)
{
    const int CH = (NN + 1023) / 1024;   // 49
    int v = blockIdx.x;
    const int* d = deg + v * NN;
    int* rp = rowptr + v * (NN + 1);
    int* cur = cursor + v * NN;
    int t = threadIdx.x;
    int lane = t & 31, w = t >> 5;
    __shared__ int warpsums[32];

    int base = t * CH;
    int local[CH];
    int sum = 0;
#pragma unroll
    for (int k = 0; k < CH; ++k) {
        int idx = base + k;
        int val = (idx < NN) ? d[idx] : 0;
        local[k] = sum;
        sum += val;
    }
    int s = sum;
#pragma unroll
    for (int o = 1; o < 32; o <<= 1) {
        int y = __shfl_up_sync(0xffffffffu, s, o);
        if (lane >= o) s += y;
    }
    if (lane == 31) warpsums[w] = s;
    __syncthreads();
    if (w == 0) {
        int ws = warpsums[lane];
#pragma unroll
        for (int o = 1; o < 32; o <<= 1) {
            int y = __shfl_up_sync(0xffffffffu, ws, o);
            if (lane >= o) ws += y;
        }
        warpsums[lane] = ws;
    }
    __syncthreads();
    int offset = (w > 0 ? warpsums[w - 1] : 0) + (s - sum);
#pragma unroll
    for (int k = 0; k < CH; ++k) {
        int idx = base + k;
        if (idx < NN) {
            int val = offset + local[k];
            rp[idx] = val;
            cur[idx] = val;
        }
    }
    if (t == 1023) rp[NN] = EE;
}

__global__ __launch_bounds__(256)
void scatter_kernel(const int* __restrict__ src, const int* __restrict__ dst,
                    const float* __restrict__ vals, int* __restrict__ cursor,
                    int* __restrict__ esrc, float* __restrict__ eval_)
{
    int i = blockIdx.x * 256 + threadIdx.x;
    if (i >= 3 * EE) return;
    int v = i / EE;
    int d = dst[i];
    int pos = atomicAdd(&cursor[v * NN + d], 1);
    esrc[(size_t)v * EE + pos] = src[i];
    eval_[(size_t)v * EE + pos] = vals[i];
}

// ---------------- CSR SpMM + bias + PReLU -> split-bf16 only (one view) ---------
__global__ __launch_bounds__(256)
void spmm_csr_kernel(const float4* __restrict__ ftv, const int* __restrict__ rp,
                     const int* __restrict__ es, const float* __restrict__ ev,
                     uint32_t* __restrict__ zhiv, uint32_t* __restrict__ zlov,
                     const float* __restrict__ bvp, const float* __restrict__ avp)
{
    int gid = blockIdx.x * 256 + threadIdx.x;
    if (gid >= NN * 64) return;
    int n = gid >> 6;
    int c = gid & 63;
    int i  = rp[n];
    int s1 = rp[n + 1];

    float4 acc = make_float4(0.f, 0.f, 0.f, 0.f);
    for (; i + 2 <= s1; i += 2) {
        int sa = es[i];     float va = ev[i];
        int sb = es[i + 1]; float vb = ev[i + 1];
        float4 fa = ftv[(size_t)sa * 64 + c];
        float4 fb = ftv[(size_t)sb * 64 + c];
        acc.x += va * fa.x; acc.y += va * fa.y; acc.z += va * fa.z; acc.w += va * fa.w;
        acc.x += vb * fb.x; acc.y += vb * fb.y; acc.z += vb * fb.z; acc.w += vb * fb.w;
    }
    if (i < s1) {
        int sa = es[i]; float va = ev[i];
        float4 fa = ftv[(size_t)sa * 64 + c];
        acc.x += va * fa.x; acc.y += va * fa.y; acc.z += va * fa.z; acc.w += va * fa.w;
    }

    float a = *avp;
    float4 bv = *(const float4*)(bvp + (c << 2));
    acc.x += bv.x; acc.y += bv.y; acc.z += bv.z; acc.w += bv.w;
    acc.x = acc.x >= 0.f ? acc.x : a * acc.x;
    acc.y = acc.y >= 0.f ? acc.y : a * acc.y;
    acc.z = acc.z >= 0.f ? acc.z : a * acc.z;
    acc.w = acc.w >= 0.f ? acc.w : a * acc.w;

    size_t p = ((size_t)n * 64 + c) << 1;
    zhiv[p]     = pack_hi(acc.x, acc.y);
    zhiv[p + 1] = pack_hi(acc.z, acc.w);
    zlov[p]     = pack_lo(acc.x, acc.y);
    zlov[p + 1] = pack_lo(acc.z, acc.w);
}

// ---------------- split-bf16 GEMM ------------------------------------------------
// Block tile 128x128, BK=16 elems (8 u32), 8 warps (2m x 4n), warp tile 64x32.
// 3 MMAs per atom. Fragment loads via ldmatrix.x4 (conflict-free at TPAD=12).
#define TBM 128
#define TBN 128
#define TPAD 12
#define STG_BYTES (TBM * TPAD * 4)

#define GS_DECL()                                                                   \
    __shared__ __align__(16) uint32_t AsH[2][TBM][TPAD];                            \
    __shared__ __align__(16) uint32_t AsL[2][TBM][TPAD];                            \
    __shared__ __align__(16) uint32_t WsH[2][TBN][TPAD];                            \
    __shared__ __align__(16) uint32_t WsL[2][TBN][TPAD];                            \
    const int tid  = threadIdx.x;                                                   \
    const int wid  = tid >> 5;                                                      \
    const int lane = tid & 31;                                                      \
    const int g    = lane >> 2;                                                     \
    const int t    = lane & 3;                                                      \
    const int wm   = (wid & 1) << 6;                                                \
    const int wn   = (wid >> 1) << 5;                                               \
    const int bm   = blockIdx.y * TBM;                                              \
    const int bn   = blockIdx.x * TBN;                                              \
    const uint32_t sAsH = (uint32_t)__cvta_generic_to_shared(&AsH[0][0][0]);        \
    const uint32_t sAsL = (uint32_t)__cvta_generic_to_shared(&AsL[0][0][0]);        \
    const uint32_t sWsH = (uint32_t)__cvta_generic_to_shared(&WsH[0][0][0]);        \
    const uint32_t sWsL = (uint32_t)__cvta_generic_to_shared(&WsL[0][0][0]);        \
    const uint32_t offA = (uint32_t)(((wm + (lane & 7) + ((lane >> 3) & 1) * 8)     \
                                      * TPAD + ((lane >> 4) << 2)) * 4);            \
    const uint32_t offB = (uint32_t)(((wn + ((lane >> 4) & 1) * 8 + (lane & 7))     \
                                      * TPAD + (((lane >> 3) & 1) << 2)) * 4);      \
    float acc[4][4][4] = {};

#define GS_LOAD(S, KP0)                                                             \
    {                                                                               \
        int r  = tid >> 1, ch = (tid & 1) << 2;                                     \
        int gp = (KP0) + ch;                                                        \
        bool pa = (gp < Kp) && (bm + r < M);                                        \
        size_t offa = (size_t)(bm + r) * Kp + gp;                                   \
        cp16((uint32_t)__cvta_generic_to_shared(&AsH[S][r][ch]), Ahi + offa, pa);   \
        cp16((uint32_t)__cvta_generic_to_shared(&AsL[S][r][ch]), Alo + offa, pa);   \
        bool pb = (gp < Kp);                                                        \
        size_t offb = (size_t)(bn + r) * Kp + gp;                                   \
        cp16((uint32_t)__cvta_generic_to_shared(&WsH[S][r][ch]), Whi + offb, pb);   \
        cp16((uint32_t)__cvta_generic_to_shared(&WsL[S][r][ch]), Wlo + offb, pb);   \
    }

#define GS_LOAD_AF32(S, KP0)                                                        \
    {                                                                               \
        int r  = tid >> 1, ch = (tid & 1) << 2;                                     \
        int gp = (KP0) + ch;                                                        \
        float4 f0 = make_float4(0.f, 0.f, 0.f, 0.f), f1 = f0;                       \
        if (gp < Kp && bm + r < M) {                                                \
            const float* ap = Af32 + (size_t)(bm + r) * (Kp * 2) + gp * 2;          \
            f0 = *(const float4*)ap;                                                \
            f1 = *(const float4*)(ap + 4);                                          \
        }                                                                           \
        AsH[S][r][ch + 0] = pack_hi(f0.x, f0.y); AsL[S][r][ch + 0] = pack_lo(f0.x, f0.y); \
        AsH[S][r][ch + 1] = pack_hi(f0.z, f0.w); AsL[S][r][ch + 1] = pack_lo(f0.z, f0.w); \
        AsH[S][r][ch + 2] = pack_hi(f1.x, f1.y); AsL[S][r][ch + 2] = pack_lo(f1.x, f1.y); \
        AsH[S][r][ch + 3] = pack_hi(f1.z, f1.w); AsL[S][r][ch + 3] = pack_lo(f1.z, f1.w); \
        bool pb = (gp < Kp);                                                        \
        size_t offb = (size_t)(bn + r) * Kp + gp;                                   \
        cp16((uint32_t)__cvta_generic_to_shared(&WsH[S][r][ch]), Whi + offb, pb);   \
        cp16((uint32_t)__cvta_generic_to_shared(&WsL[S][r][ch]), Wlo + offb, pb);   \
    }

#define GS_COMPUTE()                                                                \
    {                                                                               \
        uint32_t aH[4][4], aL[4][4], bH[4][2], bL[4][2];                            \
        uint32_t bs = (uint32_t)buf * STG_BYTES;                                    \
        _Pragma("unroll")                                                           \
        for (int i = 0; i < 4; ++i) {                                               \
            uint32_t ao = bs + offA + (uint32_t)(i * 16 * TPAD * 4);                \
            ldsm_x4(aH[i], sAsH + ao);                                              \
            ldsm_x4(aL[i], sAsL + ao);                                              \
        }                                                                           \
        _Pragma("unroll")                                                           \
        for (int jj = 0; jj < 2; ++jj) {                                            \
            uint32_t bo = bs + offB + (uint32_t)(jj * 16 * TPAD * 4);               \
            uint32_t tH[4], tL[4];                                                  \
            ldsm_x4(tH, sWsH + bo);                                                 \
            ldsm_x4(tL, sWsL + bo);                                                 \
            bH[2 * jj][0] = tH[0]; bH[2 * jj][1] = tH[1];                           \
            bH[2 * jj + 1][0] = tH[2]; bH[2 * jj + 1][1] = tH[3];                   \
            bL[2 * jj][0] = tL[0]; bL[2 * jj][1] = tL[1];                           \
            bL[2 * jj + 1][0] = tL[2]; bL[2 * jj + 1][1] = tL[3];                   \
        }                                                                           \
        _Pragma("unroll")                                                           \
        for (int i = 0; i < 4; ++i)                                                 \
            _Pragma("unroll")                                                       \
            for (int j = 0; j < 4; ++j) {                                           \
                mma_bf16(acc[i][j], aL[i], bH[j]);                                  \
                mma_bf16(acc[i][j], aH[i], bL[j]);                                  \
                mma_bf16(acc[i][j], aH[i], bH[j]);                                  \
            }                                                                       \
    }

#define GS_MAINLOOP(LOADM)                                                          \
    LOADM(0, 0);                                                                    \
    asm volatile("cp.async.commit_group;\n" ::: "memory");                          \
    int buf = 0;                                                                    \
    for (int kp0 = 0; kp0 < Kp; kp0 += 8) {                                         \
        if (kp0 + 8 < Kp) LOADM(buf ^ 1, kp0 + 8);                                  \
        asm volatile("cp.async.commit_group;\n" ::: "memory");                      \
        asm volatile("cp.async.wait_group 1;\n" ::: "memory");                      \
        __syncthreads();                                                            \
        GS_COMPUTE();                                                               \
        __syncthreads();                                                            \
        buf ^= 1;                                                                   \
    }

// EPI: 0 = raw f32 view-major, 2 = bias f32, 3 = bias -> split bf16 + BN stats
template<int EPI>
__global__ __launch_bounds__(256, 2)
void gemm_bf16s_kernel(const uint32_t* __restrict__ Ahi, const uint32_t* __restrict__ Alo,
                       const uint32_t* __restrict__ Whi, const uint32_t* __restrict__ Wlo,
                       const float* __restrict__ bias, float* __restrict__ C,
                       uint32_t* __restrict__ Chi, uint32_t* __restrict__ Clo,
                       float* __restrict__ stats, int M, int Nc, int Kp)
{
    GS_DECL();
    GS_MAINLOOP(GS_LOAD);

    float* sSum = (float*)&AsH[0][0][0];
    float* sSq  = sSum + 128;
    if (EPI == 3) {
        __syncthreads();
        if (tid < 128) { sSum[tid] = 0.f; sSq[tid] = 0.f; }
        __syncthreads();
    }

#pragma unroll
    for (int j = 0; j < 4; ++j) {
        float cs0 = 0.f, cq0 = 0.f, cs1 = 0.f, cq1 = 0.f;
#pragma unroll
        for (int i = 0; i < 4; ++i) {
            int r0 = bm + wm + (i << 4) + g;
            int r1 = r0 + 8;
            int c0 = bn + wn + (j << 3) + (t << 1);
            float bx = 0.f, by = 0.f;
            if (EPI >= 2) { bx = bias[c0]; by = bias[c0 + 1]; }
            float v0 = acc[i][j][0] + bx, v1 = acc[i][j][1] + by;
            float v2 = acc[i][j][2] + bx, v3 = acc[i][j][3] + by;
            if (EPI == 0) {
                int vv = c0 >> 8;
                int cc = c0 & 255;
                float* base = C + (size_t)vv * NN * HH + cc;
                if (r0 < M) *(float2*)(base + (size_t)r0 * HH) = make_float2(v0, v1);
                if (r1 < M) *(float2*)(base + (size_t)r1 * HH) = make_float2(v2, v3);
            } else if (EPI == 2) {
                if (r0 < M) *(float2*)(C + (size_t)r0 * Nc + c0) = make_float2(v0, v1);
                if (r1 < M) *(float2*)(C + (size_t)r1 * Nc + c0) = make_float2(v2, v3);
            } else {
                int pc = c0 >> 1;
                if (r0 < M) {
                    Chi[(size_t)r0 * (Nc / 2) + pc] = pack_hi(v0, v1);
                    Clo[(size_t)r0 * (Nc / 2) + pc] = pack_lo(v0, v1);
                    cs0 += v0; cq0 += v0 * v0; cs1 += v1; cq1 += v1 * v1;
                }
                if (r1 < M) {
                    Chi[(size_t)r1 * (Nc / 2) + pc] = pack_hi(v2, v3);
                    Clo[(size_t)r1 * (Nc / 2) + pc] = pack_lo(v2, v3);
                    cs0 += v2; cq0 += v2 * v2; cs1 += v3; cq1 += v3 * v3;
                }
            }
        }
        if (EPI == 3) {
            int lc = wn + (j << 3) + (t << 1);
            atomicAdd(&sSum[lc], cs0);     atomicAdd(&sSq[lc], cq0);
            atomicAdd(&sSum[lc + 1], cs1); atomicAdd(&sSq[lc + 1], cq1);
        }
    }
    if (EPI == 3) {
        __syncthreads();
        if (tid < 128) {
            atomicAdd(&stats[bn + tid], sSum[tid]);
            atomicAdd(&stats[PHH + bn + tid], sSq[tid]);
        }
    }
}

// feats GEMM: A = raw f32, epilogue bias+ELU -> split bf16 h
__global__ __launch_bounds__(256, 2)
void gemm_bf16s_af32_kernel(const float* __restrict__ Af32,
                            const uint32_t* __restrict__ Whi, const uint32_t* __restrict__ Wlo,
                            const float* __restrict__ bias,
                            uint32_t* __restrict__ Chi, uint32_t* __restrict__ Clo,
                            int M, int Nc, int Kp)
{
    GS_DECL();
    GS_MAINLOOP(GS_LOAD_AF32);

#pragma unroll
    for (int i = 0; i < 4; ++i) {
#pragma unroll
        for (int j = 0; j < 4; ++j) {
            int r0 = bm + wm + (i << 4) + g;
            int r1 = r0 + 8;
            int c0 = bn + wn + (j << 3) + (t << 1);
            float bx = bias[c0], by = bias[c0 + 1];
            float v0 = acc[i][j][0] + bx, v1 = acc[i][j][1] + by;
            float v2 = acc[i][j][2] + bx, v3 = acc[i][j][3] + by;
            v0 = v0 > 0.f ? v0 : expm1f(v0);
            v1 = v1 > 0.f ? v1 : expm1f(v1);
            v2 = v2 > 0.f ? v2 : expm1f(v2);
            v3 = v3 > 0.f ? v3 : expm1f(v3);
            int pc = c0 >> 1;
            if (r0 < M) {
                Chi[(size_t)r0 * (Nc / 2) + pc] = pack_hi(v0, v1);
                Clo[(size_t)r0 * (Nc / 2) + pc] = pack_lo(v0, v1);
            }
            if (r1 < M) {
                Chi[(size_t)r1 * (Nc / 2) + pc] = pack_hi(v2, v3);
                Clo[(size_t)r1 * (Nc / 2) + pc] = pack_lo(v2, v3);
            }
        }
    }
}

// attention GEMM: z hi-only x split W (zH*WH + zH*WL).
// blockIdx.z = view; beta index = (view+2)%3.
__global__ __launch_bounds__(256, 2)
void gemm_att_bf16_kernel(const uint32_t* __restrict__ Zhi,
                          const uint32_t* __restrict__ Whi, const uint32_t* __restrict__ Wlo,
                          const float* __restrict__ bias, const float* __restrict__ att,
                          float* __restrict__ beta_raw, int M, int Kp)
{
    __shared__ __align__(16) uint32_t AsH[2][TBM][TPAD];
    __shared__ __align__(16) uint32_t WsH[2][TBN][TPAD];
    __shared__ __align__(16) uint32_t WsL[2][TBN][TPAD];
    const int tid  = threadIdx.x;
    const int wid  = tid >> 5;
    const int lane = tid & 31;
    const int g    = lane >> 2;
    const int t    = lane & 3;
    const int wm   = (wid & 1) << 6;
    const int wn   = (wid >> 1) << 5;
    const int bm   = blockIdx.y * TBM;
    const int bn   = blockIdx.x * TBN;
    const int view = blockIdx.z;
    const uint32_t* Ahi = Zhi + (size_t)view * NN * (HH / 2);
    const uint32_t sAsH = (uint32_t)__cvta_generic_to_shared(&AsH[0][0][0]);
    const uint32_t sWsH = (uint32_t)__cvta_generic_to_shared(&WsH[0][0][0]);
    const uint32_t sWsL = (uint32_t)__cvta_generic_to_shared(&WsL[0][0][0]);
    const uint32_t offA = (uint32_t)(((wm + (lane & 7) + ((lane >> 3) & 1) * 8)
                                      * TPAD + ((lane >> 4) << 2)) * 4);
    const uint32_t offB = (uint32_t)(((wn + ((lane >> 4) & 1) * 8 + (lane & 7))
                                      * TPAD + (((lane >> 3) & 1) << 2)) * 4);
    float acc[4][4][4] = {};

#define GA_LOAD(S, KP0)                                                             \
    {                                                                               \
        int r  = tid >> 1, ch = (tid & 1) << 2;                                     \
        int gp = (KP0) + ch;                                                        \
        bool pa = (gp < Kp) && (bm + r < M);                                        \
        cp16((uint32_t)__cvta_generic_to_shared(&AsH[S][r][ch]),                    \
             Ahi + (size_t)(bm + r) * Kp + gp, pa);                                 \
        bool pb = (gp < Kp);                                                        \
        cp16((uint32_t)__cvta_generic_to_shared(&WsH[S][r][ch]),                    \
             Whi + (size_t)(bn + r) * Kp + gp, pb);                                 \
        cp16((uint32_t)__cvta_generic_to_shared(&WsL[S][r][ch]),                    \
             Wlo + (size_t)(bn + r) * Kp + gp, pb);                                 \
    }

    GA_LOAD(0, 0);
    asm volatile("cp.async.commit_group;\n" ::: "memory");
    int buf = 0;
    for (int kp0 = 0; kp0 < Kp; kp0 += 8) {
        if (kp0 + 8 < Kp) GA_LOAD(buf ^ 1, kp0 + 8);
        asm volatile("cp.async.commit_group;\n" ::: "memory");
        asm volatile("cp.async.wait_group 1;\n" ::: "memory");
        __syncthreads();
        uint32_t aH[4][4], bH[4][2], bL[4][2];
        uint32_t bs = (uint32_t)buf * STG_BYTES;
#pragma unroll
        for (int i = 0; i < 4; ++i)
            ldsm_x4(aH[i], sAsH + bs + offA + (uint32_t)(i * 16 * TPAD * 4));
#pragma unroll
        for (int jj = 0; jj < 2; ++jj) {
            uint32_t bo = bs + offB + (uint32_t)(jj * 16 * TPAD * 4);
            uint32_t tH[4], tL[4];
            ldsm_x4(tH, sWsH + bo);
            ldsm_x4(tL, sWsL + bo);
            bH[2 * jj][0] = tH[0]; bH[2 * jj][1] = tH[1];
            bH[2 * jj + 1][0] = tH[2]; bH[2 * jj + 1][1] = tH[3];
            bL[2 * jj][0] = tL[0]; bL[2 * jj][1] = tL[1];
            bL[2 * jj + 1][0] = tL[2]; bL[2 * jj + 1][1] = tL[3];
        }
#pragma unroll
        for (int i = 0; i < 4; ++i)
#pragma unroll
            for (int j = 0; j < 4; ++j) {
                mma_bf16(acc[i][j], aH[i], bL[j]);
                mma_bf16(acc[i][j], aH[i], bH[j]);
            }
        __syncthreads();
        buf ^= 1;
    }
#undef GA_LOAD

    float s = 0.f;
#pragma unroll
    for (int i = 0; i < 4; ++i) {
#pragma unroll
        for (int j = 0; j < 4; ++j) {
            int r0 = bm + wm + (i << 4) + g;
            int r1 = r0 + 8;
            int c0 = bn + wn + (j << 3) + (t << 1);
            float bx = bias[c0], by = bias[c0 + 1];
            float ax = att[c0],  ay = att[c0 + 1];
            if (r0 < M) s += tanhf(acc[i][j][0] + bx) * ax + tanhf(acc[i][j][1] + by) * ay;
            if (r1 < M) s += tanhf(acc[i][j][2] + bx) * ax + tanhf(acc[i][j][3] + by) * ay;
        }
    }
    float* red = (float*)&AsH[0][0][0];
    __syncthreads();
    red[tid] = s;
    __syncthreads();
    for (int o = 128; o > 0; o >>= 1) {
        if (tid < o) red[tid] += red[tid + o];
        __syncthreads();
    }
    if (tid == 0) {
        int bidx = (view + 2) % 3;
        atomicAdd(&beta_raw[bidx], red[0]);
    }
}

// ---------------- BN + PReLU on split-bf16 x (in place) -------------------------
__global__ __launch_bounds__(256)
void bn_prelu_kernel(uint32_t* __restrict__ xhi, uint32_t* __restrict__ xlo,
                     const float* __restrict__ stats,
                     const float* __restrict__ g, const float* __restrict__ b,
                     const float* __restrict__ a_ptr)
{
    int i = blockIdx.x * blockDim.x + threadIdx.x;
    if (i >= NN * (PHH / 4)) return;
    int c = (i & (PHH / 4 - 1)) << 2;
    float a = *a_ptr;
    float4 sm = *(const float4*)(stats + c);
    float4 sq = *(const float4*)(stats + PHH + c);
    float4 gv = *(const float4*)(g + c);
    float4 bv = *(const float4*)(b + c);
    uint2 h = ((const uint2*)xhi)[i];
    uint2 l = ((const uint2*)xlo)[i];
    float4 v;
    unpack2(h.x, l.x, v.x, v.y);
    unpack2(h.y, l.y, v.z, v.w);
    float invN = 1.f / (float)NN;

    float mu, var, sc, sh, y;
    mu = sm.x * invN; var = sq.x * invN - mu * mu; sc = gv.x * rsqrtf(var + BN_EPS);
    sh = bv.x - mu * sc; y = v.x * sc + sh; v.x = y >= 0.f ? y : a * y;
    mu = sm.y * invN; var = sq.y * invN - mu * mu; sc = gv.y * rsqrtf(var + BN_EPS);
    sh = bv.y - mu * sc; y = v.y * sc + sh; v.y = y >= 0.f ? y : a * y;
    mu = sm.z * invN; var = sq.z * invN - mu * mu; sc = gv.z * rsqrtf(var + BN_EPS);
    sh = bv.z - mu * sc; y = v.z * sc + sh; v.z = y >= 0.f ? y : a * y;
    mu = sm.w * invN; var = sq.w * invN - mu * mu; sc = gv.w * rsqrtf(var + BN_EPS);
    sh = bv.w - mu * sc; y = v.w * sc + sh; v.w = y >= 0.f ? y : a * y;

    uint2 nh, nl;
    nh.x = pack_hi(v.x, v.y); nl.x = pack_lo(v.x, v.y);
    nh.y = pack_hi(v.z, v.w); nl.y = pack_lo(v.z, v.w);
    ((uint2*)xhi)[i] = nh;
    ((uint2*)xlo)[i] = nl;
}

// ---------------- cosine loss (one warp per node; teachers from split-bf16) -----
__global__ __launch_bounds__(256)
void loss_kernel(const float4* __restrict__ p,
                 const uint32_t* __restrict__ zh, const uint32_t* __restrict__ zl,
                 float* __restrict__ acc)
{
    const uint32_t* t1h = zh + (size_t)NN * (HH / 2);
    const uint32_t* t1l = zl + (size_t)NN * (HH / 2);
    const uint32_t* t2h = zh + (size_t)2 * NN * (HH / 2);
    const uint32_t* t2l = zl + (size_t)2 * NN * (HH / 2);
    int gid  = blockIdx.x * blockDim.x + threadIdx.x;
    int node = gid >> 5;
    int lane = gid & 31;
    float pp = 0.f, n1 = 0.f, n2 = 0.f, d1 = 0.f, d2 = 0.f;
    if (node < NN) {
        size_t base4 = (size_t)node * 64;
        size_t baseu = (size_t)node * 128;
#pragma unroll
        for (int r = 0; r < 2; ++r) {
            int q = lane + 32 * r;
            float4 a = p[base4 + q];
            uint2 h1 = *(const uint2*)&t1h[baseu + 2 * q];
            uint2 l1 = *(const uint2*)&t1l[baseu + 2 * q];
            uint2 h2 = *(const uint2*)&t2h[baseu + 2 * q];
            uint2 l2 = *(const uint2*)&t2l[baseu + 2 * q];
            float4 b, cc;
            unpack2(h1.x, l1.x, b.x, b.y);  unpack2(h1.y, l1.y, b.z, b.w);
            unpack2(h2.x, l2.x, cc.x, cc.y); unpack2(h2.y, l2.y, cc.z, cc.w);
            pp += a.x * a.x + a.y * a.y + a.z * a.z + a.w * a.w;
            n1 += b.x * b.x + b.y * b.y + b.z * b.z + b.w * b.w;
            n2 += cc.x * cc.x + cc.y * cc.y + cc.z * cc.z + cc.w * cc.w;
            d1 += a.x * b.x + a.y * b.y + a.z * b.z + a.w * b.w;
            d2 += a.x * cc.x + a.y * cc.y + a.z * cc.z + a.w * cc.w;
        }
    }
#pragma unroll
    for (int o = 16; o > 0; o >>= 1) {
        pp += __shfl_down_sync(0xffffffffu, pp, o);
        n1 += __shfl_down_sync(0xffffffffu, n1, o);
        n2 += __shfl_down_sync(0xffffffffu, n2, o);
        d1 += __shfl_down_sync(0xffffffffu, d1, o);
        d2 += __shfl_down_sync(0xffffffffu, d2, o);
    }
    __shared__ float sacc[8];
    float contrib = 0.f;
    if (lane == 0 && node < NN) {
        float np  = fmaxf(sqrtf(pp), 1e-12f);
        float nn1 = fmaxf(sqrtf(n1), 1e-12f);
        float nn2 = fmaxf(sqrtf(n2), 1e-12f);
        contrib = d1 / (np * nn1) + d2 / (np * nn2);
    }
    int wid = threadIdx.x >> 5;
    if (lane == 0) sacc[wid] = contrib;
    __syncthreads();
    if (threadIdx.x == 0) {
        float s = 0.f;
#pragma unroll
        for (int i = 0; i < 8; ++i) s += sacc[i];
        atomicAdd(acc, s);
    }
}

// ---------------- finalize: softmax(beta), loss --------------------------------
__global__ void finalize_kernel(float* __restrict__ out_loss, int write_loss)
{
    float invN = 1.f / (float)NN;
    float b0 = g_beta_raw[0] * invN;
    float b1 = g_beta_raw[1] * invN;
    float b2 = g_beta_raw[2] * invN;
    float m = fmaxf(b0, fmaxf(b1, b2));
    float e0 = expf(b0 - m), e1 = expf(b1 - m), e2 = expf(b2 - m);
    float s = e0 + e1 + e2;
    g_beta[0] = e0 / s;
    g_beta[1] = e1 / s;
    g_beta[2] = e2 / s;
    if (write_loss) *out_loss = 2.0f - g_loss_acc * invN;
}

// ---------------- z_out = b0*z1 + b1*z2 + b2*z0 (from split-bf16) ----------------
__global__ __launch_bounds__(256)
void zout_kernel(float4* __restrict__ out, const uint32_t* __restrict__ zh,
                 const uint32_t* __restrict__ zl)
{
    int i = blockIdx.x * blockDim.x + threadIdx.x;
    if (i >= NN * 64) return;
    float b2 = g_beta[2], b0 = g_beta[0], b1 = g_beta[1];
    const size_t vstride = (size_t)NN * (HH / 2);
    size_t u = (size_t)i * 2;
    uint2 h0 = *(const uint2*)&zh[u];
    uint2 l0 = *(const uint2*)&zl[u];
    uint2 h1 = *(const uint2*)&zh[vstride + u];
    uint2 l1 = *(const uint2*)&zl[vstride + u];
    uint2 h2 = *(const uint2*)&zh[2 * vstride + u];
    uint2 l2 = *(const uint2*)&zl[2 * vstride + u];
    float4 a, b, c;
    unpack2(h0.x, l0.x, c.x, c.y); unpack2(h0.y, l0.y, c.z, c.w);
    unpack2(h1.x, l1.x, a.x, a.y); unpack2(h1.y, l1.y, a.z, a.w);
    unpack2(h2.x, l2.x, b.x, b.y); unpack2(h2.y, l2.y, b.z, b.w);
    float4 r;
    r.x = b0 * a.x + b1 * b.x + b2 * c.x;
    r.y = b0 * a.y + b1 * b.y + b2 * c.y;
    r.z = b0 * a.z + b1 * b.z + b2 * c.z;
    r.w = b0 * a.w + b1 * b.w + b2 * c.w;
    out[i] = r;
}

// ---------------- host ----------------------------------------------------------
#define GETSYM(var, sym) cudaGetSymbolAddress((void**)&var, sym)

extern "C" void kernel_launch(void* const* d_in, const int* in_sizes, int n_in,
                              void* d_out, int out_size)
{
    const float* feats   = (const float*)d_in[0];
    const int*   src     = (const int*)  d_in[1];
    const int*   dst     = (const int*)  d_in[2];
    const float* vals    = (const float*)d_in[3];
    const float* W_trans = (const float*)d_in[4];
    const float* b_trans = (const float*)d_in[5];
    const float* W_gcn   = (const float*)d_in[6];
    const float* b_gcn   = (const float*)d_in[7];
    const float* a_gcn   = (const float*)d_in[8];
    const float* W1      = (const float*)d_in[9];
    const float* b1      = (const float*)d_in[10];
    const float* bn_g    = (const float*)d_in[11];
    const float* bn_b    = (const float*)d_in[12];
    const float* a_pred  = (const float*)d_in[13];
    const float* W2      = (const float*)d_in[14];
    const float* b2      = (const float*)d_in[15];
    const float* W_att   = (const float*)d_in[16];
    const float* b_att   = (const float*)d_in[17];
    const float* att     = (const float*)d_in[18];

    uint32_t *h_hi, *h_lo, *zh, *zl;
    uint32_t *x_hi, *x_lo, *wt_hi, *wt_lo, *wg_hi, *wg_lo, *w1_hi, *w1_lo;
    uint32_t *w2_hi, *w2_lo, *wa_hi, *wa_lo;
    float *ft, *vp, *stats, *beta_raw, *loss_acc;
    int *deg, *rowptr, *cursor, *esrc;
    float *eval_;
    GETSYM(h_hi, g_h_hi);   GETSYM(h_lo, g_h_lo);
    GETSYM(zh, g_z_hi); GETSYM(zl, g_z_lo);
    GETSYM(x_hi, g_x_hi); GETSYM(x_lo, g_x_lo);
    GETSYM(wt_hi, g_wt_hi); GETSYM(wt_lo, g_wt_lo);
    GETSYM(wg_hi, g_wg_hi); GETSYM(wg_lo, g_wg_lo);
    GETSYM(w1_hi, g_w1_hi); GETSYM(w1_lo, g_w1_lo);
    GETSYM(w2_hi, g_w2_hi); GETSYM(w2_lo, g_w2_lo);
    GETSYM(wa_hi, g_wa_hi); GETSYM(wa_lo, g_wa_lo);
    GETSYM(ft, g_ft);
    GETSYM(vp, g_vp);
    GETSYM(stats, g_stats); GETSYM(beta_raw, g_beta_raw); GETSYM(loss_acc, g_loss_acc);
    GETSYM(deg, g_deg); GETSYM(rowptr, g_rowptr); GETSYM(cursor, g_cursor);
    GETSYM(esrc, g_esrc); GETSYM(eval_, g_eval);

    // side stream + fork/join events (host-side only; created per call,
    // not destroyed during capture — kernel_launch runs a bounded few times)
    cudaStream_t s2;
    cudaStreamCreateWithFlags(&s2, cudaStreamNonBlocking);
    cudaEvent_t eFork, eCSR, eSpmm, eAtt;
    cudaEventCreateWithFlags(&eFork, cudaEventDisableTiming);
    cudaEventCreateWithFlags(&eCSR,  cudaEventDisableTiming);
    cudaEventCreateWithFlags(&eSpmm, cudaEventDisableTiming);
    cudaEventCreateWithFlags(&eAtt,  cudaEventDisableTiming);

    cudaMemsetAsync(deg, 0, 3 * NN * sizeof(int));
    cudaMemsetAsync(stats, 0, 2 * PHH * sizeof(float));
    cudaMemsetAsync(beta_raw, 0, 3 * sizeof(float));
    cudaMemsetAsync(loss_acc, 0, sizeof(float));

    // fork: CSR build runs on s2, concurrent with weight splits + front GEMMs
    cudaEventRecord(eFork, 0);
    cudaStreamWaitEvent(s2, eFork, 0);
    hist_kernel<<<(3 * EE + 255) / 256, 256, 0, s2>>>(dst, deg);
    scan_kernel<<<3, 1024, 0, s2>>>(deg, rowptr, cursor);
    scatter_kernel<<<(3 * EE + 255) / 256, 256, 0, s2>>>(src, dst, vals, cursor,
                                                         esrc, eval_);
    cudaEventRecord(eCSR, s2);

    // main stream: weight splits
    {
        size_t np = (size_t)HH * (FEATD / 2);
        split_kernel<<<(int)((np + 255) / 256), 256>>>((const float2*)W_trans, wt_hi, wt_lo, np);
        np = (size_t)3 * HH * (HH / 2);
        split_kernel<<<(int)((np + 255) / 256), 256>>>((const float2*)W_gcn, wg_hi, wg_lo, np);
        np = (size_t)PHH * (HH / 2);
        split_kernel<<<(int)((np + 255) / 256), 256>>>((const float2*)W1, w1_hi, w1_lo, np);
        np = (size_t)HH * (PHH / 2);
        split_kernel<<<(int)((np + 255) / 256), 256>>>((const float2*)W2, w2_hi, w2_lo, np);
        np = (size_t)HH * (HH / 2);
        split_kernel<<<(int)((np + 255) / 256), 256>>>((const float2*)W_att, wa_hi, wa_lo, np);
    }

    const int mb = (NN + TBM - 1) / TBM;   // 391

    // h = elu(feats @ W_trans^T + b_trans): A read as f32, split in-kernel
    gemm_bf16s_af32_kernel<<<dim3(HH / TBN, mb), 256>>>(
        feats, wt_hi, wt_lo, b_trans, h_hi, h_lo, NN, HH, FEATD / 2);

    // fused GCN GEMM -> view-major ft [3][N][256]
    gemm_bf16s_kernel<0><<<dim3(3 * HH / TBN, mb), 256>>>(
        h_hi, h_lo, wg_hi, wg_lo, nullptr, ft, nullptr, nullptr, nullptr,
        NN, 3 * HH, HH / 2);

    // join CSR before SpMM
    cudaStreamWaitEvent(0, eCSR, 0);

    // CSR SpMM per view -> split-bf16 z only
    for (int v = 0; v < PP; ++v) {
        spmm_csr_kernel<<<(NN * 64 + 255) / 256, 256>>>(
            (const float4*)(ft + (size_t)v * NN * HH),
            rowptr + v * (NN + 1),
            esrc + (size_t)v * EE, eval_ + (size_t)v * EE,
            zh + (size_t)v * NN * (HH / 2), zl + (size_t)v * NN * (HH / 2),
            b_gcn + (size_t)v * HH, a_gcn + v);
    }

    // fork attention GEMM (depends only on zh) onto s2, concurrent with predictor
    cudaEventRecord(eSpmm, 0);
    cudaStreamWaitEvent(s2, eSpmm, 0);
    gemm_att_bf16_kernel<<<dim3(HH / TBN, mb, 3), 256, 0, s2>>>(
        zh, wa_hi, wa_lo, b_att, att, beta_raw, NN, HH / 2);
    cudaEventRecord(eAtt, s2);

    // main: student predictor chain + loss
    gemm_bf16s_kernel<3><<<dim3(PHH / TBN, mb), 256>>>(
        zh, zl, w1_hi, w1_lo, b1, nullptr, x_hi, x_lo, stats, NN, PHH, HH / 2);
    bn_prelu_kernel<<<(NN * PHH / 4) / 256, 256>>>(x_hi, x_lo, stats, bn_g, bn_b, a_pred);
    gemm_bf16s_kernel<2><<<dim3(HH / TBN, mb), 256>>>(
        x_hi, x_lo, w2_hi, w2_lo, b2, vp, nullptr, nullptr, nullptr, NN, HH, PHH / 2);
    loss_kernel<<<(NN * 32) / 256, 256>>>((const float4*)vp, zh, zl, loss_acc);

    // join attention before finalize
    cudaStreamWaitEvent(0, eAtt, 0);

    float* outf = (float*)d_out;
    int write_loss = (out_size > NN * HH) ? 1 : 0;
    finalize_kernel<<<1, 1>>>(outf + (size_t)NN * HH, write_loss);
    zout_kernel<<<(NN * 64) / 256, 256>>>((float4*)outf, zh, zl);
}

// round 14
// speedup vs baseline: 1.6143x; 1.0123x over previous
#include <cuda_runtime.h>
#include <math.h>
#include <stdint.h>

// ---------------- problem constants ----------------
#define NN   50000
#define PP   3
#define EE   800000
#define FEATD 1000
#define HH   256
#define PHH  512
#define BN_EPS 1e-5f

// ---------------- device scratch (no allocations allowed) ----------------
__device__ uint32_t g_h_hi [(size_t)NN * (HH / 2)];
__device__ uint32_t g_h_lo [(size_t)NN * (HH / 2)];
__device__ float    g_ft[(size_t)3 * NN * HH];         // view-major [3][N][256]
__device__ uint32_t g_z_hi[(size_t)3 * NN * (HH / 2)];
__device__ uint32_t g_z_lo[(size_t)3 * NN * (HH / 2)];
__device__ uint32_t g_x_hi[(size_t)NN * (PHH / 2)];
__device__ uint32_t g_x_lo[(size_t)NN * (PHH / 2)];
__device__ float    g_vp[(size_t)NN * HH];
// CSR scratch
__device__ int   g_deg[3 * NN];
__device__ int   g_rowptr[3 * (NN + 1)];
__device__ int   g_cursor[3 * NN];
__device__ int   g_esrc[(size_t)3 * EE];
__device__ float g_eval[(size_t)3 * EE];
// split weights
__device__ uint32_t g_wt_hi[HH * (FEATD / 2)];
__device__ uint32_t g_wt_lo[HH * (FEATD / 2)];
__device__ uint32_t g_wg_hi[3 * HH * (HH / 2)];
__device__ uint32_t g_wg_lo[3 * HH * (HH / 2)];
__device__ uint32_t g_w1_hi[PHH * (HH / 2)];
__device__ uint32_t g_w1_lo[PHH * (HH / 2)];
__device__ uint32_t g_w2_hi[HH * (PHH / 2)];
__device__ uint32_t g_w2_lo[HH * (PHH / 2)];
__device__ uint32_t g_wa_hi[HH * (HH / 2)];
__device__ uint32_t g_wa_lo[HH * (HH / 2)];
__device__ float g_stats[2 * PHH];
__device__ float g_beta_raw[3];
__device__ float g_beta[3];
__device__ float g_loss_acc;

// ---------------- bf16 split helpers --------------------------------------------
__device__ __forceinline__ uint32_t pack_hi(float x0, float x1)
{
    uint32_t r;
    asm("prmt.b32 %0, %1, %2, 0x7632;"
        : "=r"(r) : "r"(__float_as_uint(x0)), "r"(__float_as_uint(x1)));
    return r;
}

__device__ __forceinline__ uint32_t pack_lo(float x0, float x1)
{
    float h0 = __uint_as_float(__float_as_uint(x0) & 0xFFFF0000u);
    float h1 = __uint_as_float(__float_as_uint(x1) & 0xFFFF0000u);
    uint32_t r;
    asm("cvt.rn.bf16x2.f32 %0, %1, %2;" : "=r"(r) : "f"(x1 - h1), "f"(x0 - h0));
    return r;
}

__device__ __forceinline__ void unpack2(uint32_t hi, uint32_t lo, float& f0, float& f1)
{
    f0 = __uint_as_float(hi << 16)          + __uint_as_float(lo << 16);
    f1 = __uint_as_float(hi & 0xFFFF0000u)  + __uint_as_float(lo & 0xFFFF0000u);
}

__device__ __forceinline__ void mma_bf16(float* c, const uint32_t* a, const uint32_t* b)
{
    asm volatile(
        "mma.sync.aligned.m16n8k16.row.col.f32.bf16.bf16.f32 "
        "{%0,%1,%2,%3}, {%4,%5,%6,%7}, {%8,%9}, {%0,%1,%2,%3};\n"
        : "+f"(c[0]), "+f"(c[1]), "+f"(c[2]), "+f"(c[3])
        : "r"(a[0]), "r"(a[1]), "r"(a[2]), "r"(a[3]), "r"(b[0]), "r"(b[1]));
}

__device__ __forceinline__ void ldsm_x4(uint32_t* r, uint32_t saddr)
{
    asm volatile("ldmatrix.sync.aligned.m8n8.x4.shared.b16 {%0,%1,%2,%3}, [%4];"
                 : "=r"(r[0]), "=r"(r[1]), "=r"(r[2]), "=r"(r[3]) : "r"(saddr));
}

__device__ __forceinline__ void cp16(uint32_t saddr, const void* gmem, bool pred)
{
    int sz = pred ? 16 : 0;
    asm volatile("cp.async.cg.shared.global [%0], [%1], 16, %2;\n"
                 :: "r"(saddr), "l"(gmem), "r"(sz));
}

// ---------------- generic f32 -> split-bf16 pass (weights only) -----------------
__global__ __launch_bounds__(256)
void split_kernel(const float2* __restrict__ in, uint32_t* __restrict__ hi,
                  uint32_t* __restrict__ lo, size_t npairs)
{
    size_t i = (size_t)blockIdx.x * blockDim.x + threadIdx.x;
    if (i >= npairs) return;
    float2 v = in[i];
    hi[i] = pack_hi(v.x, v.y);
    if (lo) lo[i] = pack_lo(v.x, v.y);
}

// ---------------- CSR build ------------------------------------------------------
__global__ __launch_bounds__(256)
void hist_kernel(const int* __restrict__ dst, int* __restrict__ deg)
{
    int i = blockIdx.x * 256 + threadIdx.x;
    if (i >= 3 * EE) return;
    int v = i / EE;
    atomicAdd(&deg[v * NN + dst[i]], 1);
}

__global__ __launch_bounds__(1024)
void scan_kernel(const int* __restrict__ deg, int* __restrict__ rowptr,
                 int* __restrict__ cursor)
{
    const int CH = (NN + 1023) / 1024;   // 49
    int v = blockIdx.x;
    const int* d = deg + v * NN;
    int* rp = rowptr + v * (NN + 1);
    int* cur = cursor + v * NN;
    int t = threadIdx.x;
    int lane = t & 31, w = t >> 5;
    __shared__ int warpsums[32];

    int base = t * CH;
    int local[CH];
    int sum = 0;
#pragma unroll
    for (int k = 0; k < CH; ++k) {
        int idx = base + k;
        int val = (idx < NN) ? d[idx] : 0;
        local[k] = sum;
        sum += val;
    }
    int s = sum;
#pragma unroll
    for (int o = 1; o < 32; o <<= 1) {
        int y = __shfl_up_sync(0xffffffffu, s, o);
        if (lane >= o) s += y;
    }
    if (lane == 31) warpsums[w] = s;
    __syncthreads();
    if (w == 0) {
        int ws = warpsums[lane];
#pragma unroll
        for (int o = 1; o < 32; o <<= 1) {
            int y = __shfl_up_sync(0xffffffffu, ws, o);
            if (lane >= o) ws += y;
        }
        warpsums[lane] = ws;
    }
    __syncthreads();
    int offset = (w > 0 ? warpsums[w - 1] : 0) + (s - sum);
#pragma unroll
    for (int k = 0; k < CH; ++k) {
        int idx = base + k;
        if (idx < NN) {
            int val = offset + local[k];
            rp[idx] = val;
            cur[idx] = val;
        }
    }
    if (t == 1023) rp[NN] = EE;
}

__global__ __launch_bounds__(256)
void scatter_kernel(const int* __restrict__ src, const int* __restrict__ dst,
                    const float* __restrict__ vals, int* __restrict__ cursor,
                    int* __restrict__ esrc, float* __restrict__ eval_)
{
    int i = blockIdx.x * 256 + threadIdx.x;
    if (i >= 3 * EE) return;
    int v = i / EE;
    int d = dst[i];
    int pos = atomicAdd(&cursor[v * NN + d], 1);
    esrc[(size_t)v * EE + pos] = src[i];
    eval_[(size_t)v * EE + pos] = vals[i];
}

// ---------------- CSR SpMM + bias + PReLU -> split-bf16 only (one view) ---------
__global__ __launch_bounds__(256)
void spmm_csr_kernel(const float4* __restrict__ ftv, const int* __restrict__ rp,
                     const int* __restrict__ es, const float* __restrict__ ev,
                     uint32_t* __restrict__ zhiv, uint32_t* __restrict__ zlov,
                     const float* __restrict__ bvp, const float* __restrict__ avp)
{
    int gid = blockIdx.x * 256 + threadIdx.x;
    if (gid >= NN * 64) return;
    int n = gid >> 6;
    int c = gid & 63;
    int i  = rp[n];
    int s1 = rp[n + 1];

    float4 acc = make_float4(0.f, 0.f, 0.f, 0.f);
    for (; i + 2 <= s1; i += 2) {
        int sa = es[i];     float va = ev[i];
        int sb = es[i + 1]; float vb = ev[i + 1];
        float4 fa = ftv[(size_t)sa * 64 + c];
        float4 fb = ftv[(size_t)sb * 64 + c];
        acc.x += va * fa.x; acc.y += va * fa.y; acc.z += va * fa.z; acc.w += va * fa.w;
        acc.x += vb * fb.x; acc.y += vb * fb.y; acc.z += vb * fb.z; acc.w += vb * fb.w;
    }
    if (i < s1) {
        int sa = es[i]; float va = ev[i];
        float4 fa = ftv[(size_t)sa * 64 + c];
        acc.x += va * fa.x; acc.y += va * fa.y; acc.z += va * fa.z; acc.w += va * fa.w;
    }

    float a = *avp;
    float4 bv = *(const float4*)(bvp + (c << 2));
    acc.x += bv.x; acc.y += bv.y; acc.z += bv.z; acc.w += bv.w;
    acc.x = acc.x >= 0.f ? acc.x : a * acc.x;
    acc.y = acc.y >= 0.f ? acc.y : a * acc.y;
    acc.z = acc.z >= 0.f ? acc.z : a * acc.z;
    acc.w = acc.w >= 0.f ? acc.w : a * acc.w;

    size_t p = ((size_t)n * 64 + c) << 1;
    zhiv[p]     = pack_hi(acc.x, acc.y);
    zhiv[p + 1] = pack_hi(acc.z, acc.w);
    zlov[p]     = pack_lo(acc.x, acc.y);
    zlov[p + 1] = pack_lo(acc.z, acc.w);
}

// ---------------- split-bf16 GEMM ------------------------------------------------
// Block tile 128x128, BK=16 elems (8 u32), 8 warps (2m x 4n), warp tile 64x32.
// 3 MMAs per atom. Fragment loads via ldmatrix.x4 (conflict-free at TPAD=12).
#define TBM 128
#define TBN 128
#define TPAD 12
#define STG_BYTES (TBM * TPAD * 4)

#define GS_DECL()                                                                   \
    __shared__ __align__(16) uint32_t AsH[2][TBM][TPAD];                            \
    __shared__ __align__(16) uint32_t AsL[2][TBM][TPAD];                            \
    __shared__ __align__(16) uint32_t WsH[2][TBN][TPAD];                            \
    __shared__ __align__(16) uint32_t WsL[2][TBN][TPAD];                            \
    const int tid  = threadIdx.x;                                                   \
    const int wid  = tid >> 5;                                                      \
    const int lane = tid & 31;                                                      \
    const int g    = lane >> 2;                                                     \
    const int t    = lane & 3;                                                      \
    const int wm   = (wid & 1) << 6;                                                \
    const int wn   = (wid >> 1) << 5;                                               \
    const int bm   = blockIdx.y * TBM;                                              \
    const int bn   = blockIdx.x * TBN;                                              \
    const uint32_t sAsH = (uint32_t)__cvta_generic_to_shared(&AsH[0][0][0]);        \
    const uint32_t sAsL = (uint32_t)__cvta_generic_to_shared(&AsL[0][0][0]);        \
    const uint32_t sWsH = (uint32_t)__cvta_generic_to_shared(&WsH[0][0][0]);        \
    const uint32_t sWsL = (uint32_t)__cvta_generic_to_shared(&WsL[0][0][0]);        \
    const uint32_t offA = (uint32_t)(((wm + (lane & 7) + ((lane >> 3) & 1) * 8)     \
                                      * TPAD + ((lane >> 4) << 2)) * 4);            \
    const uint32_t offB = (uint32_t)(((wn + ((lane >> 4) & 1) * 8 + (lane & 7))     \
                                      * TPAD + (((lane >> 3) & 1) << 2)) * 4);      \
    float acc[4][4][4] = {};

#define GS_LOAD(S, KP0)                                                             \
    {                                                                               \
        int r  = tid >> 1, ch = (tid & 1) << 2;                                     \
        int gp = (KP0) + ch;                                                        \
        bool pa = (gp < Kp) && (bm + r < M);                                        \
        size_t offa = (size_t)(bm + r) * Kp + gp;                                   \
        cp16((uint32_t)__cvta_generic_to_shared(&AsH[S][r][ch]), Ahi + offa, pa);   \
        cp16((uint32_t)__cvta_generic_to_shared(&AsL[S][r][ch]), Alo + offa, pa);   \
        bool pb = (gp < Kp);                                                        \
        size_t offb = (size_t)(bn + r) * Kp + gp;                                   \
        cp16((uint32_t)__cvta_generic_to_shared(&WsH[S][r][ch]), Whi + offb, pb);   \
        cp16((uint32_t)__cvta_generic_to_shared(&WsL[S][r][ch]), Wlo + offb, pb);   \
    }

#define GS_LOAD_AF32(S, KP0)                                                        \
    {                                                                               \
        int r  = tid >> 1, ch = (tid & 1) << 2;                                     \
        int gp = (KP0) + ch;                                                        \
        float4 f0 = make_float4(0.f, 0.f, 0.f, 0.f), f1 = f0;                       \
        if (gp < Kp && bm + r < M) {                                                \
            const float* ap = Af32 + (size_t)(bm + r) * (Kp * 2) + gp * 2;          \
            f0 = *(const float4*)ap;                                                \
            f1 = *(const float4*)(ap + 4);                                          \
        }                                                                           \
        AsH[S][r][ch + 0] = pack_hi(f0.x, f0.y); AsL[S][r][ch + 0] = pack_lo(f0.x, f0.y); \
        AsH[S][r][ch + 1] = pack_hi(f0.z, f0.w); AsL[S][r][ch + 1] = pack_lo(f0.z, f0.w); \
        AsH[S][r][ch + 2] = pack_hi(f1.x, f1.y); AsL[S][r][ch + 2] = pack_lo(f1.x, f1.y); \
        AsH[S][r][ch + 3] = pack_hi(f1.z, f1.w); AsL[S][r][ch + 3] = pack_lo(f1.z, f1.w); \
        bool pb = (gp < Kp);                                                        \
        size_t offb = (size_t)(bn + r) * Kp + gp;                                   \
        cp16((uint32_t)__cvta_generic_to_shared(&WsH[S][r][ch]), Whi + offb, pb);   \
        cp16((uint32_t)__cvta_generic_to_shared(&WsL[S][r][ch]), Wlo + offb, pb);   \
    }

#define GS_COMPUTE()                                                                \
    {                                                                               \
        uint32_t aH[4][4], aL[4][4], bH[4][2], bL[4][2];                            \
        uint32_t bs = (uint32_t)buf * STG_BYTES;                                    \
        _Pragma("unroll")                                                           \
        for (int i = 0; i < 4; ++i) {                                               \
            uint32_t ao = bs + offA + (uint32_t)(i * 16 * TPAD * 4);                \
            ldsm_x4(aH[i], sAsH + ao);                                              \
            ldsm_x4(aL[i], sAsL + ao);                                              \
        }                                                                           \
        _Pragma("unroll")                                                           \
        for (int jj = 0; jj < 2; ++jj) {                                            \
            uint32_t bo = bs + offB + (uint32_t)(jj * 16 * TPAD * 4);               \
            uint32_t tH[4], tL[4];                                                  \
            ldsm_x4(tH, sWsH + bo);                                                 \
            ldsm_x4(tL, sWsL + bo);                                                 \
            bH[2 * jj][0] = tH[0]; bH[2 * jj][1] = tH[1];                           \
            bH[2 * jj + 1][0] = tH[2]; bH[2 * jj + 1][1] = tH[3];                   \
            bL[2 * jj][0] = tL[0]; bL[2 * jj][1] = tL[1];                           \
            bL[2 * jj + 1][0] = tL[2]; bL[2 * jj + 1][1] = tL[3];                   \
        }                                                                           \
        _Pragma("unroll")                                                           \
        for (int i = 0; i < 4; ++i)                                                 \
            _Pragma("unroll")                                                       \
            for (int j = 0; j < 4; ++j) {                                           \
                mma_bf16(acc[i][j], aL[i], bH[j]);                                  \
                mma_bf16(acc[i][j], aH[i], bL[j]);                                  \
                mma_bf16(acc[i][j], aH[i], bH[j]);                                  \
            }                                                                       \
    }

#define GS_MAINLOOP(LOADM)                                                          \
    LOADM(0, 0);                                                                    \
    asm volatile("cp.async.commit_group;\n" ::: "memory");                          \
    int buf = 0;                                                                    \
    for (int kp0 = 0; kp0 < Kp; kp0 += 8) {                                         \
        if (kp0 + 8 < Kp) LOADM(buf ^ 1, kp0 + 8);                                  \
        asm volatile("cp.async.commit_group;\n" ::: "memory");                      \
        asm volatile("cp.async.wait_group 1;\n" ::: "memory");                      \
        __syncthreads();                                                            \
        GS_COMPUTE();                                                               \
        __syncthreads();                                                            \
        buf ^= 1;                                                                   \
    }

// EPI: 0 = raw f32 row-major (no bias), 2 = bias f32, 3 = bias -> split bf16 + BN stats
template<int EPI>
__global__ __launch_bounds__(256, 2)
void gemm_bf16s_kernel(const uint32_t* __restrict__ Ahi, const uint32_t* __restrict__ Alo,
                       const uint32_t* __restrict__ Whi, const uint32_t* __restrict__ Wlo,
                       const float* __restrict__ bias, float* __restrict__ C,
                       uint32_t* __restrict__ Chi, uint32_t* __restrict__ Clo,
                       float* __restrict__ stats, int M, int Nc, int Kp)
{
    GS_DECL();
    GS_MAINLOOP(GS_LOAD);

    float* sSum = (float*)&AsH[0][0][0];
    float* sSq  = sSum + 128;
    if (EPI == 3) {
        __syncthreads();
        if (tid < 128) { sSum[tid] = 0.f; sSq[tid] = 0.f; }
        __syncthreads();
    }

#pragma unroll
    for (int j = 0; j < 4; ++j) {
        float cs0 = 0.f, cq0 = 0.f, cs1 = 0.f, cq1 = 0.f;
#pragma unroll
        for (int i = 0; i < 4; ++i) {
            int r0 = bm + wm + (i << 4) + g;
            int r1 = r0 + 8;
            int c0 = bn + wn + (j << 3) + (t << 1);
            float bx = 0.f, by = 0.f;
            if (EPI >= 2) { bx = bias[c0]; by = bias[c0 + 1]; }
            float v0 = acc[i][j][0] + bx, v1 = acc[i][j][1] + by;
            float v2 = acc[i][j][2] + bx, v3 = acc[i][j][3] + by;
            if (EPI == 0 || EPI == 2) {
                if (r0 < M) *(float2*)(C + (size_t)r0 * Nc + c0) = make_float2(v0, v1);
                if (r1 < M) *(float2*)(C + (size_t)r1 * Nc + c0) = make_float2(v2, v3);
            } else {
                int pc = c0 >> 1;
                if (r0 < M) {
                    Chi[(size_t)r0 * (Nc / 2) + pc] = pack_hi(v0, v1);
                    Clo[(size_t)r0 * (Nc / 2) + pc] = pack_lo(v0, v1);
                    cs0 += v0; cq0 += v0 * v0; cs1 += v1; cq1 += v1 * v1;
                }
                if (r1 < M) {
                    Chi[(size_t)r1 * (Nc / 2) + pc] = pack_hi(v2, v3);
                    Clo[(size_t)r1 * (Nc / 2) + pc] = pack_lo(v2, v3);
                    cs0 += v2; cq0 += v2 * v2; cs1 += v3; cq1 += v3 * v3;
                }
            }
        }
        if (EPI == 3) {
            int lc = wn + (j << 3) + (t << 1);
            atomicAdd(&sSum[lc], cs0);     atomicAdd(&sSq[lc], cq0);
            atomicAdd(&sSum[lc + 1], cs1); atomicAdd(&sSq[lc + 1], cq1);
        }
    }
    if (EPI == 3) {
        __syncthreads();
        if (tid < 128) {
            atomicAdd(&stats[bn + tid], sSum[tid]);
            atomicAdd(&stats[PHH + bn + tid], sSq[tid]);
        }
    }
}

// feats GEMM: A = raw f32, epilogue bias+ELU -> split bf16 h
__global__ __launch_bounds__(256, 2)
void gemm_bf16s_af32_kernel(const float* __restrict__ Af32,
                            const uint32_t* __restrict__ Whi, const uint32_t* __restrict__ Wlo,
                            const float* __restrict__ bias,
                            uint32_t* __restrict__ Chi, uint32_t* __restrict__ Clo,
                            int M, int Nc, int Kp)
{
    GS_DECL();
    GS_MAINLOOP(GS_LOAD_AF32);

#pragma unroll
    for (int i = 0; i < 4; ++i) {
#pragma unroll
        for (int j = 0; j < 4; ++j) {
            int r0 = bm + wm + (i << 4) + g;
            int r1 = r0 + 8;
            int c0 = bn + wn + (j << 3) + (t << 1);
            float bx = bias[c0], by = bias[c0 + 1];
            float v0 = acc[i][j][0] + bx, v1 = acc[i][j][1] + by;
            float v2 = acc[i][j][2] + bx, v3 = acc[i][j][3] + by;
            v0 = v0 > 0.f ? v0 : expm1f(v0);
            v1 = v1 > 0.f ? v1 : expm1f(v1);
            v2 = v2 > 0.f ? v2 : expm1f(v2);
            v3 = v3 > 0.f ? v3 : expm1f(v3);
            int pc = c0 >> 1;
            if (r0 < M) {
                Chi[(size_t)r0 * (Nc / 2) + pc] = pack_hi(v0, v1);
                Clo[(size_t)r0 * (Nc / 2) + pc] = pack_lo(v0, v1);
            }
            if (r1 < M) {
                Chi[(size_t)r1 * (Nc / 2) + pc] = pack_hi(v2, v3);
                Clo[(size_t)r1 * (Nc / 2) + pc] = pack_lo(v2, v3);
            }
        }
    }
}

// attention GEMM: z hi-only x split W (zH*WH + zH*WL).
// blockIdx.z = view; beta index = (view+2)%3.
__global__ __launch_bounds__(256, 2)
void gemm_att_bf16_kernel(const uint32_t* __restrict__ Zhi,
                          const uint32_t* __restrict__ Whi, const uint32_t* __restrict__ Wlo,
                          const float* __restrict__ bias, const float* __restrict__ att,
                          float* __restrict__ beta_raw, int M, int Kp)
{
    __shared__ __align__(16) uint32_t AsH[2][TBM][TPAD];
    __shared__ __align__(16) uint32_t WsH[2][TBN][TPAD];
    __shared__ __align__(16) uint32_t WsL[2][TBN][TPAD];
    const int tid  = threadIdx.x;
    const int wid  = tid >> 5;
    const int lane = tid & 31;
    const int g    = lane >> 2;
    const int t    = lane & 3;
    const int wm   = (wid & 1) << 6;
    const int wn   = (wid >> 1) << 5;
    const int bm   = blockIdx.y * TBM;
    const int bn   = blockIdx.x * TBN;
    const int view = blockIdx.z;
    const uint32_t* Ahi = Zhi + (size_t)view * NN * (HH / 2);
    const uint32_t sAsH = (uint32_t)__cvta_generic_to_shared(&AsH[0][0][0]);
    const uint32_t sWsH = (uint32_t)__cvta_generic_to_shared(&WsH[0][0][0]);
    const uint32_t sWsL = (uint32_t)__cvta_generic_to_shared(&WsL[0][0][0]);
    const uint32_t offA = (uint32_t)(((wm + (lane & 7) + ((lane >> 3) & 1) * 8)
                                      * TPAD + ((lane >> 4) << 2)) * 4);
    const uint32_t offB = (uint32_t)(((wn + ((lane >> 4) & 1) * 8 + (lane & 7))
                                      * TPAD + (((lane >> 3) & 1) << 2)) * 4);
    float acc[4][4][4] = {};

#define GA_LOAD(S, KP0)                                                             \
    {                                                                               \
        int r  = tid >> 1, ch = (tid & 1) << 2;                                     \
        int gp = (KP0) + ch;                                                        \
        bool pa = (gp < Kp) && (bm + r < M);                                        \
        cp16((uint32_t)__cvta_generic_to_shared(&AsH[S][r][ch]),                    \
             Ahi + (size_t)(bm + r) * Kp + gp, pa);                                 \
        bool pb = (gp < Kp);                                                        \
        cp16((uint32_t)__cvta_generic_to_shared(&WsH[S][r][ch]),                    \
             Whi + (size_t)(bn + r) * Kp + gp, pb);                                 \
        cp16((uint32_t)__cvta_generic_to_shared(&WsL[S][r][ch]),                    \
             Wlo + (size_t)(bn + r) * Kp + gp, pb);                                 \
    }

    GA_LOAD(0, 0);
    asm volatile("cp.async.commit_group;\n" ::: "memory");
    int buf = 0;
    for (int kp0 = 0; kp0 < Kp; kp0 += 8) {
        if (kp0 + 8 < Kp) GA_LOAD(buf ^ 1, kp0 + 8);
        asm volatile("cp.async.commit_group;\n" ::: "memory");
        asm volatile("cp.async.wait_group 1;\n" ::: "memory");
        __syncthreads();
        uint32_t aH[4][4], bH[4][2], bL[4][2];
        uint32_t bs = (uint32_t)buf * STG_BYTES;
#pragma unroll
        for (int i = 0; i < 4; ++i)
            ldsm_x4(aH[i], sAsH + bs + offA + (uint32_t)(i * 16 * TPAD * 4));
#pragma unroll
        for (int jj = 0; jj < 2; ++jj) {
            uint32_t bo = bs + offB + (uint32_t)(jj * 16 * TPAD * 4);
            uint32_t tH[4], tL[4];
            ldsm_x4(tH, sWsH + bo);
            ldsm_x4(tL, sWsL + bo);
            bH[2 * jj][0] = tH[0]; bH[2 * jj][1] = tH[1];
            bH[2 * jj + 1][0] = tH[2]; bH[2 * jj + 1][1] = tH[3];
            bL[2 * jj][0] = tL[0]; bL[2 * jj][1] = tL[1];
            bL[2 * jj + 1][0] = tL[2]; bL[2 * jj + 1][1] = tL[3];
        }
#pragma unroll
        for (int i = 0; i < 4; ++i)
#pragma unroll
            for (int j = 0; j < 4; ++j) {
                mma_bf16(acc[i][j], aH[i], bL[j]);
                mma_bf16(acc[i][j], aH[i], bH[j]);
            }
        __syncthreads();
        buf ^= 1;
    }
#undef GA_LOAD

    float s = 0.f;
#pragma unroll
    for (int i = 0; i < 4; ++i) {
#pragma unroll
        for (int j = 0; j < 4; ++j) {
            int r0 = bm + wm + (i << 4) + g;
            int r1 = r0 + 8;
            int c0 = bn + wn + (j << 3) + (t << 1);
            float bx = bias[c0], by = bias[c0 + 1];
            float ax = att[c0],  ay = att[c0 + 1];
            if (r0 < M) s += tanhf(acc[i][j][0] + bx) * ax + tanhf(acc[i][j][1] + by) * ay;
            if (r1 < M) s += tanhf(acc[i][j][2] + bx) * ax + tanhf(acc[i][j][3] + by) * ay;
        }
    }
    float* red = (float*)&AsH[0][0][0];
    __syncthreads();
    red[tid] = s;
    __syncthreads();
    for (int o = 128; o > 0; o >>= 1) {
        if (tid < o) red[tid] += red[tid + o];
        __syncthreads();
    }
    if (tid == 0) {
        int bidx = (view + 2) % 3;
        atomicAdd(&beta_raw[bidx], red[0]);
    }
}

// ---------------- BN + PReLU on split-bf16 x (in place) -------------------------
__global__ __launch_bounds__(256)
void bn_prelu_kernel(uint32_t* __restrict__ xhi, uint32_t* __restrict__ xlo,
                     const float* __restrict__ stats,
                     const float* __restrict__ g, const float* __restrict__ b,
                     const float* __restrict__ a_ptr)
{
    int i = blockIdx.x * blockDim.x + threadIdx.x;
    if (i >= NN * (PHH / 4)) return;
    int c = (i & (PHH / 4 - 1)) << 2;
    float a = *a_ptr;
    float4 sm = *(const float4*)(stats + c);
    float4 sq = *(const float4*)(stats + PHH + c);
    float4 gv = *(const float4*)(g + c);
    float4 bv = *(const float4*)(b + c);
    uint2 h = ((const uint2*)xhi)[i];
    uint2 l = ((const uint2*)xlo)[i];
    float4 v;
    unpack2(h.x, l.x, v.x, v.y);
    unpack2(h.y, l.y, v.z, v.w);
    float invN = 1.f / (float)NN;

    float mu, var, sc, sh, y;
    mu = sm.x * invN; var = sq.x * invN - mu * mu; sc = gv.x * rsqrtf(var + BN_EPS);
    sh = bv.x - mu * sc; y = v.x * sc + sh; v.x = y >= 0.f ? y : a * y;
    mu = sm.y * invN; var = sq.y * invN - mu * mu; sc = gv.y * rsqrtf(var + BN_EPS);
    sh = bv.y - mu * sc; y = v.y * sc + sh; v.y = y >= 0.f ? y : a * y;
    mu = sm.z * invN; var = sq.z * invN - mu * mu; sc = gv.z * rsqrtf(var + BN_EPS);
    sh = bv.z - mu * sc; y = v.z * sc + sh; v.z = y >= 0.f ? y : a * y;
    mu = sm.w * invN; var = sq.w * invN - mu * mu; sc = gv.w * rsqrtf(var + BN_EPS);
    sh = bv.w - mu * sc; y = v.w * sc + sh; v.w = y >= 0.f ? y : a * y;

    uint2 nh, nl;
    nh.x = pack_hi(v.x, v.y); nl.x = pack_lo(v.x, v.y);
    nh.y = pack_hi(v.z, v.w); nl.y = pack_lo(v.z, v.w);
    ((uint2*)xhi)[i] = nh;
    ((uint2*)xlo)[i] = nl;
}

// ---------------- cosine loss (one warp per node; teachers from split-bf16) -----
__global__ __launch_bounds__(256)
void loss_kernel(const float4* __restrict__ p,
                 const uint32_t* __restrict__ zh, const uint32_t* __restrict__ zl,
                 float* __restrict__ acc)
{
    const uint32_t* t1h = zh + (size_t)NN * (HH / 2);
    const uint32_t* t1l = zl + (size_t)NN * (HH / 2);
    const uint32_t* t2h = zh + (size_t)2 * NN * (HH / 2);
    const uint32_t* t2l = zl + (size_t)2 * NN * (HH / 2);
    int gid  = blockIdx.x * blockDim.x + threadIdx.x;
    int node = gid >> 5;
    int lane = gid & 31;
    float pp = 0.f, n1 = 0.f, n2 = 0.f, d1 = 0.f, d2 = 0.f;
    if (node < NN) {
        size_t base4 = (size_t)node * 64;
        size_t baseu = (size_t)node * 128;
#pragma unroll
        for (int r = 0; r < 2; ++r) {
            int q = lane + 32 * r;
            float4 a = p[base4 + q];
            uint2 h1 = *(const uint2*)&t1h[baseu + 2 * q];
            uint2 l1 = *(const uint2*)&t1l[baseu + 2 * q];
            uint2 h2 = *(const uint2*)&t2h[baseu + 2 * q];
            uint2 l2 = *(const uint2*)&t2l[baseu + 2 * q];
            float4 b, cc;
            unpack2(h1.x, l1.x, b.x, b.y);  unpack2(h1.y, l1.y, b.z, b.w);
            unpack2(h2.x, l2.x, cc.x, cc.y); unpack2(h2.y, l2.y, cc.z, cc.w);
            pp += a.x * a.x + a.y * a.y + a.z * a.z + a.w * a.w;
            n1 += b.x * b.x + b.y * b.y + b.z * b.z + b.w * b.w;
            n2 += cc.x * cc.x + cc.y * cc.y + cc.z * cc.z + cc.w * cc.w;
            d1 += a.x * b.x + a.y * b.y + a.z * b.z + a.w * b.w;
            d2 += a.x * cc.x + a.y * cc.y + a.z * cc.z + a.w * cc.w;
        }
    }
#pragma unroll
    for (int o = 16; o > 0; o >>= 1) {
        pp += __shfl_down_sync(0xffffffffu, pp, o);
        n1 += __shfl_down_sync(0xffffffffu, n1, o);
        n2 += __shfl_down_sync(0xffffffffu, n2, o);
        d1 += __shfl_down_sync(0xffffffffu, d1, o);
        d2 += __shfl_down_sync(0xffffffffu, d2, o);
    }
    __shared__ float sacc[8];
    float contrib = 0.f;
    if (lane == 0 && node < NN) {
        float np  = fmaxf(sqrtf(pp), 1e-12f);
        float nn1 = fmaxf(sqrtf(n1), 1e-12f);
        float nn2 = fmaxf(sqrtf(n2), 1e-12f);
        contrib = d1 / (np * nn1) + d2 / (np * nn2);
    }
    int wid = threadIdx.x >> 5;
    if (lane == 0) sacc[wid] = contrib;
    __syncthreads();
    if (threadIdx.x == 0) {
        float s = 0.f;
#pragma unroll
        for (int i = 0; i < 8; ++i) s += sacc[i];
        atomicAdd(acc, s);
    }
}

// ---------------- finalize: softmax(beta), loss --------------------------------
__global__ void finalize_kernel(float* __restrict__ out_loss, int write_loss)
{
    float invN = 1.f / (float)NN;
    float b0 = g_beta_raw[0] * invN;
    float b1 = g_beta_raw[1] * invN;
    float b2 = g_beta_raw[2] * invN;
    float m = fmaxf(b0, fmaxf(b1, b2));
    float e0 = expf(b0 - m), e1 = expf(b1 - m), e2 = expf(b2 - m);
    float s = e0 + e1 + e2;
    g_beta[0] = e0 / s;
    g_beta[1] = e1 / s;
    g_beta[2] = e2 / s;
    if (write_loss) *out_loss = 2.0f - g_loss_acc * invN;
}

// ---------------- z_out = b0*z1 + b1*z2 + b2*z0 (from split-bf16) ----------------
__global__ __launch_bounds__(256)
void zout_kernel(float4* __restrict__ out, const uint32_t* __restrict__ zh,
                 const uint32_t* __restrict__ zl)
{
    int i = blockIdx.x * blockDim.x + threadIdx.x;
    if (i >= NN * 64) return;
    float b2 = g_beta[2], b0 = g_beta[0], b1 = g_beta[1];
    const size_t vstride = (size_t)NN * (HH / 2);
    size_t u = (size_t)i * 2;
    uint2 h0 = *(const uint2*)&zh[u];
    uint2 l0 = *(const uint2*)&zl[u];
    uint2 h1 = *(const uint2*)&zh[vstride + u];
    uint2 l1 = *(const uint2*)&zl[vstride + u];
    uint2 h2 = *(const uint2*)&zh[2 * vstride + u];
    uint2 l2 = *(const uint2*)&zl[2 * vstride + u];
    float4 a, b, c;
    unpack2(h0.x, l0.x, c.x, c.y); unpack2(h0.y, l0.y, c.z, c.w);
    unpack2(h1.x, l1.x, a.x, a.y); unpack2(h1.y, l1.y, a.z, a.w);
    unpack2(h2.x, l2.x, b.x, b.y); unpack2(h2.y, l2.y, b.z, b.w);
    float4 r;
    r.x = b0 * a.x + b1 * b.x + b2 * c.x;
    r.y = b0 * a.y + b1 * b.y + b2 * c.y;
    r.z = b0 * a.z + b1 * b.z + b2 * c.z;
    r.w = b0 * a.w + b1 * b.w + b2 * c.w;
    out[i] = r;
}

// ---------------- host ----------------------------------------------------------
#define GETSYM(var, sym) cudaGetSymbolAddress((void**)&var, sym)

extern "C" void kernel_launch(void* const* d_in, const int* in_sizes, int n_in,
                              void* d_out, int out_size)
{
    const float* feats   = (const float*)d_in[0];
    const int*   src     = (const int*)  d_in[1];
    const int*   dst     = (const int*)  d_in[2];
    const float* vals    = (const float*)d_in[3];
    const float* W_trans = (const float*)d_in[4];
    const float* b_trans = (const float*)d_in[5];
    const float* W_gcn   = (const float*)d_in[6];
    const float* b_gcn   = (const float*)d_in[7];
    const float* a_gcn   = (const float*)d_in[8];
    const float* W1      = (const float*)d_in[9];
    const float* b1      = (const float*)d_in[10];
    const float* bn_g    = (const float*)d_in[11];
    const float* bn_b    = (const float*)d_in[12];
    const float* a_pred  = (const float*)d_in[13];
    const float* W2      = (const float*)d_in[14];
    const float* b2      = (const float*)d_in[15];
    const float* W_att   = (const float*)d_in[16];
    const float* b_att   = (const float*)d_in[17];
    const float* att     = (const float*)d_in[18];

    uint32_t *h_hi, *h_lo, *zh, *zl;
    uint32_t *x_hi, *x_lo, *wt_hi, *wt_lo, *wg_hi, *wg_lo, *w1_hi, *w1_lo;
    uint32_t *w2_hi, *w2_lo, *wa_hi, *wa_lo;
    float *ft, *vp, *stats, *beta_raw, *loss_acc;
    int *deg, *rowptr, *cursor, *esrc;
    float *eval_;
    GETSYM(h_hi, g_h_hi);   GETSYM(h_lo, g_h_lo);
    GETSYM(zh, g_z_hi); GETSYM(zl, g_z_lo);
    GETSYM(x_hi, g_x_hi); GETSYM(x_lo, g_x_lo);
    GETSYM(wt_hi, g_wt_hi); GETSYM(wt_lo, g_wt_lo);
    GETSYM(wg_hi, g_wg_hi); GETSYM(wg_lo, g_wg_lo);
    GETSYM(w1_hi, g_w1_hi); GETSYM(w1_lo, g_w1_lo);
    GETSYM(w2_hi, g_w2_hi); GETSYM(w2_lo, g_w2_lo);
    GETSYM(wa_hi, g_wa_hi); GETSYM(wa_lo, g_wa_lo);
    GETSYM(ft, g_ft);
    GETSYM(vp, g_vp);
    GETSYM(stats, g_stats); GETSYM(beta_raw, g_beta_raw); GETSYM(loss_acc, g_loss_acc);
    GETSYM(deg, g_deg); GETSYM(rowptr, g_rowptr); GETSYM(cursor, g_cursor);
    GETSYM(esrc, g_esrc); GETSYM(eval_, g_eval);

    cudaStream_t s2;
    cudaStreamCreateWithFlags(&s2, cudaStreamNonBlocking);
    cudaEvent_t eFork, eSplit, eG[3], eS0, eS2, eAtt;
    cudaEventCreateWithFlags(&eFork,  cudaEventDisableTiming);
    cudaEventCreateWithFlags(&eSplit, cudaEventDisableTiming);
    for (int v = 0; v < 3; ++v) cudaEventCreateWithFlags(&eG[v], cudaEventDisableTiming);
    cudaEventCreateWithFlags(&eS0,  cudaEventDisableTiming);
    cudaEventCreateWithFlags(&eS2,  cudaEventDisableTiming);
    cudaEventCreateWithFlags(&eAtt, cudaEventDisableTiming);

    cudaMemsetAsync(deg, 0, 3 * NN * sizeof(int));
    cudaMemsetAsync(stats, 0, 2 * PHH * sizeof(float));
    cudaMemsetAsync(beta_raw, 0, 3 * sizeof(float));
    cudaMemsetAsync(loss_acc, 0, sizeof(float));

    // fork: CSR build on s2, concurrent with splits + feats GEMM
    cudaEventRecord(eFork, 0);
    cudaStreamWaitEvent(s2, eFork, 0);
    hist_kernel<<<(3 * EE + 255) / 256, 256, 0, s2>>>(dst, deg);
    scan_kernel<<<3, 1024, 0, s2>>>(deg, rowptr, cursor);
    scatter_kernel<<<(3 * EE + 255) / 256, 256, 0, s2>>>(src, dst, vals, cursor,
                                                         esrc, eval_);

    // main: weight splits
    {
        size_t np = (size_t)HH * (FEATD / 2);
        split_kernel<<<(int)((np + 255) / 256), 256>>>((const float2*)W_trans, wt_hi, wt_lo, np);
        np = (size_t)3 * HH * (HH / 2);
        split_kernel<<<(int)((np + 255) / 256), 256>>>((const float2*)W_gcn, wg_hi, wg_lo, np);
        np = (size_t)PHH * (HH / 2);
        split_kernel<<<(int)((np + 255) / 256), 256>>>((const float2*)W1, w1_hi, w1_lo, np);
        np = (size_t)HH * (PHH / 2);
        split_kernel<<<(int)((np + 255) / 256), 256>>>((const float2*)W2, w2_hi, w2_lo, np);
        np = (size_t)HH * (HH / 2);
        split_kernel<<<(int)((np + 255) / 256), 256>>>((const float2*)W_att, wa_hi, wa_lo, np);
    }
    cudaEventRecord(eSplit, 0);

    const int mb = (NN + TBM - 1) / TBM;   // 391

    // main: h = elu(feats @ W_trans^T + b_trans)
    gemm_bf16s_af32_kernel<<<dim3(HH / TBN, mb), 256>>>(
        feats, wt_hi, wt_lo, b_trans, h_hi, h_lo, NN, HH, FEATD / 2);

    // main: per-view GCN GEMMs (each records its event)
    for (int v = 0; v < PP; ++v) {
        gemm_bf16s_kernel<0><<<dim3(HH / TBN, mb), 256>>>(
            h_hi, h_lo,
            wg_hi + (size_t)v * HH * (HH / 2), wg_lo + (size_t)v * HH * (HH / 2),
            nullptr, ft + (size_t)v * NN * HH, nullptr, nullptr, nullptr,
            NN, HH, HH / 2);
        cudaEventRecord(eG[v], 0);
    }

    // s2: SpMM(v) as soon as GEMM(v) done (CSR already sequenced on s2)
    for (int v = 0; v < PP; ++v) {
        cudaStreamWaitEvent(s2, eG[v], 0);
        spmm_csr_kernel<<<(NN * 64 + 255) / 256, 256, 0, s2>>>(
            (const float4*)(ft + (size_t)v * NN * HH),
            rowptr + v * (NN + 1),
            esrc + (size_t)v * EE, eval_ + (size_t)v * EE,
            zh + (size_t)v * NN * (HH / 2), zl + (size_t)v * NN * (HH / 2),
            b_gcn + (size_t)v * HH, a_gcn + v);
        if (v == 0) cudaEventRecord(eS0, s2);
    }
    cudaEventRecord(eS2, s2);

    // s2: attention GEMM after all z ready (splits done long before; same-stream
    // order on main guarantees wa via eSplit)
    cudaStreamWaitEvent(s2, eSplit, 0);
    gemm_att_bf16_kernel<<<dim3(HH / TBN, mb, 3), 256, 0, s2>>>(
        zh, wa_hi, wa_lo, b_att, att, beta_raw, NN, HH / 2);
    cudaEventRecord(eAtt, s2);

    // main: predictor chain (needs z0 only) + loss (needs z1,z2)
    cudaStreamWaitEvent(0, eS0, 0);
    gemm_bf16s_kernel<3><<<dim3(PHH / TBN, mb), 256>>>(
        zh, zl, w1_hi, w1_lo, b1, nullptr, x_hi, x_lo, stats, NN, PHH, HH / 2);
    bn_prelu_kernel<<<(NN * PHH / 4) / 256, 256>>>(x_hi, x_lo, stats, bn_g, bn_b, a_pred);
    gemm_bf16s_kernel<2><<<dim3(HH / TBN, mb), 256>>>(
        x_hi, x_lo, w2_hi, w2_lo, b2, vp, nullptr, nullptr, nullptr, NN, HH, PHH / 2);
    cudaStreamWaitEvent(0, eS2, 0);
    loss_kernel<<<(NN * 32) / 256, 256>>>((const float4*)vp, zh, zl, loss_acc);

    // join attention, then finalize + z_out
    cudaStreamWaitEvent(0, eAtt, 0);
    float* outf = (float*)d_out;
    int write_loss = (out_size > NN * HH) ? 1 : 0;
    finalize_kernel<<<1, 1>>>(outf + (size_t)NN * HH, write_loss);
    zout_kernel<<<(NN * 64) / 256, 256>>>((float4*)outf, zh, zl);
}

// round 15
// speedup vs baseline: 1.7385x; 1.0769x over previous
#include <cuda_runtime.h>
#include <math.h>
#include <stdint.h>

// ---------------- problem constants ----------------
#define NN   50000
#define PP   3
#define EE   800000
#define FEATD 1000
#define HH   256
#define PHH  512
#define BN_EPS 1e-5f

// ---------------- device scratch (no allocations allowed) ----------------
__device__ uint32_t g_h_hi [(size_t)NN * (HH / 2)];
__device__ uint32_t g_h_lo [(size_t)NN * (HH / 2)];
__device__ float    g_ft[(size_t)3 * NN * HH];         // view-major [3][N][256]
__device__ uint32_t g_z_hi[(size_t)3 * NN * (HH / 2)];
__device__ uint32_t g_z_lo[(size_t)3 * NN * (HH / 2)];
__device__ uint32_t g_x_hi[(size_t)NN * (PHH / 2)];
__device__ float    g_vp[(size_t)NN * HH];
// CSR scratch
__device__ int   g_deg[3 * NN];
__device__ int   g_rowptr[3 * (NN + 1)];
__device__ int   g_cursor[3 * NN];
__device__ int   g_esrc[(size_t)3 * EE];
__device__ float g_eval[(size_t)3 * EE];
// split weights
__device__ uint32_t g_wt_hi[HH * (FEATD / 2)];
__device__ uint32_t g_wt_lo[HH * (FEATD / 2)];
__device__ uint32_t g_wg_hi[3 * HH * (HH / 2)];
__device__ uint32_t g_wg_lo[3 * HH * (HH / 2)];
__device__ uint32_t g_w1_hi[PHH * (HH / 2)];
__device__ uint32_t g_w1_lo[PHH * (HH / 2)];
__device__ uint32_t g_w2_hi[HH * (PHH / 2)];
__device__ uint32_t g_w2_lo[HH * (PHH / 2)];
__device__ uint32_t g_wa_hi[HH * (HH / 2)];
__device__ uint32_t g_wa_lo[HH * (HH / 2)];
__device__ float g_stats[2 * PHH];
__device__ float g_beta_raw[3];
__device__ float g_beta[3];
__device__ float g_loss_acc;

// ---------------- bf16 split helpers --------------------------------------------
__device__ __forceinline__ uint32_t pack_hi(float x0, float x1)
{
    uint32_t r;
    asm("prmt.b32 %0, %1, %2, 0x7632;"
        : "=r"(r) : "r"(__float_as_uint(x0)), "r"(__float_as_uint(x1)));
    return r;
}

__device__ __forceinline__ uint32_t pack_lo(float x0, float x1)
{
    float h0 = __uint_as_float(__float_as_uint(x0) & 0xFFFF0000u);
    float h1 = __uint_as_float(__float_as_uint(x1) & 0xFFFF0000u);
    uint32_t r;
    asm("cvt.rn.bf16x2.f32 %0, %1, %2;" : "=r"(r) : "f"(x1 - h1), "f"(x0 - h0));
    return r;
}

__device__ __forceinline__ void unpack2(uint32_t hi, uint32_t lo, float& f0, float& f1)
{
    f0 = __uint_as_float(hi << 16)          + __uint_as_float(lo << 16);
    f1 = __uint_as_float(hi & 0xFFFF0000u)  + __uint_as_float(lo & 0xFFFF0000u);
}

__device__ __forceinline__ void unpack2_hi(uint32_t hi, float& f0, float& f1)
{
    f0 = __uint_as_float(hi << 16);
    f1 = __uint_as_float(hi & 0xFFFF0000u);
}

__device__ __forceinline__ void mma_bf16(float* c, const uint32_t* a, const uint32_t* b)
{
    asm volatile(
        "mma.sync.aligned.m16n8k16.row.col.f32.bf16.bf16.f32 "
        "{%0,%1,%2,%3}, {%4,%5,%6,%7}, {%8,%9}, {%0,%1,%2,%3};\n"
        : "+f"(c[0]), "+f"(c[1]), "+f"(c[2]), "+f"(c[3])
        : "r"(a[0]), "r"(a[1]), "r"(a[2]), "r"(a[3]), "r"(b[0]), "r"(b[1]));
}

__device__ __forceinline__ void ldsm_x4(uint32_t* r, uint32_t saddr)
{
    asm volatile("ldmatrix.sync.aligned.m8n8.x4.shared.b16 {%0,%1,%2,%3}, [%4];"
                 : "=r"(r[0]), "=r"(r[1]), "=r"(r[2]), "=r"(r[3]) : "r"(saddr));
}

__device__ __forceinline__ void cp16(uint32_t saddr, const void* gmem, bool pred)
{
    int sz = pred ? 16 : 0;
    asm volatile("cp.async.cg.shared.global [%0], [%1], 16, %2;\n"
                 :: "r"(saddr), "l"(gmem), "r"(sz));
}

// ---------------- generic f32 -> split-bf16 pass (weights only) -----------------
__global__ __launch_bounds__(256)
void split_kernel(const float2* __restrict__ in, uint32_t* __restrict__ hi,
                  uint32_t* __restrict__ lo, size_t npairs)
{
    size_t i = (size_t)blockIdx.x * blockDim.x + threadIdx.x;
    if (i >= npairs) return;
    float2 v = in[i];
    hi[i] = pack_hi(v.x, v.y);
    if (lo) lo[i] = pack_lo(v.x, v.y);
}

// ---------------- CSR build ------------------------------------------------------
__global__ __launch_bounds__(256)
void hist_kernel(const int* __restrict__ dst, int* __restrict__ deg)
{
    int i = blockIdx.x * 256 + threadIdx.x;
    if (i >= 3 * EE) return;
    int v = i / EE;
    atomicAdd(&deg[v * NN + dst[i]], 1);
}

__global__ __launch_bounds__(1024)
void scan_kernel(const int* __restrict__ deg, int* __restrict__ rowptr,
                 int* __restrict__ cursor)
{
    const int CH = (NN + 1023) / 1024;   // 49
    int v = blockIdx.x;
    const int* d = deg + v * NN;
    int* rp = rowptr + v * (NN + 1);
    int* cur = cursor + v * NN;
    int t = threadIdx.x;
    int lane = t & 31, w = t >> 5;
    __shared__ int warpsums[32];

    int base = t * CH;
    int local[CH];
    int sum = 0;
#pragma unroll
    for (int k = 0; k < CH; ++k) {
        int idx = base + k;
        int val = (idx < NN) ? d[idx] : 0;
        local[k] = sum;
        sum += val;
    }
    int s = sum;
#pragma unroll
    for (int o = 1; o < 32; o <<= 1) {
        int y = __shfl_up_sync(0xffffffffu, s, o);
        if (lane >= o) s += y;
    }
    if (lane == 31) warpsums[w] = s;
    __syncthreads();
    if (w == 0) {
        int ws = warpsums[lane];
#pragma unroll
        for (int o = 1; o < 32; o <<= 1) {
            int y = __shfl_up_sync(0xffffffffu, ws, o);
            if (lane >= o) ws += y;
        }
        warpsums[lane] = ws;
    }
    __syncthreads();
    int offset = (w > 0 ? warpsums[w - 1] : 0) + (s - sum);
#pragma unroll
    for (int k = 0; k < CH; ++k) {
        int idx = base + k;
        if (idx < NN) {
            int val = offset + local[k];
            rp[idx] = val;
            cur[idx] = val;
        }
    }
    if (t == 1023) rp[NN] = EE;
}

__global__ __launch_bounds__(256)
void scatter_kernel(const int* __restrict__ src, const int* __restrict__ dst,
                    const float* __restrict__ vals, int* __restrict__ cursor,
                    int* __restrict__ esrc, float* __restrict__ eval_)
{
    int i = blockIdx.x * 256 + threadIdx.x;
    if (i >= 3 * EE) return;
    int v = i / EE;
    int d = dst[i];
    int pos = atomicAdd(&cursor[v * NN + d], 1);
    esrc[(size_t)v * EE + pos] = src[i];
    eval_[(size_t)v * EE + pos] = vals[i];
}

// ---------------- CSR SpMM + bias + PReLU -> split-bf16 only (one view) ---------
__global__ __launch_bounds__(256)
void spmm_csr_kernel(const float4* __restrict__ ftv, const int* __restrict__ rp,
                     const int* __restrict__ es, const float* __restrict__ ev,
                     uint32_t* __restrict__ zhiv, uint32_t* __restrict__ zlov,
                     const float* __restrict__ bvp, const float* __restrict__ avp)
{
    int gid = blockIdx.x * 256 + threadIdx.x;
    if (gid >= NN * 64) return;
    int n = gid >> 6;
    int c = gid & 63;
    int i  = rp[n];
    int s1 = rp[n + 1];

    float4 acc = make_float4(0.f, 0.f, 0.f, 0.f);
    for (; i + 2 <= s1; i += 2) {
        int sa = es[i];     float va = ev[i];
        int sb = es[i + 1]; float vb = ev[i + 1];
        float4 fa = ftv[(size_t)sa * 64 + c];
        float4 fb = ftv[(size_t)sb * 64 + c];
        acc.x += va * fa.x; acc.y += va * fa.y; acc.z += va * fa.z; acc.w += va * fa.w;
        acc.x += vb * fb.x; acc.y += vb * fb.y; acc.z += vb * fb.z; acc.w += vb * fb.w;
    }
    if (i < s1) {
        int sa = es[i]; float va = ev[i];
        float4 fa = ftv[(size_t)sa * 64 + c];
        acc.x += va * fa.x; acc.y += va * fa.y; acc.z += va * fa.z; acc.w += va * fa.w;
    }

    float a = *avp;
    float4 bv = *(const float4*)(bvp + (c << 2));
    acc.x += bv.x; acc.y += bv.y; acc.z += bv.z; acc.w += bv.w;
    acc.x = acc.x >= 0.f ? acc.x : a * acc.x;
    acc.y = acc.y >= 0.f ? acc.y : a * acc.y;
    acc.z = acc.z >= 0.f ? acc.z : a * acc.z;
    acc.w = acc.w >= 0.f ? acc.w : a * acc.w;

    size_t p = ((size_t)n * 64 + c) << 1;
    zhiv[p]     = pack_hi(acc.x, acc.y);
    zhiv[p + 1] = pack_hi(acc.z, acc.w);
    zlov[p]     = pack_lo(acc.x, acc.y);
    zlov[p + 1] = pack_lo(acc.z, acc.w);
}

// ---------------- split-bf16 GEMM (3-term) ---------------------------------------
// Block tile 128x128, BK=16 elems (8 u32), 8 warps (2m x 4n), warp tile 64x32.
// Fragment loads via ldmatrix.x4 (conflict-free at TPAD=12).
#define TBM 128
#define TBN 128
#define TPAD 12
#define STG_BYTES (TBM * TPAD * 4)

#define GS_DECL()                                                                   \
    __shared__ __align__(16) uint32_t AsH[2][TBM][TPAD];                            \
    __shared__ __align__(16) uint32_t AsL[2][TBM][TPAD];                            \
    __shared__ __align__(16) uint32_t WsH[2][TBN][TPAD];                            \
    __shared__ __align__(16) uint32_t WsL[2][TBN][TPAD];                            \
    const int tid  = threadIdx.x;                                                   \
    const int wid  = tid >> 5;                                                      \
    const int lane = tid & 31;                                                      \
    const int g    = lane >> 2;                                                     \
    const int t    = lane & 3;                                                      \
    const int wm   = (wid & 1) << 6;                                                \
    const int wn   = (wid >> 1) << 5;                                               \
    const int bm   = blockIdx.y * TBM;                                              \
    const int bn   = blockIdx.x * TBN;                                              \
    const uint32_t sAsH = (uint32_t)__cvta_generic_to_shared(&AsH[0][0][0]);        \
    const uint32_t sAsL = (uint32_t)__cvta_generic_to_shared(&AsL[0][0][0]);        \
    const uint32_t sWsH = (uint32_t)__cvta_generic_to_shared(&WsH[0][0][0]);        \
    const uint32_t sWsL = (uint32_t)__cvta_generic_to_shared(&WsL[0][0][0]);        \
    const uint32_t offA = (uint32_t)(((wm + (lane & 7) + ((lane >> 3) & 1) * 8)     \
                                      * TPAD + ((lane >> 4) << 2)) * 4);            \
    const uint32_t offB = (uint32_t)(((wn + ((lane >> 4) & 1) * 8 + (lane & 7))     \
                                      * TPAD + (((lane >> 3) & 1) << 2)) * 4);      \
    float acc[4][4][4] = {};

#define GS_LOAD(S, KP0)                                                             \
    {                                                                               \
        int r  = tid >> 1, ch = (tid & 1) << 2;                                     \
        int gp = (KP0) + ch;                                                        \
        bool pa = (gp < Kp) && (bm + r < M);                                        \
        size_t offa = (size_t)(bm + r) * Kp + gp;                                   \
        cp16((uint32_t)__cvta_generic_to_shared(&AsH[S][r][ch]), Ahi + offa, pa);   \
        cp16((uint32_t)__cvta_generic_to_shared(&AsL[S][r][ch]), Alo + offa, pa);   \
        bool pb = (gp < Kp);                                                        \
        size_t offb = (size_t)(bn + r) * Kp + gp;                                   \
        cp16((uint32_t)__cvta_generic_to_shared(&WsH[S][r][ch]), Whi + offb, pb);   \
        cp16((uint32_t)__cvta_generic_to_shared(&WsL[S][r][ch]), Wlo + offb, pb);   \
    }

#define GS_LOAD_AF32(S, KP0)                                                        \
    {                                                                               \
        int r  = tid >> 1, ch = (tid & 1) << 2;                                     \
        int gp = (KP0) + ch;                                                        \
        float4 f0 = make_float4(0.f, 0.f, 0.f, 0.f), f1 = f0;                       \
        if (gp < Kp && bm + r < M) {                                                \
            const float* ap = Af32 + (size_t)(bm + r) * (Kp * 2) + gp * 2;          \
            f0 = *(const float4*)ap;                                                \
            f1 = *(const float4*)(ap + 4);                                          \
        }                                                                           \
        AsH[S][r][ch + 0] = pack_hi(f0.x, f0.y); AsL[S][r][ch + 0] = pack_lo(f0.x, f0.y); \
        AsH[S][r][ch + 1] = pack_hi(f0.z, f0.w); AsL[S][r][ch + 1] = pack_lo(f0.z, f0.w); \
        AsH[S][r][ch + 2] = pack_hi(f1.x, f1.y); AsL[S][r][ch + 2] = pack_lo(f1.x, f1.y); \
        AsH[S][r][ch + 3] = pack_hi(f1.z, f1.w); AsL[S][r][ch + 3] = pack_lo(f1.z, f1.w); \
        bool pb = (gp < Kp);                                                        \
        size_t offb = (size_t)(bn + r) * Kp + gp;                                   \
        cp16((uint32_t)__cvta_generic_to_shared(&WsH[S][r][ch]), Whi + offb, pb);   \
        cp16((uint32_t)__cvta_generic_to_shared(&WsL[S][r][ch]), Wlo + offb, pb);   \
    }

#define GS_COMPUTE()                                                                \
    {                                                                               \
        uint32_t aH[4][4], aL[4][4], bH[4][2], bL[4][2];                            \
        uint32_t bs = (uint32_t)buf * STG_BYTES;                                    \
        _Pragma("unroll")                                                           \
        for (int i = 0; i < 4; ++i) {                                               \
            uint32_t ao = bs + offA + (uint32_t)(i * 16 * TPAD * 4);                \
            ldsm_x4(aH[i], sAsH + ao);                                              \
            ldsm_x4(aL[i], sAsL + ao);                                              \
        }                                                                           \
        _Pragma("unroll")                                                           \
        for (int jj = 0; jj < 2; ++jj) {                                            \
            uint32_t bo = bs + offB + (uint32_t)(jj * 16 * TPAD * 4);               \
            uint32_t tH[4], tL[4];                                                  \
            ldsm_x4(tH, sWsH + bo);                                                 \
            ldsm_x4(tL, sWsL + bo);                                                 \
            bH[2 * jj][0] = tH[0]; bH[2 * jj][1] = tH[1];                           \
            bH[2 * jj + 1][0] = tH[2]; bH[2 * jj + 1][1] = tH[3];                   \
            bL[2 * jj][0] = tL[0]; bL[2 * jj][1] = tL[1];                           \
            bL[2 * jj + 1][0] = tL[2]; bL[2 * jj + 1][1] = tL[3];                   \
        }                                                                           \
        _Pragma("unroll")                                                           \
        for (int i = 0; i < 4; ++i)                                                 \
            _Pragma("unroll")                                                       \
            for (int j = 0; j < 4; ++j) {                                           \
                mma_bf16(acc[i][j], aL[i], bH[j]);                                  \
                mma_bf16(acc[i][j], aH[i], bL[j]);                                  \
                mma_bf16(acc[i][j], aH[i], bH[j]);                                  \
            }                                                                       \
    }

#define GS_MAINLOOP(LOADM)                                                          \
    LOADM(0, 0);                                                                    \
    asm volatile("cp.async.commit_group;\n" ::: "memory");                          \
    int buf = 0;                                                                    \
    for (int kp0 = 0; kp0 < Kp; kp0 += 8) {                                         \
        if (kp0 + 8 < Kp) LOADM(buf ^ 1, kp0 + 8);                                  \
        asm volatile("cp.async.commit_group;\n" ::: "memory");                      \
        asm volatile("cp.async.wait_group 1;\n" ::: "memory");                      \
        __syncthreads();                                                            \
        GS_COMPUTE();                                                               \
        __syncthreads();                                                            \
        buf ^= 1;                                                                   \
    }

// 3-term GEMM, EPI 0 = raw f32 row-major (no bias). Used for GCN GEMMs.
__global__ __launch_bounds__(256, 2)
void gemm_bf16s_kernel(const uint32_t* __restrict__ Ahi, const uint32_t* __restrict__ Alo,
                       const uint32_t* __restrict__ Whi, const uint32_t* __restrict__ Wlo,
                       float* __restrict__ C, int M, int Nc, int Kp)
{
    GS_DECL();
    GS_MAINLOOP(GS_LOAD);

#pragma unroll
    for (int i = 0; i < 4; ++i) {
#pragma unroll
        for (int j = 0; j < 4; ++j) {
            int r0 = bm + wm + (i << 4) + g;
            int r1 = r0 + 8;
            int c0 = bn + wn + (j << 3) + (t << 1);
            float v0 = acc[i][j][0], v1 = acc[i][j][1];
            float v2 = acc[i][j][2], v3 = acc[i][j][3];
            if (r0 < M) *(float2*)(C + (size_t)r0 * Nc + c0) = make_float2(v0, v1);
            if (r1 < M) *(float2*)(C + (size_t)r1 * Nc + c0) = make_float2(v2, v3);
        }
    }
}

// feats GEMM: A = raw f32, epilogue bias+ELU -> split bf16 h
__global__ __launch_bounds__(256, 2)
void gemm_bf16s_af32_kernel(const float* __restrict__ Af32,
                            const uint32_t* __restrict__ Whi, const uint32_t* __restrict__ Wlo,
                            const float* __restrict__ bias,
                            uint32_t* __restrict__ Chi, uint32_t* __restrict__ Clo,
                            int M, int Nc, int Kp)
{
    GS_DECL();
    GS_MAINLOOP(GS_LOAD_AF32);

#pragma unroll
    for (int i = 0; i < 4; ++i) {
#pragma unroll
        for (int j = 0; j < 4; ++j) {
            int r0 = bm + wm + (i << 4) + g;
            int r1 = r0 + 8;
            int c0 = bn + wn + (j << 3) + (t << 1);
            float bx = bias[c0], by = bias[c0 + 1];
            float v0 = acc[i][j][0] + bx, v1 = acc[i][j][1] + by;
            float v2 = acc[i][j][2] + bx, v3 = acc[i][j][3] + by;
            v0 = v0 > 0.f ? v0 : expm1f(v0);
            v1 = v1 > 0.f ? v1 : expm1f(v1);
            v2 = v2 > 0.f ? v2 : expm1f(v2);
            v3 = v3 > 0.f ? v3 : expm1f(v3);
            int pc = c0 >> 1;
            if (r0 < M) {
                Chi[(size_t)r0 * (Nc / 2) + pc] = pack_hi(v0, v1);
                Clo[(size_t)r0 * (Nc / 2) + pc] = pack_lo(v0, v1);
            }
            if (r1 < M) {
                Chi[(size_t)r1 * (Nc / 2) + pc] = pack_hi(v2, v3);
                Clo[(size_t)r1 * (Nc / 2) + pc] = pack_lo(v2, v3);
            }
        }
    }
}

// ---------------- 2-term GEMM: A hi-only x split W ------------------------------
// EPI: 2 = bias -> f32 C; 3 = bias -> hi-only bf16 Chi + BN column stats.
template<int EPI>
__global__ __launch_bounds__(256, 2)
void gemm2_bf16_kernel(const uint32_t* __restrict__ Ahi,
                       const uint32_t* __restrict__ Whi, const uint32_t* __restrict__ Wlo,
                       const float* __restrict__ bias, float* __restrict__ C,
                       uint32_t* __restrict__ Chi, float* __restrict__ stats,
                       int M, int Nc, int Kp)
{
    __shared__ __align__(16) uint32_t AsH[2][TBM][TPAD];
    __shared__ __align__(16) uint32_t WsH[2][TBN][TPAD];
    __shared__ __align__(16) uint32_t WsL[2][TBN][TPAD];
    const int tid  = threadIdx.x;
    const int wid  = tid >> 5;
    const int lane = tid & 31;
    const int g    = lane >> 2;
    const int t    = lane & 3;
    const int wm   = (wid & 1) << 6;
    const int wn   = (wid >> 1) << 5;
    const int bm   = blockIdx.y * TBM;
    const int bn   = blockIdx.x * TBN;
    const uint32_t sAsH = (uint32_t)__cvta_generic_to_shared(&AsH[0][0][0]);
    const uint32_t sWsH = (uint32_t)__cvta_generic_to_shared(&WsH[0][0][0]);
    const uint32_t sWsL = (uint32_t)__cvta_generic_to_shared(&WsL[0][0][0]);
    const uint32_t offA = (uint32_t)(((wm + (lane & 7) + ((lane >> 3) & 1) * 8)
                                      * TPAD + ((lane >> 4) << 2)) * 4);
    const uint32_t offB = (uint32_t)(((wn + ((lane >> 4) & 1) * 8 + (lane & 7))
                                      * TPAD + (((lane >> 3) & 1) << 2)) * 4);
    float acc[4][4][4] = {};

#define G2_LOAD(S, KP0)                                                             \
    {                                                                               \
        int r  = tid >> 1, ch = (tid & 1) << 2;                                     \
        int gp = (KP0) + ch;                                                        \
        bool pa = (gp < Kp) && (bm + r < M);                                        \
        cp16((uint32_t)__cvta_generic_to_shared(&AsH[S][r][ch]),                    \
             Ahi + (size_t)(bm + r) * Kp + gp, pa);                                 \
        bool pb = (gp < Kp);                                                        \
        cp16((uint32_t)__cvta_generic_to_shared(&WsH[S][r][ch]),                    \
             Whi + (size_t)(bn + r) * Kp + gp, pb);                                 \
        cp16((uint32_t)__cvta_generic_to_shared(&WsL[S][r][ch]),                    \
             Wlo + (size_t)(bn + r) * Kp + gp, pb);                                 \
    }

    G2_LOAD(0, 0);
    asm volatile("cp.async.commit_group;\n" ::: "memory");
    int buf = 0;
    for (int kp0 = 0; kp0 < Kp; kp0 += 8) {
        if (kp0 + 8 < Kp) G2_LOAD(buf ^ 1, kp0 + 8);
        asm volatile("cp.async.commit_group;\n" ::: "memory");
        asm volatile("cp.async.wait_group 1;\n" ::: "memory");
        __syncthreads();
        uint32_t aH[4][4], bH[4][2], bL[4][2];
        uint32_t bs = (uint32_t)buf * STG_BYTES;
#pragma unroll
        for (int i = 0; i < 4; ++i)
            ldsm_x4(aH[i], sAsH + bs + offA + (uint32_t)(i * 16 * TPAD * 4));
#pragma unroll
        for (int jj = 0; jj < 2; ++jj) {
            uint32_t bo = bs + offB + (uint32_t)(jj * 16 * TPAD * 4);
            uint32_t tH[4], tL[4];
            ldsm_x4(tH, sWsH + bo);
            ldsm_x4(tL, sWsL + bo);
            bH[2 * jj][0] = tH[0]; bH[2 * jj][1] = tH[1];
            bH[2 * jj + 1][0] = tH[2]; bH[2 * jj + 1][1] = tH[3];
            bL[2 * jj][0] = tL[0]; bL[2 * jj][1] = tL[1];
            bL[2 * jj + 1][0] = tL[2]; bL[2 * jj + 1][1] = tL[3];
        }
#pragma unroll
        for (int i = 0; i < 4; ++i)
#pragma unroll
            for (int j = 0; j < 4; ++j) {
                mma_bf16(acc[i][j], aH[i], bL[j]);
                mma_bf16(acc[i][j], aH[i], bH[j]);
            }
        __syncthreads();
        buf ^= 1;
    }
#undef G2_LOAD

    float* sSum = (float*)&AsH[0][0][0];
    float* sSq  = sSum + 128;
    if (EPI == 3) {
        __syncthreads();
        if (tid < 128) { sSum[tid] = 0.f; sSq[tid] = 0.f; }
        __syncthreads();
    }

#pragma unroll
    for (int j = 0; j < 4; ++j) {
        float cs0 = 0.f, cq0 = 0.f, cs1 = 0.f, cq1 = 0.f;
#pragma unroll
        for (int i = 0; i < 4; ++i) {
            int r0 = bm + wm + (i << 4) + g;
            int r1 = r0 + 8;
            int c0 = bn + wn + (j << 3) + (t << 1);
            float bx = bias[c0], by = bias[c0 + 1];
            float v0 = acc[i][j][0] + bx, v1 = acc[i][j][1] + by;
            float v2 = acc[i][j][2] + bx, v3 = acc[i][j][3] + by;
            if (EPI == 2) {
                if (r0 < M) *(float2*)(C + (size_t)r0 * Nc + c0) = make_float2(v0, v1);
                if (r1 < M) *(float2*)(C + (size_t)r1 * Nc + c0) = make_float2(v2, v3);
            } else {
                int pc = c0 >> 1;
                if (r0 < M) {
                    Chi[(size_t)r0 * (Nc / 2) + pc] = pack_hi(v0, v1);
                    cs0 += v0; cq0 += v0 * v0; cs1 += v1; cq1 += v1 * v1;
                }
                if (r1 < M) {
                    Chi[(size_t)r1 * (Nc / 2) + pc] = pack_hi(v2, v3);
                    cs0 += v2; cq0 += v2 * v2; cs1 += v3; cq1 += v3 * v3;
                }
            }
        }
        if (EPI == 3) {
            int lc = wn + (j << 3) + (t << 1);
            atomicAdd(&sSum[lc], cs0);     atomicAdd(&sSq[lc], cq0);
            atomicAdd(&sSum[lc + 1], cs1); atomicAdd(&sSq[lc + 1], cq1);
        }
    }
    if (EPI == 3) {
        __syncthreads();
        if (tid < 128) {
            atomicAdd(&stats[bn + tid], sSum[tid]);
            atomicAdd(&stats[PHH + bn + tid], sSq[tid]);
        }
    }
}

// attention GEMM: z hi-only x split W; epilogue tanh-att reduce to beta.
// blockIdx.z = view; beta index = (view+2)%3.
__global__ __launch_bounds__(256, 2)
void gemm_att_bf16_kernel(const uint32_t* __restrict__ Zhi,
                          const uint32_t* __restrict__ Whi, const uint32_t* __restrict__ Wlo,
                          const float* __restrict__ bias, const float* __restrict__ att,
                          float* __restrict__ beta_raw, int M, int Kp)
{
    __shared__ __align__(16) uint32_t AsH[2][TBM][TPAD];
    __shared__ __align__(16) uint32_t WsH[2][TBN][TPAD];
    __shared__ __align__(16) uint32_t WsL[2][TBN][TPAD];
    const int tid  = threadIdx.x;
    const int wid  = tid >> 5;
    const int lane = tid & 31;
    const int g    = lane >> 2;
    const int t    = lane & 3;
    const int wm   = (wid & 1) << 6;
    const int wn   = (wid >> 1) << 5;
    const int bm   = blockIdx.y * TBM;
    const int bn   = blockIdx.x * TBN;
    const int view = blockIdx.z;
    const uint32_t* Ahi = Zhi + (size_t)view * NN * (HH / 2);
    const uint32_t sAsH = (uint32_t)__cvta_generic_to_shared(&AsH[0][0][0]);
    const uint32_t sWsH = (uint32_t)__cvta_generic_to_shared(&WsH[0][0][0]);
    const uint32_t sWsL = (uint32_t)__cvta_generic_to_shared(&WsL[0][0][0]);
    const uint32_t offA = (uint32_t)(((wm + (lane & 7) + ((lane >> 3) & 1) * 8)
                                      * TPAD + ((lane >> 4) << 2)) * 4);
    const uint32_t offB = (uint32_t)(((wn + ((lane >> 4) & 1) * 8 + (lane & 7))
                                      * TPAD + (((lane >> 3) & 1) << 2)) * 4);
    float acc[4][4][4] = {};

#define GA_LOAD(S, KP0)                                                             \
    {                                                                               \
        int r  = tid >> 1, ch = (tid & 1) << 2;                                     \
        int gp = (KP0) + ch;                                                        \
        bool pa = (gp < Kp) && (bm + r < M);                                        \
        cp16((uint32_t)__cvta_generic_to_shared(&AsH[S][r][ch]),                    \
             Ahi + (size_t)(bm + r) * Kp + gp, pa);                                 \
        bool pb = (gp < Kp);                                                        \
        cp16((uint32_t)__cvta_generic_to_shared(&WsH[S][r][ch]),                    \
             Whi + (size_t)(bn + r) * Kp + gp, pb);                                 \
        cp16((uint32_t)__cvta_generic_to_shared(&WsL[S][r][ch]),                    \
             Wlo + (size_t)(bn + r) * Kp + gp, pb);                                 \
    }

    GA_LOAD(0, 0);
    asm volatile("cp.async.commit_group;\n" ::: "memory");
    int buf = 0;
    for (int kp0 = 0; kp0 < Kp; kp0 += 8) {
        if (kp0 + 8 < Kp) GA_LOAD(buf ^ 1, kp0 + 8);
        asm volatile("cp.async.commit_group;\n" ::: "memory");
        asm volatile("cp.async.wait_group 1;\n" ::: "memory");
        __syncthreads();
        uint32_t aH[4][4], bH[4][2], bL[4][2];
        uint32_t bs = (uint32_t)buf * STG_BYTES;
#pragma unroll
        for (int i = 0; i < 4; ++i)
            ldsm_x4(aH[i], sAsH + bs + offA + (uint32_t)(i * 16 * TPAD * 4));
#pragma unroll
        for (int jj = 0; jj < 2; ++jj) {
            uint32_t bo = bs + offB + (uint32_t)(jj * 16 * TPAD * 4);
            uint32_t tH[4], tL[4];
            ldsm_x4(tH, sWsH + bo);
            ldsm_x4(tL, sWsL + bo);
            bH[2 * jj][0] = tH[0]; bH[2 * jj][1] = tH[1];
            bH[2 * jj + 1][0] = tH[2]; bH[2 * jj + 1][1] = tH[3];
            bL[2 * jj][0] = tL[0]; bL[2 * jj][1] = tL[1];
            bL[2 * jj + 1][0] = tL[2]; bL[2 * jj + 1][1] = tL[3];
        }
#pragma unroll
        for (int i = 0; i < 4; ++i)
#pragma unroll
            for (int j = 0; j < 4; ++j) {
                mma_bf16(acc[i][j], aH[i], bL[j]);
                mma_bf16(acc[i][j], aH[i], bH[j]);
            }
        __syncthreads();
        buf ^= 1;
    }
#undef GA_LOAD

    float s = 0.f;
#pragma unroll
    for (int i = 0; i < 4; ++i) {
#pragma unroll
        for (int j = 0; j < 4; ++j) {
            int r0 = bm + wm + (i << 4) + g;
            int r1 = r0 + 8;
            int c0 = bn + wn + (j << 3) + (t << 1);
            float bx = bias[c0], by = bias[c0 + 1];
            float ax = att[c0],  ay = att[c0 + 1];
            if (r0 < M) s += tanhf(acc[i][j][0] + bx) * ax + tanhf(acc[i][j][1] + by) * ay;
            if (r1 < M) s += tanhf(acc[i][j][2] + bx) * ax + tanhf(acc[i][j][3] + by) * ay;
        }
    }
    float* red = (float*)&AsH[0][0][0];
    __syncthreads();
    red[tid] = s;
    __syncthreads();
    for (int o = 128; o > 0; o >>= 1) {
        if (tid < o) red[tid] += red[tid + o];
        __syncthreads();
    }
    if (tid == 0) {
        int bidx = (view + 2) % 3;
        atomicAdd(&beta_raw[bidx], red[0]);
    }
}

// ---------------- BN + PReLU on hi-only bf16 x (in place) -----------------------
__global__ __launch_bounds__(256)
void bn_prelu_hi_kernel(uint32_t* __restrict__ xhi, const float* __restrict__ stats,
                        const float* __restrict__ g, const float* __restrict__ b,
                        const float* __restrict__ a_ptr)
{
    int i = blockIdx.x * blockDim.x + threadIdx.x;
    if (i >= NN * (PHH / 4)) return;
    int c = (i & (PHH / 4 - 1)) << 2;
    float a = *a_ptr;
    float4 sm = *(const float4*)(stats + c);
    float4 sq = *(const float4*)(stats + PHH + c);
    float4 gv = *(const float4*)(g + c);
    float4 bv = *(const float4*)(b + c);
    uint2 h = ((const uint2*)xhi)[i];
    float4 v;
    unpack2_hi(h.x, v.x, v.y);
    unpack2_hi(h.y, v.z, v.w);
    float invN = 1.f / (float)NN;

    float mu, var, sc, sh, y;
    mu = sm.x * invN; var = sq.x * invN - mu * mu; sc = gv.x * rsqrtf(var + BN_EPS);
    sh = bv.x - mu * sc; y = v.x * sc + sh; v.x = y >= 0.f ? y : a * y;
    mu = sm.y * invN; var = sq.y * invN - mu * mu; sc = gv.y * rsqrtf(var + BN_EPS);
    sh = bv.y - mu * sc; y = v.y * sc + sh; v.y = y >= 0.f ? y : a * y;
    mu = sm.z * invN; var = sq.z * invN - mu * mu; sc = gv.z * rsqrtf(var + BN_EPS);
    sh = bv.z - mu * sc; y = v.z * sc + sh; v.z = y >= 0.f ? y : a * y;
    mu = sm.w * invN; var = sq.w * invN - mu * mu; sc = gv.w * rsqrtf(var + BN_EPS);
    sh = bv.w - mu * sc; y = v.w * sc + sh; v.w = y >= 0.f ? y : a * y;

    uint2 nh;
    nh.x = pack_hi(v.x, v.y);
    nh.y = pack_hi(v.z, v.w);
    ((uint2*)xhi)[i] = nh;
}

// ---------------- cosine loss (one warp per node; teachers from split-bf16) -----
__global__ __launch_bounds__(256)
void loss_kernel(const float4* __restrict__ p,
                 const uint32_t* __restrict__ zh, const uint32_t* __restrict__ zl,
                 float* __restrict__ acc)
{
    const uint32_t* t1h = zh + (size_t)NN * (HH / 2);
    const uint32_t* t1l = zl + (size_t)NN * (HH / 2);
    const uint32_t* t2h = zh + (size_t)2 * NN * (HH / 2);
    const uint32_t* t2l = zl + (size_t)2 * NN * (HH / 2);
    int gid  = blockIdx.x * blockDim.x + threadIdx.x;
    int node = gid >> 5;
    int lane = gid & 31;
    float pp = 0.f, n1 = 0.f, n2 = 0.f, d1 = 0.f, d2 = 0.f;
    if (node < NN) {
        size_t base4 = (size_t)node * 64;
        size_t baseu = (size_t)node * 128;
#pragma unroll
        for (int r = 0; r < 2; ++r) {
            int q = lane + 32 * r;
            float4 a = p[base4 + q];
            uint2 h1 = *(const uint2*)&t1h[baseu + 2 * q];
            uint2 l1 = *(const uint2*)&t1l[baseu + 2 * q];
            uint2 h2 = *(const uint2*)&t2h[baseu + 2 * q];
            uint2 l2 = *(const uint2*)&t2l[baseu + 2 * q];
            float4 b, cc;
            unpack2(h1.x, l1.x, b.x, b.y);  unpack2(h1.y, l1.y, b.z, b.w);
            unpack2(h2.x, l2.x, cc.x, cc.y); unpack2(h2.y, l2.y, cc.z, cc.w);
            pp += a.x * a.x + a.y * a.y + a.z * a.z + a.w * a.w;
            n1 += b.x * b.x + b.y * b.y + b.z * b.z + b.w * b.w;
            n2 += cc.x * cc.x + cc.y * cc.y + cc.z * cc.z + cc.w * cc.w;
            d1 += a.x * b.x + a.y * b.y + a.z * b.z + a.w * b.w;
            d2 += a.x * cc.x + a.y * cc.y + a.z * cc.z + a.w * cc.w;
        }
    }
#pragma unroll
    for (int o = 16; o > 0; o >>= 1) {
        pp += __shfl_down_sync(0xffffffffu, pp, o);
        n1 += __shfl_down_sync(0xffffffffu, n1, o);
        n2 += __shfl_down_sync(0xffffffffu, n2, o);
        d1 += __shfl_down_sync(0xffffffffu, d1, o);
        d2 += __shfl_down_sync(0xffffffffu, d2, o);
    }
    __shared__ float sacc[8];
    float contrib = 0.f;
    if (lane == 0 && node < NN) {
        float np  = fmaxf(sqrtf(pp), 1e-12f);
        float nn1 = fmaxf(sqrtf(n1), 1e-12f);
        float nn2 = fmaxf(sqrtf(n2), 1e-12f);
        contrib = d1 / (np * nn1) + d2 / (np * nn2);
    }
    int wid = threadIdx.x >> 5;
    if (lane == 0) sacc[wid] = contrib;
    __syncthreads();
    if (threadIdx.x == 0) {
        float s = 0.f;
#pragma unroll
        for (int i = 0; i < 8; ++i) s += sacc[i];
        atomicAdd(acc, s);
    }
}

// ---------------- finalize: softmax(beta), loss --------------------------------
__global__ void finalize_kernel(float* __restrict__ out_loss, int write_loss)
{
    float invN = 1.f / (float)NN;
    float b0 = g_beta_raw[0] * invN;
    float b1 = g_beta_raw[1] * invN;
    float b2 = g_beta_raw[2] * invN;
    float m = fmaxf(b0, fmaxf(b1, b2));
    float e0 = expf(b0 - m), e1 = expf(b1 - m), e2 = expf(b2 - m);
    float s = e0 + e1 + e2;
    g_beta[0] = e0 / s;
    g_beta[1] = e1 / s;
    g_beta[2] = e2 / s;
    if (write_loss) *out_loss = 2.0f - g_loss_acc * invN;
}

// ---------------- z_out = b0*z1 + b1*z2 + b2*z0 (from split-bf16) ----------------
__global__ __launch_bounds__(256)
void zout_kernel(float4* __restrict__ out, const uint32_t* __restrict__ zh,
                 const uint32_t* __restrict__ zl)
{
    int i = blockIdx.x * blockDim.x + threadIdx.x;
    if (i >= NN * 64) return;
    float b2 = g_beta[2], b0 = g_beta[0], b1 = g_beta[1];
    const size_t vstride = (size_t)NN * (HH / 2);
    size_t u = (size_t)i * 2;
    uint2 h0 = *(const uint2*)&zh[u];
    uint2 l0 = *(const uint2*)&zl[u];
    uint2 h1 = *(const uint2*)&zh[vstride + u];
    uint2 l1 = *(const uint2*)&zl[vstride + u];
    uint2 h2 = *(const uint2*)&zh[2 * vstride + u];
    uint2 l2 = *(const uint2*)&zl[2 * vstride + u];
    float4 a, b, c;
    unpack2(h0.x, l0.x, c.x, c.y); unpack2(h0.y, l0.y, c.z, c.w);
    unpack2(h1.x, l1.x, a.x, a.y); unpack2(h1.y, l1.y, a.z, a.w);
    unpack2(h2.x, l2.x, b.x, b.y); unpack2(h2.y, l2.y, b.z, b.w);
    float4 r;
    r.x = b0 * a.x + b1 * b.x + b2 * c.x;
    r.y = b0 * a.y + b1 * b.y + b2 * c.y;
    r.z = b0 * a.z + b1 * b.z + b2 * c.z;
    r.w = b0 * a.w + b1 * b.w + b2 * c.w;
    out[i] = r;
}

// ---------------- host ----------------------------------------------------------
#define GETSYM(var, sym) cudaGetSymbolAddress((void**)&var, sym)

extern "C" void kernel_launch(void* const* d_in, const int* in_sizes, int n_in,
                              void* d_out, int out_size)
{
    const float* feats   = (const float*)d_in[0];
    const int*   src     = (const int*)  d_in[1];
    const int*   dst     = (const int*)  d_in[2];
    const float* vals    = (const float*)d_in[3];
    const float* W_trans = (const float*)d_in[4];
    const float* b_trans = (const float*)d_in[5];
    const float* W_gcn   = (const float*)d_in[6];
    const float* b_gcn   = (const float*)d_in[7];
    const float* a_gcn   = (const float*)d_in[8];
    const float* W1      = (const float*)d_in[9];
    const float* b1      = (const float*)d_in[10];
    const float* bn_g    = (const float*)d_in[11];
    const float* bn_b    = (const float*)d_in[12];
    const float* a_pred  = (const float*)d_in[13];
    const float* W2      = (const float*)d_in[14];
    const float* b2      = (const float*)d_in[15];
    const float* W_att   = (const float*)d_in[16];
    const float* b_att   = (const float*)d_in[17];
    const float* att     = (const float*)d_in[18];

    uint32_t *h_hi, *h_lo, *zh, *zl;
    uint32_t *x_hi, *wt_hi, *wt_lo, *wg_hi, *wg_lo, *w1_hi, *w1_lo;
    uint32_t *w2_hi, *w2_lo, *wa_hi, *wa_lo;
    float *ft, *vp, *stats, *beta_raw, *loss_acc;
    int *deg, *rowptr, *cursor, *esrc;
    float *eval_;
    GETSYM(h_hi, g_h_hi);   GETSYM(h_lo, g_h_lo);
    GETSYM(zh, g_z_hi); GETSYM(zl, g_z_lo);
    GETSYM(x_hi, g_x_hi);
    GETSYM(wt_hi, g_wt_hi); GETSYM(wt_lo, g_wt_lo);
    GETSYM(wg_hi, g_wg_hi); GETSYM(wg_lo, g_wg_lo);
    GETSYM(w1_hi, g_w1_hi); GETSYM(w1_lo, g_w1_lo);
    GETSYM(w2_hi, g_w2_hi); GETSYM(w2_lo, g_w2_lo);
    GETSYM(wa_hi, g_wa_hi); GETSYM(wa_lo, g_wa_lo);
    GETSYM(ft, g_ft);
    GETSYM(vp, g_vp);
    GETSYM(stats, g_stats); GETSYM(beta_raw, g_beta_raw); GETSYM(loss_acc, g_loss_acc);
    GETSYM(deg, g_deg); GETSYM(rowptr, g_rowptr); GETSYM(cursor, g_cursor);
    GETSYM(esrc, g_esrc); GETSYM(eval_, g_eval);

    cudaStream_t s2;
    cudaStreamCreateWithFlags(&s2, cudaStreamNonBlocking);
    cudaEvent_t eFork, eSplit, eG[3], eS0, eS2, eAtt;
    cudaEventCreateWithFlags(&eFork,  cudaEventDisableTiming);
    cudaEventCreateWithFlags(&eSplit, cudaEventDisableTiming);
    for (int v = 0; v < 3; ++v) cudaEventCreateWithFlags(&eG[v], cudaEventDisableTiming);
    cudaEventCreateWithFlags(&eS0,  cudaEventDisableTiming);
    cudaEventCreateWithFlags(&eS2,  cudaEventDisableTiming);
    cudaEventCreateWithFlags(&eAtt, cudaEventDisableTiming);

    cudaMemsetAsync(deg, 0, 3 * NN * sizeof(int));
    cudaMemsetAsync(stats, 0, 2 * PHH * sizeof(float));
    cudaMemsetAsync(beta_raw, 0, 3 * sizeof(float));
    cudaMemsetAsync(loss_acc, 0, sizeof(float));

    // fork: CSR build on s2, concurrent with splits + feats GEMM
    cudaEventRecord(eFork, 0);
    cudaStreamWaitEvent(s2, eFork, 0);
    hist_kernel<<<(3 * EE + 255) / 256, 256, 0, s2>>>(dst, deg);
    scan_kernel<<<3, 1024, 0, s2>>>(deg, rowptr, cursor);
    scatter_kernel<<<(3 * EE + 255) / 256, 256, 0, s2>>>(src, dst, vals, cursor,
                                                         esrc, eval_);

    // main: weight splits
    {
        size_t np = (size_t)HH * (FEATD / 2);
        split_kernel<<<(int)((np + 255) / 256), 256>>>((const float2*)W_trans, wt_hi, wt_lo, np);
        np = (size_t)3 * HH * (HH / 2);
        split_kernel<<<(int)((np + 255) / 256), 256>>>((const float2*)W_gcn, wg_hi, wg_lo, np);
        np = (size_t)PHH * (HH / 2);
        split_kernel<<<(int)((np + 255) / 256), 256>>>((const float2*)W1, w1_hi, w1_lo, np);
        np = (size_t)HH * (PHH / 2);
        split_kernel<<<(int)((np + 255) / 256), 256>>>((const float2*)W2, w2_hi, w2_lo, np);
        np = (size_t)HH * (HH / 2);
        split_kernel<<<(int)((np + 255) / 256), 256>>>((const float2*)W_att, wa_hi, wa_lo, np);
    }
    cudaEventRecord(eSplit, 0);

    const int mb = (NN + TBM - 1) / TBM;   // 391

    // main: h = elu(feats @ W_trans^T + b_trans)
    gemm_bf16s_af32_kernel<<<dim3(HH / TBN, mb), 256>>>(
        feats, wt_hi, wt_lo, b_trans, h_hi, h_lo, NN, HH, FEATD / 2);

    // main: per-view GCN GEMMs
    for (int v = 0; v < PP; ++v) {
        gemm_bf16s_kernel<<<dim3(HH / TBN, mb), 256>>>(
            h_hi, h_lo,
            wg_hi + (size_t)v * HH * (HH / 2), wg_lo + (size_t)v * HH * (HH / 2),
            ft + (size_t)v * NN * HH, NN, HH, HH / 2);
        cudaEventRecord(eG[v], 0);
    }

    // s2: SpMM(v) as soon as GEMM(v) done
    for (int v = 0; v < PP; ++v) {
        cudaStreamWaitEvent(s2, eG[v], 0);
        spmm_csr_kernel<<<(NN * 64 + 255) / 256, 256, 0, s2>>>(
            (const float4*)(ft + (size_t)v * NN * HH),
            rowptr + v * (NN + 1),
            esrc + (size_t)v * EE, eval_ + (size_t)v * EE,
            zh + (size_t)v * NN * (HH / 2), zl + (size_t)v * NN * (HH / 2),
            b_gcn + (size_t)v * HH, a_gcn + v);
        if (v == 0) cudaEventRecord(eS0, s2);
    }
    cudaEventRecord(eS2, s2);

    // s2: attention GEMM after all z ready
    cudaStreamWaitEvent(s2, eSplit, 0);
    gemm_att_bf16_kernel<<<dim3(HH / TBN, mb, 3), 256, 0, s2>>>(
        zh, wa_hi, wa_lo, b_att, att, beta_raw, NN, HH / 2);
    cudaEventRecord(eAtt, s2);

    // main: predictor chain (2-term, loss-only precision) + loss
    cudaStreamWaitEvent(0, eS0, 0);
    gemm2_bf16_kernel<3><<<dim3(PHH / TBN, mb), 256>>>(
        zh, w1_hi, w1_lo, b1, nullptr, x_hi, stats, NN, PHH, HH / 2);
    bn_prelu_hi_kernel<<<(NN * PHH / 4) / 256, 256>>>(x_hi, stats, bn_g, bn_b, a_pred);
    gemm2_bf16_kernel<2><<<dim3(HH / TBN, mb), 256>>>(
        x_hi, w2_hi, w2_lo, b2, vp, nullptr, nullptr, NN, HH, PHH / 2);
    cudaStreamWaitEvent(0, eS2, 0);
    loss_kernel<<<(NN * 32) / 256, 256>>>((const float4*)vp, zh, zl, loss_acc);

    // join attention, then finalize + z_out
    cudaStreamWaitEvent(0, eAtt, 0);
    float* outf = (float*)d_out;
    int write_loss = (out_size > NN * HH) ? 1 : 0;
    finalize_kernel<<<1, 1>>>(outf + (size_t)NN * HH, write_loss);
    zout_kernel<<<(NN * 64) / 256, 256>>>((float4*)outf, zh, zl);
}

// round 16
// speedup vs baseline: 1.7643x; 1.0148x over previous
#include <cuda_runtime.h>
#include <math.h>
#include <stdint.h>

// ---------------- problem constants ----------------
#define NN   50000
#define PP   3
#define EE   800000
#define FEATD 1000
#define HH   256
#define PHH  512
#define BN_EPS 1e-5f

// ---------------- device scratch (no allocations allowed) ----------------
__device__ uint32_t g_h_hi [(size_t)NN * (HH / 2)];
__device__ uint32_t g_h_lo [(size_t)NN * (HH / 2)];
__device__ float    g_ft[(size_t)3 * NN * HH];         // view-major [3][N][256]
__device__ uint32_t g_z_hi[(size_t)3 * NN * (HH / 2)];
__device__ uint32_t g_z_lo[(size_t)3 * NN * (HH / 2)];
__device__ uint32_t g_x_hi[(size_t)NN * (PHH / 2)];
__device__ uint32_t g_vp_hi[(size_t)NN * (HH / 2)];
// CSR scratch
__device__ int   g_deg[3 * NN];
__device__ int   g_rowptr[3 * (NN + 1)];
__device__ int   g_cursor[3 * NN];
__device__ int   g_esrc[(size_t)3 * EE];
__device__ float g_eval[(size_t)3 * EE];
// split weights
__device__ uint32_t g_wt_hi[HH * (FEATD / 2)];
__device__ uint32_t g_wt_lo[HH * (FEATD / 2)];
__device__ uint32_t g_wg_hi[3 * HH * (HH / 2)];
__device__ uint32_t g_wg_lo[3 * HH * (HH / 2)];
__device__ uint32_t g_w1_hi[PHH * (HH / 2)];
__device__ uint32_t g_w1_lo[PHH * (HH / 2)];
__device__ uint32_t g_w2_hi[HH * (PHH / 2)];
__device__ uint32_t g_w2_lo[HH * (PHH / 2)];
__device__ uint32_t g_wa_hi[HH * (HH / 2)];
__device__ uint32_t g_wa_lo[HH * (HH / 2)];
__device__ float g_stats[2 * PHH];
__device__ float g_beta_raw[3];
__device__ float g_beta[3];
__device__ float g_loss_acc;

// ---------------- bf16 split helpers --------------------------------------------
__device__ __forceinline__ uint32_t pack_hi(float x0, float x1)
{
    uint32_t r;
    asm("prmt.b32 %0, %1, %2, 0x7632;"
        : "=r"(r) : "r"(__float_as_uint(x0)), "r"(__float_as_uint(x1)));
    return r;
}

__device__ __forceinline__ uint32_t pack_lo(float x0, float x1)
{
    float h0 = __uint_as_float(__float_as_uint(x0) & 0xFFFF0000u);
    float h1 = __uint_as_float(__float_as_uint(x1) & 0xFFFF0000u);
    uint32_t r;
    asm("cvt.rn.bf16x2.f32 %0, %1, %2;" : "=r"(r) : "f"(x1 - h1), "f"(x0 - h0));
    return r;
}

__device__ __forceinline__ void unpack2(uint32_t hi, uint32_t lo, float& f0, float& f1)
{
    f0 = __uint_as_float(hi << 16)          + __uint_as_float(lo << 16);
    f1 = __uint_as_float(hi & 0xFFFF0000u)  + __uint_as_float(lo & 0xFFFF0000u);
}

__device__ __forceinline__ void unpack2_hi(uint32_t hi, float& f0, float& f1)
{
    f0 = __uint_as_float(hi << 16);
    f1 = __uint_as_float(hi & 0xFFFF0000u);
}

__device__ __forceinline__ void mma_bf16(float* c, const uint32_t* a, const uint32_t* b)
{
    asm volatile(
        "mma.sync.aligned.m16n8k16.row.col.f32.bf16.bf16.f32 "
        "{%0,%1,%2,%3}, {%4,%5,%6,%7}, {%8,%9}, {%0,%1,%2,%3};\n"
        : "+f"(c[0]), "+f"(c[1]), "+f"(c[2]), "+f"(c[3])
        : "r"(a[0]), "r"(a[1]), "r"(a[2]), "r"(a[3]), "r"(b[0]), "r"(b[1]));
}

__device__ __forceinline__ void ldsm_x4(uint32_t* r, uint32_t saddr)
{
    asm volatile("ldmatrix.sync.aligned.m8n8.x4.shared.b16 {%0,%1,%2,%3}, [%4];"
                 : "=r"(r[0]), "=r"(r[1]), "=r"(r[2]), "=r"(r[3]) : "r"(saddr));
}

__device__ __forceinline__ void cp16(uint32_t saddr, const void* gmem, bool pred)
{
    int sz = pred ? 16 : 0;
    asm volatile("cp.async.cg.shared.global [%0], [%1], 16, %2;\n"
                 :: "r"(saddr), "l"(gmem), "r"(sz));
}

// ---------------- generic f32 -> split-bf16 pass (weights only) -----------------
__global__ __launch_bounds__(256)
void split_kernel(const float2* __restrict__ in, uint32_t* __restrict__ hi,
                  uint32_t* __restrict__ lo, size_t npairs)
{
    size_t i = (size_t)blockIdx.x * blockDim.x + threadIdx.x;
    if (i >= npairs) return;
    float2 v = in[i];
    hi[i] = pack_hi(v.x, v.y);
    if (lo) lo[i] = pack_lo(v.x, v.y);
}

// ---------------- CSR build ------------------------------------------------------
__global__ __launch_bounds__(256)
void hist_kernel(const int* __restrict__ dst, int* __restrict__ deg)
{
    int i = blockIdx.x * 256 + threadIdx.x;
    if (i >= 3 * EE) return;
    int v = i / EE;
    atomicAdd(&deg[v * NN + dst[i]], 1);
}

__global__ __launch_bounds__(1024)
void scan_kernel(const int* __restrict__ deg, int* __restrict__ rowptr,
                 int* __restrict__ cursor)
{
    const int CH = (NN + 1023) / 1024;   // 49
    int v = blockIdx.x;
    const int* d = deg + v * NN;
    int* rp = rowptr + v * (NN + 1);
    int* cur = cursor + v * NN;
    int t = threadIdx.x;
    int lane = t & 31, w = t >> 5;
    __shared__ int warpsums[32];

    int base = t * CH;
    int local[CH];
    int sum = 0;
#pragma unroll
    for (int k = 0; k < CH; ++k) {
        int idx = base + k;
        int val = (idx < NN) ? d[idx] : 0;
        local[k] = sum;
        sum += val;
    }
    int s = sum;
#pragma unroll
    for (int o = 1; o < 32; o <<= 1) {
        int y = __shfl_up_sync(0xffffffffu, s, o);
        if (lane >= o) s += y;
    }
    if (lane == 31) warpsums[w] = s;
    __syncthreads();
    if (w == 0) {
        int ws = warpsums[lane];
#pragma unroll
        for (int o = 1; o < 32; o <<= 1) {
            int y = __shfl_up_sync(0xffffffffu, ws, o);
            if (lane >= o) ws += y;
        }
        warpsums[lane] = ws;
    }
    __syncthreads();
    int offset = (w > 0 ? warpsums[w - 1] : 0) + (s - sum);
#pragma unroll
    for (int k = 0; k < CH; ++k) {
        int idx = base + k;
        if (idx < NN) {
            int val = offset + local[k];
            rp[idx] = val;
            cur[idx] = val;
        }
    }
    if (t == 1023) rp[NN] = EE;
}

__global__ __launch_bounds__(256)
void scatter_kernel(const int* __restrict__ src, const int* __restrict__ dst,
                    const float* __restrict__ vals, int* __restrict__ cursor,
                    int* __restrict__ esrc, float* __restrict__ eval_)
{
    int i = blockIdx.x * 256 + threadIdx.x;
    if (i >= 3 * EE) return;
    int v = i / EE;
    int d = dst[i];
    int pos = atomicAdd(&cursor[v * NN + d], 1);
    esrc[(size_t)v * EE + pos] = src[i];
    eval_[(size_t)v * EE + pos] = vals[i];
}

// ---------------- CSR SpMM + bias + PReLU -> split-bf16 only (one view) ---------
__global__ __launch_bounds__(256)
void spmm_csr_kernel(const float4* __restrict__ ftv, const int* __restrict__ rp,
                     const int* __restrict__ es, const float* __restrict__ ev,
                     uint32_t* __restrict__ zhiv, uint32_t* __restrict__ zlov,
                     const float* __restrict__ bvp, const float* __restrict__ avp)
{
    int gid = blockIdx.x * 256 + threadIdx.x;
    if (gid >= NN * 64) return;
    int n = gid >> 6;
    int c = gid & 63;
    int i  = rp[n];
    int s1 = rp[n + 1];

    float4 acc = make_float4(0.f, 0.f, 0.f, 0.f);
    for (; i + 2 <= s1; i += 2) {
        int sa = es[i];     float va = ev[i];
        int sb = es[i + 1]; float vb = ev[i + 1];
        float4 fa = ftv[(size_t)sa * 64 + c];
        float4 fb = ftv[(size_t)sb * 64 + c];
        acc.x += va * fa.x; acc.y += va * fa.y; acc.z += va * fa.z; acc.w += va * fa.w;
        acc.x += vb * fb.x; acc.y += vb * fb.y; acc.z += vb * fb.z; acc.w += vb * fb.w;
    }
    if (i < s1) {
        int sa = es[i]; float va = ev[i];
        float4 fa = ftv[(size_t)sa * 64 + c];
        acc.x += va * fa.x; acc.y += va * fa.y; acc.z += va * fa.z; acc.w += va * fa.w;
    }

    float a = *avp;
    float4 bv = *(const float4*)(bvp + (c << 2));
    acc.x += bv.x; acc.y += bv.y; acc.z += bv.z; acc.w += bv.w;
    acc.x = acc.x >= 0.f ? acc.x : a * acc.x;
    acc.y = acc.y >= 0.f ? acc.y : a * acc.y;
    acc.z = acc.z >= 0.f ? acc.z : a * acc.z;
    acc.w = acc.w >= 0.f ? acc.w : a * acc.w;

    size_t p = ((size_t)n * 64 + c) << 1;
    zhiv[p]     = pack_hi(acc.x, acc.y);
    zhiv[p + 1] = pack_hi(acc.z, acc.w);
    zlov[p]     = pack_lo(acc.x, acc.y);
    zlov[p + 1] = pack_lo(acc.z, acc.w);
}

// ---------------- split-bf16 GEMM (3-term) ---------------------------------------
#define TBM 128
#define TBN 128
#define TPAD 12
#define STG_BYTES (TBM * TPAD * 4)

#define GS_DECL()                                                                   \
    __shared__ __align__(16) uint32_t AsH[2][TBM][TPAD];                            \
    __shared__ __align__(16) uint32_t AsL[2][TBM][TPAD];                            \
    __shared__ __align__(16) uint32_t WsH[2][TBN][TPAD];                            \
    __shared__ __align__(16) uint32_t WsL[2][TBN][TPAD];                            \
    const int tid  = threadIdx.x;                                                   \
    const int wid  = tid >> 5;                                                      \
    const int lane = tid & 31;                                                      \
    const int g    = lane >> 2;                                                     \
    const int t    = lane & 3;                                                      \
    const int wm   = (wid & 1) << 6;                                                \
    const int wn   = (wid >> 1) << 5;                                               \
    const int bm   = blockIdx.y * TBM;                                              \
    const int bn   = blockIdx.x * TBN;                                              \
    const uint32_t sAsH = (uint32_t)__cvta_generic_to_shared(&AsH[0][0][0]);        \
    const uint32_t sAsL = (uint32_t)__cvta_generic_to_shared(&AsL[0][0][0]);        \
    const uint32_t sWsH = (uint32_t)__cvta_generic_to_shared(&WsH[0][0][0]);        \
    const uint32_t sWsL = (uint32_t)__cvta_generic_to_shared(&WsL[0][0][0]);        \
    const uint32_t offA = (uint32_t)(((wm + (lane & 7) + ((lane >> 3) & 1) * 8)     \
                                      * TPAD + ((lane >> 4) << 2)) * 4);            \
    const uint32_t offB = (uint32_t)(((wn + ((lane >> 4) & 1) * 8 + (lane & 7))     \
                                      * TPAD + (((lane >> 3) & 1) << 2)) * 4);      \
    float acc[4][4][4] = {};

#define GS_LOAD(S, KP0)                                                             \
    {                                                                               \
        int r  = tid >> 1, ch = (tid & 1) << 2;                                     \
        int gp = (KP0) + ch;                                                        \
        bool pa = (gp < Kp) && (bm + r < M);                                        \
        size_t offa = (size_t)(bm + r) * Kp + gp;                                   \
        cp16((uint32_t)__cvta_generic_to_shared(&AsH[S][r][ch]), Ahi + offa, pa);   \
        cp16((uint32_t)__cvta_generic_to_shared(&AsL[S][r][ch]), Alo + offa, pa);   \
        bool pb = (gp < Kp);                                                        \
        size_t offb = (size_t)(bn + r) * Kp + gp;                                   \
        cp16((uint32_t)__cvta_generic_to_shared(&WsH[S][r][ch]), Whi + offb, pb);   \
        cp16((uint32_t)__cvta_generic_to_shared(&WsL[S][r][ch]), Wlo + offb, pb);   \
    }

#define GS_LOAD_AF32(S, KP0)                                                        \
    {                                                                               \
        int r  = tid >> 1, ch = (tid & 1) << 2;                                     \
        int gp = (KP0) + ch;                                                        \
        float4 f0 = make_float4(0.f, 0.f, 0.f, 0.f), f1 = f0;                       \
        if (gp < Kp && bm + r < M) {                                                \
            const float* ap = Af32 + (size_t)(bm + r) * (Kp * 2) + gp * 2;          \
            f0 = *(const float4*)ap;                                                \
            f1 = *(const float4*)(ap + 4);                                          \
        }                                                                           \
        AsH[S][r][ch + 0] = pack_hi(f0.x, f0.y); AsL[S][r][ch + 0] = pack_lo(f0.x, f0.y); \
        AsH[S][r][ch + 1] = pack_hi(f0.z, f0.w); AsL[S][r][ch + 1] = pack_lo(f0.z, f0.w); \
        AsH[S][r][ch + 2] = pack_hi(f1.x, f1.y); AsL[S][r][ch + 2] = pack_lo(f1.x, f1.y); \
        AsH[S][r][ch + 3] = pack_hi(f1.z, f1.w); AsL[S][r][ch + 3] = pack_lo(f1.z, f1.w); \
        bool pb = (gp < Kp);                                                        \
        size_t offb = (size_t)(bn + r) * Kp + gp;                                   \
        cp16((uint32_t)__cvta_generic_to_shared(&WsH[S][r][ch]), Whi + offb, pb);   \
        cp16((uint32_t)__cvta_generic_to_shared(&WsL[S][r][ch]), Wlo + offb, pb);   \
    }

#define GS_COMPUTE()                                                                \
    {                                                                               \
        uint32_t aH[4][4], aL[4][4], bH[4][2], bL[4][2];                            \
        uint32_t bs = (uint32_t)buf * STG_BYTES;                                    \
        _Pragma("unroll")                                                           \
        for (int i = 0; i < 4; ++i) {                                               \
            uint32_t ao = bs + offA + (uint32_t)(i * 16 * TPAD * 4);                \
            ldsm_x4(aH[i], sAsH + ao);                                              \
            ldsm_x4(aL[i], sAsL + ao);                                              \
        }                                                                           \
        _Pragma("unroll")                                                           \
        for (int jj = 0; jj < 2; ++jj) {                                            \
            uint32_t bo = bs + offB + (uint32_t)(jj * 16 * TPAD * 4);               \
            uint32_t tH[4], tL[4];                                                  \
            ldsm_x4(tH, sWsH + bo);                                                 \
            ldsm_x4(tL, sWsL + bo);                                                 \
            bH[2 * jj][0] = tH[0]; bH[2 * jj][1] = tH[1];                           \
            bH[2 * jj + 1][0] = tH[2]; bH[2 * jj + 1][1] = tH[3];                   \
            bL[2 * jj][0] = tL[0]; bL[2 * jj][1] = tL[1];                           \
            bL[2 * jj + 1][0] = tL[2]; bL[2 * jj + 1][1] = tL[3];                   \
        }                                                                           \
        _Pragma("unroll")                                                           \
        for (int i = 0; i < 4; ++i)                                                 \
            _Pragma("unroll")                                                       \
            for (int j = 0; j < 4; ++j) {                                           \
                mma_bf16(acc[i][j], aL[i], bH[j]);                                  \
                mma_bf16(acc[i][j], aH[i], bL[j]);                                  \
                mma_bf16(acc[i][j], aH[i], bH[j]);                                  \
            }                                                                       \
    }

#define GS_MAINLOOP(LOADM)                                                          \
    LOADM(0, 0);                                                                    \
    asm volatile("cp.async.commit_group;\n" ::: "memory");                          \
    int buf = 0;                                                                    \
    for (int kp0 = 0; kp0 < Kp; kp0 += 8) {                                         \
        if (kp0 + 8 < Kp) LOADM(buf ^ 1, kp0 + 8);                                  \
        asm volatile("cp.async.commit_group;\n" ::: "memory");                      \
        asm volatile("cp.async.wait_group 1;\n" ::: "memory");                      \
        __syncthreads();                                                            \
        GS_COMPUTE();                                                               \
        __syncthreads();                                                            \
        buf ^= 1;                                                                   \
    }

// 3-term GEMM, raw f32 row-major output (no bias). Used for GCN GEMMs.
__global__ __launch_bounds__(256, 2)
void gemm_bf16s_kernel(const uint32_t* __restrict__ Ahi, const uint32_t* __restrict__ Alo,
                       const uint32_t* __restrict__ Whi, const uint32_t* __restrict__ Wlo,
                       float* __restrict__ C, int M, int Nc, int Kp)
{
    GS_DECL();
    GS_MAINLOOP(GS_LOAD);

#pragma unroll
    for (int i = 0; i < 4; ++i) {
#pragma unroll
        for (int j = 0; j < 4; ++j) {
            int r0 = bm + wm + (i << 4) + g;
            int r1 = r0 + 8;
            int c0 = bn + wn + (j << 3) + (t << 1);
            float v0 = acc[i][j][0], v1 = acc[i][j][1];
            float v2 = acc[i][j][2], v3 = acc[i][j][3];
            if (r0 < M) *(float2*)(C + (size_t)r0 * Nc + c0) = make_float2(v0, v1);
            if (r1 < M) *(float2*)(C + (size_t)r1 * Nc + c0) = make_float2(v2, v3);
        }
    }
}

// feats GEMM: A = raw f32, epilogue bias+ELU -> split bf16 h
__global__ __launch_bounds__(256, 2)
void gemm_bf16s_af32_kernel(const float* __restrict__ Af32,
                            const uint32_t* __restrict__ Whi, const uint32_t* __restrict__ Wlo,
                            const float* __restrict__ bias,
                            uint32_t* __restrict__ Chi, uint32_t* __restrict__ Clo,
                            int M, int Nc, int Kp)
{
    GS_DECL();
    GS_MAINLOOP(GS_LOAD_AF32);

#pragma unroll
    for (int i = 0; i < 4; ++i) {
#pragma unroll
        for (int j = 0; j < 4; ++j) {
            int r0 = bm + wm + (i << 4) + g;
            int r1 = r0 + 8;
            int c0 = bn + wn + (j << 3) + (t << 1);
            float bx = bias[c0], by = bias[c0 + 1];
            float v0 = acc[i][j][0] + bx, v1 = acc[i][j][1] + by;
            float v2 = acc[i][j][2] + bx, v3 = acc[i][j][3] + by;
            v0 = v0 > 0.f ? v0 : expm1f(v0);
            v1 = v1 > 0.f ? v1 : expm1f(v1);
            v2 = v2 > 0.f ? v2 : expm1f(v2);
            v3 = v3 > 0.f ? v3 : expm1f(v3);
            int pc = c0 >> 1;
            if (r0 < M) {
                Chi[(size_t)r0 * (Nc / 2) + pc] = pack_hi(v0, v1);
                Clo[(size_t)r0 * (Nc / 2) + pc] = pack_lo(v0, v1);
            }
            if (r1 < M) {
                Chi[(size_t)r1 * (Nc / 2) + pc] = pack_hi(v2, v3);
                Clo[(size_t)r1 * (Nc / 2) + pc] = pack_lo(v2, v3);
            }
        }
    }
}

// ---------------- 2-term GEMM: A hi-only x split W ------------------------------
// EPI: 3 = bias -> hi bf16 + BN stats (x); 4 = bias -> hi bf16 only (vp).
template<int EPI>
__global__ __launch_bounds__(256, 2)
void gemm2_bf16_kernel(const uint32_t* __restrict__ Ahi,
                       const uint32_t* __restrict__ Whi, const uint32_t* __restrict__ Wlo,
                       const float* __restrict__ bias,
                       uint32_t* __restrict__ Chi, float* __restrict__ stats,
                       int M, int Nc, int Kp)
{
    __shared__ __align__(16) uint32_t AsH[2][TBM][TPAD];
    __shared__ __align__(16) uint32_t WsH[2][TBN][TPAD];
    __shared__ __align__(16) uint32_t WsL[2][TBN][TPAD];
    const int tid  = threadIdx.x;
    const int wid  = tid >> 5;
    const int lane = tid & 31;
    const int g    = lane >> 2;
    const int t    = lane & 3;
    const int wm   = (wid & 1) << 6;
    const int wn   = (wid >> 1) << 5;
    const int bm   = blockIdx.y * TBM;
    const int bn   = blockIdx.x * TBN;
    const uint32_t sAsH = (uint32_t)__cvta_generic_to_shared(&AsH[0][0][0]);
    const uint32_t sWsH = (uint32_t)__cvta_generic_to_shared(&WsH[0][0][0]);
    const uint32_t sWsL = (uint32_t)__cvta_generic_to_shared(&WsL[0][0][0]);
    const uint32_t offA = (uint32_t)(((wm + (lane & 7) + ((lane >> 3) & 1) * 8)
                                      * TPAD + ((lane >> 4) << 2)) * 4);
    const uint32_t offB = (uint32_t)(((wn + ((lane >> 4) & 1) * 8 + (lane & 7))
                                      * TPAD + (((lane >> 3) & 1) << 2)) * 4);
    float acc[4][4][4] = {};

#define G2_LOAD(S, KP0)                                                             \
    {                                                                               \
        int r  = tid >> 1, ch = (tid & 1) << 2;                                     \
        int gp = (KP0) + ch;                                                        \
        bool pa = (gp < Kp) && (bm + r < M);                                        \
        cp16((uint32_t)__cvta_generic_to_shared(&AsH[S][r][ch]),                    \
             Ahi + (size_t)(bm + r) * Kp + gp, pa);                                 \
        bool pb = (gp < Kp);                                                        \
        cp16((uint32_t)__cvta_generic_to_shared(&WsH[S][r][ch]),                    \
             Whi + (size_t)(bn + r) * Kp + gp, pb);                                 \
        cp16((uint32_t)__cvta_generic_to_shared(&WsL[S][r][ch]),                    \
             Wlo + (size_t)(bn + r) * Kp + gp, pb);                                 \
    }

    G2_LOAD(0, 0);
    asm volatile("cp.async.commit_group;\n" ::: "memory");
    int buf = 0;
    for (int kp0 = 0; kp0 < Kp; kp0 += 8) {
        if (kp0 + 8 < Kp) G2_LOAD(buf ^ 1, kp0 + 8);
        asm volatile("cp.async.commit_group;\n" ::: "memory");
        asm volatile("cp.async.wait_group 1;\n" ::: "memory");
        __syncthreads();
        uint32_t aH[4][4], bH[4][2], bL[4][2];
        uint32_t bs = (uint32_t)buf * STG_BYTES;
#pragma unroll
        for (int i = 0; i < 4; ++i)
            ldsm_x4(aH[i], sAsH + bs + offA + (uint32_t)(i * 16 * TPAD * 4));
#pragma unroll
        for (int jj = 0; jj < 2; ++jj) {
            uint32_t bo = bs + offB + (uint32_t)(jj * 16 * TPAD * 4);
            uint32_t tH[4], tL[4];
            ldsm_x4(tH, sWsH + bo);
            ldsm_x4(tL, sWsL + bo);
            bH[2 * jj][0] = tH[0]; bH[2 * jj][1] = tH[1];
            bH[2 * jj + 1][0] = tH[2]; bH[2 * jj + 1][1] = tH[3];
            bL[2 * jj][0] = tL[0]; bL[2 * jj][1] = tL[1];
            bL[2 * jj + 1][0] = tL[2]; bL[2 * jj + 1][1] = tL[3];
        }
#pragma unroll
        for (int i = 0; i < 4; ++i)
#pragma unroll
            for (int j = 0; j < 4; ++j) {
                mma_bf16(acc[i][j], aH[i], bL[j]);
                mma_bf16(acc[i][j], aH[i], bH[j]);
            }
        __syncthreads();
        buf ^= 1;
    }
#undef G2_LOAD

    float* sSum = (float*)&AsH[0][0][0];
    float* sSq  = sSum + 128;
    if (EPI == 3) {
        __syncthreads();
        if (tid < 128) { sSum[tid] = 0.f; sSq[tid] = 0.f; }
        __syncthreads();
    }

#pragma unroll
    for (int j = 0; j < 4; ++j) {
        float cs0 = 0.f, cq0 = 0.f, cs1 = 0.f, cq1 = 0.f;
#pragma unroll
        for (int i = 0; i < 4; ++i) {
            int r0 = bm + wm + (i << 4) + g;
            int r1 = r0 + 8;
            int c0 = bn + wn + (j << 3) + (t << 1);
            float bx = bias[c0], by = bias[c0 + 1];
            float v0 = acc[i][j][0] + bx, v1 = acc[i][j][1] + by;
            float v2 = acc[i][j][2] + bx, v3 = acc[i][j][3] + by;
            int pc = c0 >> 1;
            if (r0 < M) {
                Chi[(size_t)r0 * (Nc / 2) + pc] = pack_hi(v0, v1);
                if (EPI == 3) { cs0 += v0; cq0 += v0 * v0; cs1 += v1; cq1 += v1 * v1; }
            }
            if (r1 < M) {
                Chi[(size_t)r1 * (Nc / 2) + pc] = pack_hi(v2, v3);
                if (EPI == 3) { cs0 += v2; cq0 += v2 * v2; cs1 += v3; cq1 += v3 * v3; }
            }
        }
        if (EPI == 3) {
            int lc = wn + (j << 3) + (t << 1);
            atomicAdd(&sSum[lc], cs0);     atomicAdd(&sSq[lc], cq0);
            atomicAdd(&sSum[lc + 1], cs1); atomicAdd(&sSq[lc + 1], cq1);
        }
    }
    if (EPI == 3) {
        __syncthreads();
        if (tid < 128) {
            atomicAdd(&stats[bn + tid], sSum[tid]);
            atomicAdd(&stats[PHH + bn + tid], sSq[tid]);
        }
    }
}

// attention GEMM: z hi-only x split W; epilogue tanh-att reduce to beta.
// blockIdx.z = view; beta index = (view+2)%3.
__global__ __launch_bounds__(256, 2)
void gemm_att_bf16_kernel(const uint32_t* __restrict__ Zhi,
                          const uint32_t* __restrict__ Whi, const uint32_t* __restrict__ Wlo,
                          const float* __restrict__ bias, const float* __restrict__ att,
                          float* __restrict__ beta_raw, int M, int Kp)
{
    __shared__ __align__(16) uint32_t AsH[2][TBM][TPAD];
    __shared__ __align__(16) uint32_t WsH[2][TBN][TPAD];
    __shared__ __align__(16) uint32_t WsL[2][TBN][TPAD];
    const int tid  = threadIdx.x;
    const int wid  = tid >> 5;
    const int lane = tid & 31;
    const int g    = lane >> 2;
    const int t    = lane & 3;
    const int wm   = (wid & 1) << 6;
    const int wn   = (wid >> 1) << 5;
    const int bm   = blockIdx.y * TBM;
    const int bn   = blockIdx.x * TBN;
    const int view = blockIdx.z;
    const uint32_t* Ahi = Zhi + (size_t)view * NN * (HH / 2);
    const uint32_t sAsH = (uint32_t)__cvta_generic_to_shared(&AsH[0][0][0]);
    const uint32_t sWsH = (uint32_t)__cvta_generic_to_shared(&WsH[0][0][0]);
    const uint32_t sWsL = (uint32_t)__cvta_generic_to_shared(&WsL[0][0][0]);
    const uint32_t offA = (uint32_t)(((wm + (lane & 7) + ((lane >> 3) & 1) * 8)
                                      * TPAD + ((lane >> 4) << 2)) * 4);
    const uint32_t offB = (uint32_t)(((wn + ((lane >> 4) & 1) * 8 + (lane & 7))
                                      * TPAD + (((lane >> 3) & 1) << 2)) * 4);
    float acc[4][4][4] = {};

#define GA_LOAD(S, KP0)                                                             \
    {                                                                               \
        int r  = tid >> 1, ch = (tid & 1) << 2;                                     \
        int gp = (KP0) + ch;                                                        \
        bool pa = (gp < Kp) && (bm + r < M);                                        \
        cp16((uint32_t)__cvta_generic_to_shared(&AsH[S][r][ch]),                    \
             Ahi + (size_t)(bm + r) * Kp + gp, pa);                                 \
        bool pb = (gp < Kp);                                                        \
        cp16((uint32_t)__cvta_generic_to_shared(&WsH[S][r][ch]),                    \
             Whi + (size_t)(bn + r) * Kp + gp, pb);                                 \
        cp16((uint32_t)__cvta_generic_to_shared(&WsL[S][r][ch]),                    \
             Wlo + (size_t)(bn + r) * Kp + gp, pb);                                 \
    }

    GA_LOAD(0, 0);
    asm volatile("cp.async.commit_group;\n" ::: "memory");
    int buf = 0;
    for (int kp0 = 0; kp0 < Kp; kp0 += 8) {
        if (kp0 + 8 < Kp) GA_LOAD(buf ^ 1, kp0 + 8);
        asm volatile("cp.async.commit_group;\n" ::: "memory");
        asm volatile("cp.async.wait_group 1;\n" ::: "memory");
        __syncthreads();
        uint32_t aH[4][4], bH[4][2], bL[4][2];
        uint32_t bs = (uint32_t)buf * STG_BYTES;
#pragma unroll
        for (int i = 0; i < 4; ++i)
            ldsm_x4(aH[i], sAsH + bs + offA + (uint32_t)(i * 16 * TPAD * 4));
#pragma unroll
        for (int jj = 0; jj < 2; ++jj) {
            uint32_t bo = bs + offB + (uint32_t)(jj * 16 * TPAD * 4);
            uint32_t tH[4], tL[4];
            ldsm_x4(tH, sWsH + bo);
            ldsm_x4(tL, sWsL + bo);
            bH[2 * jj][0] = tH[0]; bH[2 * jj][1] = tH[1];
            bH[2 * jj + 1][0] = tH[2]; bH[2 * jj + 1][1] = tH[3];
            bL[2 * jj][0] = tL[0]; bL[2 * jj][1] = tL[1];
            bL[2 * jj + 1][0] = tL[2]; bL[2 * jj + 1][1] = tL[3];
        }
#pragma unroll
        for (int i = 0; i < 4; ++i)
#pragma unroll
            for (int j = 0; j < 4; ++j) {
                mma_bf16(acc[i][j], aH[i], bL[j]);
                mma_bf16(acc[i][j], aH[i], bH[j]);
            }
        __syncthreads();
        buf ^= 1;
    }
#undef GA_LOAD

    float s = 0.f;
#pragma unroll
    for (int i = 0; i < 4; ++i) {
#pragma unroll
        for (int j = 0; j < 4; ++j) {
            int r0 = bm + wm + (i << 4) + g;
            int r1 = r0 + 8;
            int c0 = bn + wn + (j << 3) + (t << 1);
            float bx = bias[c0], by = bias[c0 + 1];
            float ax = att[c0],  ay = att[c0 + 1];
            if (r0 < M) s += tanhf(acc[i][j][0] + bx) * ax + tanhf(acc[i][j][1] + by) * ay;
            if (r1 < M) s += tanhf(acc[i][j][2] + bx) * ax + tanhf(acc[i][j][3] + by) * ay;
        }
    }
    float* red = (float*)&AsH[0][0][0];
    __syncthreads();
    red[tid] = s;
    __syncthreads();
    for (int o = 128; o > 0; o >>= 1) {
        if (tid < o) red[tid] += red[tid + o];
        __syncthreads();
    }
    if (tid == 0) {
        int bidx = (view + 2) % 3;
        atomicAdd(&beta_raw[bidx], red[0]);
    }
}

// ---------------- BN + PReLU on hi-only bf16 x (in place) -----------------------
__global__ __launch_bounds__(256)
void bn_prelu_hi_kernel(uint32_t* __restrict__ xhi, const float* __restrict__ stats,
                        const float* __restrict__ g, const float* __restrict__ b,
                        const float* __restrict__ a_ptr)
{
    int i = blockIdx.x * blockDim.x + threadIdx.x;
    if (i >= NN * (PHH / 4)) return;
    int c = (i & (PHH / 4 - 1)) << 2;
    float a = *a_ptr;
    float4 sm = *(const float4*)(stats + c);
    float4 sq = *(const float4*)(stats + PHH + c);
    float4 gv = *(const float4*)(g + c);
    float4 bv = *(const float4*)(b + c);
    uint2 h = ((const uint2*)xhi)[i];
    float4 v;
    unpack2_hi(h.x, v.x, v.y);
    unpack2_hi(h.y, v.z, v.w);
    float invN = 1.f / (float)NN;

    float mu, var, sc, sh, y;
    mu = sm.x * invN; var = sq.x * invN - mu * mu; sc = gv.x * rsqrtf(var + BN_EPS);
    sh = bv.x - mu * sc; y = v.x * sc + sh; v.x = y >= 0.f ? y : a * y;
    mu = sm.y * invN; var = sq.y * invN - mu * mu; sc = gv.y * rsqrtf(var + BN_EPS);
    sh = bv.y - mu * sc; y = v.y * sc + sh; v.y = y >= 0.f ? y : a * y;
    mu = sm.z * invN; var = sq.z * invN - mu * mu; sc = gv.z * rsqrtf(var + BN_EPS);
    sh = bv.z - mu * sc; y = v.z * sc + sh; v.z = y >= 0.f ? y : a * y;
    mu = sm.w * invN; var = sq.w * invN - mu * mu; sc = gv.w * rsqrtf(var + BN_EPS);
    sh = bv.w - mu * sc; y = v.w * sc + sh; v.w = y >= 0.f ? y : a * y;

    uint2 nh;
    nh.x = pack_hi(v.x, v.y);
    nh.y = pack_hi(v.z, v.w);
    ((uint2*)xhi)[i] = nh;
}

// ---------------- cosine loss (hi-only bf16 inputs) ------------------------------
__global__ __launch_bounds__(256)
void loss_kernel(const uint32_t* __restrict__ vph, const uint32_t* __restrict__ zh,
                 float* __restrict__ acc)
{
    const uint32_t* t1h = zh + (size_t)NN * (HH / 2);
    const uint32_t* t2h = zh + (size_t)2 * NN * (HH / 2);
    int gid  = blockIdx.x * blockDim.x + threadIdx.x;
    int node = gid >> 5;
    int lane = gid & 31;
    float pp = 0.f, n1 = 0.f, n2 = 0.f, d1 = 0.f, d2 = 0.f;
    if (node < NN) {
        size_t baseu = (size_t)node * 128;
#pragma unroll
        for (int r = 0; r < 2; ++r) {
            int q = lane + 32 * r;
            uint2 hp = *(const uint2*)&vph[baseu + 2 * q];
            uint2 h1 = *(const uint2*)&t1h[baseu + 2 * q];
            uint2 h2 = *(const uint2*)&t2h[baseu + 2 * q];
            float4 a, b, cc;
            unpack2_hi(hp.x, a.x, a.y);  unpack2_hi(hp.y, a.z, a.w);
            unpack2_hi(h1.x, b.x, b.y);  unpack2_hi(h1.y, b.z, b.w);
            unpack2_hi(h2.x, cc.x, cc.y); unpack2_hi(h2.y, cc.z, cc.w);
            pp += a.x * a.x + a.y * a.y + a.z * a.z + a.w * a.w;
            n1 += b.x * b.x + b.y * b.y + b.z * b.z + b.w * b.w;
            n2 += cc.x * cc.x + cc.y * cc.y + cc.z * cc.z + cc.w * cc.w;
            d1 += a.x * b.x + a.y * b.y + a.z * b.z + a.w * b.w;
            d2 += a.x * cc.x + a.y * cc.y + a.z * cc.z + a.w * cc.w;
        }
    }
#pragma unroll
    for (int o = 16; o > 0; o >>= 1) {
        pp += __shfl_down_sync(0xffffffffu, pp, o);
        n1 += __shfl_down_sync(0xffffffffu, n1, o);
        n2 += __shfl_down_sync(0xffffffffu, n2, o);
        d1 += __shfl_down_sync(0xffffffffu, d1, o);
        d2 += __shfl_down_sync(0xffffffffu, d2, o);
    }
    __shared__ float sacc[8];
    float contrib = 0.f;
    if (lane == 0 && node < NN) {
        float np  = fmaxf(sqrtf(pp), 1e-12f);
        float nn1 = fmaxf(sqrtf(n1), 1e-12f);
        float nn2 = fmaxf(sqrtf(n2), 1e-12f);
        contrib = d1 / (np * nn1) + d2 / (np * nn2);
    }
    int wid = threadIdx.x >> 5;
    if (lane == 0) sacc[wid] = contrib;
    __syncthreads();
    if (threadIdx.x == 0) {
        float s = 0.f;
#pragma unroll
        for (int i = 0; i < 8; ++i) s += sacc[i];
        atomicAdd(acc, s);
    }
}

// ---------------- finalize beta only (softmax) -----------------------------------
__global__ void finalize_beta_kernel()
{
    float invN = 1.f / (float)NN;
    float b0 = g_beta_raw[0] * invN;
    float b1 = g_beta_raw[1] * invN;
    float b2 = g_beta_raw[2] * invN;
    float m = fmaxf(b0, fmaxf(b1, b2));
    float e0 = expf(b0 - m), e1 = expf(b1 - m), e2 = expf(b2 - m);
    float s = e0 + e1 + e2;
    g_beta[0] = e0 / s;
    g_beta[1] = e1 / s;
    g_beta[2] = e2 / s;
}

// ---------------- write loss scalar ----------------------------------------------
__global__ void write_loss_kernel(float* __restrict__ out_loss, int write_loss)
{
    if (write_loss) *out_loss = 2.0f - g_loss_acc / (float)NN;
}

// ---------------- z_out = b0*z1 + b1*z2 + b2*z0 (from split-bf16) ----------------
__global__ __launch_bounds__(256)
void zout_kernel(float4* __restrict__ out, const uint32_t* __restrict__ zh,
                 const uint32_t* __restrict__ zl)
{
    int i = blockIdx.x * blockDim.x + threadIdx.x;
    if (i >= NN * 64) return;
    float b2 = g_beta[2], b0 = g_beta[0], b1 = g_beta[1];
    const size_t vstride = (size_t)NN * (HH / 2);
    size_t u = (size_t)i * 2;
    uint2 h0 = *(const uint2*)&zh[u];
    uint2 l0 = *(const uint2*)&zl[u];
    uint2 h1 = *(const uint2*)&zh[vstride + u];
    uint2 l1 = *(const uint2*)&zl[vstride + u];
    uint2 h2 = *(const uint2*)&zh[2 * vstride + u];
    uint2 l2 = *(const uint2*)&zl[2 * vstride + u];
    float4 a, b, c;
    unpack2(h0.x, l0.x, c.x, c.y); unpack2(h0.y, l0.y, c.z, c.w);
    unpack2(h1.x, l1.x, a.x, a.y); unpack2(h1.y, l1.y, a.z, a.w);
    unpack2(h2.x, l2.x, b.x, b.y); unpack2(h2.y, l2.y, b.z, b.w);
    float4 r;
    r.x = b0 * a.x + b1 * b.x + b2 * c.x;
    r.y = b0 * a.y + b1 * b.y + b2 * c.y;
    r.z = b0 * a.z + b1 * b.z + b2 * c.z;
    r.w = b0 * a.w + b1 * b.w + b2 * c.w;
    out[i] = r;
}

// ---------------- host ----------------------------------------------------------
#define GETSYM(var, sym) cudaGetSymbolAddress((void**)&var, sym)

extern "C" void kernel_launch(void* const* d_in, const int* in_sizes, int n_in,
                              void* d_out, int out_size)
{
    const float* feats   = (const float*)d_in[0];
    const int*   src     = (const int*)  d_in[1];
    const int*   dst     = (const int*)  d_in[2];
    const float* vals    = (const float*)d_in[3];
    const float* W_trans = (const float*)d_in[4];
    const float* b_trans = (const float*)d_in[5];
    const float* W_gcn   = (const float*)d_in[6];
    const float* b_gcn   = (const float*)d_in[7];
    const float* a_gcn   = (const float*)d_in[8];
    const float* W1      = (const float*)d_in[9];
    const float* b1      = (const float*)d_in[10];
    const float* bn_g    = (const float*)d_in[11];
    const float* bn_b    = (const float*)d_in[12];
    const float* a_pred  = (const float*)d_in[13];
    const float* W2      = (const float*)d_in[14];
    const float* b2      = (const float*)d_in[15];
    const float* W_att   = (const float*)d_in[16];
    const float* b_att   = (const float*)d_in[17];
    const float* att     = (const float*)d_in[18];

    uint32_t *h_hi, *h_lo, *zh, *zl;
    uint32_t *x_hi, *vp_hi, *wt_hi, *wt_lo, *wg_hi, *wg_lo, *w1_hi, *w1_lo;
    uint32_t *w2_hi, *w2_lo, *wa_hi, *wa_lo;
    float *ft, *stats, *beta_raw, *loss_acc;
    int *deg, *rowptr, *cursor, *esrc;
    float *eval_;
    GETSYM(h_hi, g_h_hi);   GETSYM(h_lo, g_h_lo);
    GETSYM(zh, g_z_hi); GETSYM(zl, g_z_lo);
    GETSYM(x_hi, g_x_hi); GETSYM(vp_hi, g_vp_hi);
    GETSYM(wt_hi, g_wt_hi); GETSYM(wt_lo, g_wt_lo);
    GETSYM(wg_hi, g_wg_hi); GETSYM(wg_lo, g_wg_lo);
    GETSYM(w1_hi, g_w1_hi); GETSYM(w1_lo, g_w1_lo);
    GETSYM(w2_hi, g_w2_hi); GETSYM(w2_lo, g_w2_lo);
    GETSYM(wa_hi, g_wa_hi); GETSYM(wa_lo, g_wa_lo);
    GETSYM(ft, g_ft);
    GETSYM(stats, g_stats); GETSYM(beta_raw, g_beta_raw); GETSYM(loss_acc, g_loss_acc);
    GETSYM(deg, g_deg); GETSYM(rowptr, g_rowptr); GETSYM(cursor, g_cursor);
    GETSYM(esrc, g_esrc); GETSYM(eval_, g_eval);

    cudaStream_t s2;
    cudaStreamCreateWithFlags(&s2, cudaStreamNonBlocking);
    cudaEvent_t eFork, eSplit, eG[3], eS0, eVp, eAtt, eLoss;
    cudaEventCreateWithFlags(&eFork,  cudaEventDisableTiming);
    cudaEventCreateWithFlags(&eSplit, cudaEventDisableTiming);
    for (int v = 0; v < 3; ++v) cudaEventCreateWithFlags(&eG[v], cudaEventDisableTiming);
    cudaEventCreateWithFlags(&eS0,   cudaEventDisableTiming);
    cudaEventCreateWithFlags(&eVp,   cudaEventDisableTiming);
    cudaEventCreateWithFlags(&eAtt,  cudaEventDisableTiming);
    cudaEventCreateWithFlags(&eLoss, cudaEventDisableTiming);

    cudaMemsetAsync(deg, 0, 3 * NN * sizeof(int));
    cudaMemsetAsync(stats, 0, 2 * PHH * sizeof(float));
    cudaMemsetAsync(beta_raw, 0, 3 * sizeof(float));
    cudaMemsetAsync(loss_acc, 0, sizeof(float));

    // fork: CSR build on s2, concurrent with splits + feats GEMM
    cudaEventRecord(eFork, 0);
    cudaStreamWaitEvent(s2, eFork, 0);
    hist_kernel<<<(3 * EE + 255) / 256, 256, 0, s2>>>(dst, deg);
    scan_kernel<<<3, 1024, 0, s2>>>(deg, rowptr, cursor);
    scatter_kernel<<<(3 * EE + 255) / 256, 256, 0, s2>>>(src, dst, vals, cursor,
                                                         esrc, eval_);

    // main: weight splits
    {
        size_t np = (size_t)HH * (FEATD / 2);
        split_kernel<<<(int)((np + 255) / 256), 256>>>((const float2*)W_trans, wt_hi, wt_lo, np);
        np = (size_t)3 * HH * (HH / 2);
        split_kernel<<<(int)((np + 255) / 256), 256>>>((const float2*)W_gcn, wg_hi, wg_lo, np);
        np = (size_t)PHH * (HH / 2);
        split_kernel<<<(int)((np + 255) / 256), 256>>>((const float2*)W1, w1_hi, w1_lo, np);
        np = (size_t)HH * (PHH / 2);
        split_kernel<<<(int)((np + 255) / 256), 256>>>((const float2*)W2, w2_hi, w2_lo, np);
        np = (size_t)HH * (HH / 2);
        split_kernel<<<(int)((np + 255) / 256), 256>>>((const float2*)W_att, wa_hi, wa_lo, np);
    }
    cudaEventRecord(eSplit, 0);

    const int mb = (NN + TBM - 1) / TBM;   // 391

    // main: h = elu(feats @ W_trans^T + b_trans)
    gemm_bf16s_af32_kernel<<<dim3(HH / TBN, mb), 256>>>(
        feats, wt_hi, wt_lo, b_trans, h_hi, h_lo, NN, HH, FEATD / 2);

    // main: per-view GCN GEMMs
    for (int v = 0; v < PP; ++v) {
        gemm_bf16s_kernel<<<dim3(HH / TBN, mb), 256>>>(
            h_hi, h_lo,
            wg_hi + (size_t)v * HH * (HH / 2), wg_lo + (size_t)v * HH * (HH / 2),
            ft + (size_t)v * NN * HH, NN, HH, HH / 2);
        cudaEventRecord(eG[v], 0);
    }

    // s2: SpMM(v) as soon as GEMM(v) done
    for (int v = 0; v < PP; ++v) {
        cudaStreamWaitEvent(s2, eG[v], 0);
        spmm_csr_kernel<<<(NN * 64 + 255) / 256, 256, 0, s2>>>(
            (const float4*)(ft + (size_t)v * NN * HH),
            rowptr + v * (NN + 1),
            esrc + (size_t)v * EE, eval_ + (size_t)v * EE,
            zh + (size_t)v * NN * (HH / 2), zl + (size_t)v * NN * (HH / 2),
            b_gcn + (size_t)v * HH, a_gcn + v);
        if (v == 0) cudaEventRecord(eS0, s2);
    }

    // s2: attention GEMM after all z ready
    cudaStreamWaitEvent(s2, eSplit, 0);
    gemm_att_bf16_kernel<<<dim3(HH / TBN, mb, 3), 256, 0, s2>>>(
        zh, wa_hi, wa_lo, b_att, att, beta_raw, NN, HH / 2);
    cudaEventRecord(eAtt, s2);

    // main: predictor chain (2-term, loss-only precision)
    cudaStreamWaitEvent(0, eS0, 0);
    gemm2_bf16_kernel<3><<<dim3(PHH / TBN, mb), 256>>>(
        zh, w1_hi, w1_lo, b1, x_hi, stats, NN, PHH, HH / 2);
    bn_prelu_hi_kernel<<<(NN * PHH / 4) / 256, 256>>>(x_hi, stats, bn_g, bn_b, a_pred);
    gemm2_bf16_kernel<4><<<dim3(HH / TBN, mb), 256>>>(
        x_hi, w2_hi, w2_lo, b2, vp_hi, nullptr, NN, HH, PHH / 2);
    cudaEventRecord(eVp, 0);

    float* outf = (float*)d_out;
    int write_loss = (out_size > NN * HH) ? 1 : 0;

    // s2: loss chain (off the output critical path); z1/z2 already on s2 order
    cudaStreamWaitEvent(s2, eVp, 0);
    loss_kernel<<<(NN * 32) / 256, 256, 0, s2>>>(vp_hi, zh, loss_acc);
    write_loss_kernel<<<1, 1, 0, s2>>>(outf + (size_t)NN * HH, write_loss);
    cudaEventRecord(eLoss, s2);

    // main: beta softmax (needs att only) then z_out; join loss at the end
    cudaStreamWaitEvent(0, eAtt, 0);
    finalize_beta_kernel<<<1, 1>>>();
    zout_kernel<<<(NN * 64) / 256, 256>>>((float4*)outf, zh, zl);
    cudaStreamWaitEvent(0, eLoss, 0);
}

// round 17
// speedup vs baseline: 1.7806x; 1.0093x over previous
#include <cuda_runtime.h>
#include <math.h>
#include <stdint.h>

// ---------------- problem constants ----------------
#define NN   50000
#define PP   3
#define EE   800000
#define FEATD 1000
#define HH   256
#define PHH  512
#define BN_EPS 1e-5f

// ---------------- device scratch (no allocations allowed) ----------------
__device__ uint32_t g_h_hi [(size_t)NN * (HH / 2)];
__device__ uint32_t g_h_lo [(size_t)NN * (HH / 2)];
__device__ float    g_ft[(size_t)3 * NN * HH];         // view-major [3][N][256]
__device__ uint32_t g_z_hi[(size_t)3 * NN * (HH / 2)];
__device__ uint32_t g_z_lo[(size_t)3 * NN * (HH / 2)];
__device__ uint32_t g_x_hi[(size_t)NN * (PHH / 2)];
__device__ uint32_t g_vp_hi[(size_t)NN * (HH / 2)];
// CSR scratch
__device__ int   g_deg[3 * NN];
__device__ int   g_rowptr[3 * (NN + 1)];
__device__ int   g_cursor[3 * NN];
__device__ int   g_esrc[(size_t)3 * EE];
__device__ float g_eval[(size_t)3 * EE];
// split weights
__device__ uint32_t g_wt_hi[HH * (FEATD / 2)];
__device__ uint32_t g_wt_lo[HH * (FEATD / 2)];
__device__ uint32_t g_wg_hi[3 * HH * (HH / 2)];
__device__ uint32_t g_wg_lo[3 * HH * (HH / 2)];
__device__ uint32_t g_w1_hi[PHH * (HH / 2)];
__device__ uint32_t g_w1_lo[PHH * (HH / 2)];
__device__ uint32_t g_w2_hi[HH * (PHH / 2)];
__device__ uint32_t g_w2_lo[HH * (PHH / 2)];
__device__ uint32_t g_wa_hi[HH * (HH / 2)];
__device__ uint32_t g_wa_lo[HH * (HH / 2)];
__device__ float g_stats[2 * PHH];
__device__ float g_beta_raw[3];
__device__ float g_beta[3];
__device__ float g_loss_acc;

// ---------------- bf16 split helpers --------------------------------------------
__device__ __forceinline__ uint32_t pack_hi(float x0, float x1)
{
    uint32_t r;
    asm("prmt.b32 %0, %1, %2, 0x7632;"
        : "=r"(r) : "r"(__float_as_uint(x0)), "r"(__float_as_uint(x1)));
    return r;
}

__device__ __forceinline__ uint32_t pack_lo(float x0, float x1)
{
    float h0 = __uint_as_float(__float_as_uint(x0) & 0xFFFF0000u);
    float h1 = __uint_as_float(__float_as_uint(x1) & 0xFFFF0000u);
    uint32_t r;
    asm("cvt.rn.bf16x2.f32 %0, %1, %2;" : "=r"(r) : "f"(x1 - h1), "f"(x0 - h0));
    return r;
}

__device__ __forceinline__ void unpack2(uint32_t hi, uint32_t lo, float& f0, float& f1)
{
    f0 = __uint_as_float(hi << 16)          + __uint_as_float(lo << 16);
    f1 = __uint_as_float(hi & 0xFFFF0000u)  + __uint_as_float(lo & 0xFFFF0000u);
}

__device__ __forceinline__ void unpack2_hi(uint32_t hi, float& f0, float& f1)
{
    f0 = __uint_as_float(hi << 16);
    f1 = __uint_as_float(hi & 0xFFFF0000u);
}

__device__ __forceinline__ void mma_bf16(float* c, const uint32_t* a, const uint32_t* b)
{
    asm volatile(
        "mma.sync.aligned.m16n8k16.row.col.f32.bf16.bf16.f32 "
        "{%0,%1,%2,%3}, {%4,%5,%6,%7}, {%8,%9}, {%0,%1,%2,%3};\n"
        : "+f"(c[0]), "+f"(c[1]), "+f"(c[2]), "+f"(c[3])
        : "r"(a[0]), "r"(a[1]), "r"(a[2]), "r"(a[3]), "r"(b[0]), "r"(b[1]));
}

__device__ __forceinline__ void ldsm_x4(uint32_t* r, uint32_t saddr)
{
    asm volatile("ldmatrix.sync.aligned.m8n8.x4.shared.b16 {%0,%1,%2,%3}, [%4];"
                 : "=r"(r[0]), "=r"(r[1]), "=r"(r[2]), "=r"(r[3]) : "r"(saddr));
}

__device__ __forceinline__ void cp16(uint32_t saddr, const void* gmem, bool pred)
{
    int sz = pred ? 16 : 0;
    asm volatile("cp.async.cg.shared.global [%0], [%1], 16, %2;\n"
                 :: "r"(saddr), "l"(gmem), "r"(sz));
}

// ---------------- generic f32 -> split-bf16 pass (weights only) -----------------
__global__ __launch_bounds__(256)
void split_kernel(const float2* __restrict__ in, uint32_t* __restrict__ hi,
                  uint32_t* __restrict__ lo, size_t npairs)
{
    size_t i = (size_t)blockIdx.x * blockDim.x + threadIdx.x;
    if (i >= npairs) return;
    float2 v = in[i];
    hi[i] = pack_hi(v.x, v.y);
    if (lo) lo[i] = pack_lo(v.x, v.y);
}

// ---------------- CSR build ------------------------------------------------------
__global__ __launch_bounds__(256)
void hist_kernel(const int* __restrict__ dst, int* __restrict__ deg)
{
    int i = blockIdx.x * 256 + threadIdx.x;
    if (i >= 3 * EE) return;
    int v = i / EE;
    atomicAdd(&deg[v * NN + dst[i]], 1);
}

__global__ __launch_bounds__(1024)
void scan_kernel(const int* __restrict__ deg, int* __restrict__ rowptr,
                 int* __restrict__ cursor)
{
    const int CH = (NN + 1023) / 1024;   // 49
    int v = blockIdx.x;
    const int* d = deg + v * NN;
    int* rp = rowptr + v * (NN + 1);
    int* cur = cursor + v * NN;
    int t = threadIdx.x;
    int lane = t & 31, w = t >> 5;
    __shared__ int warpsums[32];

    int base = t * CH;
    int local[CH];
    int sum = 0;
#pragma unroll
    for (int k = 0; k < CH; ++k) {
        int idx = base + k;
        int val = (idx < NN) ? d[idx] : 0;
        local[k] = sum;
        sum += val;
    }
    int s = sum;
#pragma unroll
    for (int o = 1; o < 32; o <<= 1) {
        int y = __shfl_up_sync(0xffffffffu, s, o);
        if (lane >= o) s += y;
    }
    if (lane == 31) warpsums[w] = s;
    __syncthreads();
    if (w == 0) {
        int ws = warpsums[lane];
#pragma unroll
        for (int o = 1; o < 32; o <<= 1) {
            int y = __shfl_up_sync(0xffffffffu, ws, o);
            if (lane >= o) ws += y;
        }
        warpsums[lane] = ws;
    }
    __syncthreads();
    int offset = (w > 0 ? warpsums[w - 1] : 0) + (s - sum);
#pragma unroll
    for (int k = 0; k < CH; ++k) {
        int idx = base + k;
        if (idx < NN) {
            int val = offset + local[k];
            rp[idx] = val;
            cur[idx] = val;
        }
    }
    if (t == 1023) rp[NN] = EE;
}

__global__ __launch_bounds__(256)
void scatter_kernel(const int* __restrict__ src, const int* __restrict__ dst,
                    const float* __restrict__ vals, int* __restrict__ cursor,
                    int* __restrict__ esrc, float* __restrict__ eval_)
{
    int i = blockIdx.x * 256 + threadIdx.x;
    if (i >= 3 * EE) return;
    int v = i / EE;
    int d = dst[i];
    int pos = atomicAdd(&cursor[v * NN + d], 1);
    esrc[(size_t)v * EE + pos] = src[i];
    eval_[(size_t)v * EE + pos] = vals[i];
}

// ---------------- CSR SpMM + bias + PReLU -> split-bf16 only (one view) ---------
__global__ __launch_bounds__(256)
void spmm_csr_kernel(const float4* __restrict__ ftv, const int* __restrict__ rp,
                     const int* __restrict__ es, const float* __restrict__ ev,
                     uint32_t* __restrict__ zhiv, uint32_t* __restrict__ zlov,
                     const float* __restrict__ bvp, const float* __restrict__ avp)
{
    int gid = blockIdx.x * 256 + threadIdx.x;
    if (gid >= NN * 64) return;
    int n = gid >> 6;
    int c = gid & 63;
    int i  = rp[n];
    int s1 = rp[n + 1];

    float4 acc = make_float4(0.f, 0.f, 0.f, 0.f);
    for (; i + 2 <= s1; i += 2) {
        int sa = es[i];     float va = ev[i];
        int sb = es[i + 1]; float vb = ev[i + 1];
        float4 fa = ftv[(size_t)sa * 64 + c];
        float4 fb = ftv[(size_t)sb * 64 + c];
        acc.x += va * fa.x; acc.y += va * fa.y; acc.z += va * fa.z; acc.w += va * fa.w;
        acc.x += vb * fb.x; acc.y += vb * fb.y; acc.z += vb * fb.z; acc.w += vb * fb.w;
    }
    if (i < s1) {
        int sa = es[i]; float va = ev[i];
        float4 fa = ftv[(size_t)sa * 64 + c];
        acc.x += va * fa.x; acc.y += va * fa.y; acc.z += va * fa.z; acc.w += va * fa.w;
    }

    float a = *avp;
    float4 bv = *(const float4*)(bvp + (c << 2));
    acc.x += bv.x; acc.y += bv.y; acc.z += bv.z; acc.w += bv.w;
    acc.x = acc.x >= 0.f ? acc.x : a * acc.x;
    acc.y = acc.y >= 0.f ? acc.y : a * acc.y;
    acc.z = acc.z >= 0.f ? acc.z : a * acc.z;
    acc.w = acc.w >= 0.f ? acc.w : a * acc.w;

    size_t p = ((size_t)n * 64 + c) << 1;
    zhiv[p]     = pack_hi(acc.x, acc.y);
    zhiv[p + 1] = pack_hi(acc.z, acc.w);
    zlov[p]     = pack_lo(acc.x, acc.y);
    zlov[p + 1] = pack_lo(acc.z, acc.w);
}

// ---------------- split-bf16 GEMM (3-term) ---------------------------------------
// Block tile 128x128, BK=16 elems (8 u32), 8 warps (2m x 4n), warp tile 64x32.
// Register-lean compute: B fragments hoisted per chunk, A fragments loaded per-i
// (peak live ~110 regs -> no spills under launch_bounds(256,2)).
#define TBM 128
#define TBN 128
#define TPAD 12
#define STG_BYTES (TBM * TPAD * 4)

#define GS_DECL()                                                                   \
    __shared__ __align__(16) uint32_t AsH[2][TBM][TPAD];                            \
    __shared__ __align__(16) uint32_t AsL[2][TBM][TPAD];                            \
    __shared__ __align__(16) uint32_t WsH[2][TBN][TPAD];                            \
    __shared__ __align__(16) uint32_t WsL[2][TBN][TPAD];                            \
    const int tid  = threadIdx.x;                                                   \
    const int wid  = tid >> 5;                                                      \
    const int lane = tid & 31;                                                      \
    const int g    = lane >> 2;                                                     \
    const int t    = lane & 3;                                                      \
    const int wm   = (wid & 1) << 6;                                                \
    const int wn   = (wid >> 1) << 5;                                               \
    const int bm   = blockIdx.y * TBM;                                              \
    const int bn   = blockIdx.x * TBN;                                              \
    const uint32_t sAsH = (uint32_t)__cvta_generic_to_shared(&AsH[0][0][0]);        \
    const uint32_t sAsL = (uint32_t)__cvta_generic_to_shared(&AsL[0][0][0]);        \
    const uint32_t sWsH = (uint32_t)__cvta_generic_to_shared(&WsH[0][0][0]);        \
    const uint32_t sWsL = (uint32_t)__cvta_generic_to_shared(&WsL[0][0][0]);        \
    const uint32_t offA = (uint32_t)(((wm + (lane & 7) + ((lane >> 3) & 1) * 8)     \
                                      * TPAD + ((lane >> 4) << 2)) * 4);            \
    const uint32_t offB = (uint32_t)(((wn + ((lane >> 4) & 1) * 8 + (lane & 7))     \
                                      * TPAD + (((lane >> 3) & 1) << 2)) * 4);      \
    float acc[4][4][4] = {};

#define GS_LOAD(S, KP0)                                                             \
    {                                                                               \
        int r  = tid >> 1, ch = (tid & 1) << 2;                                     \
        int gp = (KP0) + ch;                                                        \
        bool pa = (gp < Kp) && (bm + r < M);                                        \
        size_t offa = (size_t)(bm + r) * Kp + gp;                                   \
        cp16((uint32_t)__cvta_generic_to_shared(&AsH[S][r][ch]), Ahi + offa, pa);   \
        cp16((uint32_t)__cvta_generic_to_shared(&AsL[S][r][ch]), Alo + offa, pa);   \
        bool pb = (gp < Kp);                                                        \
        size_t offb = (size_t)(bn + r) * Kp + gp;                                   \
        cp16((uint32_t)__cvta_generic_to_shared(&WsH[S][r][ch]), Whi + offb, pb);   \
        cp16((uint32_t)__cvta_generic_to_shared(&WsL[S][r][ch]), Wlo + offb, pb);   \
    }

#define GS_LOAD_AF32(S, KP0)                                                        \
    {                                                                               \
        int r  = tid >> 1, ch = (tid & 1) << 2;                                     \
        int gp = (KP0) + ch;                                                        \
        float4 f0 = make_float4(0.f, 0.f, 0.f, 0.f), f1 = f0;                       \
        if (gp < Kp && bm + r < M) {                                                \
            const float* ap = Af32 + (size_t)(bm + r) * (Kp * 2) + gp * 2;          \
            f0 = *(const float4*)ap;                                                \
            f1 = *(const float4*)(ap + 4);                                          \
        }                                                                           \
        AsH[S][r][ch + 0] = pack_hi(f0.x, f0.y); AsL[S][r][ch + 0] = pack_lo(f0.x, f0.y); \
        AsH[S][r][ch + 1] = pack_hi(f0.z, f0.w); AsL[S][r][ch + 1] = pack_lo(f0.z, f0.w); \
        AsH[S][r][ch + 2] = pack_hi(f1.x, f1.y); AsL[S][r][ch + 2] = pack_lo(f1.x, f1.y); \
        AsH[S][r][ch + 3] = pack_hi(f1.z, f1.w); AsL[S][r][ch + 3] = pack_lo(f1.z, f1.w); \
        bool pb = (gp < Kp);                                                        \
        size_t offb = (size_t)(bn + r) * Kp + gp;                                   \
        cp16((uint32_t)__cvta_generic_to_shared(&WsH[S][r][ch]), Whi + offb, pb);   \
        cp16((uint32_t)__cvta_generic_to_shared(&WsL[S][r][ch]), Wlo + offb, pb);   \
    }

// register-lean: B hoisted, A per-i (same FP order: per (i,j) -> L*H, H*L, H*H)
#define GS_COMPUTE()                                                                \
    {                                                                               \
        uint32_t bH[4][2], bL[4][2];                                                \
        uint32_t bs = (uint32_t)buf * STG_BYTES;                                    \
        _Pragma("unroll")                                                           \
        for (int jj = 0; jj < 2; ++jj) {                                            \
            uint32_t bo = bs + offB + (uint32_t)(jj * 16 * TPAD * 4);               \
            uint32_t tH[4], tL[4];                                                  \
            ldsm_x4(tH, sWsH + bo);                                                 \
            ldsm_x4(tL, sWsL + bo);                                                 \
            bH[2 * jj][0] = tH[0]; bH[2 * jj][1] = tH[1];                           \
            bH[2 * jj + 1][0] = tH[2]; bH[2 * jj + 1][1] = tH[3];                   \
            bL[2 * jj][0] = tL[0]; bL[2 * jj][1] = tL[1];                           \
            bL[2 * jj + 1][0] = tL[2]; bL[2 * jj + 1][1] = tL[3];                   \
        }                                                                           \
        _Pragma("unroll")                                                           \
        for (int i = 0; i < 4; ++i) {                                               \
            uint32_t aH[4], aL[4];                                                  \
            uint32_t ao = bs + offA + (uint32_t)(i * 16 * TPAD * 4);                \
            ldsm_x4(aH, sAsH + ao);                                                 \
            ldsm_x4(aL, sAsL + ao);                                                 \
            _Pragma("unroll")                                                       \
            for (int j = 0; j < 4; ++j) {                                           \
                mma_bf16(acc[i][j], aL, bH[j]);                                     \
                mma_bf16(acc[i][j], aH, bL[j]);                                     \
                mma_bf16(acc[i][j], aH, bH[j]);                                     \
            }                                                                       \
        }                                                                           \
    }

#define GS_MAINLOOP(LOADM)                                                          \
    LOADM(0, 0);                                                                    \
    asm volatile("cp.async.commit_group;\n" ::: "memory");                          \
    int buf = 0;                                                                    \
    for (int kp0 = 0; kp0 < Kp; kp0 += 8) {                                         \
        if (kp0 + 8 < Kp) LOADM(buf ^ 1, kp0 + 8);                                  \
        asm volatile("cp.async.commit_group;\n" ::: "memory");                      \
        asm volatile("cp.async.wait_group 1;\n" ::: "memory");                      \
        __syncthreads();                                                            \
        GS_COMPUTE();                                                               \
        __syncthreads();                                                            \
        buf ^= 1;                                                                   \
    }

// 3-term GEMM, raw f32 row-major output (no bias). Used for GCN GEMMs.
__global__ __launch_bounds__(256, 2)
void gemm_bf16s_kernel(const uint32_t* __restrict__ Ahi, const uint32_t* __restrict__ Alo,
                       const uint32_t* __restrict__ Whi, const uint32_t* __restrict__ Wlo,
                       float* __restrict__ C, int M, int Nc, int Kp)
{
    GS_DECL();
    GS_MAINLOOP(GS_LOAD);

#pragma unroll
    for (int i = 0; i < 4; ++i) {
#pragma unroll
        for (int j = 0; j < 4; ++j) {
            int r0 = bm + wm + (i << 4) + g;
            int r1 = r0 + 8;
            int c0 = bn + wn + (j << 3) + (t << 1);
            float v0 = acc[i][j][0], v1 = acc[i][j][1];
            float v2 = acc[i][j][2], v3 = acc[i][j][3];
            if (r0 < M) *(float2*)(C + (size_t)r0 * Nc + c0) = make_float2(v0, v1);
            if (r1 < M) *(float2*)(C + (size_t)r1 * Nc + c0) = make_float2(v2, v3);
        }
    }
}

// feats GEMM: A = raw f32, epilogue bias+ELU -> split bf16 h
__global__ __launch_bounds__(256, 2)
void gemm_bf16s_af32_kernel(const float* __restrict__ Af32,
                            const uint32_t* __restrict__ Whi, const uint32_t* __restrict__ Wlo,
                            const float* __restrict__ bias,
                            uint32_t* __restrict__ Chi, uint32_t* __restrict__ Clo,
                            int M, int Nc, int Kp)
{
    GS_DECL();
    GS_MAINLOOP(GS_LOAD_AF32);

#pragma unroll
    for (int i = 0; i < 4; ++i) {
#pragma unroll
        for (int j = 0; j < 4; ++j) {
            int r0 = bm + wm + (i << 4) + g;
            int r1 = r0 + 8;
            int c0 = bn + wn + (j << 3) + (t << 1);
            float bx = bias[c0], by = bias[c0 + 1];
            float v0 = acc[i][j][0] + bx, v1 = acc[i][j][1] + by;
            float v2 = acc[i][j][2] + bx, v3 = acc[i][j][3] + by;
            v0 = v0 > 0.f ? v0 : expm1f(v0);
            v1 = v1 > 0.f ? v1 : expm1f(v1);
            v2 = v2 > 0.f ? v2 : expm1f(v2);
            v3 = v3 > 0.f ? v3 : expm1f(v3);
            int pc = c0 >> 1;
            if (r0 < M) {
                Chi[(size_t)r0 * (Nc / 2) + pc] = pack_hi(v0, v1);
                Clo[(size_t)r0 * (Nc / 2) + pc] = pack_lo(v0, v1);
            }
            if (r1 < M) {
                Chi[(size_t)r1 * (Nc / 2) + pc] = pack_hi(v2, v3);
                Clo[(size_t)r1 * (Nc / 2) + pc] = pack_lo(v2, v3);
            }
        }
    }
}

// ---------------- 2-term GEMM: A hi-only x split W ------------------------------
// EPI: 3 = bias -> hi bf16 + BN stats (x); 4 = bias -> hi bf16 only (vp).
template<int EPI>
__global__ __launch_bounds__(256, 2)
void gemm2_bf16_kernel(const uint32_t* __restrict__ Ahi,
                       const uint32_t* __restrict__ Whi, const uint32_t* __restrict__ Wlo,
                       const float* __restrict__ bias,
                       uint32_t* __restrict__ Chi, float* __restrict__ stats,
                       int M, int Nc, int Kp)
{
    __shared__ __align__(16) uint32_t AsH[2][TBM][TPAD];
    __shared__ __align__(16) uint32_t WsH[2][TBN][TPAD];
    __shared__ __align__(16) uint32_t WsL[2][TBN][TPAD];
    const int tid  = threadIdx.x;
    const int wid  = tid >> 5;
    const int lane = tid & 31;
    const int g    = lane >> 2;
    const int t    = lane & 3;
    const int wm   = (wid & 1) << 6;
    const int wn   = (wid >> 1) << 5;
    const int bm   = blockIdx.y * TBM;
    const int bn   = blockIdx.x * TBN;
    const uint32_t sAsH = (uint32_t)__cvta_generic_to_shared(&AsH[0][0][0]);
    const uint32_t sWsH = (uint32_t)__cvta_generic_to_shared(&WsH[0][0][0]);
    const uint32_t sWsL = (uint32_t)__cvta_generic_to_shared(&WsL[0][0][0]);
    const uint32_t offA = (uint32_t)(((wm + (lane & 7) + ((lane >> 3) & 1) * 8)
                                      * TPAD + ((lane >> 4) << 2)) * 4);
    const uint32_t offB = (uint32_t)(((wn + ((lane >> 4) & 1) * 8 + (lane & 7))
                                      * TPAD + (((lane >> 3) & 1) << 2)) * 4);
    float acc[4][4][4] = {};

#define G2_LOAD(S, KP0)                                                             \
    {                                                                               \
        int r  = tid >> 1, ch = (tid & 1) << 2;                                     \
        int gp = (KP0) + ch;                                                        \
        bool pa = (gp < Kp) && (bm + r < M);                                        \
        cp16((uint32_t)__cvta_generic_to_shared(&AsH[S][r][ch]),                    \
             Ahi + (size_t)(bm + r) * Kp + gp, pa);                                 \
        bool pb = (gp < Kp);                                                        \
        cp16((uint32_t)__cvta_generic_to_shared(&WsH[S][r][ch]),                    \
             Whi + (size_t)(bn + r) * Kp + gp, pb);                                 \
        cp16((uint32_t)__cvta_generic_to_shared(&WsL[S][r][ch]),                    \
             Wlo + (size_t)(bn + r) * Kp + gp, pb);                                 \
    }

    G2_LOAD(0, 0);
    asm volatile("cp.async.commit_group;\n" ::: "memory");
    int buf = 0;
    for (int kp0 = 0; kp0 < Kp; kp0 += 8) {
        if (kp0 + 8 < Kp) G2_LOAD(buf ^ 1, kp0 + 8);
        asm volatile("cp.async.commit_group;\n" ::: "memory");
        asm volatile("cp.async.wait_group 1;\n" ::: "memory");
        __syncthreads();
        uint32_t bH[4][2], bL[4][2];
        uint32_t bs = (uint32_t)buf * STG_BYTES;
#pragma unroll
        for (int jj = 0; jj < 2; ++jj) {
            uint32_t bo = bs + offB + (uint32_t)(jj * 16 * TPAD * 4);
            uint32_t tH[4], tL[4];
            ldsm_x4(tH, sWsH + bo);
            ldsm_x4(tL, sWsL + bo);
            bH[2 * jj][0] = tH[0]; bH[2 * jj][1] = tH[1];
            bH[2 * jj + 1][0] = tH[2]; bH[2 * jj + 1][1] = tH[3];
            bL[2 * jj][0] = tL[0]; bL[2 * jj][1] = tL[1];
            bL[2 * jj + 1][0] = tL[2]; bL[2 * jj + 1][1] = tL[3];
        }
#pragma unroll
        for (int i = 0; i < 4; ++i) {
            uint32_t aH[4];
            ldsm_x4(aH, sAsH + bs + offA + (uint32_t)(i * 16 * TPAD * 4));
#pragma unroll
            for (int j = 0; j < 4; ++j) {
                mma_bf16(acc[i][j], aH, bL[j]);
                mma_bf16(acc[i][j], aH, bH[j]);
            }
        }
        __syncthreads();
        buf ^= 1;
    }
#undef G2_LOAD

    float* sSum = (float*)&AsH[0][0][0];
    float* sSq  = sSum + 128;
    if (EPI == 3) {
        __syncthreads();
        if (tid < 128) { sSum[tid] = 0.f; sSq[tid] = 0.f; }
        __syncthreads();
    }

#pragma unroll
    for (int j = 0; j < 4; ++j) {
        float cs0 = 0.f, cq0 = 0.f, cs1 = 0.f, cq1 = 0.f;
#pragma unroll
        for (int i = 0; i < 4; ++i) {
            int r0 = bm + wm + (i << 4) + g;
            int r1 = r0 + 8;
            int c0 = bn + wn + (j << 3) + (t << 1);
            float bx = bias[c0], by = bias[c0 + 1];
            float v0 = acc[i][j][0] + bx, v1 = acc[i][j][1] + by;
            float v2 = acc[i][j][2] + bx, v3 = acc[i][j][3] + by;
            int pc = c0 >> 1;
            if (r0 < M) {
                Chi[(size_t)r0 * (Nc / 2) + pc] = pack_hi(v0, v1);
                if (EPI == 3) { cs0 += v0; cq0 += v0 * v0; cs1 += v1; cq1 += v1 * v1; }
            }
            if (r1 < M) {
                Chi[(size_t)r1 * (Nc / 2) + pc] = pack_hi(v2, v3);
                if (EPI == 3) { cs0 += v2; cq0 += v2 * v2; cs1 += v3; cq1 += v3 * v3; }
            }
        }
        if (EPI == 3) {
            int lc = wn + (j << 3) + (t << 1);
            atomicAdd(&sSum[lc], cs0);     atomicAdd(&sSq[lc], cq0);
            atomicAdd(&sSum[lc + 1], cs1); atomicAdd(&sSq[lc + 1], cq1);
        }
    }
    if (EPI == 3) {
        __syncthreads();
        if (tid < 128) {
            atomicAdd(&stats[bn + tid], sSum[tid]);
            atomicAdd(&stats[PHH + bn + tid], sSq[tid]);
        }
    }
}

// attention GEMM: z hi-only x split W; epilogue tanh-att reduce to beta.
// blockIdx.z = view; beta index = (view+2)%3.
__global__ __launch_bounds__(256, 2)
void gemm_att_bf16_kernel(const uint32_t* __restrict__ Zhi,
                          const uint32_t* __restrict__ Whi, const uint32_t* __restrict__ Wlo,
                          const float* __restrict__ bias, const float* __restrict__ att,
                          float* __restrict__ beta_raw, int M, int Kp)
{
    __shared__ __align__(16) uint32_t AsH[2][TBM][TPAD];
    __shared__ __align__(16) uint32_t WsH[2][TBN][TPAD];
    __shared__ __align__(16) uint32_t WsL[2][TBN][TPAD];
    const int tid  = threadIdx.x;
    const int wid  = tid >> 5;
    const int lane = tid & 31;
    const int g    = lane >> 2;
    const int t    = lane & 3;
    const int wm   = (wid & 1) << 6;
    const int wn   = (wid >> 1) << 5;
    const int bm   = blockIdx.y * TBM;
    const int bn   = blockIdx.x * TBN;
    const int view = blockIdx.z;
    const uint32_t* Ahi = Zhi + (size_t)view * NN * (HH / 2);
    const uint32_t sAsH = (uint32_t)__cvta_generic_to_shared(&AsH[0][0][0]);
    const uint32_t sWsH = (uint32_t)__cvta_generic_to_shared(&WsH[0][0][0]);
    const uint32_t sWsL = (uint32_t)__cvta_generic_to_shared(&WsL[0][0][0]);
    const uint32_t offA = (uint32_t)(((wm + (lane & 7) + ((lane >> 3) & 1) * 8)
                                      * TPAD + ((lane >> 4) << 2)) * 4);
    const uint32_t offB = (uint32_t)(((wn + ((lane >> 4) & 1) * 8 + (lane & 7))
                                      * TPAD + (((lane >> 3) & 1) << 2)) * 4);
    float acc[4][4][4] = {};

#define GA_LOAD(S, KP0)                                                             \
    {                                                                               \
        int r  = tid >> 1, ch = (tid & 1) << 2;                                     \
        int gp = (KP0) + ch;                                                        \
        bool pa = (gp < Kp) && (bm + r < M);                                        \
        cp16((uint32_t)__cvta_generic_to_shared(&AsH[S][r][ch]),                    \
             Ahi + (size_t)(bm + r) * Kp + gp, pa);                                 \
        bool pb = (gp < Kp);                                                        \
        cp16((uint32_t)__cvta_generic_to_shared(&WsH[S][r][ch]),                    \
             Whi + (size_t)(bn + r) * Kp + gp, pb);                                 \
        cp16((uint32_t)__cvta_generic_to_shared(&WsL[S][r][ch]),                    \
             Wlo + (size_t)(bn + r) * Kp + gp, pb);                                 \
    }

    GA_LOAD(0, 0);
    asm volatile("cp.async.commit_group;\n" ::: "memory");
    int buf = 0;
    for (int kp0 = 0; kp0 < Kp; kp0 += 8) {
        if (kp0 + 8 < Kp) GA_LOAD(buf ^ 1, kp0 + 8);
        asm volatile("cp.async.commit_group;\n" ::: "memory");
        asm volatile("cp.async.wait_group 1;\n" ::: "memory");
        __syncthreads();
        uint32_t bH[4][2], bL[4][2];
        uint32_t bs = (uint32_t)buf * STG_BYTES;
#pragma unroll
        for (int jj = 0; jj < 2; ++jj) {
            uint32_t bo = bs + offB + (uint32_t)(jj * 16 * TPAD * 4);
            uint32_t tH[4], tL[4];
            ldsm_x4(tH, sWsH + bo);
            ldsm_x4(tL, sWsL + bo);
            bH[2 * jj][0] = tH[0]; bH[2 * jj][1] = tH[1];
            bH[2 * jj + 1][0] = tH[2]; bH[2 * jj + 1][1] = tH[3];
            bL[2 * jj][0] = tL[0]; bL[2 * jj][1] = tL[1];
            bL[2 * jj + 1][0] = tL[2]; bL[2 * jj + 1][1] = tL[3];
        }
#pragma unroll
        for (int i = 0; i < 4; ++i) {
            uint32_t aH[4];
            ldsm_x4(aH, sAsH + bs + offA + (uint32_t)(i * 16 * TPAD * 4));
#pragma unroll
            for (int j = 0; j < 4; ++j) {
                mma_bf16(acc[i][j], aH, bL[j]);
                mma_bf16(acc[i][j], aH, bH[j]);
            }
        }
        __syncthreads();
        buf ^= 1;
    }
#undef GA_LOAD

    float s = 0.f;
#pragma unroll
    for (int i = 0; i < 4; ++i) {
#pragma unroll
        for (int j = 0; j < 4; ++j) {
            int r0 = bm + wm + (i << 4) + g;
            int r1 = r0 + 8;
            int c0 = bn + wn + (j << 3) + (t << 1);
            float bx = bias[c0], by = bias[c0 + 1];
            float ax = att[c0],  ay = att[c0 + 1];
            if (r0 < M) s += tanhf(acc[i][j][0] + bx) * ax + tanhf(acc[i][j][1] + by) * ay;
            if (r1 < M) s += tanhf(acc[i][j][2] + bx) * ax + tanhf(acc[i][j][3] + by) * ay;
        }
    }
    float* red = (float*)&AsH[0][0][0];
    __syncthreads();
    red[tid] = s;
    __syncthreads();
    for (int o = 128; o > 0; o >>= 1) {
        if (tid < o) red[tid] += red[tid + o];
        __syncthreads();
    }
    if (tid == 0) {
        int bidx = (view + 2) % 3;
        atomicAdd(&beta_raw[bidx], red[0]);
    }
}

// ---------------- BN + PReLU on hi-only bf16 x (in place) -----------------------
__global__ __launch_bounds__(256)
void bn_prelu_hi_kernel(uint32_t* __restrict__ xhi, const float* __restrict__ stats,
                        const float* __restrict__ g, const float* __restrict__ b,
                        const float* __restrict__ a_ptr)
{
    int i = blockIdx.x * blockDim.x + threadIdx.x;
    if (i >= NN * (PHH / 4)) return;
    int c = (i & (PHH / 4 - 1)) << 2;
    float a = *a_ptr;
    float4 sm = *(const float4*)(stats + c);
    float4 sq = *(const float4*)(stats + PHH + c);
    float4 gv = *(const float4*)(g + c);
    float4 bv = *(const float4*)(b + c);
    uint2 h = ((const uint2*)xhi)[i];
    float4 v;
    unpack2_hi(h.x, v.x, v.y);
    unpack2_hi(h.y, v.z, v.w);
    float invN = 1.f / (float)NN;

    float mu, var, sc, sh, y;
    mu = sm.x * invN; var = sq.x * invN - mu * mu; sc = gv.x * rsqrtf(var + BN_EPS);
    sh = bv.x - mu * sc; y = v.x * sc + sh; v.x = y >= 0.f ? y : a * y;
    mu = sm.y * invN; var = sq.y * invN - mu * mu; sc = gv.y * rsqrtf(var + BN_EPS);
    sh = bv.y - mu * sc; y = v.y * sc + sh; v.y = y >= 0.f ? y : a * y;
    mu = sm.z * invN; var = sq.z * invN - mu * mu; sc = gv.z * rsqrtf(var + BN_EPS);
    sh = bv.z - mu * sc; y = v.z * sc + sh; v.z = y >= 0.f ? y : a * y;
    mu = sm.w * invN; var = sq.w * invN - mu * mu; sc = gv.w * rsqrtf(var + BN_EPS);
    sh = bv.w - mu * sc; y = v.w * sc + sh; v.w = y >= 0.f ? y : a * y;

    uint2 nh;
    nh.x = pack_hi(v.x, v.y);
    nh.y = pack_hi(v.z, v.w);
    ((uint2*)xhi)[i] = nh;
}

// ---------------- cosine loss (hi-only bf16 inputs) ------------------------------
__global__ __launch_bounds__(256)
void loss_kernel(const uint32_t* __restrict__ vph, const uint32_t* __restrict__ zh,
                 float* __restrict__ acc)
{
    const uint32_t* t1h = zh + (size_t)NN * (HH / 2);
    const uint32_t* t2h = zh + (size_t)2 * NN * (HH / 2);
    int gid  = blockIdx.x * blockDim.x + threadIdx.x;
    int node = gid >> 5;
    int lane = gid & 31;
    float pp = 0.f, n1 = 0.f, n2 = 0.f, d1 = 0.f, d2 = 0.f;
    if (node < NN) {
        size_t baseu = (size_t)node * 128;
#pragma unroll
        for (int r = 0; r < 2; ++r) {
            int q = lane + 32 * r;
            uint2 hp = *(const uint2*)&vph[baseu + 2 * q];
            uint2 h1 = *(const uint2*)&t1h[baseu + 2 * q];
            uint2 h2 = *(const uint2*)&t2h[baseu + 2 * q];
            float4 a, b, cc;
            unpack2_hi(hp.x, a.x, a.y);  unpack2_hi(hp.y, a.z, a.w);
            unpack2_hi(h1.x, b.x, b.y);  unpack2_hi(h1.y, b.z, b.w);
            unpack2_hi(h2.x, cc.x, cc.y); unpack2_hi(h2.y, cc.z, cc.w);
            pp += a.x * a.x + a.y * a.y + a.z * a.z + a.w * a.w;
            n1 += b.x * b.x + b.y * b.y + b.z * b.z + b.w * b.w;
            n2 += cc.x * cc.x + cc.y * cc.y + cc.z * cc.z + cc.w * cc.w;
            d1 += a.x * b.x + a.y * b.y + a.z * b.z + a.w * b.w;
            d2 += a.x * cc.x + a.y * cc.y + a.z * cc.z + a.w * cc.w;
        }
    }
#pragma unroll
    for (int o = 16; o > 0; o >>= 1) {
        pp += __shfl_down_sync(0xffffffffu, pp, o);
        n1 += __shfl_down_sync(0xffffffffu, n1, o);
        n2 += __shfl_down_sync(0xffffffffu, n2, o);
        d1 += __shfl_down_sync(0xffffffffu, d1, o);
        d2 += __shfl_down_sync(0xffffffffu, d2, o);
    }
    __shared__ float sacc[8];
    float contrib = 0.f;
    if (lane == 0 && node < NN) {
        float np  = fmaxf(sqrtf(pp), 1e-12f);
        float nn1 = fmaxf(sqrtf(n1), 1e-12f);
        float nn2 = fmaxf(sqrtf(n2), 1e-12f);
        contrib = d1 / (np * nn1) + d2 / (np * nn2);
    }
    int wid = threadIdx.x >> 5;
    if (lane == 0) sacc[wid] = contrib;
    __syncthreads();
    if (threadIdx.x == 0) {
        float s = 0.f;
#pragma unroll
        for (int i = 0; i < 8; ++i) s += sacc[i];
        atomicAdd(acc, s);
    }
}

// ---------------- finalize beta only (softmax) -----------------------------------
__global__ void finalize_beta_kernel()
{
    float invN = 1.f / (float)NN;
    float b0 = g_beta_raw[0] * invN;
    float b1 = g_beta_raw[1] * invN;
    float b2 = g_beta_raw[2] * invN;
    float m = fmaxf(b0, fmaxf(b1, b2));
    float e0 = expf(b0 - m), e1 = expf(b1 - m), e2 = expf(b2 - m);
    float s = e0 + e1 + e2;
    g_beta[0] = e0 / s;
    g_beta[1] = e1 / s;
    g_beta[2] = e2 / s;
}

// ---------------- write loss scalar ----------------------------------------------
__global__ void write_loss_kernel(float* __restrict__ out_loss, int write_loss)
{
    if (write_loss) *out_loss = 2.0f - g_loss_acc / (float)NN;
}

// ---------------- z_out = b0*z1 + b1*z2 + b2*z0 (from split-bf16) ----------------
__global__ __launch_bounds__(256)
void zout_kernel(float4* __restrict__ out, const uint32_t* __restrict__ zh,
                 const uint32_t* __restrict__ zl)
{
    int i = blockIdx.x * blockDim.x + threadIdx.x;
    if (i >= NN * 64) return;
    float b2 = g_beta[2], b0 = g_beta[0], b1 = g_beta[1];
    const size_t vstride = (size_t)NN * (HH / 2);
    size_t u = (size_t)i * 2;
    uint2 h0 = *(const uint2*)&zh[u];
    uint2 l0 = *(const uint2*)&zl[u];
    uint2 h1 = *(const uint2*)&zh[vstride + u];
    uint2 l1 = *(const uint2*)&zl[vstride + u];
    uint2 h2 = *(const uint2*)&zh[2 * vstride + u];
    uint2 l2 = *(const uint2*)&zl[2 * vstride + u];
    float4 a, b, c;
    unpack2(h0.x, l0.x, c.x, c.y); unpack2(h0.y, l0.y, c.z, c.w);
    unpack2(h1.x, l1.x, a.x, a.y); unpack2(h1.y, l1.y, a.z, a.w);
    unpack2(h2.x, l2.x, b.x, b.y); unpack2(h2.y, l2.y, b.z, b.w);
    float4 r;
    r.x = b0 * a.x + b1 * b.x + b2 * c.x;
    r.y = b0 * a.y + b1 * b.y + b2 * c.y;
    r.z = b0 * a.z + b1 * b.z + b2 * c.z;
    r.w = b0 * a.w + b1 * b.w + b2 * c.w;
    out[i] = r;
}

// ---------------- host ----------------------------------------------------------
#define GETSYM(var, sym) cudaGetSymbolAddress((void**)&var, sym)

extern "C" void kernel_launch(void* const* d_in, const int* in_sizes, int n_in,
                              void* d_out, int out_size)
{
    const float* feats   = (const float*)d_in[0];
    const int*   src     = (const int*)  d_in[1];
    const int*   dst     = (const int*)  d_in[2];
    const float* vals    = (const float*)d_in[3];
    const float* W_trans = (const float*)d_in[4];
    const float* b_trans = (const float*)d_in[5];
    const float* W_gcn   = (const float*)d_in[6];
    const float* b_gcn   = (const float*)d_in[7];
    const float* a_gcn   = (const float*)d_in[8];
    const float* W1      = (const float*)d_in[9];
    const float* b1      = (const float*)d_in[10];
    const float* bn_g    = (const float*)d_in[11];
    const float* bn_b    = (const float*)d_in[12];
    const float* a_pred  = (const float*)d_in[13];
    const float* W2      = (const float*)d_in[14];
    const float* b2      = (const float*)d_in[15];
    const float* W_att   = (const float*)d_in[16];
    const float* b_att   = (const float*)d_in[17];
    const float* att     = (const float*)d_in[18];

    uint32_t *h_hi, *h_lo, *zh, *zl;
    uint32_t *x_hi, *vp_hi, *wt_hi, *wt_lo, *wg_hi, *wg_lo, *w1_hi, *w1_lo;
    uint32_t *w2_hi, *w2_lo, *wa_hi, *wa_lo;
    float *ft, *stats, *beta_raw, *loss_acc;
    int *deg, *rowptr, *cursor, *esrc;
    float *eval_;
    GETSYM(h_hi, g_h_hi);   GETSYM(h_lo, g_h_lo);
    GETSYM(zh, g_z_hi); GETSYM(zl, g_z_lo);
    GETSYM(x_hi, g_x_hi); GETSYM(vp_hi, g_vp_hi);
    GETSYM(wt_hi, g_wt_hi); GETSYM(wt_lo, g_wt_lo);
    GETSYM(wg_hi, g_wg_hi); GETSYM(wg_lo, g_wg_lo);
    GETSYM(w1_hi, g_w1_hi); GETSYM(w1_lo, g_w1_lo);
    GETSYM(w2_hi, g_w2_hi); GETSYM(w2_lo, g_w2_lo);
    GETSYM(wa_hi, g_wa_hi); GETSYM(wa_lo, g_wa_lo);
    GETSYM(ft, g_ft);
    GETSYM(stats, g_stats); GETSYM(beta_raw, g_beta_raw); GETSYM(loss_acc, g_loss_acc);
    GETSYM(deg, g_deg); GETSYM(rowptr, g_rowptr); GETSYM(cursor, g_cursor);
    GETSYM(esrc, g_esrc); GETSYM(eval_, g_eval);

    cudaStream_t s2;
    cudaStreamCreateWithFlags(&s2, cudaStreamNonBlocking);
    cudaEvent_t eFork, eSplit, eG[3], eS0, eVp, eAtt, eLoss;
    cudaEventCreateWithFlags(&eFork,  cudaEventDisableTiming);
    cudaEventCreateWithFlags(&eSplit, cudaEventDisableTiming);
    for (int v = 0; v < 3; ++v) cudaEventCreateWithFlags(&eG[v], cudaEventDisableTiming);
    cudaEventCreateWithFlags(&eS0,   cudaEventDisableTiming);
    cudaEventCreateWithFlags(&eVp,   cudaEventDisableTiming);
    cudaEventCreateWithFlags(&eAtt,  cudaEventDisableTiming);
    cudaEventCreateWithFlags(&eLoss, cudaEventDisableTiming);

    cudaMemsetAsync(deg, 0, 3 * NN * sizeof(int));
    cudaMemsetAsync(stats, 0, 2 * PHH * sizeof(float));
    cudaMemsetAsync(beta_raw, 0, 3 * sizeof(float));
    cudaMemsetAsync(loss_acc, 0, sizeof(float));

    // fork: CSR build on s2, concurrent with splits + feats GEMM
    cudaEventRecord(eFork, 0);
    cudaStreamWaitEvent(s2, eFork, 0);
    hist_kernel<<<(3 * EE + 255) / 256, 256, 0, s2>>>(dst, deg);
    scan_kernel<<<3, 1024, 0, s2>>>(deg, rowptr, cursor);
    scatter_kernel<<<(3 * EE + 255) / 256, 256, 0, s2>>>(src, dst, vals, cursor,
                                                         esrc, eval_);

    // main: weight splits
    {
        size_t np = (size_t)HH * (FEATD / 2);
        split_kernel<<<(int)((np + 255) / 256), 256>>>((const float2*)W_trans, wt_hi, wt_lo, np);
        np = (size_t)3 * HH * (HH / 2);
        split_kernel<<<(int)((np + 255) / 256), 256>>>((const float2*)W_gcn, wg_hi, wg_lo, np);
        np = (size_t)PHH * (HH / 2);
        split_kernel<<<(int)((np + 255) / 256), 256>>>((const float2*)W1, w1_hi, w1_lo, np);
        np = (size_t)HH * (PHH / 2);
        split_kernel<<<(int)((np + 255) / 256), 256>>>((const float2*)W2, w2_hi, w2_lo, np);
        np = (size_t)HH * (HH / 2);
        split_kernel<<<(int)((np + 255) / 256), 256>>>((const float2*)W_att, wa_hi, wa_lo, np);
    }
    cudaEventRecord(eSplit, 0);

    const int mb = (NN + TBM - 1) / TBM;   // 391

    // main: h = elu(feats @ W_trans^T + b_trans)
    gemm_bf16s_af32_kernel<<<dim3(HH / TBN, mb), 256>>>(
        feats, wt_hi, wt_lo, b_trans, h_hi, h_lo, NN, HH, FEATD / 2);

    // main: per-view GCN GEMMs
    for (int v = 0; v < PP; ++v) {
        gemm_bf16s_kernel<<<dim3(HH / TBN, mb), 256>>>(
            h_hi, h_lo,
            wg_hi + (size_t)v * HH * (HH / 2), wg_lo + (size_t)v * HH * (HH / 2),
            ft + (size_t)v * NN * HH, NN, HH, HH / 2);
        cudaEventRecord(eG[v], 0);
    }

    // s2: SpMM(v) as soon as GEMM(v) done
    for (int v = 0; v < PP; ++v) {
        cudaStreamWaitEvent(s2, eG[v], 0);
        spmm_csr_kernel<<<(NN * 64 + 255) / 256, 256, 0, s2>>>(
            (const float4*)(ft + (size_t)v * NN * HH),
            rowptr + v * (NN + 1),
            esrc + (size_t)v * EE, eval_ + (size_t)v * EE,
            zh + (size_t)v * NN * (HH / 2), zl + (size_t)v * NN * (HH / 2),
            b_gcn + (size_t)v * HH, a_gcn + v);
        if (v == 0) cudaEventRecord(eS0, s2);
    }

    // s2: attention GEMM after all z ready
    cudaStreamWaitEvent(s2, eSplit, 0);
    gemm_att_bf16_kernel<<<dim3(HH / TBN, mb, 3), 256, 0, s2>>>(
        zh, wa_hi, wa_lo, b_att, att, beta_raw, NN, HH / 2);
    cudaEventRecord(eAtt, s2);

    // main: predictor chain (2-term, loss-only precision)
    cudaStreamWaitEvent(0, eS0, 0);
    gemm2_bf16_kernel<3><<<dim3(PHH / TBN, mb), 256>>>(
        zh, w1_hi, w1_lo, b1, x_hi, stats, NN, PHH, HH / 2);
    bn_prelu_hi_kernel<<<(NN * PHH / 4) / 256, 256>>>(x_hi, stats, bn_g, bn_b, a_pred);
    gemm2_bf16_kernel<4><<<dim3(HH / TBN, mb), 256>>>(
        x_hi, w2_hi, w2_lo, b2, vp_hi, nullptr, NN, HH, PHH / 2);
    cudaEventRecord(eVp, 0);

    float* outf = (float*)d_out;
    int write_loss = (out_size > NN * HH) ? 1 : 0;

    // s2: loss chain (off the output critical path); z1/z2 already on s2 order
    cudaStreamWaitEvent(s2, eVp, 0);
    loss_kernel<<<(NN * 32) / 256, 256, 0, s2>>>(vp_hi, zh, loss_acc);
    write_loss_kernel<<<1, 1, 0, s2>>>(outf + (size_t)NN * HH, write_loss);
    cudaEventRecord(eLoss, s2);

    // main: beta softmax (needs att only) then z_out; join loss at the end
    cudaStreamWaitEvent(0, eAtt, 0);
    finalize_beta_kernel<<<1, 1>>>();
    zout_kernel<<<(NN * 64) / 256, 256>>>((float4*)outf, zh, zl);
    cudaStreamWaitEvent(0, eLoss, 0);
}